// round 1
// baseline (speedup 1.0000x reference)
#include <cuda_runtime.h>
#include <math.h>

#define T_ 8
#define N_ 10000
#define E_ 320000
#define F_ 128
#define D1_ 128
#define D2_ 64
#define H_ 4
#define NCOM_ 100
#define DR_ 128
#define DD_ 64

// ------------------------- device scratch -------------------------
__device__ int   g_is64;
__device__ float g_h1[(size_t)T_ * N_ * D1_];        // 41MB
__device__ float g_g1[(size_t)T_ * N_ * D1_];        // 41MB
__device__ float g_h2[(size_t)T_ * N_ * D2_];        // 20MB
__device__ float g_agg[(size_t)T_ * N_ * 128];       // 41MB  [g2 | meso]
__device__ float g_as[T_ * N_ * H_];
__device__ float g_ad[T_ * N_ * H_];
__device__ float g_m[T_ * N_ * H_];
__device__ float g_den[T_ * N_ * H_];
__device__ float g_ex[(size_t)T_ * E_ * H_];         // 41MB
__device__ int   g_cnt[T_ * N_];
__device__ int   g_rowptr[T_ * (N_ + 1)];
__device__ int   g_cursor[T_ * N_];
__device__ int   g_sorted[T_ * E_];                  // 10MB
__device__ float g_comnum[T_ * NCOM_ * D2_];
__device__ float g_comden[T_ * NCOM_];
__device__ float g_Zx[(size_t)T_ * N_ * 512];        // 164MB
__device__ float g_hbuf[N_ * DR_];
__device__ float g_cbuf[N_ * DR_];
__device__ float g_embp[N_ * DD_];
__device__ float g_scalp[N_ * DD_];
__device__ float g_P[N_ * 128];                      // [emb | scal]
__device__ float g_sq[N_];
__device__ float g_colsq[DD_];

// ------------------------- helpers -------------------------
__device__ __forceinline__ long long ld_idx(const void* p, size_t i) {
    if (g_is64) return ((const long long*)p)[i];
    return (long long)((const int*)p)[i];
}

__device__ __forceinline__ void atomicMaxF(float* addr, float v) {
    if (v >= 0.f) atomicMax((int*)addr, __float_as_int(v));
    else          atomicMin((unsigned int*)addr, __float_as_uint(v));
}

__device__ __forceinline__ float sigf(float x) { return 1.f / (1.f + expf(-x)); }

// detect int64 vs int32 indices: int64 values < 2^31 have zero high words.
__global__ void detect64_kernel(const int* ei32) {
    int ok = 1;
    for (int i = 1; i < 64; i += 2)
        if (ei32[i] != 0) ok = 0;
    g_is64 = ok;
}

__global__ void fill_f(float* p, float v, int n) {
    int i = blockIdx.x * blockDim.x + threadIdx.x;
    if (i < n) p[i] = v;
}
__global__ void fill_i(int* p, int v, int n) {
    int i = blockIdx.x * blockDim.x + threadIdx.x;
    if (i < n) p[i] = v;
}

// ------------------------- GEMM (K = 128 fixed) -------------------------
// C[M x Dn] = A[M x 128] @ B[128 x Dn]  (optionally +=), batched over z.
// BM=BN=64, 128 threads, thread tile 4x8, full K in smem.
#define GEMM_SMEM ((64 * 132 + 128 * 68) * 4)
__global__ __launch_bounds__(128) void gemm128(
    const float* __restrict__ A, const float* __restrict__ B,
    float* __restrict__ C, int M, int Dn,
    long long sA, long long sC, int accumulate)
{
    extern __shared__ float smem[];
    float* As = smem;             // [64][132]
    float* Bs = smem + 64 * 132;  // [128][68]

    int t = blockIdx.z;
    A += (size_t)t * sA;
    C += (size_t)t * sC;
    int m0 = blockIdx.x * 64;
    int n0 = blockIdx.y * 64;
    int tid = threadIdx.x;

    // A tile: 64 rows x 128 cols = 2048 float4
#pragma unroll
    for (int i = 0; i < 16; i++) {
        int f = tid + i * 128;
        int row = f >> 5, k4 = f & 31;
        float4 v = make_float4(0.f, 0.f, 0.f, 0.f);
        if (m0 + row < M) v = ((const float4*)A)[(size_t)(m0 + row) * 32 + k4];
        *((float4*)&As[row * 132 + k4 * 4]) = v;
    }
    // B tile: 128 rows x 64 cols
    int dn4 = Dn >> 2;
#pragma unroll
    for (int i = 0; i < 16; i++) {
        int f = tid + i * 128;
        int row = f >> 4, c4 = f & 15;
        float4 v = ((const float4*)B)[(size_t)row * dn4 + (n0 >> 2) + c4];
        *((float4*)&Bs[row * 68 + c4 * 4]) = v;
    }
    __syncthreads();

    int ty = tid >> 3, tx = tid & 7;
    float acc[4][8];
#pragma unroll
    for (int r = 0; r < 4; r++)
#pragma unroll
        for (int c = 0; c < 8; c++) acc[r][c] = 0.f;

#pragma unroll 4
    for (int k4 = 0; k4 < 32; k4++) {
        float av[4][4], bv[4][8];
#pragma unroll
        for (int r = 0; r < 4; r++) {
            float4 a = *((float4*)&As[(ty * 4 + r) * 132 + k4 * 4]);
            av[r][0] = a.x; av[r][1] = a.y; av[r][2] = a.z; av[r][3] = a.w;
        }
#pragma unroll
        for (int kk = 0; kk < 4; kk++) {
            float4 b0 = *((float4*)&Bs[(k4 * 4 + kk) * 68 + tx * 8]);
            float4 b1 = *((float4*)&Bs[(k4 * 4 + kk) * 68 + tx * 8 + 4]);
            bv[kk][0] = b0.x; bv[kk][1] = b0.y; bv[kk][2] = b0.z; bv[kk][3] = b0.w;
            bv[kk][4] = b1.x; bv[kk][5] = b1.y; bv[kk][6] = b1.z; bv[kk][7] = b1.w;
        }
#pragma unroll
        for (int kk = 0; kk < 4; kk++)
#pragma unroll
            for (int r = 0; r < 4; r++)
#pragma unroll
                for (int c = 0; c < 8; c++)
                    acc[r][c] += av[r][kk] * bv[kk][c];
    }

#pragma unroll
    for (int r = 0; r < 4; r++) {
        int row = m0 + ty * 4 + r;
        if (row < M) {
#pragma unroll
            for (int c = 0; c < 8; c++) {
                size_t idx = (size_t)row * Dn + n0 + tx * 8 + c;
                C[idx] = accumulate ? (C[idx] + acc[r][c]) : acc[r][c];
            }
        }
    }
}

// ------------------------- GAT kernels -------------------------
__global__ void alpha_kernel(const float* __restrict__ h,
                             const float* __restrict__ a_s,
                             const float* __restrict__ a_d, int dh) {
    int idx = blockIdx.x * blockDim.x + threadIdx.x;
    if (idx >= T_ * N_ * H_) return;
    int hh = idx & 3;
    int tn = idx >> 2;
    const float* hr = h + (size_t)tn * (H_ * dh) + hh * dh;
    float s = 0.f, d = 0.f;
    for (int k = 0; k < dh; k++) {
        float v = hr[k];
        s += v * a_s[hh * dh + k];
        d += v * a_d[hh * dh + k];
    }
    g_as[idx] = s;
    g_ad[idx] = d;
}

__global__ void csr_count(const void* ei) {
    int idx = blockIdx.x * blockDim.x + threadIdx.x;
    if (idx >= T_ * E_) return;
    int t = idx / E_, e = idx - t * E_;
    int dst = (int)ld_idx(ei, (size_t)t * 2 * E_ + E_ + e);
    atomicAdd(&g_cnt[t * N_ + dst], 1);
}

__global__ void csr_scan() {
    int t = blockIdx.x;
    int tid = threadIdx.x;
    __shared__ int sh[1024];
    int off = 0;
    for (int chunk = 0; chunk < N_; chunk += 1024) {
        int i = chunk + tid;
        int v = (i < N_) ? g_cnt[t * N_ + i] : 0;
        sh[tid] = v;
        __syncthreads();
        for (int d2 = 1; d2 < 1024; d2 <<= 1) {
            int x = 0;
            if (tid >= d2) x = sh[tid - d2];
            __syncthreads();
            sh[tid] += x;
            __syncthreads();
        }
        if (i < N_) g_rowptr[t * (N_ + 1) + i] = off + sh[tid] - v;
        int tot = sh[1023];
        __syncthreads();
        off += tot;
    }
    if (tid == 0) g_rowptr[t * (N_ + 1) + N_] = off;
}

__global__ void csr_scatter(const void* ei) {
    int idx = blockIdx.x * blockDim.x + threadIdx.x;
    if (idx >= T_ * E_) return;
    int t = idx / E_, e = idx - t * E_;
    int dst = (int)ld_idx(ei, (size_t)t * 2 * E_ + E_ + e);
    int pos = atomicAdd(&g_cursor[t * N_ + dst], 1);
    g_sorted[t * E_ + g_rowptr[t * (N_ + 1) + dst] + pos] = e;
}

__global__ void edge_max(const void* ei) {
    int idx = blockIdx.x * blockDim.x + threadIdx.x;
    if (idx >= T_ * E_) return;
    int t = idx / E_, e = idx - t * E_;
    int src = (int)ld_idx(ei, (size_t)t * 2 * E_ + e);
    int dst = (int)ld_idx(ei, (size_t)t * 2 * E_ + E_ + e);
    float4 s4 = *(const float4*)&g_as[(t * N_ + src) * 4];
    float4 d4 = *(const float4*)&g_ad[(t * N_ + dst) * 4];
    float ev[4] = {s4.x + d4.x, s4.y + d4.y, s4.z + d4.z, s4.w + d4.w};
#pragma unroll
    for (int h = 0; h < 4; h++) {
        float v = ev[h] > 0.f ? ev[h] : 0.2f * ev[h];
        atomicMaxF(&g_m[(t * N_ + dst) * 4 + h], v);
    }
}

__global__ void edge_ex(const void* ei, const float* __restrict__ ew) {
    int idx = blockIdx.x * blockDim.x + threadIdx.x;
    if (idx >= T_ * E_) return;
    int t = idx / E_, e = idx - t * E_;
    int src = (int)ld_idx(ei, (size_t)t * 2 * E_ + e);
    int dst = (int)ld_idx(ei, (size_t)t * 2 * E_ + E_ + e);
    float4 s4 = *(const float4*)&g_as[(t * N_ + src) * 4];
    float4 d4 = *(const float4*)&g_ad[(t * N_ + dst) * 4];
    float4 m4 = *(const float4*)&g_m[(t * N_ + dst) * 4];
    float w = ew[(size_t)t * E_ + e];
    float ev[4] = {s4.x + d4.x, s4.y + d4.y, s4.z + d4.z, s4.w + d4.w};
    float mv[4] = {m4.x, m4.y, m4.z, m4.w};
    float xo[4];
#pragma unroll
    for (int h = 0; h < 4; h++) {
        float v = ev[h] > 0.f ? ev[h] : 0.2f * ev[h];
        float x = expf(v - mv[h]) * w;
        xo[h] = x;
        atomicAdd(&g_den[(t * N_ + dst) * 4 + h], x);
    }
    *(float4*)&g_ex[((size_t)t * E_ + e) * 4] = make_float4(xo[0], xo[1], xo[2], xo[3]);
}

template <int D, int DH>
__global__ void gat_gather(const void* ei, const float* __restrict__ hsrc,
                           float* __restrict__ out, int outStride) {
    int t = blockIdx.y, n = blockIdx.x, tid = threadIdx.x;
    int start = g_rowptr[t * (N_ + 1) + n];
    int end = g_rowptr[t * (N_ + 1) + n + 1];
    int head = tid / DH;
    __shared__ int s_src[64];
    __shared__ float s_ex[64][4];
    float acc = 0.f;
    for (int base = start; base < end; base += 64) {
        int cnt = min(64, end - base);
        __syncthreads();
        for (int i = tid; i < cnt; i += D) {
            int eid = g_sorted[t * E_ + base + i];
            s_src[i] = (int)ld_idx(ei, (size_t)t * 2 * E_ + eid);
            float4 x = *(const float4*)&g_ex[((size_t)t * E_ + eid) * 4];
            s_ex[i][0] = x.x; s_ex[i][1] = x.y; s_ex[i][2] = x.z; s_ex[i][3] = x.w;
        }
        __syncthreads();
#pragma unroll 4
        for (int i = 0; i < cnt; i++) {
            acc += s_ex[i][head] * hsrc[((size_t)t * N_ + s_src[i]) * D + tid];
        }
    }
    float dn = g_den[(t * N_ + n) * 4 + head];
    float v = acc / (dn + 1e-16f);
    v = v > 0.f ? v : expf(v) - 1.f;
    out[((size_t)t * N_ + n) * outStride + tid] = v;
}

// ------------------------- meso -------------------------
#define MCHUNK 500
__global__ void meso_acc(const void* part, const float* __restrict__ Dw) {
    int t = blockIdx.y;
    int c0 = blockIdx.x * MCHUNK;
    int tid = threadIdx.x;
    __shared__ float sn[NCOM_ * D2_];
    __shared__ float sd[NCOM_];
    __shared__ int sp[MCHUNK];
    __shared__ float sD[MCHUNK];
    for (int i = tid; i < NCOM_ * D2_; i += blockDim.x) sn[i] = 0.f;
    for (int i = tid; i < NCOM_; i += blockDim.x) sd[i] = 0.f;
    int nmax = min(MCHUNK, N_ - c0);
    for (int i = tid; i < nmax; i += blockDim.x) {
        sp[i] = (int)ld_idx(part, (size_t)t * N_ + c0 + i);
        sD[i] = Dw[(size_t)t * N_ + c0 + i];
    }
    __syncthreads();
    for (int idx = tid; idx < nmax * 64; idx += blockDim.x) {
        int nl = idx >> 6, c = idx & 63;
        float g = g_agg[((size_t)t * N_ + c0 + nl) * 128 + c];
        atomicAdd(&sn[sp[nl] * 64 + c], sD[nl] * g);
        if (c == 0) atomicAdd(&sd[sp[nl]], sD[nl]);
    }
    __syncthreads();
    for (int i = tid; i < NCOM_ * 64; i += blockDim.x)
        atomicAdd(&g_comnum[t * NCOM_ * 64 + i], sn[i]);
    for (int i = tid; i < NCOM_; i += blockDim.x)
        atomicAdd(&g_comden[t * NCOM_ + i], sd[i]);
}

__global__ void meso_scatter(const void* part) {
    int idx = blockIdx.x * blockDim.x + threadIdx.x;
    if (idx >= T_ * N_ * 64) return;
    int t = idx / (N_ * 64);
    int r = idx - t * N_ * 64;
    int n = r >> 6, c = r & 63;
    int p = (int)ld_idx(part, (size_t)t * N_ + n);
    float mean = g_comnum[(t * NCOM_ + p) * 64 + c] / (g_comden[t * NCOM_ + p] + 1e-16f);
    g_agg[((size_t)t * N_ + n) * 128 + 64 + c] = mean;
}

// ------------------------- LSTM -------------------------
__global__ void lstm_pw(const float* __restrict__ b, int t) {
    int idx = blockIdx.x * blockDim.x + threadIdx.x;
    if (idx >= N_ * 128) return;
    int n = idx >> 7, j = idx & 127;
    const float* z = g_Zx + (size_t)t * N_ * 512 + (size_t)n * 512;
    float i_ = z[j] + b[j];
    float f_ = z[128 + j] + b[128 + j];
    float gg = z[256 + j] + b[256 + j];
    float o_ = z[384 + j] + b[384 + j];
    float c = sigf(f_) * g_cbuf[idx] + sigf(i_) * tanhf(gg);
    float h = sigf(o_) * tanhf(c);
    g_cbuf[idx] = c;
    g_hbuf[idx] = h;
}

// ------------------------- decoder -------------------------
__global__ void emb_tanh(const float* __restrict__ emb_b) {
    __shared__ float s[64];
    int tid = threadIdx.x;
    if (tid < 64) s[tid] = 0.f;
    __syncthreads();
    int idx = blockIdx.x * 256 + tid;
    if (idx < N_ * 64) {
        int c = idx & 63;
        float v = tanhf(g_embp[idx] + emb_b[c]);
        g_embp[idx] = v;
        atomicAdd(&s[c], v * v);
    }
    __syncthreads();
    if (tid < 64) atomicAdd(&g_colsq[tid], s[tid]);
}

__global__ void build_P(const float* __restrict__ scal_b) {
    int n = blockIdx.x;
    int c = threadIdx.x;
    float e = g_embp[n * 64 + c] / sqrtf(g_colsq[c]);
    g_P[n * 128 + c] = e;
    float s = sigf(g_scalp[n * 64 + c] + scal_b[c]);
    g_P[n * 128 + 64 + c] = s;
    float v = e * e;
#pragma unroll
    for (int o = 16; o; o >>= 1) v += __shfl_down_sync(0xffffffff, v, o);
    __shared__ float sh[2];
    if ((c & 31) == 0) sh[c >> 5] = v;
    __syncthreads();
    if (c == 0) g_sq[n] = sh[0] + sh[1];
}

// ------------------------- pairwise decoder (fused dual GEMM, symmetric) -------------------------
#define PW_SMEM ((64 * 132 * 2 + 64 * 65 + 128) * 4)
__global__ __launch_bounds__(128) void pairwise(float* __restrict__ out) {
    int bi = blockIdx.y, bj = blockIdx.x;
    if (bi > bj) return;
    extern __shared__ float smem[];
    float* Ap = smem;                 // [64][132]
    float* Bp = smem + 64 * 132;      // [64][132]
    float* tT = smem + 2 * 64 * 132;  // [64][65]
    float* sqA = tT + 64 * 65;        // [64]
    float* sqB = sqA + 64;            // [64]

    int tid = threadIdx.x;
    int i0 = bi * 64, j0 = bj * 64;

#pragma unroll
    for (int i = 0; i < 16; i++) {
        int f = tid + i * 128;
        int row = f >> 5, k4 = f & 31;
        float4 va = make_float4(0.f, 0.f, 0.f, 0.f);
        float4 vb = make_float4(0.f, 0.f, 0.f, 0.f);
        if (i0 + row < N_) va = ((const float4*)g_P)[(size_t)(i0 + row) * 32 + k4];
        if (j0 + row < N_) vb = ((const float4*)g_P)[(size_t)(j0 + row) * 32 + k4];
        *((float4*)&Ap[row * 132 + k4 * 4]) = va;
        *((float4*)&Bp[row * 132 + k4 * 4]) = vb;
    }
    if (tid < 64) {
        sqA[tid] = (i0 + tid < N_) ? g_sq[i0 + tid] : 0.f;
        sqB[tid] = (j0 + tid < N_) ? g_sq[j0 + tid] : 0.f;
    }
    __syncthreads();

    int ty = tid >> 3, tx = tid & 7;
    float aG[4][8], aS[4][8];
#pragma unroll
    for (int r = 0; r < 4; r++)
#pragma unroll
        for (int c = 0; c < 8; c++) { aG[r][c] = 0.f; aS[r][c] = 0.f; }

#pragma unroll 2
    for (int k4 = 0; k4 < 32; k4++) {
        float av[4][4], bv[4][8];
#pragma unroll
        for (int r = 0; r < 4; r++) {
            float4 a = *((float4*)&Ap[(ty * 4 + r) * 132 + k4 * 4]);
            av[r][0] = a.x; av[r][1] = a.y; av[r][2] = a.z; av[r][3] = a.w;
        }
#pragma unroll
        for (int kk = 0; kk < 4; kk++) {
            float4 b = *((float4*)&Bp[(tx * 8 + kk * 2) * 0 + 0]);  // placeholder removed below
        }
        // B operand here is rows of P for the j-tile: we need Bp[jrow][k].
        // Load b values: for each of 8 columns (j rows), the 4 k values.
#pragma unroll
        for (int c = 0; c < 8; c++) {
            float4 b = *((float4*)&Bp[(tx * 8 + c) * 132 + k4 * 4]);
            bv[0][c] = b.x; bv[1][c] = b.y; bv[2][c] = b.z; bv[3][c] = b.w;
        }
        if (k4 < 16) {
#pragma unroll
            for (int kk = 0; kk < 4; kk++)
#pragma unroll
                for (int r = 0; r < 4; r++)
#pragma unroll
                    for (int c = 0; c < 8; c++)
                        aG[r][c] += av[r][kk] * bv[kk][c];
        } else {
#pragma unroll
            for (int kk = 0; kk < 4; kk++)
#pragma unroll
                for (int r = 0; r < 4; r++)
#pragma unroll
                    for (int c = 0; c < 8; c++)
                        aS[r][c] += av[r][kk] * bv[kk][c];
        }
    }

#pragma unroll
    for (int r = 0; r < 4; r++) {
        int i = i0 + ty * 4 + r;
#pragma unroll
        for (int c = 0; c < 8; c++) {
            int j = j0 + tx * 8 + c;
            float G = aG[r][c], S = aS[r][c];
            float d = 2.f * G - sqA[ty * 4 + r] - sqB[tx * 8 + c];
            float v = 1.f + tanhf(d * S);
            if (i < N_ && j < N_) out[(size_t)i * N_ + j] = v;
            tT[(tx * 8 + c) * 65 + (ty * 4 + r)] = v;
        }
    }
    if (bi != bj) {
        __syncthreads();
        for (int f = tid; f < 64 * 64; f += 128) {
            int rr = f >> 6, cc = f & 63;
            int j = j0 + rr, i = i0 + cc;
            if (j < N_ && i < N_) out[(size_t)j * N_ + i] = tT[rr * 65 + cc];
        }
    }
}

// ------------------------- host -------------------------
extern "C" void kernel_launch(void* const* d_in, const int* in_sizes, int n_in,
                              void* d_out, int out_size) {
    const float* feat   = (const float*)d_in[0];
    const float* ew     = (const float*)d_in[1];
    const float* Dw     = (const float*)d_in[2];
    const float* W1     = (const float*)d_in[3];
    const float* a_s1   = (const float*)d_in[4];
    const float* a_d1   = (const float*)d_in[5];
    const float* W2     = (const float*)d_in[6];
    const float* a_s2   = (const float*)d_in[7];
    const float* a_d2   = (const float*)d_in[8];
    const float* Wx     = (const float*)d_in[9];
    const float* Wh     = (const float*)d_in[10];
    const float* b_lstm = (const float*)d_in[11];
    const float* embW   = (const float*)d_in[12];
    const float* embB   = (const float*)d_in[13];
    const float* scalW  = (const float*)d_in[14];
    const float* scalB  = (const float*)d_in[15];
    const void*  ei     = (const void*)d_in[16];
    const void*  part   = (const void*)d_in[17];
    float* out = (float*)d_out;

    cudaFuncSetAttribute(gemm128, cudaFuncAttributeMaxDynamicSharedMemorySize, GEMM_SMEM);
    cudaFuncSetAttribute(pairwise, cudaFuncAttributeMaxDynamicSharedMemorySize, PW_SMEM);

    float *h1, *g1, *h2, *agg, *m_, *den_, *Zx, *hbuf, *cbuf, *embp, *scalp;
    float *comnum, *comden, *colsq;
    int *cnt, *cursor;
    cudaGetSymbolAddress((void**)&h1, g_h1);
    cudaGetSymbolAddress((void**)&g1, g_g1);
    cudaGetSymbolAddress((void**)&h2, g_h2);
    cudaGetSymbolAddress((void**)&agg, g_agg);
    cudaGetSymbolAddress((void**)&m_, g_m);
    cudaGetSymbolAddress((void**)&den_, g_den);
    cudaGetSymbolAddress((void**)&Zx, g_Zx);
    cudaGetSymbolAddress((void**)&hbuf, g_hbuf);
    cudaGetSymbolAddress((void**)&cbuf, g_cbuf);
    cudaGetSymbolAddress((void**)&embp, g_embp);
    cudaGetSymbolAddress((void**)&scalp, g_scalp);
    cudaGetSymbolAddress((void**)&comnum, g_comnum);
    cudaGetSymbolAddress((void**)&comden, g_comden);
    cudaGetSymbolAddress((void**)&colsq, g_colsq);
    cudaGetSymbolAddress((void**)&cnt, g_cnt);
    cudaGetSymbolAddress((void**)&cursor, g_cursor);

    const int MT = 157;  // ceil(10000/64)
    const int TE = T_ * E_;
    const int TNH = T_ * N_ * H_;

    // dtype detection for indices
    detect64_kernel<<<1, 1>>>((const int*)ei);

    // ---- GAT layer 1 ----
    gemm128<<<dim3(MT, 2, 8), 128, GEMM_SMEM>>>(feat, W1, h1, N_, 128,
                                                (long long)N_ * F_, (long long)N_ * 128, 0);
    alpha_kernel<<<(TNH + 255) / 256, 256>>>(h1, a_s1, a_d1, 32);

    // CSR build (shared by both layers)
    fill_i<<<(T_ * N_ + 255) / 256, 256>>>(cnt, 0, T_ * N_);
    csr_count<<<(TE + 255) / 256, 256>>>(ei);
    csr_scan<<<T_, 1024>>>();
    fill_i<<<(T_ * N_ + 255) / 256, 256>>>(cursor, 0, T_ * N_);
    csr_scatter<<<(TE + 255) / 256, 256>>>(ei);

    fill_f<<<(TNH + 255) / 256, 256>>>(m_, -INFINITY, TNH);
    fill_f<<<(TNH + 255) / 256, 256>>>(den_, 0.f, TNH);
    edge_max<<<(TE + 255) / 256, 256>>>(ei);
    edge_ex<<<(TE + 255) / 256, 256>>>(ei, ew);
    gat_gather<128, 32><<<dim3(N_, T_), 128>>>(ei, h1, g1, 128);

    // ---- GAT layer 2 ----
    gemm128<<<dim3(MT, 1, 8), 128, GEMM_SMEM>>>(g1, W2, h2, N_, 64,
                                                (long long)N_ * 128, (long long)N_ * 64, 0);
    alpha_kernel<<<(TNH + 255) / 256, 256>>>(h2, a_s2, a_d2, 16);
    fill_f<<<(TNH + 255) / 256, 256>>>(m_, -INFINITY, TNH);
    fill_f<<<(TNH + 255) / 256, 256>>>(den_, 0.f, TNH);
    edge_max<<<(TE + 255) / 256, 256>>>(ei);
    edge_ex<<<(TE + 255) / 256, 256>>>(ei, ew);
    gat_gather<64, 16><<<dim3(N_, T_), 64>>>(ei, h2, agg, 128);

    // ---- meso ----
    fill_f<<<(T_ * NCOM_ * D2_ + 255) / 256, 256>>>(comnum, 0.f, T_ * NCOM_ * D2_);
    fill_f<<<(T_ * NCOM_ + 255) / 256, 256>>>(comden, 0.f, T_ * NCOM_);
    meso_acc<<<dim3((N_ + MCHUNK - 1) / MCHUNK, T_), 256>>>(part, Dw);
    meso_scatter<<<(T_ * N_ * 64 + 255) / 256, 256>>>(part);

    // ---- LSTM ----
    gemm128<<<dim3(MT, 8, 8), 128, GEMM_SMEM>>>(agg, Wx, Zx, N_, 512,
                                                (long long)N_ * 128, (long long)N_ * 512, 0);
    fill_f<<<(N_ * 128 + 255) / 256, 256>>>(hbuf, 0.f, N_ * 128);
    fill_f<<<(N_ * 128 + 255) / 256, 256>>>(cbuf, 0.f, N_ * 128);
    for (int t = 0; t < T_; t++) {
        gemm128<<<dim3(MT, 8, 1), 128, GEMM_SMEM>>>(hbuf, Wh, Zx + (size_t)t * N_ * 512,
                                                    N_, 512, 0, 0, 1);
        lstm_pw<<<(N_ * 128 + 255) / 256, 256>>>(b_lstm, t);
    }

    // ---- decoder ----
    gemm128<<<dim3(MT, 1, 1), 128, GEMM_SMEM>>>(hbuf, embW, embp, N_, 64, 0, 0, 0);
    gemm128<<<dim3(MT, 1, 1), 128, GEMM_SMEM>>>(hbuf, scalW, scalp, N_, 64, 0, 0, 0);
    fill_f<<<1, 64>>>(colsq, 0.f, 64);
    emb_tanh<<<(N_ * 64 + 255) / 256, 256>>>(embB);
    build_P<<<N_, 64>>>(scalB);
    pairwise<<<dim3(MT, MT), 128, PW_SMEM>>>(out);
}

// round 2
// speedup vs baseline: 1.0010x; 1.0010x over previous
#include <cuda_runtime.h>
#include <math.h>

#define T_ 8
#define N_ 10000
#define E_ 320000
#define F_ 128
#define D1_ 128
#define D2_ 64
#define H_ 4
#define NCOM_ 100
#define DR_ 128
#define DD_ 64

// ------------------------- device scratch -------------------------
__device__ int   g_is64;
__device__ float g_h1[(size_t)T_ * N_ * D1_];        // 41MB
__device__ float g_g1[(size_t)T_ * N_ * D1_];        // 41MB
__device__ float g_h2[(size_t)T_ * N_ * D2_];        // 20MB
__device__ float g_agg[(size_t)T_ * N_ * 128];       // 41MB  [g2 | meso]
__device__ float g_as[T_ * N_ * H_];
__device__ float g_ad[T_ * N_ * H_];
__device__ float g_m[T_ * N_ * H_];
__device__ float g_den[T_ * N_ * H_];
__device__ float g_ex[(size_t)T_ * E_ * H_];         // 41MB
__device__ int   g_cnt[T_ * N_];
__device__ int   g_rowptr[T_ * (N_ + 1)];
__device__ int   g_cursor[T_ * N_];
__device__ int   g_sorted[T_ * E_];                  // 10MB
__device__ float g_comnum[T_ * NCOM_ * D2_];
__device__ float g_comden[T_ * NCOM_];
__device__ float g_Zx[(size_t)T_ * N_ * 512];        // 164MB
__device__ float g_hbuf[N_ * DR_];
__device__ float g_cbuf[N_ * DR_];
__device__ float g_embp[N_ * DD_];
__device__ float g_scalp[N_ * DD_];
__device__ float g_P[N_ * 128];                      // [emb | scal]
__device__ float g_sq[N_];
__device__ float g_colsq[DD_];

// ------------------------- helpers -------------------------
__device__ __forceinline__ long long ld_idx(const void* p, size_t i) {
    if (g_is64) return ((const long long*)p)[i];
    return (long long)((const int*)p)[i];
}

__device__ __forceinline__ void atomicMaxF(float* addr, float v) {
    if (v >= 0.f) atomicMax((int*)addr, __float_as_int(v));
    else          atomicMin((unsigned int*)addr, __float_as_uint(v));
}

__device__ __forceinline__ float sigf(float x) { return 1.f / (1.f + expf(-x)); }

// detect int64 vs int32 indices: int64 values < 2^31 have zero high words.
__global__ void detect64_kernel(const int* ei32) {
    int ok = 1;
    for (int i = 1; i < 64; i += 2)
        if (ei32[i] != 0) ok = 0;
    g_is64 = ok;
}

__global__ void fill_f(float* p, float v, int n) {
    int i = blockIdx.x * blockDim.x + threadIdx.x;
    if (i < n) p[i] = v;
}
__global__ void fill_i(int* p, int v, int n) {
    int i = blockIdx.x * blockDim.x + threadIdx.x;
    if (i < n) p[i] = v;
}

// ------------------------- GEMM (K = 128 fixed) -------------------------
// C[M x Dn] = A[M x 128] @ B[128 x Dn]  (optionally +=), batched over z.
// BM=BN=64, 128 threads, thread tile 4x8, full K in smem.
#define GEMM_SMEM ((64 * 132 + 128 * 68) * 4)
__global__ __launch_bounds__(128) void gemm128(
    const float* __restrict__ A, const float* __restrict__ B,
    float* __restrict__ C, int M, int Dn,
    long long sA, long long sC, int accumulate)
{
    extern __shared__ float smem[];
    float* As = smem;             // [64][132]
    float* Bs = smem + 64 * 132;  // [128][68]

    int t = blockIdx.z;
    A += (size_t)t * sA;
    C += (size_t)t * sC;
    int m0 = blockIdx.x * 64;
    int n0 = blockIdx.y * 64;
    int tid = threadIdx.x;

    // A tile: 64 rows x 128 cols = 2048 float4
#pragma unroll
    for (int i = 0; i < 16; i++) {
        int f = tid + i * 128;
        int row = f >> 5, k4 = f & 31;
        float4 v = make_float4(0.f, 0.f, 0.f, 0.f);
        if (m0 + row < M) v = ((const float4*)A)[(size_t)(m0 + row) * 32 + k4];
        *((float4*)&As[row * 132 + k4 * 4]) = v;
    }
    // B tile: 128 rows x 64 cols
    int dn4 = Dn >> 2;
#pragma unroll
    for (int i = 0; i < 16; i++) {
        int f = tid + i * 128;
        int row = f >> 4, c4 = f & 15;
        float4 v = ((const float4*)B)[(size_t)row * dn4 + (n0 >> 2) + c4];
        *((float4*)&Bs[row * 68 + c4 * 4]) = v;
    }
    __syncthreads();

    int ty = tid >> 3, tx = tid & 7;
    float acc[4][8];
#pragma unroll
    for (int r = 0; r < 4; r++)
#pragma unroll
        for (int c = 0; c < 8; c++) acc[r][c] = 0.f;

#pragma unroll 4
    for (int k4 = 0; k4 < 32; k4++) {
        float av[4][4], bv[4][8];
#pragma unroll
        for (int r = 0; r < 4; r++) {
            float4 a = *((float4*)&As[(ty * 4 + r) * 132 + k4 * 4]);
            av[r][0] = a.x; av[r][1] = a.y; av[r][2] = a.z; av[r][3] = a.w;
        }
#pragma unroll
        for (int kk = 0; kk < 4; kk++) {
            float4 b0 = *((float4*)&Bs[(k4 * 4 + kk) * 68 + tx * 8]);
            float4 b1 = *((float4*)&Bs[(k4 * 4 + kk) * 68 + tx * 8 + 4]);
            bv[kk][0] = b0.x; bv[kk][1] = b0.y; bv[kk][2] = b0.z; bv[kk][3] = b0.w;
            bv[kk][4] = b1.x; bv[kk][5] = b1.y; bv[kk][6] = b1.z; bv[kk][7] = b1.w;
        }
#pragma unroll
        for (int kk = 0; kk < 4; kk++)
#pragma unroll
            for (int r = 0; r < 4; r++)
#pragma unroll
                for (int c = 0; c < 8; c++)
                    acc[r][c] += av[r][kk] * bv[kk][c];
    }

#pragma unroll
    for (int r = 0; r < 4; r++) {
        int row = m0 + ty * 4 + r;
        if (row < M) {
#pragma unroll
            for (int c = 0; c < 8; c++) {
                size_t idx = (size_t)row * Dn + n0 + tx * 8 + c;
                C[idx] = accumulate ? (C[idx] + acc[r][c]) : acc[r][c];
            }
        }
    }
}

// ------------------------- GAT kernels -------------------------
__global__ void alpha_kernel(const float* __restrict__ h,
                             const float* __restrict__ a_s,
                             const float* __restrict__ a_d, int dh) {
    int idx = blockIdx.x * blockDim.x + threadIdx.x;
    if (idx >= T_ * N_ * H_) return;
    int hh = idx & 3;
    int tn = idx >> 2;
    const float* hr = h + (size_t)tn * (H_ * dh) + hh * dh;
    float s = 0.f, d = 0.f;
    for (int k = 0; k < dh; k++) {
        float v = hr[k];
        s += v * a_s[hh * dh + k];
        d += v * a_d[hh * dh + k];
    }
    g_as[idx] = s;
    g_ad[idx] = d;
}

__global__ void csr_count(const void* ei) {
    int idx = blockIdx.x * blockDim.x + threadIdx.x;
    if (idx >= T_ * E_) return;
    int t = idx / E_, e = idx - t * E_;
    int dst = (int)ld_idx(ei, (size_t)t * 2 * E_ + E_ + e);
    atomicAdd(&g_cnt[t * N_ + dst], 1);
}

__global__ void csr_scan() {
    int t = blockIdx.x;
    int tid = threadIdx.x;
    __shared__ int sh[1024];
    int off = 0;
    for (int chunk = 0; chunk < N_; chunk += 1024) {
        int i = chunk + tid;
        int v = (i < N_) ? g_cnt[t * N_ + i] : 0;
        sh[tid] = v;
        __syncthreads();
        for (int d2 = 1; d2 < 1024; d2 <<= 1) {
            int x = 0;
            if (tid >= d2) x = sh[tid - d2];
            __syncthreads();
            sh[tid] += x;
            __syncthreads();
        }
        if (i < N_) g_rowptr[t * (N_ + 1) + i] = off + sh[tid] - v;
        int tot = sh[1023];
        __syncthreads();
        off += tot;
    }
    if (tid == 0) g_rowptr[t * (N_ + 1) + N_] = off;
}

__global__ void csr_scatter(const void* ei) {
    int idx = blockIdx.x * blockDim.x + threadIdx.x;
    if (idx >= T_ * E_) return;
    int t = idx / E_, e = idx - t * E_;
    int dst = (int)ld_idx(ei, (size_t)t * 2 * E_ + E_ + e);
    int pos = atomicAdd(&g_cursor[t * N_ + dst], 1);
    g_sorted[t * E_ + g_rowptr[t * (N_ + 1) + dst] + pos] = e;
}

__global__ void edge_max(const void* ei) {
    int idx = blockIdx.x * blockDim.x + threadIdx.x;
    if (idx >= T_ * E_) return;
    int t = idx / E_, e = idx - t * E_;
    int src = (int)ld_idx(ei, (size_t)t * 2 * E_ + e);
    int dst = (int)ld_idx(ei, (size_t)t * 2 * E_ + E_ + e);
    float4 s4 = *(const float4*)&g_as[(t * N_ + src) * 4];
    float4 d4 = *(const float4*)&g_ad[(t * N_ + dst) * 4];
    float ev[4] = {s4.x + d4.x, s4.y + d4.y, s4.z + d4.z, s4.w + d4.w};
#pragma unroll
    for (int h = 0; h < 4; h++) {
        float v = ev[h] > 0.f ? ev[h] : 0.2f * ev[h];
        atomicMaxF(&g_m[(t * N_ + dst) * 4 + h], v);
    }
}

__global__ void edge_ex(const void* ei, const float* __restrict__ ew) {
    int idx = blockIdx.x * blockDim.x + threadIdx.x;
    if (idx >= T_ * E_) return;
    int t = idx / E_, e = idx - t * E_;
    int src = (int)ld_idx(ei, (size_t)t * 2 * E_ + e);
    int dst = (int)ld_idx(ei, (size_t)t * 2 * E_ + E_ + e);
    float4 s4 = *(const float4*)&g_as[(t * N_ + src) * 4];
    float4 d4 = *(const float4*)&g_ad[(t * N_ + dst) * 4];
    float4 m4 = *(const float4*)&g_m[(t * N_ + dst) * 4];
    float w = ew[(size_t)t * E_ + e];
    float ev[4] = {s4.x + d4.x, s4.y + d4.y, s4.z + d4.z, s4.w + d4.w};
    float mv[4] = {m4.x, m4.y, m4.z, m4.w};
    float xo[4];
#pragma unroll
    for (int h = 0; h < 4; h++) {
        float v = ev[h] > 0.f ? ev[h] : 0.2f * ev[h];
        float x = expf(v - mv[h]) * w;
        xo[h] = x;
        atomicAdd(&g_den[(t * N_ + dst) * 4 + h], x);
    }
    *(float4*)&g_ex[((size_t)t * E_ + e) * 4] = make_float4(xo[0], xo[1], xo[2], xo[3]);
}

template <int D, int DH>
__global__ void gat_gather(const void* ei, const float* __restrict__ hsrc,
                           float* __restrict__ out, int outStride) {
    int t = blockIdx.y, n = blockIdx.x, tid = threadIdx.x;
    int start = g_rowptr[t * (N_ + 1) + n];
    int end = g_rowptr[t * (N_ + 1) + n + 1];
    int head = tid / DH;
    __shared__ int s_src[64];
    __shared__ float s_ex[64][4];
    float acc = 0.f;
    for (int base = start; base < end; base += 64) {
        int cnt = min(64, end - base);
        __syncthreads();
        for (int i = tid; i < cnt; i += D) {
            int eid = g_sorted[t * E_ + base + i];
            s_src[i] = (int)ld_idx(ei, (size_t)t * 2 * E_ + eid);
            float4 x = *(const float4*)&g_ex[((size_t)t * E_ + eid) * 4];
            s_ex[i][0] = x.x; s_ex[i][1] = x.y; s_ex[i][2] = x.z; s_ex[i][3] = x.w;
        }
        __syncthreads();
#pragma unroll 4
        for (int i = 0; i < cnt; i++) {
            acc += s_ex[i][head] * hsrc[((size_t)t * N_ + s_src[i]) * D + tid];
        }
    }
    float dn = g_den[(t * N_ + n) * 4 + head];
    float v = acc / (dn + 1e-16f);
    v = v > 0.f ? v : expf(v) - 1.f;
    out[((size_t)t * N_ + n) * outStride + tid] = v;
}

// ------------------------- meso -------------------------
#define MCHUNK 500
__global__ void meso_acc(const void* part, const float* __restrict__ Dw) {
    int t = blockIdx.y;
    int c0 = blockIdx.x * MCHUNK;
    int tid = threadIdx.x;
    __shared__ float sn[NCOM_ * D2_];
    __shared__ float sd[NCOM_];
    __shared__ int sp[MCHUNK];
    __shared__ float sD[MCHUNK];
    for (int i = tid; i < NCOM_ * D2_; i += blockDim.x) sn[i] = 0.f;
    for (int i = tid; i < NCOM_; i += blockDim.x) sd[i] = 0.f;
    int nmax = min(MCHUNK, N_ - c0);
    for (int i = tid; i < nmax; i += blockDim.x) {
        sp[i] = (int)ld_idx(part, (size_t)t * N_ + c0 + i);
        sD[i] = Dw[(size_t)t * N_ + c0 + i];
    }
    __syncthreads();
    for (int idx = tid; idx < nmax * 64; idx += blockDim.x) {
        int nl = idx >> 6, c = idx & 63;
        float g = g_agg[((size_t)t * N_ + c0 + nl) * 128 + c];
        atomicAdd(&sn[sp[nl] * 64 + c], sD[nl] * g);
        if (c == 0) atomicAdd(&sd[sp[nl]], sD[nl]);
    }
    __syncthreads();
    for (int i = tid; i < NCOM_ * 64; i += blockDim.x)
        atomicAdd(&g_comnum[t * NCOM_ * 64 + i], sn[i]);
    for (int i = tid; i < NCOM_; i += blockDim.x)
        atomicAdd(&g_comden[t * NCOM_ + i], sd[i]);
}

__global__ void meso_scatter(const void* part) {
    int idx = blockIdx.x * blockDim.x + threadIdx.x;
    if (idx >= T_ * N_ * 64) return;
    int t = idx / (N_ * 64);
    int r = idx - t * N_ * 64;
    int n = r >> 6, c = r & 63;
    int p = (int)ld_idx(part, (size_t)t * N_ + n);
    float mean = g_comnum[(t * NCOM_ + p) * 64 + c] / (g_comden[t * NCOM_ + p] + 1e-16f);
    g_agg[((size_t)t * N_ + n) * 128 + 64 + c] = mean;
}

// ------------------------- LSTM -------------------------
__global__ void lstm_pw(const float* __restrict__ b, int t) {
    int idx = blockIdx.x * blockDim.x + threadIdx.x;
    if (idx >= N_ * 128) return;
    int n = idx >> 7, j = idx & 127;
    const float* z = g_Zx + (size_t)t * N_ * 512 + (size_t)n * 512;
    float i_ = z[j] + b[j];
    float f_ = z[128 + j] + b[128 + j];
    float gg = z[256 + j] + b[256 + j];
    float o_ = z[384 + j] + b[384 + j];
    float c = sigf(f_) * g_cbuf[idx] + sigf(i_) * tanhf(gg);
    float h = sigf(o_) * tanhf(c);
    g_cbuf[idx] = c;
    g_hbuf[idx] = h;
}

// ------------------------- decoder -------------------------
__global__ void emb_tanh(const float* __restrict__ emb_b) {
    __shared__ float s[64];
    int tid = threadIdx.x;
    if (tid < 64) s[tid] = 0.f;
    __syncthreads();
    int idx = blockIdx.x * 256 + tid;
    if (idx < N_ * 64) {
        int c = idx & 63;
        float v = tanhf(g_embp[idx] + emb_b[c]);
        g_embp[idx] = v;
        atomicAdd(&s[c], v * v);
    }
    __syncthreads();
    if (tid < 64) atomicAdd(&g_colsq[tid], s[tid]);
}

__global__ void build_P(const float* __restrict__ scal_b) {
    int n = blockIdx.x;
    int c = threadIdx.x;
    float e = g_embp[n * 64 + c] / sqrtf(g_colsq[c]);
    g_P[n * 128 + c] = e;
    float s = sigf(g_scalp[n * 64 + c] + scal_b[c]);
    g_P[n * 128 + 64 + c] = s;
    float v = e * e;
#pragma unroll
    for (int o = 16; o; o >>= 1) v += __shfl_down_sync(0xffffffff, v, o);
    __shared__ float sh[2];
    if ((c & 31) == 0) sh[c >> 5] = v;
    __syncthreads();
    if (c == 0) g_sq[n] = sh[0] + sh[1];
}

// ------------------------- pairwise decoder (fused dual GEMM, symmetric) -------------------------
#define PW_SMEM ((64 * 132 * 2 + 64 * 65 + 128) * 4)
__global__ __launch_bounds__(128) void pairwise(float* __restrict__ out) {
    int bi = blockIdx.y, bj = blockIdx.x;
    if (bi > bj) return;
    extern __shared__ float smem[];
    float* Ap = smem;                 // [64][132]
    float* Bp = smem + 64 * 132;      // [64][132]
    float* tT = smem + 2 * 64 * 132;  // [64][65]
    float* sqA = tT + 64 * 65;        // [64]
    float* sqB = sqA + 64;            // [64]

    int tid = threadIdx.x;
    int i0 = bi * 64, j0 = bj * 64;

#pragma unroll
    for (int i = 0; i < 16; i++) {
        int f = tid + i * 128;
        int row = f >> 5, k4 = f & 31;
        float4 va = make_float4(0.f, 0.f, 0.f, 0.f);
        float4 vb = make_float4(0.f, 0.f, 0.f, 0.f);
        if (i0 + row < N_) va = ((const float4*)g_P)[(size_t)(i0 + row) * 32 + k4];
        if (j0 + row < N_) vb = ((const float4*)g_P)[(size_t)(j0 + row) * 32 + k4];
        *((float4*)&Ap[row * 132 + k4 * 4]) = va;
        *((float4*)&Bp[row * 132 + k4 * 4]) = vb;
    }
    if (tid < 64) {
        sqA[tid] = (i0 + tid < N_) ? g_sq[i0 + tid] : 0.f;
        sqB[tid] = (j0 + tid < N_) ? g_sq[j0 + tid] : 0.f;
    }
    __syncthreads();

    int ty = tid >> 3, tx = tid & 7;
    float aG[4][8], aS[4][8];
#pragma unroll
    for (int r = 0; r < 4; r++)
#pragma unroll
        for (int c = 0; c < 8; c++) { aG[r][c] = 0.f; aS[r][c] = 0.f; }

#pragma unroll 2
    for (int k4 = 0; k4 < 32; k4++) {
        float av[4][4], bv[4][8];
#pragma unroll
        for (int r = 0; r < 4; r++) {
            float4 a = *((float4*)&Ap[(ty * 4 + r) * 132 + k4 * 4]);
            av[r][0] = a.x; av[r][1] = a.y; av[r][2] = a.z; av[r][3] = a.w;
        }
#pragma unroll
        for (int kk = 0; kk < 4; kk++) {
            float4 b = *((float4*)&Bp[(tx * 8 + kk * 2) * 0 + 0]);  // placeholder removed below
        }
        // B operand here is rows of P for the j-tile: we need Bp[jrow][k].
        // Load b values: for each of 8 columns (j rows), the 4 k values.
#pragma unroll
        for (int c = 0; c < 8; c++) {
            float4 b = *((float4*)&Bp[(tx * 8 + c) * 132 + k4 * 4]);
            bv[0][c] = b.x; bv[1][c] = b.y; bv[2][c] = b.z; bv[3][c] = b.w;
        }
        if (k4 < 16) {
#pragma unroll
            for (int kk = 0; kk < 4; kk++)
#pragma unroll
                for (int r = 0; r < 4; r++)
#pragma unroll
                    for (int c = 0; c < 8; c++)
                        aG[r][c] += av[r][kk] * bv[kk][c];
        } else {
#pragma unroll
            for (int kk = 0; kk < 4; kk++)
#pragma unroll
                for (int r = 0; r < 4; r++)
#pragma unroll
                    for (int c = 0; c < 8; c++)
                        aS[r][c] += av[r][kk] * bv[kk][c];
        }
    }

#pragma unroll
    for (int r = 0; r < 4; r++) {
        int i = i0 + ty * 4 + r;
#pragma unroll
        for (int c = 0; c < 8; c++) {
            int j = j0 + tx * 8 + c;
            float G = aG[r][c], S = aS[r][c];
            float d = 2.f * G - sqA[ty * 4 + r] - sqB[tx * 8 + c];
            float v = 1.f + tanhf(d * S);
            if (i < N_ && j < N_) out[(size_t)i * N_ + j] = v;
            tT[(tx * 8 + c) * 65 + (ty * 4 + r)] = v;
        }
    }
    if (bi != bj) {
        __syncthreads();
        for (int f = tid; f < 64 * 64; f += 128) {
            int rr = f >> 6, cc = f & 63;
            int j = j0 + rr, i = i0 + cc;
            if (j < N_ && i < N_) out[(size_t)j * N_ + i] = tT[rr * 65 + cc];
        }
    }
}

// ------------------------- host -------------------------
extern "C" void kernel_launch(void* const* d_in, const int* in_sizes, int n_in,
                              void* d_out, int out_size) {
    const float* feat   = (const float*)d_in[0];
    const float* ew     = (const float*)d_in[1];
    const float* Dw     = (const float*)d_in[2];
    const float* W1     = (const float*)d_in[3];
    const float* a_s1   = (const float*)d_in[4];
    const float* a_d1   = (const float*)d_in[5];
    const float* W2     = (const float*)d_in[6];
    const float* a_s2   = (const float*)d_in[7];
    const float* a_d2   = (const float*)d_in[8];
    const float* Wx     = (const float*)d_in[9];
    const float* Wh     = (const float*)d_in[10];
    const float* b_lstm = (const float*)d_in[11];
    const float* embW   = (const float*)d_in[12];
    const float* embB   = (const float*)d_in[13];
    const float* scalW  = (const float*)d_in[14];
    const float* scalB  = (const float*)d_in[15];
    const void*  ei     = (const void*)d_in[16];
    const void*  part   = (const void*)d_in[17];
    float* out = (float*)d_out;

    cudaFuncSetAttribute(gemm128, cudaFuncAttributeMaxDynamicSharedMemorySize, GEMM_SMEM);
    cudaFuncSetAttribute(pairwise, cudaFuncAttributeMaxDynamicSharedMemorySize, PW_SMEM);

    float *h1, *g1, *h2, *agg, *m_, *den_, *Zx, *hbuf, *cbuf, *embp, *scalp;
    float *comnum, *comden, *colsq;
    int *cnt, *cursor;
    cudaGetSymbolAddress((void**)&h1, g_h1);
    cudaGetSymbolAddress((void**)&g1, g_g1);
    cudaGetSymbolAddress((void**)&h2, g_h2);
    cudaGetSymbolAddress((void**)&agg, g_agg);
    cudaGetSymbolAddress((void**)&m_, g_m);
    cudaGetSymbolAddress((void**)&den_, g_den);
    cudaGetSymbolAddress((void**)&Zx, g_Zx);
    cudaGetSymbolAddress((void**)&hbuf, g_hbuf);
    cudaGetSymbolAddress((void**)&cbuf, g_cbuf);
    cudaGetSymbolAddress((void**)&embp, g_embp);
    cudaGetSymbolAddress((void**)&scalp, g_scalp);
    cudaGetSymbolAddress((void**)&comnum, g_comnum);
    cudaGetSymbolAddress((void**)&comden, g_comden);
    cudaGetSymbolAddress((void**)&colsq, g_colsq);
    cudaGetSymbolAddress((void**)&cnt, g_cnt);
    cudaGetSymbolAddress((void**)&cursor, g_cursor);

    const int MT = 157;  // ceil(10000/64)
    const int TE = T_ * E_;
    const int TNH = T_ * N_ * H_;

    // dtype detection for indices
    detect64_kernel<<<1, 1>>>((const int*)ei);

    // ---- GAT layer 1 ----
    gemm128<<<dim3(MT, 2, 8), 128, GEMM_SMEM>>>(feat, W1, h1, N_, 128,
                                                (long long)N_ * F_, (long long)N_ * 128, 0);
    alpha_kernel<<<(TNH + 255) / 256, 256>>>(h1, a_s1, a_d1, 32);

    // CSR build (shared by both layers)
    fill_i<<<(T_ * N_ + 255) / 256, 256>>>(cnt, 0, T_ * N_);
    csr_count<<<(TE + 255) / 256, 256>>>(ei);
    csr_scan<<<T_, 1024>>>();
    fill_i<<<(T_ * N_ + 255) / 256, 256>>>(cursor, 0, T_ * N_);
    csr_scatter<<<(TE + 255) / 256, 256>>>(ei);

    fill_f<<<(TNH + 255) / 256, 256>>>(m_, -INFINITY, TNH);
    fill_f<<<(TNH + 255) / 256, 256>>>(den_, 0.f, TNH);
    edge_max<<<(TE + 255) / 256, 256>>>(ei);
    edge_ex<<<(TE + 255) / 256, 256>>>(ei, ew);
    gat_gather<128, 32><<<dim3(N_, T_), 128>>>(ei, h1, g1, 128);

    // ---- GAT layer 2 ----
    gemm128<<<dim3(MT, 1, 8), 128, GEMM_SMEM>>>(g1, W2, h2, N_, 64,
                                                (long long)N_ * 128, (long long)N_ * 64, 0);
    alpha_kernel<<<(TNH + 255) / 256, 256>>>(h2, a_s2, a_d2, 16);
    fill_f<<<(TNH + 255) / 256, 256>>>(m_, -INFINITY, TNH);
    fill_f<<<(TNH + 255) / 256, 256>>>(den_, 0.f, TNH);
    edge_max<<<(TE + 255) / 256, 256>>>(ei);
    edge_ex<<<(TE + 255) / 256, 256>>>(ei, ew);
    gat_gather<64, 16><<<dim3(N_, T_), 64>>>(ei, h2, agg, 128);

    // ---- meso ----
    fill_f<<<(T_ * NCOM_ * D2_ + 255) / 256, 256>>>(comnum, 0.f, T_ * NCOM_ * D2_);
    fill_f<<<(T_ * NCOM_ + 255) / 256, 256>>>(comden, 0.f, T_ * NCOM_);
    meso_acc<<<dim3((N_ + MCHUNK - 1) / MCHUNK, T_), 256>>>(part, Dw);
    meso_scatter<<<(T_ * N_ * 64 + 255) / 256, 256>>>(part);

    // ---- LSTM ----
    gemm128<<<dim3(MT, 8, 8), 128, GEMM_SMEM>>>(agg, Wx, Zx, N_, 512,
                                                (long long)N_ * 128, (long long)N_ * 512, 0);
    fill_f<<<(N_ * 128 + 255) / 256, 256>>>(hbuf, 0.f, N_ * 128);
    fill_f<<<(N_ * 128 + 255) / 256, 256>>>(cbuf, 0.f, N_ * 128);
    for (int t = 0; t < T_; t++) {
        gemm128<<<dim3(MT, 8, 1), 128, GEMM_SMEM>>>(hbuf, Wh, Zx + (size_t)t * N_ * 512,
                                                    N_, 512, 0, 0, 1);
        lstm_pw<<<(N_ * 128 + 255) / 256, 256>>>(b_lstm, t);
    }

    // ---- decoder ----
    gemm128<<<dim3(MT, 1, 1), 128, GEMM_SMEM>>>(hbuf, embW, embp, N_, 64, 0, 0, 0);
    gemm128<<<dim3(MT, 1, 1), 128, GEMM_SMEM>>>(hbuf, scalW, scalp, N_, 64, 0, 0, 0);
    fill_f<<<1, 64>>>(colsq, 0.f, 64);
    emb_tanh<<<(N_ * 64 + 255) / 256, 256>>>(embB);
    build_P<<<N_, 64>>>(scalB);
    pairwise<<<dim3(MT, MT), 128, PW_SMEM>>>(out);
}

// round 4
// speedup vs baseline: 2.1953x; 2.1930x over previous
#include <cuda_runtime.h>
#include <cuda_bf16.h>
#include <math.h>
#include <stdint.h>

#define T_ 8
#define N_ 10000
#define E_ 320000
#define H_ 4
#define NCOM_ 100

// ===== scratch =====
__device__ int   g_is64;
__device__ __align__(16) float g_h1[(size_t)T_ * N_ * 128];
__device__ __align__(16) float g_g1[(size_t)T_ * N_ * 128];
__device__ __align__(16) float g_h2[(size_t)T_ * N_ * 64];
__device__ __align__(16) float g_agg[(size_t)T_ * N_ * 128];
__device__ __align__(16) float g_as[T_ * N_ * H_];
__device__ __align__(16) float g_ad[T_ * N_ * H_];
__device__ __align__(16) float g_m[T_ * N_ * H_];
__device__ __align__(16) float g_den[T_ * N_ * H_];
__device__ __align__(16) float g_ex[(size_t)T_ * E_ * H_];
__device__ int   g_cnt[T_ * N_];
__device__ int   g_rowptr[T_ * (N_ + 1)];
__device__ int   g_cursor[T_ * N_];
__device__ int   g_sorted[T_ * E_];
__device__ float g_comnum[T_ * NCOM_ * 64];
__device__ float g_comden[T_ * NCOM_];
__device__ __align__(16) float g_Zx[(size_t)T_ * N_ * 512];
__device__ __align__(16) float g_hbuf[N_ * 128];
__device__ __align__(16) float g_cbuf[N_ * 128];
__device__ __align__(16) float g_embp[N_ * 64];
__device__ __align__(16) float g_scalp[N_ * 64];
__device__ float g_sq[N_];
__device__ float g_colsq[64];
__device__ __align__(16) __nv_bfloat16 g_fh[(size_t)T_ * N_ * 128];
__device__ __align__(16) __nv_bfloat16 g_fl[(size_t)T_ * N_ * 128];
__device__ __align__(16) __nv_bfloat16 g_hbh[N_ * 128];
__device__ __align__(16) __nv_bfloat16 g_hbl[N_ * 128];
__device__ __align__(16) __nv_bfloat16 g_ph[N_ * 128];
__device__ __align__(16) __nv_bfloat16 g_pl[N_ * 128];
__device__ __align__(16) __nv_bfloat16 g_wth[512 * 128];
__device__ __align__(16) __nv_bfloat16 g_wtl[512 * 128];

// ===== helpers =====
__device__ __forceinline__ long long ld_idx(const void* p, size_t i) {
    if (g_is64) return ((const long long*)p)[i];
    return (long long)((const int*)p)[i];
}
__device__ __forceinline__ void atomicMaxF(float* addr, float v) {
    if (v >= 0.f) atomicMax((int*)addr, __float_as_int(v));
    else          atomicMin((unsigned int*)addr, __float_as_uint(v));
}
__device__ __forceinline__ float sigf(float x) { return 1.f / (1.f + expf(-x)); }
__device__ __forceinline__ float tanh_fast(float x) {
    float e = __expf(2.f * x);
    return 1.f - 2.f / (e + 1.f);
}
__device__ __forceinline__ void mma16816(float* c, uint32_t a0, uint32_t a1, uint32_t a2,
                                         uint32_t a3, uint32_t b0, uint32_t b1) {
    asm volatile(
        "mma.sync.aligned.m16n8k16.row.col.f32.bf16.bf16.f32 "
        "{%0,%1,%2,%3}, {%4,%5,%6,%7}, {%8,%9}, {%0,%1,%2,%3};"
        : "+f"(c[0]), "+f"(c[1]), "+f"(c[2]), "+f"(c[3])
        : "r"(a0), "r"(a1), "r"(a2), "r"(a3), "r"(b0), "r"(b1));
}

__global__ void detect64_kernel(const int* ei32) {
    int ok = 1;
    for (int i = 1; i < 64; i += 2)
        if (ei32[i] != 0) ok = 0;
    g_is64 = ok;
}
__global__ void fill_f(float* p, float v, int n) {
    int i = blockIdx.x * blockDim.x + threadIdx.x;
    if (i < n) p[i] = v;
}
__global__ void fill_i(int* p, int v, int n) {
    int i = blockIdx.x * blockDim.x + threadIdx.x;
    if (i < n) p[i] = v;
}
__global__ void split8(const float4* __restrict__ x, uint4* __restrict__ hi,
                       uint4* __restrict__ lo, int n8) {
    int i = blockIdx.x * blockDim.x + threadIdx.x;
    if (i >= n8) return;
    float4 a = x[2 * i], b = x[2 * i + 1];
    float v[8] = {a.x, a.y, a.z, a.w, b.x, b.y, b.z, b.w};
    unsigned ho[4], lo4[4];
#pragma unroll
    for (int j = 0; j < 4; j++) {
        __nv_bfloat162 h2 = __floats2bfloat162_rn(v[2 * j], v[2 * j + 1]);
        __nv_bfloat162 l2 = __floats2bfloat162_rn(v[2 * j] - __low2float(h2),
                                                  v[2 * j + 1] - __high2float(h2));
        ho[j] = *reinterpret_cast<unsigned*>(&h2);
        lo4[j] = *reinterpret_cast<unsigned*>(&l2);
    }
    hi[i] = make_uint4(ho[0], ho[1], ho[2], ho[3]);
    lo[i] = make_uint4(lo4[0], lo4[1], lo4[2], lo4[3]);
}
// transpose+split weight B[128 x Dn] -> Bt[Dn x 128]
__global__ void bsplit(const float* __restrict__ B, __nv_bfloat16* __restrict__ bth,
                       __nv_bfloat16* __restrict__ btl, int Dn) {
    int idx = blockIdx.x * blockDim.x + threadIdx.x;
    if (idx >= Dn * 128) return;
    int n = idx >> 7, k = idx & 127;
    float v = B[(size_t)k * Dn + n];
    __nv_bfloat16 h = __float2bfloat16_rn(v);
    bth[idx] = h;
    btl[idx] = __float2bfloat16_rn(v - __bfloat162float(h));
}

// ===== MMA GEMM: C[MxDn] = A[Mx128] @ B[128xDn], split bf16, tile 64x64 =====
// smem rows padded to 136 bf16 (68 b32 words) -> conflict-free fragment loads.
#define KW 68
#define ROWB 272            // bytes per row
#define BUF (64 * ROWB)     // 17408
#define SM_AH 0
#define SM_AL BUF
#define SM_BH (2 * BUF)
#define SM_BL (3 * BUF)
#define SM_SQ (4 * BUF)
#define MG_SMEM (4 * BUF + 512)

__device__ __forceinline__ void cp_tile(const uint4* __restrict__ G, char* sm, int off,
                                        int base, int Mlim, int tid) {
#pragma unroll
    for (int i = 0; i < 8; i++) {
        int idx = tid + i * 128;
        int row = idx >> 4, c = idx & 15;
        uint4 v = make_uint4(0, 0, 0, 0);
        if (base + row < Mlim) v = G[(size_t)(base + row) * 16 + c];
        ((uint4*)(sm + off))[row * 17 + c] = v;
    }
}

__global__ __launch_bounds__(128) void mma_gemm(
    const __nv_bfloat16* __restrict__ Ah, const __nv_bfloat16* __restrict__ Al,
    const __nv_bfloat16* __restrict__ Bh, const __nv_bfloat16* __restrict__ Bl,
    float* __restrict__ C, int M, int Dn,
    long long sA, long long sC, int accumulate)
{
    extern __shared__ char sm[];
    int tid = threadIdx.x, w = tid >> 5, lane = tid & 31;
    int g = lane >> 2, tq = lane & 3;
    int m0 = blockIdx.x * 64, n0 = blockIdx.y * 64, t = blockIdx.z;
    Ah += (size_t)t * sA; Al += (size_t)t * sA;
    C += (size_t)t * sC;

    cp_tile((const uint4*)Ah, sm, SM_AH, m0, M, tid);
    cp_tile((const uint4*)Al, sm, SM_AL, m0, M, tid);
    cp_tile((const uint4*)Bh, sm, SM_BH, n0, Dn, tid);
    cp_tile((const uint4*)Bl, sm, SM_BL, n0, Dn, tid);
    __syncthreads();

    const uint32_t* SAh = (const uint32_t*)(sm + SM_AH);
    const uint32_t* SAl = (const uint32_t*)(sm + SM_AL);
    const uint32_t* SBh = (const uint32_t*)(sm + SM_BH);
    const uint32_t* SBl = (const uint32_t*)(sm + SM_BL);

    float acc[8][4];
#pragma unroll
    for (int nb = 0; nb < 8; nb++)
#pragma unroll
        for (int q = 0; q < 4; q++) acc[nb][q] = 0.f;

    int ra = (w * 16 + g) * KW, rb = ra + 8 * KW;
#pragma unroll
    for (int kc = 0; kc < 8; kc++) {
        int ka = kc * 8 + tq;
        uint32_t ah0 = SAh[ra + ka],     ah1 = SAh[rb + ka];
        uint32_t ah2 = SAh[ra + ka + 4], ah3 = SAh[rb + ka + 4];
        uint32_t al0 = SAl[ra + ka],     al1 = SAl[rb + ka];
        uint32_t al2 = SAl[ra + ka + 4], al3 = SAl[rb + ka + 4];
#pragma unroll
        for (int nb = 0; nb < 8; nb++) {
            int nrow = (nb * 8 + g) * KW;
            uint32_t bh0 = SBh[nrow + ka], bh1 = SBh[nrow + ka + 4];
            uint32_t bl0 = SBl[nrow + ka], bl1 = SBl[nrow + ka + 4];
            mma16816(acc[nb], ah0, ah1, ah2, ah3, bh0, bh1);
            mma16816(acc[nb], ah0, ah1, ah2, ah3, bl0, bl1);
            mma16816(acc[nb], al0, al1, al2, al3, bh0, bh1);
        }
    }

    int r0 = m0 + w * 16 + g, r1 = r0 + 8;
#pragma unroll
    for (int nb = 0; nb < 8; nb++) {
        int col = n0 + nb * 8 + 2 * tq;
        if (r0 < M) {
            float2* p = (float2*)(C + (size_t)r0 * Dn + col);
            float2 v = make_float2(acc[nb][0], acc[nb][1]);
            if (accumulate) { float2 o = *p; v.x += o.x; v.y += o.y; }
            *p = v;
        }
        if (r1 < M) {
            float2* p = (float2*)(C + (size_t)r1 * Dn + col);
            float2 v = make_float2(acc[nb][2], acc[nb][3]);
            if (accumulate) { float2 o = *p; v.x += o.x; v.y += o.y; }
            *p = v;
        }
    }
}

// ===== pairwise decoder: tile 64x64, symmetric (bi<=bj), G from k0-63, S from k64-127 =====
__global__ __launch_bounds__(128) void pairwise_mma(float* __restrict__ out) {
    int bi = blockIdx.y, bj = blockIdx.x;
    if (bi > bj) return;
    extern __shared__ char sm[];
    int tid = threadIdx.x, w = tid >> 5, lane = tid & 31;
    int g = lane >> 2, tq = lane & 3;
    int i0 = bi * 64, j0 = bj * 64;
    float* sqB = (float*)(sm + SM_SQ);

    cp_tile((const uint4*)g_ph, sm, SM_AH, i0, N_, tid);
    cp_tile((const uint4*)g_pl, sm, SM_AL, i0, N_, tid);
    cp_tile((const uint4*)g_ph, sm, SM_BH, j0, N_, tid);
    cp_tile((const uint4*)g_pl, sm, SM_BL, j0, N_, tid);
    if (tid < 64) sqB[tid] = (j0 + tid < N_) ? g_sq[j0 + tid] : 0.f;
    __syncthreads();

    const uint32_t* SAh = (const uint32_t*)(sm + SM_AH);
    const uint32_t* SAl = (const uint32_t*)(sm + SM_AL);
    const uint32_t* SBh = (const uint32_t*)(sm + SM_BH);
    const uint32_t* SBl = (const uint32_t*)(sm + SM_BL);

    float accG[8][4], accS[8][4];
#pragma unroll
    for (int nb = 0; nb < 8; nb++)
#pragma unroll
        for (int q = 0; q < 4; q++) { accG[nb][q] = 0.f; accS[nb][q] = 0.f; }

    int ra = (w * 16 + g) * KW, rb = ra + 8 * KW;
#pragma unroll
    for (int kc = 0; kc < 8; kc++) {
        int ka = kc * 8 + tq;
        uint32_t ah0 = SAh[ra + ka],     ah1 = SAh[rb + ka];
        uint32_t ah2 = SAh[ra + ka + 4], ah3 = SAh[rb + ka + 4];
        uint32_t al0 = SAl[ra + ka],     al1 = SAl[rb + ka];
        uint32_t al2 = SAl[ra + ka + 4], al3 = SAl[rb + ka + 4];
        float (*acc)[4] = (kc < 4) ? accG : accS;
#pragma unroll
        for (int nb = 0; nb < 8; nb++) {
            int nrow = (nb * 8 + g) * KW;
            uint32_t bh0 = SBh[nrow + ka], bh1 = SBh[nrow + ka + 4];
            uint32_t bl0 = SBl[nrow + ka], bl1 = SBl[nrow + ka + 4];
            mma16816(acc[nb], ah0, ah1, ah2, ah3, bh0, bh1);
            mma16816(acc[nb], ah0, ah1, ah2, ah3, bl0, bl1);
            mma16816(acc[nb], al0, al1, al2, al3, bh0, bh1);
        }
    }

    int lr0 = w * 16 + g, lr1 = lr0 + 8;
    int ir0 = i0 + lr0, ir1 = i0 + lr1;
    float sqi0 = (ir0 < N_) ? g_sq[ir0] : 0.f;
    float sqi1 = (ir1 < N_) ? g_sq[ir1] : 0.f;

    float vv[8][4];
#pragma unroll
    for (int nb = 0; nb < 8; nb++) {
        int c0 = nb * 8 + 2 * tq, c1 = c0 + 1;
        float sj0 = sqB[c0], sj1 = sqB[c1];
        vv[nb][0] = 1.f + tanh_fast((2.f * accG[nb][0] - sqi0 - sj0) * accS[nb][0]);
        vv[nb][1] = 1.f + tanh_fast((2.f * accG[nb][1] - sqi0 - sj1) * accS[nb][1]);
        vv[nb][2] = 1.f + tanh_fast((2.f * accG[nb][2] - sqi1 - sj0) * accS[nb][2]);
        vv[nb][3] = 1.f + tanh_fast((2.f * accG[nb][3] - sqi1 - sj1) * accS[nb][3]);
    }

    bool full = (i0 + 64 <= N_) && (j0 + 64 <= N_);
#pragma unroll
    for (int nb = 0; nb < 8; nb++) {
        int c0 = nb * 8 + 2 * tq;
        if (full) {
            *(float2*)(out + (size_t)ir0 * N_ + j0 + c0) = make_float2(vv[nb][0], vv[nb][1]);
            *(float2*)(out + (size_t)ir1 * N_ + j0 + c0) = make_float2(vv[nb][2], vv[nb][3]);
        } else {
            if (ir0 < N_) {
                if (j0 + c0 < N_)     out[(size_t)ir0 * N_ + j0 + c0] = vv[nb][0];
                if (j0 + c0 + 1 < N_) out[(size_t)ir0 * N_ + j0 + c0 + 1] = vv[nb][1];
            }
            if (ir1 < N_) {
                if (j0 + c0 < N_)     out[(size_t)ir1 * N_ + j0 + c0] = vv[nb][2];
                if (j0 + c0 + 1 < N_) out[(size_t)ir1 * N_ + j0 + c0 + 1] = vv[nb][3];
            }
        }
    }

    if (bi != bj) {
        // stage transpose in smem (reuse A buffer region) then mirror write
        __syncthreads();
        float* vT = (float*)(sm + SM_AH);  // [64][65]
#pragma unroll
        for (int nb = 0; nb < 8; nb++) {
            int c0 = nb * 8 + 2 * tq;
            vT[c0 * 65 + lr0] = vv[nb][0];
            vT[(c0 + 1) * 65 + lr0] = vv[nb][1];
            vT[c0 * 65 + lr1] = vv[nb][2];
            vT[(c0 + 1) * 65 + lr1] = vv[nb][3];
        }
        __syncthreads();
        for (int idx = tid; idx < 64 * 64; idx += 128) {
            int r2 = idx >> 6, c2 = idx & 63;  // r2 = j-local, c2 = i-local
            int jj = j0 + r2, ii = i0 + c2;
            if (jj < N_ && ii < N_) out[(size_t)jj * N_ + ii] = vT[r2 * 65 + c2];
        }
    }
}

// ===== GAT kernels =====
__global__ void alpha_kernel(const float* __restrict__ h, const float* __restrict__ a_s,
                             const float* __restrict__ a_d, int dh) {
    int idx = blockIdx.x * blockDim.x + threadIdx.x;
    if (idx >= T_ * N_ * H_) return;
    int hh = idx & 3, tn = idx >> 2;
    const float* hr = h + (size_t)tn * (H_ * dh) + hh * dh;
    float s = 0.f, d = 0.f;
    for (int k = 0; k < dh; k++) {
        float v = hr[k];
        s += v * a_s[hh * dh + k];
        d += v * a_d[hh * dh + k];
    }
    g_as[idx] = s; g_ad[idx] = d;
}
__global__ void csr_count(const void* ei) {
    int idx = blockIdx.x * blockDim.x + threadIdx.x;
    if (idx >= T_ * E_) return;
    int t = idx / E_, e = idx - t * E_;
    int dst = (int)ld_idx(ei, (size_t)t * 2 * E_ + E_ + e);
    atomicAdd(&g_cnt[t * N_ + dst], 1);
}
__global__ void csr_scan() {
    int t = blockIdx.x, tid = threadIdx.x;
    __shared__ int sh[1024];
    int off = 0;
    for (int chunk = 0; chunk < N_; chunk += 1024) {
        int i = chunk + tid;
        int v = (i < N_) ? g_cnt[t * N_ + i] : 0;
        sh[tid] = v;
        __syncthreads();
        for (int d2 = 1; d2 < 1024; d2 <<= 1) {
            int x = 0;
            if (tid >= d2) x = sh[tid - d2];
            __syncthreads();
            sh[tid] += x;
            __syncthreads();
        }
        if (i < N_) g_rowptr[t * (N_ + 1) + i] = off + sh[tid] - v;
        int tot = sh[1023];
        __syncthreads();
        off += tot;
    }
    if (tid == 0) g_rowptr[t * (N_ + 1) + N_] = off;
}
__global__ void csr_scatter(const void* ei) {
    int idx = blockIdx.x * blockDim.x + threadIdx.x;
    if (idx >= T_ * E_) return;
    int t = idx / E_, e = idx - t * E_;
    int dst = (int)ld_idx(ei, (size_t)t * 2 * E_ + E_ + e);
    int pos = atomicAdd(&g_cursor[t * N_ + dst], 1);
    g_sorted[t * E_ + g_rowptr[t * (N_ + 1) + dst] + pos] = e;
}
__global__ void edge_max(const void* ei) {
    int idx = blockIdx.x * blockDim.x + threadIdx.x;
    if (idx >= T_ * E_) return;
    int t = idx / E_, e = idx - t * E_;
    int src = (int)ld_idx(ei, (size_t)t * 2 * E_ + e);
    int dst = (int)ld_idx(ei, (size_t)t * 2 * E_ + E_ + e);
    float4 s4 = *(const float4*)&g_as[(t * N_ + src) * 4];
    float4 d4 = *(const float4*)&g_ad[(t * N_ + dst) * 4];
    float ev[4] = {s4.x + d4.x, s4.y + d4.y, s4.z + d4.z, s4.w + d4.w};
#pragma unroll
    for (int h = 0; h < 4; h++) {
        float v = ev[h] > 0.f ? ev[h] : 0.2f * ev[h];
        atomicMaxF(&g_m[(t * N_ + dst) * 4 + h], v);
    }
}
__global__ void edge_ex(const void* ei, const float* __restrict__ ew) {
    int idx = blockIdx.x * blockDim.x + threadIdx.x;
    if (idx >= T_ * E_) return;
    int t = idx / E_, e = idx - t * E_;
    int src = (int)ld_idx(ei, (size_t)t * 2 * E_ + e);
    int dst = (int)ld_idx(ei, (size_t)t * 2 * E_ + E_ + e);
    float4 s4 = *(const float4*)&g_as[(t * N_ + src) * 4];
    float4 d4 = *(const float4*)&g_ad[(t * N_ + dst) * 4];
    float4 m4 = *(const float4*)&g_m[(t * N_ + dst) * 4];
    float w = ew[(size_t)t * E_ + e];
    float ev[4] = {s4.x + d4.x, s4.y + d4.y, s4.z + d4.z, s4.w + d4.w};
    float mv[4] = {m4.x, m4.y, m4.z, m4.w};
    float xo[4];
#pragma unroll
    for (int h = 0; h < 4; h++) {
        float v = ev[h] > 0.f ? ev[h] : 0.2f * ev[h];
        float x = expf(v - mv[h]) * w;
        xo[h] = x;
        atomicAdd(&g_den[(t * N_ + dst) * 4 + h], x);
    }
    *(float4*)&g_ex[((size_t)t * E_ + e) * 4] = make_float4(xo[0], xo[1], xo[2], xo[3]);
}
template <int D, int DH>
__global__ void gat_gather(const void* ei, const float* __restrict__ hsrc,
                           float* __restrict__ out, int outStride) {
    int t = blockIdx.y, n = blockIdx.x, tid = threadIdx.x;
    int start = g_rowptr[t * (N_ + 1) + n];
    int end = g_rowptr[t * (N_ + 1) + n + 1];
    int head = tid / DH;
    __shared__ int s_src[64];
    __shared__ float s_ex[64][4];
    float acc = 0.f;
    for (int base = start; base < end; base += 64) {
        int cnt = min(64, end - base);
        __syncthreads();
        for (int i = tid; i < cnt; i += D) {
            int eid = g_sorted[t * E_ + base + i];
            s_src[i] = (int)ld_idx(ei, (size_t)t * 2 * E_ + eid);
            float4 x = *(const float4*)&g_ex[((size_t)t * E_ + eid) * 4];
            s_ex[i][0] = x.x; s_ex[i][1] = x.y; s_ex[i][2] = x.z; s_ex[i][3] = x.w;
        }
        __syncthreads();
#pragma unroll 4
        for (int i = 0; i < cnt; i++)
            acc += s_ex[i][head] * hsrc[((size_t)t * N_ + s_src[i]) * D + tid];
    }
    float dn = g_den[(t * N_ + n) * 4 + head];
    float v = acc / (dn + 1e-16f);
    v = v > 0.f ? v : expf(v) - 1.f;
    out[((size_t)t * N_ + n) * outStride + tid] = v;
}

// ===== meso =====
#define MCHUNK 500
__global__ void meso_acc(const void* part, const float* __restrict__ Dw) {
    int t = blockIdx.y, c0 = blockIdx.x * MCHUNK, tid = threadIdx.x;
    __shared__ float sn[NCOM_ * 64];
    __shared__ float sd[NCOM_];
    __shared__ int sp[MCHUNK];
    __shared__ float sD[MCHUNK];
    for (int i = tid; i < NCOM_ * 64; i += blockDim.x) sn[i] = 0.f;
    for (int i = tid; i < NCOM_; i += blockDim.x) sd[i] = 0.f;
    int nmax = min(MCHUNK, N_ - c0);
    for (int i = tid; i < nmax; i += blockDim.x) {
        sp[i] = (int)ld_idx(part, (size_t)t * N_ + c0 + i);
        sD[i] = Dw[(size_t)t * N_ + c0 + i];
    }
    __syncthreads();
    for (int idx = tid; idx < nmax * 64; idx += blockDim.x) {
        int nl = idx >> 6, c = idx & 63;
        float g = g_agg[((size_t)t * N_ + c0 + nl) * 128 + c];
        atomicAdd(&sn[sp[nl] * 64 + c], sD[nl] * g);
        if (c == 0) atomicAdd(&sd[sp[nl]], sD[nl]);
    }
    __syncthreads();
    for (int i = tid; i < NCOM_ * 64; i += blockDim.x)
        atomicAdd(&g_comnum[t * NCOM_ * 64 + i], sn[i]);
    for (int i = tid; i < NCOM_; i += blockDim.x)
        atomicAdd(&g_comden[t * NCOM_ + i], sd[i]);
}
__global__ void meso_scatter(const void* part) {
    int idx = blockIdx.x * blockDim.x + threadIdx.x;
    if (idx >= T_ * N_ * 64) return;
    int t = idx / (N_ * 64);
    int r = idx - t * N_ * 64;
    int n = r >> 6, c = r & 63;
    int p = (int)ld_idx(part, (size_t)t * N_ + n);
    g_agg[((size_t)t * N_ + n) * 128 + 64 + c] =
        g_comnum[(t * NCOM_ + p) * 64 + c] / (g_comden[t * NCOM_ + p] + 1e-16f);
}

// ===== LSTM pointwise =====
__global__ void lstm_pw(const float* __restrict__ b, int t) {
    int idx = blockIdx.x * blockDim.x + threadIdx.x;
    if (idx >= N_ * 128) return;
    int n = idx >> 7, j = idx & 127;
    const float* z = g_Zx + (size_t)t * N_ * 512 + (size_t)n * 512;
    float i_ = z[j] + b[j];
    float f_ = z[128 + j] + b[128 + j];
    float gg = z[256 + j] + b[256 + j];
    float o_ = z[384 + j] + b[384 + j];
    float c = sigf(f_) * g_cbuf[idx] + sigf(i_) * tanhf(gg);
    g_cbuf[idx] = c;
    g_hbuf[idx] = sigf(o_) * tanhf(c);
}

// ===== decoder prep =====
__global__ void emb_tanh(const float* __restrict__ emb_b) {
    __shared__ float s[64];
    int tid = threadIdx.x;
    if (tid < 64) s[tid] = 0.f;
    __syncthreads();
    int idx = blockIdx.x * 256 + tid;
    if (idx < N_ * 64) {
        int c = idx & 63;
        float v = tanhf(g_embp[idx] + emb_b[c]);
        g_embp[idx] = v;
        atomicAdd(&s[c], v * v);
    }
    __syncthreads();
    if (tid < 64) atomicAdd(&g_colsq[tid], s[tid]);
}
__global__ void build_P(const float* __restrict__ scal_b) {
    int n = blockIdx.x, c = threadIdx.x;
    float e = g_embp[n * 64 + c] / sqrtf(g_colsq[c]);
    float s = sigf(g_scalp[n * 64 + c] + scal_b[c]);
    __nv_bfloat16 eh = __float2bfloat16_rn(e);
    g_ph[n * 128 + c] = eh;
    g_pl[n * 128 + c] = __float2bfloat16_rn(e - __bfloat162float(eh));
    __nv_bfloat16 sh2 = __float2bfloat16_rn(s);
    g_ph[n * 128 + 64 + c] = sh2;
    g_pl[n * 128 + 64 + c] = __float2bfloat16_rn(s - __bfloat162float(sh2));
    float v = e * e;
#pragma unroll
    for (int o = 16; o; o >>= 1) v += __shfl_down_sync(0xffffffff, v, o);
    __shared__ float shm[2];
    if ((c & 31) == 0) shm[c >> 5] = v;
    __syncthreads();
    if (c == 0) g_sq[n] = shm[0] + shm[1];
}

// ===== host =====
extern "C" void kernel_launch(void* const* d_in, const int* in_sizes, int n_in,
                              void* d_out, int out_size) {
    const float* feat   = (const float*)d_in[0];
    const float* ew     = (const float*)d_in[1];
    const float* Dw     = (const float*)d_in[2];
    const float* W1     = (const float*)d_in[3];
    const float* a_s1   = (const float*)d_in[4];
    const float* a_d1   = (const float*)d_in[5];
    const float* W2     = (const float*)d_in[6];
    const float* a_s2   = (const float*)d_in[7];
    const float* a_d2   = (const float*)d_in[8];
    const float* Wx     = (const float*)d_in[9];
    const float* Wh     = (const float*)d_in[10];
    const float* b_lstm = (const float*)d_in[11];
    const float* embW   = (const float*)d_in[12];
    const float* embB   = (const float*)d_in[13];
    const float* scalW  = (const float*)d_in[14];
    const float* scalB  = (const float*)d_in[15];
    const void*  ei     = (const void*)d_in[16];
    const void*  part   = (const void*)d_in[17];
    float* out = (float*)d_out;

    cudaFuncSetAttribute(mma_gemm, cudaFuncAttributeMaxDynamicSharedMemorySize, MG_SMEM);
    cudaFuncSetAttribute(pairwise_mma, cudaFuncAttributeMaxDynamicSharedMemorySize, MG_SMEM);

    float *h1, *g1, *h2, *agg, *m_, *den_, *Zx, *hbuf, *cbuf, *embp, *scalp;
    float *comnum, *comden, *colsq;
    int *cnt, *cursor;
    __nv_bfloat16 *fh, *fl, *hbh, *hbl, *wth, *wtl;
    cudaGetSymbolAddress((void**)&h1, g_h1);
    cudaGetSymbolAddress((void**)&g1, g_g1);
    cudaGetSymbolAddress((void**)&h2, g_h2);
    cudaGetSymbolAddress((void**)&agg, g_agg);
    cudaGetSymbolAddress((void**)&m_, g_m);
    cudaGetSymbolAddress((void**)&den_, g_den);
    cudaGetSymbolAddress((void**)&Zx, g_Zx);
    cudaGetSymbolAddress((void**)&hbuf, g_hbuf);
    cudaGetSymbolAddress((void**)&cbuf, g_cbuf);
    cudaGetSymbolAddress((void**)&embp, g_embp);
    cudaGetSymbolAddress((void**)&scalp, g_scalp);
    cudaGetSymbolAddress((void**)&comnum, g_comnum);
    cudaGetSymbolAddress((void**)&comden, g_comden);
    cudaGetSymbolAddress((void**)&colsq, g_colsq);
    cudaGetSymbolAddress((void**)&cnt, g_cnt);
    cudaGetSymbolAddress((void**)&cursor, g_cursor);
    cudaGetSymbolAddress((void**)&fh, g_fh);
    cudaGetSymbolAddress((void**)&fl, g_fl);
    cudaGetSymbolAddress((void**)&hbh, g_hbh);
    cudaGetSymbolAddress((void**)&hbl, g_hbl);
    cudaGetSymbolAddress((void**)&wth, g_wth);
    cudaGetSymbolAddress((void**)&wtl, g_wtl);

    const int MT = 157;  // ceil(10000/64)
    const int TE = T_ * E_;
    const int TNH = T_ * N_ * H_;
    const int NS8 = T_ * N_ * 128 / 8;
    const int HB8 = N_ * 128 / 8;

    detect64_kernel<<<1, 1>>>((const int*)ei);

    // GAT layer 1
    split8<<<(NS8 + 255) / 256, 256>>>((const float4*)feat, (uint4*)fh, (uint4*)fl, NS8);
    bsplit<<<(128 * 128 + 255) / 256, 256>>>(W1, wth, wtl, 128);
    mma_gemm<<<dim3(MT, 2, 8), 128, MG_SMEM>>>(fh, fl, wth, wtl, h1, N_, 128,
                                               (long long)N_ * 128, (long long)N_ * 128, 0);
    alpha_kernel<<<(TNH + 255) / 256, 256>>>(h1, a_s1, a_d1, 32);

    fill_i<<<(T_ * N_ + 255) / 256, 256>>>(cnt, 0, T_ * N_);
    csr_count<<<(TE + 255) / 256, 256>>>(ei);
    csr_scan<<<T_, 1024>>>();
    fill_i<<<(T_ * N_ + 255) / 256, 256>>>(cursor, 0, T_ * N_);
    csr_scatter<<<(TE + 255) / 256, 256>>>(ei);

    fill_f<<<(TNH + 255) / 256, 256>>>(m_, -INFINITY, TNH);
    fill_f<<<(TNH + 255) / 256, 256>>>(den_, 0.f, TNH);
    edge_max<<<(TE + 255) / 256, 256>>>(ei);
    edge_ex<<<(TE + 255) / 256, 256>>>(ei, ew);
    gat_gather<128, 32><<<dim3(N_, T_), 128>>>(ei, h1, g1, 128);

    // GAT layer 2
    split8<<<(NS8 + 255) / 256, 256>>>((const float4*)g1, (uint4*)fh, (uint4*)fl, NS8);
    bsplit<<<(64 * 128 + 255) / 256, 256>>>(W2, wth, wtl, 64);
    mma_gemm<<<dim3(MT, 1, 8), 128, MG_SMEM>>>(fh, fl, wth, wtl, h2, N_, 64,
                                               (long long)N_ * 128, (long long)N_ * 64, 0);
    alpha_kernel<<<(TNH + 255) / 256, 256>>>(h2, a_s2, a_d2, 16);
    fill_f<<<(TNH + 255) / 256, 256>>>(m_, -INFINITY, TNH);
    fill_f<<<(TNH + 255) / 256, 256>>>(den_, 0.f, TNH);
    edge_max<<<(TE + 255) / 256, 256>>>(ei);
    edge_ex<<<(TE + 255) / 256, 256>>>(ei, ew);
    gat_gather<64, 16><<<dim3(N_, T_), 64>>>(ei, h2, agg, 128);

    // meso
    fill_f<<<(T_ * NCOM_ * 64 + 255) / 256, 256>>>(comnum, 0.f, T_ * NCOM_ * 64);
    fill_f<<<(T_ * NCOM_ + 255) / 256, 256>>>(comden, 0.f, T_ * NCOM_);
    meso_acc<<<dim3((N_ + MCHUNK - 1) / MCHUNK, T_), 256>>>(part, Dw);
    meso_scatter<<<(T_ * N_ * 64 + 255) / 256, 256>>>(part);

    // LSTM
    split8<<<(NS8 + 255) / 256, 256>>>((const float4*)agg, (uint4*)fh, (uint4*)fl, NS8);
    bsplit<<<(512 * 128 + 255) / 256, 256>>>(Wx, wth, wtl, 512);
    mma_gemm<<<dim3(MT, 8, 8), 128, MG_SMEM>>>(fh, fl, wth, wtl, Zx, N_, 512,
                                               (long long)N_ * 128, (long long)N_ * 512, 0);
    bsplit<<<(512 * 128 + 255) / 256, 256>>>(Wh, wth, wtl, 512);
    fill_f<<<(N_ * 128 + 255) / 256, 256>>>(hbuf, 0.f, N_ * 128);
    fill_f<<<(N_ * 128 + 255) / 256, 256>>>(cbuf, 0.f, N_ * 128);
    for (int t = 0; t < T_; t++) {
        if (t > 0) {  // h == 0 at t=0
            split8<<<(HB8 + 255) / 256, 256>>>((const float4*)hbuf, (uint4*)hbh, (uint4*)hbl, HB8);
            mma_gemm<<<dim3(MT, 8, 1), 128, MG_SMEM>>>(hbh, hbl, wth, wtl,
                                                       Zx + (size_t)t * N_ * 512, N_, 512, 0, 0, 1);
        }
        lstm_pw<<<(N_ * 128 + 255) / 256, 256>>>(b_lstm, t);
    }

    // decoder
    split8<<<(HB8 + 255) / 256, 256>>>((const float4*)hbuf, (uint4*)hbh, (uint4*)hbl, HB8);
    bsplit<<<(64 * 128 + 255) / 256, 256>>>(embW, wth, wtl, 64);
    mma_gemm<<<dim3(MT, 1, 1), 128, MG_SMEM>>>(hbh, hbl, wth, wtl, embp, N_, 64, 0, 0, 0);
    bsplit<<<(64 * 128 + 255) / 256, 256>>>(scalW, wth, wtl, 64);
    mma_gemm<<<dim3(MT, 1, 1), 128, MG_SMEM>>>(hbh, hbl, wth, wtl, scalp, N_, 64, 0, 0, 0);
    fill_f<<<1, 64>>>(colsq, 0.f, 64);
    emb_tanh<<<(N_ * 64 + 255) / 256, 256>>>(embB);
    build_P<<<N_, 64>>>(scalB);
    pairwise_mma<<<dim3(MT, MT), 128, MG_SMEM>>>(out);
}

// round 5
// speedup vs baseline: 2.3819x; 1.0850x over previous
#include <cuda_runtime.h>
#include <cuda_bf16.h>
#include <math.h>
#include <stdint.h>

#define T_ 8
#define N_ 10000
#define E_ 320000
#define H_ 4
#define NCOM_ 100

// ===== scratch =====
__device__ int   g_is64;
__device__ __align__(16) float g_h1[(size_t)T_ * N_ * 128];
__device__ __align__(16) float g_g1[(size_t)T_ * N_ * 128];
__device__ __align__(16) float g_h2[(size_t)T_ * N_ * 64];
__device__ __align__(16) float g_agg[(size_t)T_ * N_ * 128];
__device__ __align__(16) float g_as[T_ * N_ * H_];
__device__ __align__(16) float g_ad[T_ * N_ * H_];
__device__ __align__(16) float g_den[T_ * N_ * H_];
__device__ __align__(16) float g_ex[(size_t)T_ * E_ * H_];
__device__ int   g_cnt[T_ * N_];
__device__ int   g_rowptr[T_ * (N_ + 1)];
__device__ int   g_cursor[T_ * N_];
__device__ int   g_sorted[T_ * E_];
__device__ float g_comnum[T_ * NCOM_ * 64];
__device__ float g_comden[T_ * NCOM_];
__device__ __align__(16) float g_Zx[(size_t)T_ * N_ * 512];
__device__ __align__(16) float g_cbuf[N_ * 128];
__device__ __align__(16) float g_embp[N_ * 64];
__device__ __align__(16) float g_scalp[N_ * 64];
__device__ float g_sq[N_];
__device__ float g_colsq[64];
__device__ __align__(16) __nv_bfloat16 g_fh[(size_t)T_ * N_ * 128];
__device__ __align__(16) __nv_bfloat16 g_fl[(size_t)T_ * N_ * 128];
__device__ __align__(16) __nv_bfloat16 g_hbh[N_ * 128];
__device__ __align__(16) __nv_bfloat16 g_hbl[N_ * 128];
__device__ __align__(16) __nv_bfloat16 g_ph[N_ * 128];
__device__ __align__(16) __nv_bfloat16 g_pl[N_ * 128];
__device__ __align__(16) __nv_bfloat16 g_wth[512 * 128];
__device__ __align__(16) __nv_bfloat16 g_wtl[512 * 128];

// ===== helpers =====
__device__ __forceinline__ long long ld_idx(const void* p, size_t i) {
    if (g_is64) return ((const long long*)p)[i];
    return (long long)((const int*)p)[i];
}
__device__ __forceinline__ float sigf(float x) { return 1.f / (1.f + expf(-x)); }
__device__ __forceinline__ float sigf_fast(float x) {
    return __fdividef(1.f, 1.f + __expf(-x));
}
__device__ __forceinline__ float tanh_fast(float x) {
    float e = __expf(2.f * x);
    return 1.f - __fdividef(2.f, e + 1.f);
}
__device__ __forceinline__ void mma16816(float* c, uint32_t a0, uint32_t a1, uint32_t a2,
                                         uint32_t a3, uint32_t b0, uint32_t b1) {
    asm volatile(
        "mma.sync.aligned.m16n8k16.row.col.f32.bf16.bf16.f32 "
        "{%0,%1,%2,%3}, {%4,%5,%6,%7}, {%8,%9}, {%0,%1,%2,%3};"
        : "+f"(c[0]), "+f"(c[1]), "+f"(c[2]), "+f"(c[3])
        : "r"(a0), "r"(a1), "r"(a2), "r"(a3), "r"(b0), "r"(b1));
}

__global__ void detect64_kernel(const int* ei32) {
    int ok = 1;
    for (int i = 1; i < 64; i += 2)
        if (ei32[i] != 0) ok = 0;
    g_is64 = ok;
}
__global__ void fill_f(float* p, float v, int n) {
    int i = blockIdx.x * blockDim.x + threadIdx.x;
    if (i < n) p[i] = v;
}
__global__ void fill_i(int* p, int v, int n) {
    int i = blockIdx.x * blockDim.x + threadIdx.x;
    if (i < n) p[i] = v;
}
__global__ void split8(const float4* __restrict__ x, uint4* __restrict__ hi,
                       uint4* __restrict__ lo, int n8) {
    int i = blockIdx.x * blockDim.x + threadIdx.x;
    if (i >= n8) return;
    float4 a = x[2 * i], b = x[2 * i + 1];
    float v[8] = {a.x, a.y, a.z, a.w, b.x, b.y, b.z, b.w};
    unsigned ho[4], lo4[4];
#pragma unroll
    for (int j = 0; j < 4; j++) {
        __nv_bfloat162 h2 = __floats2bfloat162_rn(v[2 * j], v[2 * j + 1]);
        __nv_bfloat162 l2 = __floats2bfloat162_rn(v[2 * j] - __low2float(h2),
                                                  v[2 * j + 1] - __high2float(h2));
        ho[j] = *reinterpret_cast<unsigned*>(&h2);
        lo4[j] = *reinterpret_cast<unsigned*>(&l2);
    }
    hi[i] = make_uint4(ho[0], ho[1], ho[2], ho[3]);
    lo[i] = make_uint4(lo4[0], lo4[1], lo4[2], lo4[3]);
}
__global__ void bsplit(const float* __restrict__ B, __nv_bfloat16* __restrict__ bth,
                       __nv_bfloat16* __restrict__ btl, int Dn) {
    int idx = blockIdx.x * blockDim.x + threadIdx.x;
    if (idx >= Dn * 128) return;
    int n = idx >> 7, k = idx & 127;
    float v = B[(size_t)k * Dn + n];
    __nv_bfloat16 h = __float2bfloat16_rn(v);
    bth[idx] = h;
    btl[idx] = __float2bfloat16_rn(v - __bfloat162float(h));
}

// ===== MMA GEMM: tile 128x64, 128 threads (4 warps x 32 rows) =====
#define KW 68            // b32 words per smem row (136 bf16, conflict-free)
#define SM_AH 0
#define SM_AL 34816
#define SM_BH 69632
#define SM_BL 87040
#define SM_SQ 104448
#define MG_SMEM 104960

__device__ __forceinline__ void cp_tile(const uint4* __restrict__ G, char* sm, int off,
                                        int base, int Mlim, int tid, int rows) {
#pragma unroll
    for (int i = 0; i < rows * 16; i += 128) {
        int idx = tid + i;
        int row = idx >> 4, c = idx & 15;
        uint4 v = make_uint4(0, 0, 0, 0);
        if (base + row < Mlim) v = G[(size_t)(base + row) * 16 + c];
        ((uint4*)(sm + off))[row * 17 + c] = v;
    }
}

__global__ __launch_bounds__(128) void mma_gemm(
    const __nv_bfloat16* __restrict__ Ah, const __nv_bfloat16* __restrict__ Al,
    const __nv_bfloat16* __restrict__ Bh, const __nv_bfloat16* __restrict__ Bl,
    float* __restrict__ C, int M, int Dn,
    long long sA, long long sC, int accumulate)
{
    extern __shared__ char sm[];
    int tid = threadIdx.x, w = tid >> 5, lane = tid & 31;
    int g = lane >> 2, tq = lane & 3;
    int m0 = blockIdx.x * 128, n0 = blockIdx.y * 64, t = blockIdx.z;
    Ah += (size_t)t * sA; Al += (size_t)t * sA;
    C += (size_t)t * sC;

    cp_tile((const uint4*)Ah, sm, SM_AH, m0, M, tid, 128);
    cp_tile((const uint4*)Al, sm, SM_AL, m0, M, tid, 128);
    cp_tile((const uint4*)Bh, sm, SM_BH, n0, Dn, tid, 64);
    cp_tile((const uint4*)Bl, sm, SM_BL, n0, Dn, tid, 64);
    __syncthreads();

    const uint32_t* SAh = (const uint32_t*)(sm + SM_AH);
    const uint32_t* SAl = (const uint32_t*)(sm + SM_AL);
    const uint32_t* SBh = (const uint32_t*)(sm + SM_BH);
    const uint32_t* SBl = (const uint32_t*)(sm + SM_BL);

    float acc[2][8][4];
#pragma unroll
    for (int gr = 0; gr < 2; gr++)
#pragma unroll
        for (int nb = 0; nb < 8; nb++)
#pragma unroll
            for (int q = 0; q < 4; q++) acc[gr][nb][q] = 0.f;

    int ra0 = (w * 32 + g) * KW;
    int rb0 = ra0 + 8 * KW, ra1 = ra0 + 16 * KW, rb1 = ra0 + 24 * KW;
#pragma unroll
    for (int kc = 0; kc < 8; kc++) {
        int ka = kc * 8 + tq;
        uint32_t ah00 = SAh[ra0 + ka],     ah01 = SAh[rb0 + ka];
        uint32_t ah02 = SAh[ra0 + ka + 4], ah03 = SAh[rb0 + ka + 4];
        uint32_t ah10 = SAh[ra1 + ka],     ah11 = SAh[rb1 + ka];
        uint32_t ah12 = SAh[ra1 + ka + 4], ah13 = SAh[rb1 + ka + 4];
        uint32_t al00 = SAl[ra0 + ka],     al01 = SAl[rb0 + ka];
        uint32_t al02 = SAl[ra0 + ka + 4], al03 = SAl[rb0 + ka + 4];
        uint32_t al10 = SAl[ra1 + ka],     al11 = SAl[rb1 + ka];
        uint32_t al12 = SAl[ra1 + ka + 4], al13 = SAl[rb1 + ka + 4];
#pragma unroll
        for (int nb = 0; nb < 8; nb++) {
            int nrow = (nb * 8 + g) * KW;
            uint32_t bh0 = SBh[nrow + ka], bh1 = SBh[nrow + ka + 4];
            uint32_t bl0 = SBl[nrow + ka], bl1 = SBl[nrow + ka + 4];
            mma16816(acc[0][nb], ah00, ah01, ah02, ah03, bh0, bh1);
            mma16816(acc[0][nb], ah00, ah01, ah02, ah03, bl0, bl1);
            mma16816(acc[0][nb], al00, al01, al02, al03, bh0, bh1);
            mma16816(acc[1][nb], ah10, ah11, ah12, ah13, bh0, bh1);
            mma16816(acc[1][nb], ah10, ah11, ah12, ah13, bl0, bl1);
            mma16816(acc[1][nb], al10, al11, al12, al13, bh0, bh1);
        }
    }

#pragma unroll
    for (int gr = 0; gr < 2; gr++) {
        int r0 = m0 + w * 32 + gr * 16 + g, r1 = r0 + 8;
#pragma unroll
        for (int nb = 0; nb < 8; nb++) {
            int col = n0 + nb * 8 + 2 * tq;
            if (r0 < M) {
                float2* p = (float2*)(C + (size_t)r0 * Dn + col);
                float2 v = make_float2(acc[gr][nb][0], acc[gr][nb][1]);
                if (accumulate) { float2 o = *p; v.x += o.x; v.y += o.y; }
                *p = v;
            }
            if (r1 < M) {
                float2* p = (float2*)(C + (size_t)r1 * Dn + col);
                float2 v = make_float2(acc[gr][nb][2], acc[gr][nb][3]);
                if (accumulate) { float2 o = *p; v.x += o.x; v.y += o.y; }
                *p = v;
            }
        }
    }
}

// ===== pairwise decoder: tile 128(i) x 64(j), symmetric culling =====
__global__ __launch_bounds__(128) void pairwise_mma(float* __restrict__ out) {
    int i0 = blockIdx.y * 128, j0 = blockIdx.x * 64;
    if (j0 + 64 <= i0) return;  // fully below diagonal -> covered by mirror
    extern __shared__ char sm[];
    int tid = threadIdx.x, w = tid >> 5, lane = tid & 31;
    int g = lane >> 2, tq = lane & 3;
    float* sqB = (float*)(sm + SM_SQ);

    cp_tile((const uint4*)g_ph, sm, SM_AH, i0, N_, tid, 128);
    cp_tile((const uint4*)g_pl, sm, SM_AL, i0, N_, tid, 128);
    cp_tile((const uint4*)g_ph, sm, SM_BH, j0, N_, tid, 64);
    cp_tile((const uint4*)g_pl, sm, SM_BL, j0, N_, tid, 64);
    if (tid < 64) sqB[tid] = (j0 + tid < N_) ? g_sq[j0 + tid] : 0.f;
    __syncthreads();

    const uint32_t* SAh = (const uint32_t*)(sm + SM_AH);
    const uint32_t* SAl = (const uint32_t*)(sm + SM_AL);
    const uint32_t* SBh = (const uint32_t*)(sm + SM_BH);
    const uint32_t* SBl = (const uint32_t*)(sm + SM_BL);

    float accG[2][8][4], accS[2][8][4];
#pragma unroll
    for (int gr = 0; gr < 2; gr++)
#pragma unroll
        for (int nb = 0; nb < 8; nb++)
#pragma unroll
            for (int q = 0; q < 4; q++) { accG[gr][nb][q] = 0.f; accS[gr][nb][q] = 0.f; }

    int ra0 = (w * 32 + g) * KW;
    int rb0 = ra0 + 8 * KW, ra1 = ra0 + 16 * KW, rb1 = ra0 + 24 * KW;
#pragma unroll
    for (int kc = 0; kc < 8; kc++) {
        int ka = kc * 8 + tq;
        uint32_t ah00 = SAh[ra0 + ka],     ah01 = SAh[rb0 + ka];
        uint32_t ah02 = SAh[ra0 + ka + 4], ah03 = SAh[rb0 + ka + 4];
        uint32_t ah10 = SAh[ra1 + ka],     ah11 = SAh[rb1 + ka];
        uint32_t ah12 = SAh[ra1 + ka + 4], ah13 = SAh[rb1 + ka + 4];
        uint32_t al00 = SAl[ra0 + ka],     al01 = SAl[rb0 + ka];
        uint32_t al02 = SAl[ra0 + ka + 4], al03 = SAl[rb0 + ka + 4];
        uint32_t al10 = SAl[ra1 + ka],     al11 = SAl[rb1 + ka];
        uint32_t al12 = SAl[ra1 + ka + 4], al13 = SAl[rb1 + ka + 4];
        float (*a0)[4] = (kc < 4) ? accG[0] : accS[0];
        float (*a1)[4] = (kc < 4) ? accG[1] : accS[1];
#pragma unroll
        for (int nb = 0; nb < 8; nb++) {
            int nrow = (nb * 8 + g) * KW;
            uint32_t bh0 = SBh[nrow + ka], bh1 = SBh[nrow + ka + 4];
            uint32_t bl0 = SBl[nrow + ka], bl1 = SBl[nrow + ka + 4];
            mma16816(a0[nb], ah00, ah01, ah02, ah03, bh0, bh1);
            mma16816(a0[nb], ah00, ah01, ah02, ah03, bl0, bl1);
            mma16816(a0[nb], al00, al01, al02, al03, bh0, bh1);
            mma16816(a1[nb], ah10, ah11, ah12, ah13, bh0, bh1);
            mma16816(a1[nb], ah10, ah11, ah12, ah13, bl0, bl1);
            mma16816(a1[nb], al10, al11, al12, al13, bh0, bh1);
        }
    }

    __syncthreads();                 // before reusing A smem for transpose stage
    float* vT = (float*)(sm + SM_AH);  // [64][129]
    bool full = (i0 + 128 <= N_) && (j0 + 64 <= N_);
#pragma unroll
    for (int gr = 0; gr < 2; gr++) {
        int lr0 = w * 32 + gr * 16 + g, lr1 = lr0 + 8;
        int ir0 = i0 + lr0, ir1 = i0 + lr1;
        float sqi0 = (ir0 < N_) ? g_sq[ir0] : 0.f;
        float sqi1 = (ir1 < N_) ? g_sq[ir1] : 0.f;
#pragma unroll
        for (int nb = 0; nb < 8; nb++) {
            int c0 = nb * 8 + 2 * tq, c1 = c0 + 1;
            float sj0 = sqB[c0], sj1 = sqB[c1];
            float v0 = 1.f + tanh_fast((2.f * accG[gr][nb][0] - sqi0 - sj0) * accS[gr][nb][0]);
            float v1 = 1.f + tanh_fast((2.f * accG[gr][nb][1] - sqi0 - sj1) * accS[gr][nb][1]);
            float v2 = 1.f + tanh_fast((2.f * accG[gr][nb][2] - sqi1 - sj0) * accS[gr][nb][2]);
            float v3 = 1.f + tanh_fast((2.f * accG[gr][nb][3] - sqi1 - sj1) * accS[gr][nb][3]);
            if (full) {
                *(float2*)(out + (size_t)ir0 * N_ + j0 + c0) = make_float2(v0, v1);
                *(float2*)(out + (size_t)ir1 * N_ + j0 + c0) = make_float2(v2, v3);
            } else {
                if (ir0 < N_) {
                    if (j0 + c0 < N_) out[(size_t)ir0 * N_ + j0 + c0] = v0;
                    if (j0 + c1 < N_) out[(size_t)ir0 * N_ + j0 + c1] = v1;
                }
                if (ir1 < N_) {
                    if (j0 + c0 < N_) out[(size_t)ir1 * N_ + j0 + c0] = v2;
                    if (j0 + c1 < N_) out[(size_t)ir1 * N_ + j0 + c1] = v3;
                }
            }
            vT[c0 * 129 + lr0] = v0;
            vT[c1 * 129 + lr0] = v1;
            vT[c0 * 129 + lr1] = v2;
            vT[c1 * 129 + lr1] = v3;
        }
    }
    __syncthreads();
    // mirror: write (jj, ii) for strict lower cells jj > ii
    for (int idx = tid; idx < 64 * 128; idx += 128) {
        int r2 = idx >> 7, c2 = idx & 127;
        int jj = j0 + r2, ii = i0 + c2;
        if (jj > ii && jj < N_ && ii < N_) out[(size_t)jj * N_ + ii] = vT[r2 * 129 + c2];
    }
}

// ===== GAT kernels =====
__global__ void alpha_kernel(const float* __restrict__ h, const float* __restrict__ a_s,
                             const float* __restrict__ a_d, int dh) {
    int idx = blockIdx.x * blockDim.x + threadIdx.x;
    if (idx >= T_ * N_ * H_) return;
    int hh = idx & 3, tn = idx >> 2;
    const float* hr = h + (size_t)tn * (H_ * dh) + hh * dh;
    float s = 0.f, d = 0.f;
    for (int k = 0; k < dh; k++) {
        float v = hr[k];
        s += v * a_s[hh * dh + k];
        d += v * a_d[hh * dh + k];
    }
    g_as[idx] = s; g_ad[idx] = d;
}
__global__ void csr_count(const void* ei) {
    int idx = blockIdx.x * blockDim.x + threadIdx.x;
    if (idx >= T_ * E_) return;
    int t = idx / E_, e = idx - t * E_;
    int dst = (int)ld_idx(ei, (size_t)t * 2 * E_ + E_ + e);
    atomicAdd(&g_cnt[t * N_ + dst], 1);
}
__global__ void csr_scan() {
    int t = blockIdx.x, tid = threadIdx.x;
    __shared__ int sh[1024];
    int off = 0;
    for (int chunk = 0; chunk < N_; chunk += 1024) {
        int i = chunk + tid;
        int v = (i < N_) ? g_cnt[t * N_ + i] : 0;
        sh[tid] = v;
        __syncthreads();
        for (int d2 = 1; d2 < 1024; d2 <<= 1) {
            int x = 0;
            if (tid >= d2) x = sh[tid - d2];
            __syncthreads();
            sh[tid] += x;
            __syncthreads();
        }
        if (i < N_) g_rowptr[t * (N_ + 1) + i] = off + sh[tid] - v;
        int tot = sh[1023];
        __syncthreads();
        off += tot;
    }
    if (tid == 0) g_rowptr[t * (N_ + 1) + N_] = off;
}
__global__ void csr_scatter(const void* ei) {
    int idx = blockIdx.x * blockDim.x + threadIdx.x;
    if (idx >= T_ * E_) return;
    int t = idx / E_, e = idx - t * E_;
    int dst = (int)ld_idx(ei, (size_t)t * 2 * E_ + E_ + e);
    int pos = atomicAdd(&g_cursor[t * N_ + dst], 1);
    g_sorted[t * E_ + g_rowptr[t * (N_ + 1) + dst] + pos] = e;
}
// softmax max cancels in num/den -> skip it entirely
__global__ void edge_ex(const void* ei, const float* __restrict__ ew) {
    int idx = blockIdx.x * blockDim.x + threadIdx.x;
    if (idx >= T_ * E_) return;
    int t = idx / E_, e = idx - t * E_;
    int src = (int)ld_idx(ei, (size_t)t * 2 * E_ + e);
    int dst = (int)ld_idx(ei, (size_t)t * 2 * E_ + E_ + e);
    float4 s4 = *(const float4*)&g_as[(t * N_ + src) * 4];
    float4 d4 = *(const float4*)&g_ad[(t * N_ + dst) * 4];
    float w = ew[(size_t)t * E_ + e];
    float ev[4] = {s4.x + d4.x, s4.y + d4.y, s4.z + d4.z, s4.w + d4.w};
    float xo[4];
#pragma unroll
    for (int h = 0; h < 4; h++) {
        float v = ev[h] > 0.f ? ev[h] : 0.2f * ev[h];
        float x = __expf(v) * w;
        xo[h] = x;
        atomicAdd(&g_den[(t * N_ + dst) * 4 + h], x);
    }
    *(float4*)&g_ex[((size_t)t * E_ + e) * 4] = make_float4(xo[0], xo[1], xo[2], xo[3]);
}
template <int D, int DH>
__global__ void gat_gather(const void* ei, const float* __restrict__ hsrc,
                           float* __restrict__ out, int outStride) {
    int t = blockIdx.y, n = blockIdx.x, tid = threadIdx.x;
    int start = g_rowptr[t * (N_ + 1) + n];
    int end = g_rowptr[t * (N_ + 1) + n + 1];
    int head = tid / DH;
    __shared__ int s_src[64];
    __shared__ float s_ex[64][4];
    float acc = 0.f;
    for (int base = start; base < end; base += 64) {
        int cnt = min(64, end - base);
        __syncthreads();
        for (int i = tid; i < cnt; i += D) {
            int eid = g_sorted[t * E_ + base + i];
            s_src[i] = (int)ld_idx(ei, (size_t)t * 2 * E_ + eid);
            float4 x = *(const float4*)&g_ex[((size_t)t * E_ + eid) * 4];
            s_ex[i][0] = x.x; s_ex[i][1] = x.y; s_ex[i][2] = x.z; s_ex[i][3] = x.w;
        }
        __syncthreads();
#pragma unroll 8
        for (int i = 0; i < cnt; i++)
            acc += s_ex[i][head] * hsrc[((size_t)t * N_ + s_src[i]) * D + tid];
    }
    float dn = g_den[(t * N_ + n) * 4 + head];
    float v = acc / (dn + 1e-16f);
    v = v > 0.f ? v : __expf(v) - 1.f;
    out[((size_t)t * N_ + n) * outStride + tid] = v;
}

// ===== meso =====
#define MCHUNK 500
__global__ void meso_acc(const void* part, const float* __restrict__ Dw) {
    int t = blockIdx.y, c0 = blockIdx.x * MCHUNK, tid = threadIdx.x;
    __shared__ float sn[NCOM_ * 64];
    __shared__ float sd[NCOM_];
    __shared__ int sp[MCHUNK];
    __shared__ float sD[MCHUNK];
    for (int i = tid; i < NCOM_ * 64; i += blockDim.x) sn[i] = 0.f;
    for (int i = tid; i < NCOM_; i += blockDim.x) sd[i] = 0.f;
    int nmax = min(MCHUNK, N_ - c0);
    for (int i = tid; i < nmax; i += blockDim.x) {
        sp[i] = (int)ld_idx(part, (size_t)t * N_ + c0 + i);
        sD[i] = Dw[(size_t)t * N_ + c0 + i];
    }
    __syncthreads();
    for (int idx = tid; idx < nmax * 64; idx += blockDim.x) {
        int nl = idx >> 6, c = idx & 63;
        float g = g_agg[((size_t)t * N_ + c0 + nl) * 128 + c];
        atomicAdd(&sn[sp[nl] * 64 + c], sD[nl] * g);
        if (c == 0) atomicAdd(&sd[sp[nl]], sD[nl]);
    }
    __syncthreads();
    for (int i = tid; i < NCOM_ * 64; i += blockDim.x)
        atomicAdd(&g_comnum[t * NCOM_ * 64 + i], sn[i]);
    for (int i = tid; i < NCOM_; i += blockDim.x)
        atomicAdd(&g_comden[t * NCOM_ + i], sd[i]);
}
__global__ void meso_scatter(const void* part) {
    int idx = blockIdx.x * blockDim.x + threadIdx.x;
    if (idx >= T_ * N_ * 64) return;
    int t = idx / (N_ * 64);
    int r = idx - t * N_ * 64;
    int n = r >> 6, c = r & 63;
    int p = (int)ld_idx(part, (size_t)t * N_ + n);
    g_agg[((size_t)t * N_ + n) * 128 + 64 + c] =
        g_comnum[(t * NCOM_ + p) * 64 + c] / (g_comden[t * NCOM_ + p] + 1e-16f);
}

// ===== LSTM pointwise (fast math + fused bf16 split of h) =====
__global__ void lstm_pw(const float* __restrict__ b, int t) {
    int idx = blockIdx.x * blockDim.x + threadIdx.x;
    if (idx >= N_ * 128) return;
    int n = idx >> 7, j = idx & 127;
    const float* z = g_Zx + (size_t)t * N_ * 512 + (size_t)n * 512;
    float i_ = z[j] + b[j];
    float f_ = z[128 + j] + b[128 + j];
    float gg = z[256 + j] + b[256 + j];
    float o_ = z[384 + j] + b[384 + j];
    float c = sigf_fast(f_) * g_cbuf[idx] + sigf_fast(i_) * tanh_fast(gg);
    g_cbuf[idx] = c;
    float h = sigf_fast(o_) * tanh_fast(c);
    __nv_bfloat16 hh = __float2bfloat16_rn(h);
    g_hbh[idx] = hh;
    g_hbl[idx] = __float2bfloat16_rn(h - __bfloat162float(hh));
}

// ===== decoder prep =====
__global__ void emb_tanh(const float* __restrict__ emb_b) {
    __shared__ float s[64];
    int tid = threadIdx.x;
    if (tid < 64) s[tid] = 0.f;
    __syncthreads();
    int idx = blockIdx.x * 256 + tid;
    if (idx < N_ * 64) {
        int c = idx & 63;
        float v = tanhf(g_embp[idx] + emb_b[c]);
        g_embp[idx] = v;
        atomicAdd(&s[c], v * v);
    }
    __syncthreads();
    if (tid < 64) atomicAdd(&g_colsq[tid], s[tid]);
}
__global__ void build_P(const float* __restrict__ scal_b) {
    int n = blockIdx.x, c = threadIdx.x;
    float e = g_embp[n * 64 + c] / sqrtf(g_colsq[c]);
    float s = sigf(g_scalp[n * 64 + c] + scal_b[c]);
    __nv_bfloat16 eh = __float2bfloat16_rn(e);
    g_ph[n * 128 + c] = eh;
    g_pl[n * 128 + c] = __float2bfloat16_rn(e - __bfloat162float(eh));
    __nv_bfloat16 sh2 = __float2bfloat16_rn(s);
    g_ph[n * 128 + 64 + c] = sh2;
    g_pl[n * 128 + 64 + c] = __float2bfloat16_rn(s - __bfloat162float(sh2));
    float v = e * e;
#pragma unroll
    for (int o = 16; o; o >>= 1) v += __shfl_down_sync(0xffffffff, v, o);
    __shared__ float shm[2];
    if ((c & 31) == 0) shm[c >> 5] = v;
    __syncthreads();
    if (c == 0) g_sq[n] = shm[0] + shm[1];
}

// ===== host =====
extern "C" void kernel_launch(void* const* d_in, const int* in_sizes, int n_in,
                              void* d_out, int out_size) {
    const float* feat   = (const float*)d_in[0];
    const float* ew     = (const float*)d_in[1];
    const float* Dw     = (const float*)d_in[2];
    const float* W1     = (const float*)d_in[3];
    const float* a_s1   = (const float*)d_in[4];
    const float* a_d1   = (const float*)d_in[5];
    const float* W2     = (const float*)d_in[6];
    const float* a_s2   = (const float*)d_in[7];
    const float* a_d2   = (const float*)d_in[8];
    const float* Wx     = (const float*)d_in[9];
    const float* Wh     = (const float*)d_in[10];
    const float* b_lstm = (const float*)d_in[11];
    const float* embW   = (const float*)d_in[12];
    const float* embB   = (const float*)d_in[13];
    const float* scalW  = (const float*)d_in[14];
    const float* scalB  = (const float*)d_in[15];
    const void*  ei     = (const void*)d_in[16];
    const void*  part   = (const void*)d_in[17];
    float* out = (float*)d_out;

    cudaFuncSetAttribute(mma_gemm, cudaFuncAttributeMaxDynamicSharedMemorySize, MG_SMEM);
    cudaFuncSetAttribute(pairwise_mma, cudaFuncAttributeMaxDynamicSharedMemorySize, MG_SMEM);

    float *h1, *g1, *h2, *agg, *den_, *Zx, *cbuf, *embp, *scalp;
    float *comnum, *comden, *colsq;
    int *cnt, *cursor;
    __nv_bfloat16 *fh, *fl, *hbh, *hbl, *wth, *wtl;
    cudaGetSymbolAddress((void**)&h1, g_h1);
    cudaGetSymbolAddress((void**)&g1, g_g1);
    cudaGetSymbolAddress((void**)&h2, g_h2);
    cudaGetSymbolAddress((void**)&agg, g_agg);
    cudaGetSymbolAddress((void**)&den_, g_den);
    cudaGetSymbolAddress((void**)&Zx, g_Zx);
    cudaGetSymbolAddress((void**)&cbuf, g_cbuf);
    cudaGetSymbolAddress((void**)&embp, g_embp);
    cudaGetSymbolAddress((void**)&scalp, g_scalp);
    cudaGetSymbolAddress((void**)&comnum, g_comnum);
    cudaGetSymbolAddress((void**)&comden, g_comden);
    cudaGetSymbolAddress((void**)&colsq, g_colsq);
    cudaGetSymbolAddress((void**)&cnt, g_cnt);
    cudaGetSymbolAddress((void**)&cursor, g_cursor);
    cudaGetSymbolAddress((void**)&fh, g_fh);
    cudaGetSymbolAddress((void**)&fl, g_fl);
    cudaGetSymbolAddress((void**)&hbh, g_hbh);
    cudaGetSymbolAddress((void**)&hbl, g_hbl);
    cudaGetSymbolAddress((void**)&wth, g_wth);
    cudaGetSymbolAddress((void**)&wtl, g_wtl);

    const int MT = 79;   // ceil(10000/128)
    const int JT = 157;  // ceil(10000/64)
    const int TE = T_ * E_;
    const int TNH = T_ * N_ * H_;
    const int NS8 = T_ * N_ * 128 / 8;

    detect64_kernel<<<1, 1>>>((const int*)ei);

    // GAT layer 1
    split8<<<(NS8 + 255) / 256, 256>>>((const float4*)feat, (uint4*)fh, (uint4*)fl, NS8);
    bsplit<<<(128 * 128 + 255) / 256, 256>>>(W1, wth, wtl, 128);
    mma_gemm<<<dim3(MT, 2, 8), 128, MG_SMEM>>>(fh, fl, wth, wtl, h1, N_, 128,
                                               (long long)N_ * 128, (long long)N_ * 128, 0);
    alpha_kernel<<<(TNH + 255) / 256, 256>>>(h1, a_s1, a_d1, 32);

    fill_i<<<(T_ * N_ + 255) / 256, 256>>>(cnt, 0, T_ * N_);
    csr_count<<<(TE + 255) / 256, 256>>>(ei);
    csr_scan<<<T_, 1024>>>();
    fill_i<<<(T_ * N_ + 255) / 256, 256>>>(cursor, 0, T_ * N_);
    csr_scatter<<<(TE + 255) / 256, 256>>>(ei);

    fill_f<<<(TNH + 255) / 256, 256>>>(den_, 0.f, TNH);
    edge_ex<<<(TE + 255) / 256, 256>>>(ei, ew);
    gat_gather<128, 32><<<dim3(N_, T_), 128>>>(ei, h1, g1, 128);

    // GAT layer 2
    split8<<<(NS8 + 255) / 256, 256>>>((const float4*)g1, (uint4*)fh, (uint4*)fl, NS8);
    bsplit<<<(64 * 128 + 255) / 256, 256>>>(W2, wth, wtl, 64);
    mma_gemm<<<dim3(MT, 1, 8), 128, MG_SMEM>>>(fh, fl, wth, wtl, h2, N_, 64,
                                               (long long)N_ * 128, (long long)N_ * 64, 0);
    alpha_kernel<<<(TNH + 255) / 256, 256>>>(h2, a_s2, a_d2, 16);
    fill_f<<<(TNH + 255) / 256, 256>>>(den_, 0.f, TNH);
    edge_ex<<<(TE + 255) / 256, 256>>>(ei, ew);
    gat_gather<64, 16><<<dim3(N_, T_), 64>>>(ei, h2, agg, 128);

    // meso
    fill_f<<<(T_ * NCOM_ * 64 + 255) / 256, 256>>>(comnum, 0.f, T_ * NCOM_ * 64);
    fill_f<<<(T_ * NCOM_ + 255) / 256, 256>>>(comden, 0.f, T_ * NCOM_);
    meso_acc<<<dim3((N_ + MCHUNK - 1) / MCHUNK, T_), 256>>>(part, Dw);
    meso_scatter<<<(T_ * N_ * 64 + 255) / 256, 256>>>(part);

    // LSTM
    split8<<<(NS8 + 255) / 256, 256>>>((const float4*)agg, (uint4*)fh, (uint4*)fl, NS8);
    bsplit<<<(512 * 128 + 255) / 256, 256>>>(Wx, wth, wtl, 512);
    mma_gemm<<<dim3(MT, 8, 8), 128, MG_SMEM>>>(fh, fl, wth, wtl, Zx, N_, 512,
                                               (long long)N_ * 128, (long long)N_ * 512, 0);
    bsplit<<<(512 * 128 + 255) / 256, 256>>>(Wh, wth, wtl, 512);
    fill_f<<<(N_ * 128 + 255) / 256, 256>>>(cbuf, 0.f, N_ * 128);
    for (int t = 0; t < T_; t++) {
        if (t > 0) {  // h == 0 at t=0; hbh/hbl written by previous lstm_pw
            mma_gemm<<<dim3(MT, 8, 1), 128, MG_SMEM>>>(hbh, hbl, wth, wtl,
                                                       Zx + (size_t)t * N_ * 512, N_, 512, 0, 0, 1);
        }
        lstm_pw<<<(N_ * 128 + 255) / 256, 256>>>(b_lstm, t);
    }

    // decoder (hbh/hbl hold h_last split)
    bsplit<<<(64 * 128 + 255) / 256, 256>>>(embW, wth, wtl, 64);
    mma_gemm<<<dim3(MT, 1, 1), 128, MG_SMEM>>>(hbh, hbl, wth, wtl, embp, N_, 64, 0, 0, 0);
    bsplit<<<(64 * 128 + 255) / 256, 256>>>(scalW, wth, wtl, 64);
    mma_gemm<<<dim3(MT, 1, 1), 128, MG_SMEM>>>(hbh, hbl, wth, wtl, scalp, N_, 64, 0, 0, 0);
    fill_f<<<1, 64>>>(colsq, 0.f, 64);
    emb_tanh<<<(N_ * 64 + 255) / 256, 256>>>(embB);
    build_P<<<N_, 64>>>(scalB);
    pairwise_mma<<<dim3(JT, MT), 128, MG_SMEM>>>(out);
}

// round 6
// speedup vs baseline: 2.6933x; 1.1307x over previous
#include <cuda_runtime.h>
#include <cuda_bf16.h>
#include <math.h>
#include <stdint.h>

#define T_ 8
#define N_ 10000
#define E_ 320000
#define H_ 4
#define NCOM_ 100

// ===== scratch =====
__device__ int   g_is64;
__device__ __align__(16) float g_h1[(size_t)T_ * N_ * 128];
__device__ __align__(16) float g_h2[(size_t)T_ * N_ * 64];
__device__ __align__(16) float g_agg[(size_t)T_ * N_ * 128];   // fp32, cols 0-63 used by meso
__device__ __align__(16) float g_as[T_ * N_ * H_];
__device__ __align__(16) float g_ad[T_ * N_ * H_];
__device__ int   g_cnt[T_ * N_];
__device__ int   g_rowptr[T_ * (N_ + 1)];
__device__ int   g_cursor[T_ * N_];
__device__ int   g_sorted[T_ * E_];
__device__ float g_comnum[T_ * NCOM_ * 64];
__device__ float g_comden[T_ * NCOM_];
__device__ __align__(16) float g_Zx[(size_t)T_ * N_ * 512];
__device__ __align__(16) float g_cbuf[N_ * 128];
__device__ __align__(16) float g_embp[N_ * 64];
__device__ __align__(16) float g_scalp[N_ * 64];
__device__ float g_sq[N_];
__device__ float g_colsq[64];
__device__ __align__(16) __nv_bfloat16 g_fh[(size_t)T_ * N_ * 128];   // universal A-split hi
__device__ __align__(16) __nv_bfloat16 g_fl[(size_t)T_ * N_ * 128];   // universal A-split lo
__device__ __align__(16) __nv_bfloat16 g_hbh[N_ * 128];
__device__ __align__(16) __nv_bfloat16 g_hbl[N_ * 128];
__device__ __align__(16) __nv_bfloat16 g_ph[N_ * 128];
__device__ __align__(16) __nv_bfloat16 g_pl[N_ * 128];
__device__ __align__(16) __nv_bfloat16 g_wth[512 * 128];
__device__ __align__(16) __nv_bfloat16 g_wtl[512 * 128];

// ===== helpers =====
__device__ __forceinline__ long long ld_idx(const void* p, size_t i) {
    if (g_is64) return ((const long long*)p)[i];
    return (long long)((const int*)p)[i];
}
__device__ __forceinline__ float sigf(float x) { return 1.f / (1.f + expf(-x)); }
__device__ __forceinline__ float sigf_fast(float x) {
    return __fdividef(1.f, 1.f + __expf(-x));
}
__device__ __forceinline__ float tanh_fast(float x) {
    float e = __expf(2.f * x);
    return 1.f - __fdividef(2.f, e + 1.f);
}
__device__ __forceinline__ float tanh_hw(float x) {
    float y;
    asm("tanh.approx.f32 %0, %1;" : "=f"(y) : "f"(x));
    return y;
}
__device__ __forceinline__ void mma16816(float* c, uint32_t a0, uint32_t a1, uint32_t a2,
                                         uint32_t a3, uint32_t b0, uint32_t b1) {
    asm volatile(
        "mma.sync.aligned.m16n8k16.row.col.f32.bf16.bf16.f32 "
        "{%0,%1,%2,%3}, {%4,%5,%6,%7}, {%8,%9}, {%0,%1,%2,%3};"
        : "+f"(c[0]), "+f"(c[1]), "+f"(c[2]), "+f"(c[3])
        : "r"(a0), "r"(a1), "r"(a2), "r"(a3), "r"(b0), "r"(b1));
}

__global__ void detect64_kernel(const int* ei32) {
    int ok = 1;
    for (int i = 1; i < 64; i += 2)
        if (ei32[i] != 0) ok = 0;
    g_is64 = ok;
}
__global__ void fill_f(float* p, float v, int n) {
    int i = blockIdx.x * blockDim.x + threadIdx.x;
    if (i < n) p[i] = v;
}
__global__ void fill_i(int* p, int v, int n) {
    int i = blockIdx.x * blockDim.x + threadIdx.x;
    if (i < n) p[i] = v;
}
__global__ void split8(const float4* __restrict__ x, uint4* __restrict__ hi,
                       uint4* __restrict__ lo, int n8) {
    int i = blockIdx.x * blockDim.x + threadIdx.x;
    if (i >= n8) return;
    float4 a = x[2 * i], b = x[2 * i + 1];
    float v[8] = {a.x, a.y, a.z, a.w, b.x, b.y, b.z, b.w};
    unsigned ho[4], lo4[4];
#pragma unroll
    for (int j = 0; j < 4; j++) {
        __nv_bfloat162 h2 = __floats2bfloat162_rn(v[2 * j], v[2 * j + 1]);
        __nv_bfloat162 l2 = __floats2bfloat162_rn(v[2 * j] - __low2float(h2),
                                                  v[2 * j + 1] - __high2float(h2));
        ho[j] = *reinterpret_cast<unsigned*>(&h2);
        lo4[j] = *reinterpret_cast<unsigned*>(&l2);
    }
    hi[i] = make_uint4(ho[0], ho[1], ho[2], ho[3]);
    lo[i] = make_uint4(lo4[0], lo4[1], lo4[2], lo4[3]);
}
__global__ void bsplit(const float* __restrict__ B, __nv_bfloat16* __restrict__ bth,
                       __nv_bfloat16* __restrict__ btl, int Dn) {
    int idx = blockIdx.x * blockDim.x + threadIdx.x;
    if (idx >= Dn * 128) return;
    int n = idx >> 7, k = idx & 127;
    float v = B[(size_t)k * Dn + n];
    __nv_bfloat16 h = __float2bfloat16_rn(v);
    bth[idx] = h;
    btl[idx] = __float2bfloat16_rn(v - __bfloat162float(h));
}

// ===== MMA GEMM: tile 64x64, interleaved hi/lo smem (u64 unit = {hi,lo}) =====
// u64 row stride 68 -> lane u64-index = 4g + tq (mod 32): conflict-free.
#define TILEBUF (64 * 68 * 8)     // 34816 bytes per tile buffer
#define SM_A 0
#define SM_B TILEBUF
#define SM_SQ (2 * TILEBUF)
#define MG_SMEM (2 * TILEBUF + 512)

__device__ __forceinline__ void cp_tile_int(const uint4* __restrict__ Gh,
                                            const uint4* __restrict__ Gl,
                                            char* sm, int off, int base, int Mlim, int tid) {
#pragma unroll
    for (int i = 0; i < 8; i++) {
        int idx = tid + i * 128;            // 0..1023
        int row = idx >> 4, c = idx & 15;   // 64 rows x 16 uint4 chunks
        uint4 vh = make_uint4(0, 0, 0, 0), vl = vh;
        if (base + row < Mlim) {
            vh = Gh[(size_t)(base + row) * 16 + c];
            vl = Gl[(size_t)(base + row) * 16 + c];
        }
        uint4 p0 = make_uint4(vh.x, vl.x, vh.y, vl.y);
        uint4 p1 = make_uint4(vh.z, vl.z, vh.w, vl.w);
        uint4* dst = (uint4*)(sm + off) + ((row * 68 + 4 * c) >> 1);
        dst[0] = p0;
        dst[1] = p1;
    }
}

__global__ __launch_bounds__(128) void mma_gemm(
    const __nv_bfloat16* __restrict__ Ah, const __nv_bfloat16* __restrict__ Al,
    const __nv_bfloat16* __restrict__ Bh, const __nv_bfloat16* __restrict__ Bl,
    float* __restrict__ C, int M, int Dn,
    long long sA, long long sC, int accumulate)
{
    extern __shared__ char sm[];
    int tid = threadIdx.x, w = tid >> 5, lane = tid & 31;
    int g = lane >> 2, tq = lane & 3;
    int m0 = blockIdx.x * 64, n0 = blockIdx.y * 64, t = blockIdx.z;
    Ah += (size_t)t * sA; Al += (size_t)t * sA;
    C += (size_t)t * sC;

    cp_tile_int((const uint4*)Ah, (const uint4*)Al, sm, SM_A, m0, M, tid);
    cp_tile_int((const uint4*)Bh, (const uint4*)Bl, sm, SM_B, n0, Dn, tid);
    __syncthreads();

    const uint2* SA = (const uint2*)(sm + SM_A);
    const uint2* SB = (const uint2*)(sm + SM_B);

    float acc[8][4];
#pragma unroll
    for (int nb = 0; nb < 8; nb++)
#pragma unroll
        for (int q = 0; q < 4; q++) acc[nb][q] = 0.f;

    int ra = (w * 16 + g) * 68, rb = ra + 8 * 68;
#pragma unroll
    for (int kc = 0; kc < 8; kc++) {
        int ka = kc * 8 + tq;
        uint2 A0 = SA[ra + ka], A1 = SA[rb + ka];
        uint2 A2 = SA[ra + ka + 4], A3 = SA[rb + ka + 4];
#pragma unroll
        for (int nb = 0; nb < 8; nb++) {
            int nr = (nb * 8 + g) * 68;
            uint2 B0 = SB[nr + ka], B1 = SB[nr + ka + 4];
            mma16816(acc[nb], A0.x, A1.x, A2.x, A3.x, B0.x, B1.x);
            mma16816(acc[nb], A0.x, A1.x, A2.x, A3.x, B0.y, B1.y);
            mma16816(acc[nb], A0.y, A1.y, A2.y, A3.y, B0.x, B1.x);
        }
    }

    int r0 = m0 + w * 16 + g, r1 = r0 + 8;
#pragma unroll
    for (int nb = 0; nb < 8; nb++) {
        int col = n0 + nb * 8 + 2 * tq;
        if (r0 < M) {
            float2* p = (float2*)(C + (size_t)r0 * Dn + col);
            float2 v = make_float2(acc[nb][0], acc[nb][1]);
            if (accumulate) { float2 o = *p; v.x += o.x; v.y += o.y; }
            *p = v;
        }
        if (r1 < M) {
            float2* p = (float2*)(C + (size_t)r1 * Dn + col);
            float2 v = make_float2(acc[nb][2], acc[nb][3]);
            if (accumulate) { float2 o = *p; v.x += o.x; v.y += o.y; }
            *p = v;
        }
    }
}

// ===== pairwise decoder: 64x64 tiles, symmetric (bi<=bj), G=k0-63, S=k64-127 =====
__global__ __launch_bounds__(128) void pairwise_mma(float* __restrict__ out) {
    int bi = blockIdx.y, bj = blockIdx.x;
    if (bi > bj) return;
    extern __shared__ char sm[];
    int tid = threadIdx.x, w = tid >> 5, lane = tid & 31;
    int g = lane >> 2, tq = lane & 3;
    int i0 = bi * 64, j0 = bj * 64;
    float* sqB = (float*)(sm + SM_SQ);

    cp_tile_int((const uint4*)g_ph, (const uint4*)g_pl, sm, SM_A, i0, N_, tid);
    cp_tile_int((const uint4*)g_ph, (const uint4*)g_pl, sm, SM_B, j0, N_, tid);
    if (tid < 64) sqB[tid] = (j0 + tid < N_) ? g_sq[j0 + tid] : 0.f;
    __syncthreads();

    const uint2* SA = (const uint2*)(sm + SM_A);
    const uint2* SB = (const uint2*)(sm + SM_B);

    float accG[8][4], accS[8][4];
#pragma unroll
    for (int nb = 0; nb < 8; nb++)
#pragma unroll
        for (int q = 0; q < 4; q++) { accG[nb][q] = 0.f; accS[nb][q] = 0.f; }

    int ra = (w * 16 + g) * 68, rb = ra + 8 * 68;
#pragma unroll
    for (int kc = 0; kc < 8; kc++) {
        int ka = kc * 8 + tq;
        uint2 A0 = SA[ra + ka], A1 = SA[rb + ka];
        uint2 A2 = SA[ra + ka + 4], A3 = SA[rb + ka + 4];
        float (*acc)[4] = (kc < 4) ? accG : accS;
#pragma unroll
        for (int nb = 0; nb < 8; nb++) {
            int nr = (nb * 8 + g) * 68;
            uint2 B0 = SB[nr + ka], B1 = SB[nr + ka + 4];
            mma16816(acc[nb], A0.x, A1.x, A2.x, A3.x, B0.x, B1.x);
            mma16816(acc[nb], A0.x, A1.x, A2.x, A3.x, B0.y, B1.y);
            mma16816(acc[nb], A0.y, A1.y, A2.y, A3.y, B0.x, B1.x);
        }
    }

    int lr0 = w * 16 + g, lr1 = lr0 + 8;
    int ir0 = i0 + lr0, ir1 = i0 + lr1;
    float sqi0 = (ir0 < N_) ? g_sq[ir0] : 0.f;
    float sqi1 = (ir1 < N_) ? g_sq[ir1] : 0.f;

    float vv[8][4];
#pragma unroll
    for (int nb = 0; nb < 8; nb++) {
        int c0 = nb * 8 + 2 * tq, c1 = c0 + 1;
        float sj0 = sqB[c0], sj1 = sqB[c1];
        vv[nb][0] = 1.f + tanh_hw((2.f * accG[nb][0] - sqi0 - sj0) * accS[nb][0]);
        vv[nb][1] = 1.f + tanh_hw((2.f * accG[nb][1] - sqi0 - sj1) * accS[nb][1]);
        vv[nb][2] = 1.f + tanh_hw((2.f * accG[nb][2] - sqi1 - sj0) * accS[nb][2]);
        vv[nb][3] = 1.f + tanh_hw((2.f * accG[nb][3] - sqi1 - sj1) * accS[nb][3]);
    }

    bool full = (i0 + 64 <= N_) && (j0 + 64 <= N_);
#pragma unroll
    for (int nb = 0; nb < 8; nb++) {
        int c0 = nb * 8 + 2 * tq;
        if (full) {
            *(float2*)(out + (size_t)ir0 * N_ + j0 + c0) = make_float2(vv[nb][0], vv[nb][1]);
            *(float2*)(out + (size_t)ir1 * N_ + j0 + c0) = make_float2(vv[nb][2], vv[nb][3]);
        } else {
            if (ir0 < N_) {
                if (j0 + c0 < N_)     out[(size_t)ir0 * N_ + j0 + c0] = vv[nb][0];
                if (j0 + c0 + 1 < N_) out[(size_t)ir0 * N_ + j0 + c0 + 1] = vv[nb][1];
            }
            if (ir1 < N_) {
                if (j0 + c0 < N_)     out[(size_t)ir1 * N_ + j0 + c0] = vv[nb][2];
                if (j0 + c0 + 1 < N_) out[(size_t)ir1 * N_ + j0 + c0 + 1] = vv[nb][3];
            }
        }
    }

    if (bi != bj) {
        __syncthreads();
        float* vT = (float*)(sm + SM_A);  // [64][65]
#pragma unroll
        for (int nb = 0; nb < 8; nb++) {
            int c0 = nb * 8 + 2 * tq, c1 = c0 + 1;
            vT[c0 * 65 + lr0] = vv[nb][0];
            vT[c1 * 65 + lr0] = vv[nb][1];
            vT[c0 * 65 + lr1] = vv[nb][2];
            vT[c1 * 65 + lr1] = vv[nb][3];
        }
        __syncthreads();
        for (int idx = tid; idx < 64 * 64; idx += 128) {
            int r2 = idx >> 6, c2 = idx & 63;
            int jj = j0 + r2, ii = i0 + c2;
            if (jj < N_ && ii < N_) out[(size_t)jj * N_ + ii] = vT[r2 * 65 + c2];
        }
    }
}

// ===== GAT kernels =====
__global__ void alpha_kernel(const float* __restrict__ h, const float* __restrict__ a_s,
                             const float* __restrict__ a_d, int dh) {
    int idx = blockIdx.x * blockDim.x + threadIdx.x;
    if (idx >= T_ * N_ * H_) return;
    int hh = idx & 3, tn = idx >> 2;
    const float* hr = h + (size_t)tn * (H_ * dh) + hh * dh;
    float s = 0.f, d = 0.f;
    for (int k = 0; k < dh; k++) {
        float v = hr[k];
        s += v * a_s[hh * dh + k];
        d += v * a_d[hh * dh + k];
    }
    g_as[idx] = s; g_ad[idx] = d;
}
__global__ void csr_count(const void* ei) {
    int idx = blockIdx.x * blockDim.x + threadIdx.x;
    if (idx >= T_ * E_) return;
    int t = idx / E_, e = idx - t * E_;
    int dst = (int)ld_idx(ei, (size_t)t * 2 * E_ + E_ + e);
    atomicAdd(&g_cnt[t * N_ + dst], 1);
}
__global__ void csr_scan() {
    int t = blockIdx.x, tid = threadIdx.x;
    __shared__ int sh[1024];
    int off = 0;
    for (int chunk = 0; chunk < N_; chunk += 1024) {
        int i = chunk + tid;
        int v = (i < N_) ? g_cnt[t * N_ + i] : 0;
        sh[tid] = v;
        __syncthreads();
        for (int d2 = 1; d2 < 1024; d2 <<= 1) {
            int x = 0;
            if (tid >= d2) x = sh[tid - d2];
            __syncthreads();
            sh[tid] += x;
            __syncthreads();
        }
        if (i < N_) g_rowptr[t * (N_ + 1) + i] = off + sh[tid] - v;
        int tot = sh[1023];
        __syncthreads();
        off += tot;
    }
    if (tid == 0) g_rowptr[t * (N_ + 1) + N_] = off;
}
__global__ void csr_scatter(const void* ei) {
    int idx = blockIdx.x * blockDim.x + threadIdx.x;
    if (idx >= T_ * E_) return;
    int t = idx / E_, e = idx - t * E_;
    int dst = (int)ld_idx(ei, (size_t)t * 2 * E_ + E_ + e);
    int pos = atomicAdd(&g_cursor[t * N_ + dst], 1);
    g_sorted[t * E_ + g_rowptr[t * (N_ + 1) + dst] + pos] = e;
}

// fused gather: computes ex = exp(leaky(as[src]+ad[dst]))*w inline, den = sum(ex),
// writes elu(num/den) as bf16 hi/lo split (and fp32 for layer 2, meso input).
template <int D, int DH, int L1>
__global__ void gat_gather(const void* ei, const float* __restrict__ ew,
                           const float* __restrict__ hsrc,
                           __nv_bfloat16* __restrict__ oh, __nv_bfloat16* __restrict__ ol,
                           float* __restrict__ ofp) {
    int t = blockIdx.y, n = blockIdx.x, tid = threadIdx.x;
    int start = g_rowptr[t * (N_ + 1) + n];
    int end = g_rowptr[t * (N_ + 1) + n + 1];
    int head = tid / DH;
    __shared__ int s_src[64];
    __shared__ float s_ex[64][4];
    float4 ad4 = *(const float4*)&g_ad[(t * N_ + n) * 4];
    float acc = 0.f, den = 0.f;
    for (int base = start; base < end; base += 64) {
        int cnt = min(64, end - base);
        __syncthreads();
        for (int i = tid; i < cnt; i += D) {
            int eid = g_sorted[t * E_ + base + i];
            int src = (int)ld_idx(ei, (size_t)t * 2 * E_ + eid);
            s_src[i] = src;
            float4 s4 = *(const float4*)&g_as[(t * N_ + src) * 4];
            float wv = ew[(size_t)t * E_ + eid];
            float e0 = s4.x + ad4.x; e0 = e0 > 0.f ? e0 : 0.2f * e0;
            float e1 = s4.y + ad4.y; e1 = e1 > 0.f ? e1 : 0.2f * e1;
            float e2 = s4.z + ad4.z; e2 = e2 > 0.f ? e2 : 0.2f * e2;
            float e3 = s4.w + ad4.w; e3 = e3 > 0.f ? e3 : 0.2f * e3;
            s_ex[i][0] = __expf(e0) * wv;
            s_ex[i][1] = __expf(e1) * wv;
            s_ex[i][2] = __expf(e2) * wv;
            s_ex[i][3] = __expf(e3) * wv;
        }
        __syncthreads();
#pragma unroll 8
        for (int i = 0; i < cnt; i++) {
            float exv = s_ex[i][head];
            den += exv;
            acc += exv * hsrc[((size_t)t * N_ + s_src[i]) * D + tid];
        }
    }
    float v = acc / (den + 1e-16f);
    v = v > 0.f ? v : __expf(v) - 1.f;
    size_t o = ((size_t)t * N_ + n) * 128 + tid;
    __nv_bfloat16 hh = __float2bfloat16_rn(v);
    oh[o] = hh;
    ol[o] = __float2bfloat16_rn(v - __bfloat162float(hh));
    if (!L1) ofp[o] = v;
}

// ===== meso =====
#define MCHUNK 500
__global__ void meso_acc(const void* part, const float* __restrict__ Dw) {
    int t = blockIdx.y, c0 = blockIdx.x * MCHUNK, tid = threadIdx.x;
    __shared__ float sn[NCOM_ * 64];
    __shared__ float sd[NCOM_];
    __shared__ int sp[MCHUNK];
    __shared__ float sD[MCHUNK];
    for (int i = tid; i < NCOM_ * 64; i += blockDim.x) sn[i] = 0.f;
    for (int i = tid; i < NCOM_; i += blockDim.x) sd[i] = 0.f;
    int nmax = min(MCHUNK, N_ - c0);
    for (int i = tid; i < nmax; i += blockDim.x) {
        sp[i] = (int)ld_idx(part, (size_t)t * N_ + c0 + i);
        sD[i] = Dw[(size_t)t * N_ + c0 + i];
    }
    __syncthreads();
    for (int idx = tid; idx < nmax * 64; idx += blockDim.x) {
        int nl = idx >> 6, c = idx & 63;
        float g = g_agg[((size_t)t * N_ + c0 + nl) * 128 + c];
        atomicAdd(&sn[sp[nl] * 64 + c], sD[nl] * g);
        if (c == 0) atomicAdd(&sd[sp[nl]], sD[nl]);
    }
    __syncthreads();
    for (int i = tid; i < NCOM_ * 64; i += blockDim.x)
        atomicAdd(&g_comnum[t * NCOM_ * 64 + i], sn[i]);
    for (int i = tid; i < NCOM_; i += blockDim.x)
        atomicAdd(&g_comden[t * NCOM_ + i], sd[i]);
}
// writes meso mean directly as bf16 split into cols 64-127 of the A-split buffers
__global__ void meso_scatter(const void* part, __nv_bfloat16* __restrict__ oh,
                             __nv_bfloat16* __restrict__ ol) {
    int idx = blockIdx.x * blockDim.x + threadIdx.x;
    if (idx >= T_ * N_ * 64) return;
    int t = idx / (N_ * 64);
    int r = idx - t * N_ * 64;
    int n = r >> 6, c = r & 63;
    int p = (int)ld_idx(part, (size_t)t * N_ + n);
    float mean = g_comnum[(t * NCOM_ + p) * 64 + c] / (g_comden[t * NCOM_ + p] + 1e-16f);
    size_t o = ((size_t)t * N_ + n) * 128 + 64 + c;
    __nv_bfloat16 hh = __float2bfloat16_rn(mean);
    oh[o] = hh;
    ol[o] = __float2bfloat16_rn(mean - __bfloat162float(hh));
}

// ===== LSTM pointwise =====
__global__ void lstm_pw(const float* __restrict__ b, int t) {
    int idx = blockIdx.x * blockDim.x + threadIdx.x;
    if (idx >= N_ * 128) return;
    int n = idx >> 7, j = idx & 127;
    const float* z = g_Zx + (size_t)t * N_ * 512 + (size_t)n * 512;
    float i_ = z[j] + b[j];
    float f_ = z[128 + j] + b[128 + j];
    float gg = z[256 + j] + b[256 + j];
    float o_ = z[384 + j] + b[384 + j];
    float c = sigf_fast(f_) * g_cbuf[idx] + sigf_fast(i_) * tanh_fast(gg);
    g_cbuf[idx] = c;
    float h = sigf_fast(o_) * tanh_fast(c);
    __nv_bfloat16 hh = __float2bfloat16_rn(h);
    g_hbh[idx] = hh;
    g_hbl[idx] = __float2bfloat16_rn(h - __bfloat162float(hh));
}

// ===== decoder prep =====
__global__ void emb_tanh(const float* __restrict__ emb_b) {
    __shared__ float s[64];
    int tid = threadIdx.x;
    if (tid < 64) s[tid] = 0.f;
    __syncthreads();
    int idx = blockIdx.x * 256 + tid;
    if (idx < N_ * 64) {
        int c = idx & 63;
        float v = tanhf(g_embp[idx] + emb_b[c]);
        g_embp[idx] = v;
        atomicAdd(&s[c], v * v);
    }
    __syncthreads();
    if (tid < 64) atomicAdd(&g_colsq[tid], s[tid]);
}
__global__ void build_P(const float* __restrict__ scal_b) {
    int n = blockIdx.x, c = threadIdx.x;
    float e = g_embp[n * 64 + c] / sqrtf(g_colsq[c]);
    float s = sigf(g_scalp[n * 64 + c] + scal_b[c]);
    __nv_bfloat16 eh = __float2bfloat16_rn(e);
    g_ph[n * 128 + c] = eh;
    g_pl[n * 128 + c] = __float2bfloat16_rn(e - __bfloat162float(eh));
    __nv_bfloat16 sh2 = __float2bfloat16_rn(s);
    g_ph[n * 128 + 64 + c] = sh2;
    g_pl[n * 128 + 64 + c] = __float2bfloat16_rn(s - __bfloat162float(sh2));
    float v = e * e;
#pragma unroll
    for (int o = 16; o; o >>= 1) v += __shfl_down_sync(0xffffffff, v, o);
    __shared__ float shm[2];
    if ((c & 31) == 0) shm[c >> 5] = v;
    __syncthreads();
    if (c == 0) g_sq[n] = shm[0] + shm[1];
}

// ===== host =====
extern "C" void kernel_launch(void* const* d_in, const int* in_sizes, int n_in,
                              void* d_out, int out_size) {
    const float* feat   = (const float*)d_in[0];
    const float* ew     = (const float*)d_in[1];
    const float* Dw     = (const float*)d_in[2];
    const float* W1     = (const float*)d_in[3];
    const float* a_s1   = (const float*)d_in[4];
    const float* a_d1   = (const float*)d_in[5];
    const float* W2     = (const float*)d_in[6];
    const float* a_s2   = (const float*)d_in[7];
    const float* a_d2   = (const float*)d_in[8];
    const float* Wx     = (const float*)d_in[9];
    const float* Wh     = (const float*)d_in[10];
    const float* b_lstm = (const float*)d_in[11];
    const float* embW   = (const float*)d_in[12];
    const float* embB   = (const float*)d_in[13];
    const float* scalW  = (const float*)d_in[14];
    const float* scalB  = (const float*)d_in[15];
    const void*  ei     = (const void*)d_in[16];
    const void*  part   = (const void*)d_in[17];
    float* out = (float*)d_out;

    cudaFuncSetAttribute(mma_gemm, cudaFuncAttributeMaxDynamicSharedMemorySize, MG_SMEM);
    cudaFuncSetAttribute(pairwise_mma, cudaFuncAttributeMaxDynamicSharedMemorySize, MG_SMEM);

    float *h1, *h2, *agg, *Zx, *cbuf, *embp, *scalp;
    float *comnum, *comden, *colsq;
    int *cnt, *cursor;
    __nv_bfloat16 *fh, *fl, *hbh, *hbl, *wth, *wtl;
    cudaGetSymbolAddress((void**)&h1, g_h1);
    cudaGetSymbolAddress((void**)&h2, g_h2);
    cudaGetSymbolAddress((void**)&agg, g_agg);
    cudaGetSymbolAddress((void**)&Zx, g_Zx);
    cudaGetSymbolAddress((void**)&cbuf, g_cbuf);
    cudaGetSymbolAddress((void**)&embp, g_embp);
    cudaGetSymbolAddress((void**)&scalp, g_scalp);
    cudaGetSymbolAddress((void**)&comnum, g_comnum);
    cudaGetSymbolAddress((void**)&comden, g_comden);
    cudaGetSymbolAddress((void**)&colsq, g_colsq);
    cudaGetSymbolAddress((void**)&cnt, g_cnt);
    cudaGetSymbolAddress((void**)&cursor, g_cursor);
    cudaGetSymbolAddress((void**)&fh, g_fh);
    cudaGetSymbolAddress((void**)&fl, g_fl);
    cudaGetSymbolAddress((void**)&hbh, g_hbh);
    cudaGetSymbolAddress((void**)&hbl, g_hbl);
    cudaGetSymbolAddress((void**)&wth, g_wth);
    cudaGetSymbolAddress((void**)&wtl, g_wtl);

    const int MT = 157;  // ceil(10000/64)
    const int TE = T_ * E_;
    const int TNH = T_ * N_ * H_;
    const int NS8 = T_ * N_ * 128 / 8;

    detect64_kernel<<<1, 1>>>((const int*)ei);

    // GAT layer 1
    split8<<<(NS8 + 255) / 256, 256>>>((const float4*)feat, (uint4*)fh, (uint4*)fl, NS8);
    bsplit<<<(128 * 128 + 255) / 256, 256>>>(W1, wth, wtl, 128);
    mma_gemm<<<dim3(MT, 2, 8), 128, MG_SMEM>>>(fh, fl, wth, wtl, h1, N_, 128,
                                               (long long)N_ * 128, (long long)N_ * 128, 0);
    alpha_kernel<<<(TNH + 255) / 256, 256>>>(h1, a_s1, a_d1, 32);

    fill_i<<<(T_ * N_ + 255) / 256, 256>>>(cnt, 0, T_ * N_);
    csr_count<<<(TE + 255) / 256, 256>>>(ei);
    csr_scan<<<T_, 1024>>>();
    fill_i<<<(T_ * N_ + 255) / 256, 256>>>(cursor, 0, T_ * N_);
    csr_scatter<<<(TE + 255) / 256, 256>>>(ei);

    // fused gather L1: writes elu output as bf16 split into fh/fl (full 128 cols)
    gat_gather<128, 32, 1><<<dim3(N_, T_), 128>>>(ei, ew, h1, fh, fl, (float*)0);

    // GAT layer 2
    bsplit<<<(64 * 128 + 255) / 256, 256>>>(W2, wth, wtl, 64);
    mma_gemm<<<dim3(MT, 1, 8), 128, MG_SMEM>>>(fh, fl, wth, wtl, h2, N_, 64,
                                               (long long)N_ * 128, (long long)N_ * 64, 0);
    alpha_kernel<<<(TNH + 255) / 256, 256>>>(h2, a_s2, a_d2, 16);
    // fused gather L2: writes bf16 split (cols 0-63 of fh/fl) + fp32 agg for meso
    gat_gather<64, 16, 0><<<dim3(N_, T_), 64>>>(ei, ew, h2, fh, fl, agg);

    // meso
    fill_f<<<(T_ * NCOM_ * 64 + 255) / 256, 256>>>(comnum, 0.f, T_ * NCOM_ * 64);
    fill_f<<<(T_ * NCOM_ + 255) / 256, 256>>>(comden, 0.f, T_ * NCOM_);
    meso_acc<<<dim3((N_ + MCHUNK - 1) / MCHUNK, T_), 256>>>(part, Dw);
    meso_scatter<<<(T_ * N_ * 64 + 255) / 256, 256>>>(part, fh, fl);

    // LSTM
    bsplit<<<(512 * 128 + 255) / 256, 256>>>(Wx, wth, wtl, 512);
    mma_gemm<<<dim3(MT, 8, 8), 128, MG_SMEM>>>(fh, fl, wth, wtl, Zx, N_, 512,
                                               (long long)N_ * 128, (long long)N_ * 512, 0);
    bsplit<<<(512 * 128 + 255) / 256, 256>>>(Wh, wth, wtl, 512);
    fill_f<<<(N_ * 128 + 255) / 256, 256>>>(cbuf, 0.f, N_ * 128);
    for (int t = 0; t < T_; t++) {
        if (t > 0) {  // h == 0 at t=0; hbh/hbl written by previous lstm_pw
            mma_gemm<<<dim3(MT, 8, 1), 128, MG_SMEM>>>(hbh, hbl, wth, wtl,
                                                       Zx + (size_t)t * N_ * 512, N_, 512, 0, 0, 1);
        }
        lstm_pw<<<(N_ * 128 + 255) / 256, 256>>>(b_lstm, t);
    }

    // decoder
    bsplit<<<(64 * 128 + 255) / 256, 256>>>(embW, wth, wtl, 64);
    mma_gemm<<<dim3(MT, 1, 1), 128, MG_SMEM>>>(hbh, hbl, wth, wtl, embp, N_, 64, 0, 0, 0);
    bsplit<<<(64 * 128 + 255) / 256, 256>>>(scalW, wth, wtl, 64);
    mma_gemm<<<dim3(MT, 1, 1), 128, MG_SMEM>>>(hbh, hbl, wth, wtl, scalp, N_, 64, 0, 0, 0);
    fill_f<<<1, 64>>>(colsq, 0.f, 64);
    emb_tanh<<<(N_ * 64 + 255) / 256, 256>>>(embB);
    build_P<<<N_, 64>>>(scalB);
    pairwise_mma<<<dim3(MT, MT), 128, MG_SMEM>>>(out);
}

// round 7
// speedup vs baseline: 2.7896x; 1.0358x over previous
#include <cuda_runtime.h>
#include <cuda_bf16.h>
#include <math.h>
#include <stdint.h>

#define T_ 8
#define N_ 10000
#define E_ 320000
#define H_ 4
#define NCOM_ 100

// ===== scratch =====
__device__ int   g_is64;
__device__ __align__(16) float g_h1[(size_t)T_ * N_ * 128];
__device__ __align__(16) float g_h2[(size_t)T_ * N_ * 64];
__device__ __align__(16) float g_agg[(size_t)T_ * N_ * 128];
__device__ __align__(16) float g_as[T_ * N_ * H_];
__device__ __align__(16) float g_ad[T_ * N_ * H_];
__device__ int   g_cnt[T_ * N_];
__device__ int   g_rowptr[T_ * (N_ + 1)];
__device__ int   g_cursor[T_ * N_];
__device__ int   g_sorted[T_ * E_];
__device__ float g_comnum[T_ * NCOM_ * 64];
__device__ float g_comden[T_ * NCOM_];
__device__ __align__(16) float g_Zx[(size_t)T_ * N_ * 512];
__device__ __align__(16) float g_cbuf[N_ * 128];
__device__ __align__(16) float g_dec[N_ * 128];          // [emb(0-63) | scal(64-127)] pre-activation
__device__ float g_sq[N_];
__device__ float g_colsq[64];
__device__ __align__(16) __nv_bfloat16 g_fh[(size_t)T_ * N_ * 128];
__device__ __align__(16) __nv_bfloat16 g_fl[(size_t)T_ * N_ * 128];
__device__ __align__(16) __nv_bfloat16 g_hbh[N_ * 128];
__device__ __align__(16) __nv_bfloat16 g_hbl[N_ * 128];
__device__ __align__(16) __nv_bfloat16 g_ph[N_ * 128];
__device__ __align__(16) __nv_bfloat16 g_pl[N_ * 128];
__device__ __align__(16) __nv_bfloat16 g_wth[512 * 128];
__device__ __align__(16) __nv_bfloat16 g_wtl[512 * 128];

// ===== helpers =====
__device__ __forceinline__ long long ld_idx(const void* p, size_t i) {
    if (g_is64) return ((const long long*)p)[i];
    return (long long)((const int*)p)[i];
}
__device__ __forceinline__ float sigf(float x) { return 1.f / (1.f + expf(-x)); }
__device__ __forceinline__ float sigf_fast(float x) {
    return __fdividef(1.f, 1.f + __expf(-x));
}
__device__ __forceinline__ float tanh_fast(float x) {
    float e = __expf(2.f * x);
    return 1.f - __fdividef(2.f, e + 1.f);
}
__device__ __forceinline__ float tanh_hw(float x) {
    float y;
    asm("tanh.approx.f32 %0, %1;" : "=f"(y) : "f"(x));
    return y;
}
__device__ __forceinline__ void mma16816(float* c, uint32_t a0, uint32_t a1, uint32_t a2,
                                         uint32_t a3, uint32_t b0, uint32_t b1) {
    asm volatile(
        "mma.sync.aligned.m16n8k16.row.col.f32.bf16.bf16.f32 "
        "{%0,%1,%2,%3}, {%4,%5,%6,%7}, {%8,%9}, {%0,%1,%2,%3};"
        : "+f"(c[0]), "+f"(c[1]), "+f"(c[2]), "+f"(c[3])
        : "r"(a0), "r"(a1), "r"(a2), "r"(a3), "r"(b0), "r"(b1));
}

__global__ void detect64_kernel(const int* ei32) {
    int ok = 1;
    for (int i = 1; i < 64; i += 2)
        if (ei32[i] != 0) ok = 0;
    g_is64 = ok;
}
__global__ void fill_f(float* p, float v, int n) {
    int i = blockIdx.x * blockDim.x + threadIdx.x;
    if (i < n) p[i] = v;
}
__global__ void fill_i(int* p, int v, int n) {
    int i = blockIdx.x * blockDim.x + threadIdx.x;
    if (i < n) p[i] = v;
}
__global__ void split8(const float4* __restrict__ x, uint4* __restrict__ hi,
                       uint4* __restrict__ lo, int n8) {
    int i = blockIdx.x * blockDim.x + threadIdx.x;
    if (i >= n8) return;
    float4 a = x[2 * i], b = x[2 * i + 1];
    float v[8] = {a.x, a.y, a.z, a.w, b.x, b.y, b.z, b.w};
    unsigned ho[4], lo4[4];
#pragma unroll
    for (int j = 0; j < 4; j++) {
        __nv_bfloat162 h2 = __floats2bfloat162_rn(v[2 * j], v[2 * j + 1]);
        __nv_bfloat162 l2 = __floats2bfloat162_rn(v[2 * j] - __low2float(h2),
                                                  v[2 * j + 1] - __high2float(h2));
        ho[j] = *reinterpret_cast<unsigned*>(&h2);
        lo4[j] = *reinterpret_cast<unsigned*>(&l2);
    }
    hi[i] = make_uint4(ho[0], ho[1], ho[2], ho[3]);
    lo[i] = make_uint4(lo4[0], lo4[1], lo4[2], lo4[3]);
}
__global__ void bsplit(const float* __restrict__ B, __nv_bfloat16* __restrict__ bth,
                       __nv_bfloat16* __restrict__ btl, int Dn) {
    int idx = blockIdx.x * blockDim.x + threadIdx.x;
    if (idx >= Dn * 128) return;
    int n = idx >> 7, k = idx & 127;
    float v = B[(size_t)k * Dn + n];
    __nv_bfloat16 h = __float2bfloat16_rn(v);
    bth[idx] = h;
    btl[idx] = __float2bfloat16_rn(v - __bfloat162float(h));
}

// ===== MMA GEMM: tile 128x64, 256 threads (8 warps x 16 rows), interleaved hi/lo =====
#define SM_A 0
#define SM_B 69632                       // A: 128 rows * 68 u64 * 8B
#define SM_SQ 104448                     // B: 64 rows * 68 u64 * 8B
#define MG_SMEM 104960

__device__ __forceinline__ void cp_tile_int(const uint4* __restrict__ Gh,
                                            const uint4* __restrict__ Gl,
                                            char* sm, int off, int base, int Mlim,
                                            int tid, int rows) {
#pragma unroll
    for (int i = 0; i < rows * 16; i += 256) {
        int idx = tid + i;
        int row = idx >> 4, c = idx & 15;
        uint4 vh = make_uint4(0, 0, 0, 0), vl = vh;
        if (base + row < Mlim) {
            vh = Gh[(size_t)(base + row) * 16 + c];
            vl = Gl[(size_t)(base + row) * 16 + c];
        }
        uint4 p0 = make_uint4(vh.x, vl.x, vh.y, vl.y);
        uint4 p1 = make_uint4(vh.z, vl.z, vh.w, vl.w);
        uint4* dst = (uint4*)(sm + off) + ((row * 68 + 4 * c) >> 1);
        dst[0] = p0;
        dst[1] = p1;
    }
}

__global__ __launch_bounds__(256) void mma_gemm(
    const __nv_bfloat16* __restrict__ Ah, const __nv_bfloat16* __restrict__ Al,
    const __nv_bfloat16* __restrict__ Bh, const __nv_bfloat16* __restrict__ Bl,
    float* __restrict__ C, int M, int Dn,
    long long sA, long long sC, int accumulate)
{
    extern __shared__ char sm[];
    int tid = threadIdx.x, w = tid >> 5, lane = tid & 31;
    int g = lane >> 2, tq = lane & 3;
    int m0 = blockIdx.x * 128, n0 = blockIdx.y * 64, t = blockIdx.z;
    Ah += (size_t)t * sA; Al += (size_t)t * sA;
    C += (size_t)t * sC;

    cp_tile_int((const uint4*)Ah, (const uint4*)Al, sm, SM_A, m0, M, tid, 128);
    cp_tile_int((const uint4*)Bh, (const uint4*)Bl, sm, SM_B, n0, Dn, tid, 64);
    __syncthreads();

    const uint2* SA = (const uint2*)(sm + SM_A);
    const uint2* SB = (const uint2*)(sm + SM_B);

    float acc[8][4];
#pragma unroll
    for (int nb = 0; nb < 8; nb++)
#pragma unroll
        for (int q = 0; q < 4; q++) acc[nb][q] = 0.f;

    int ra = (w * 16 + g) * 68, rb = ra + 8 * 68;
#pragma unroll
    for (int kc = 0; kc < 8; kc++) {
        int ka = kc * 8 + tq;
        uint2 A0 = SA[ra + ka], A1 = SA[rb + ka];
        uint2 A2 = SA[ra + ka + 4], A3 = SA[rb + ka + 4];
#pragma unroll
        for (int nb = 0; nb < 8; nb++) {
            int nr = (nb * 8 + g) * 68;
            uint2 B0 = SB[nr + ka], B1 = SB[nr + ka + 4];
            mma16816(acc[nb], A0.x, A1.x, A2.x, A3.x, B0.x, B1.x);
            mma16816(acc[nb], A0.x, A1.x, A2.x, A3.x, B0.y, B1.y);
            mma16816(acc[nb], A0.y, A1.y, A2.y, A3.y, B0.x, B1.x);
        }
    }

    int r0 = m0 + w * 16 + g, r1 = r0 + 8;
#pragma unroll
    for (int nb = 0; nb < 8; nb++) {
        int col = n0 + nb * 8 + 2 * tq;
        if (r0 < M) {
            float2* p = (float2*)(C + (size_t)r0 * Dn + col);
            float2 v = make_float2(acc[nb][0], acc[nb][1]);
            if (accumulate) { float2 o = *p; v.x += o.x; v.y += o.y; }
            *p = v;
        }
        if (r1 < M) {
            float2* p = (float2*)(C + (size_t)r1 * Dn + col);
            float2 v = make_float2(acc[nb][2], acc[nb][3]);
            if (accumulate) { float2 o = *p; v.x += o.x; v.y += o.y; }
            *p = v;
        }
    }
}

// ===== pairwise decoder: tile 128(i) x 64(j), 256 threads, symmetric culling =====
// keep tile iff j0+64 > i0; direct writes cover all in-tile cells (values symmetric);
// mirror writes cover strictly-lower cells of skipped tiles.
__global__ __launch_bounds__(256) void pairwise_mma(float* __restrict__ out) {
    int i0 = blockIdx.y * 128, j0 = blockIdx.x * 64;
    if (j0 + 64 <= i0) return;
    extern __shared__ char sm[];
    int tid = threadIdx.x, w = tid >> 5, lane = tid & 31;
    int g = lane >> 2, tq = lane & 3;
    float* sqB = (float*)(sm + SM_SQ);

    cp_tile_int((const uint4*)g_ph, (const uint4*)g_pl, sm, SM_A, i0, N_, tid, 128);
    cp_tile_int((const uint4*)g_ph, (const uint4*)g_pl, sm, SM_B, j0, N_, tid, 64);
    if (tid < 64) sqB[tid] = (j0 + tid < N_) ? g_sq[j0 + tid] : 0.f;
    __syncthreads();

    const uint2* SA = (const uint2*)(sm + SM_A);
    const uint2* SB = (const uint2*)(sm + SM_B);

    float accG[8][4], accS[8][4];
#pragma unroll
    for (int nb = 0; nb < 8; nb++)
#pragma unroll
        for (int q = 0; q < 4; q++) { accG[nb][q] = 0.f; accS[nb][q] = 0.f; }

    int ra = (w * 16 + g) * 68, rb = ra + 8 * 68;
#pragma unroll
    for (int kc = 0; kc < 8; kc++) {
        int ka = kc * 8 + tq;
        uint2 A0 = SA[ra + ka], A1 = SA[rb + ka];
        uint2 A2 = SA[ra + ka + 4], A3 = SA[rb + ka + 4];
        float (*acc)[4] = (kc < 4) ? accG : accS;
#pragma unroll
        for (int nb = 0; nb < 8; nb++) {
            int nr = (nb * 8 + g) * 68;
            uint2 B0 = SB[nr + ka], B1 = SB[nr + ka + 4];
            mma16816(acc[nb], A0.x, A1.x, A2.x, A3.x, B0.x, B1.x);
            mma16816(acc[nb], A0.x, A1.x, A2.x, A3.x, B0.y, B1.y);
            mma16816(acc[nb], A0.y, A1.y, A2.y, A3.y, B0.x, B1.x);
        }
    }

    int lr0 = w * 16 + g, lr1 = lr0 + 8;
    int ir0 = i0 + lr0, ir1 = i0 + lr1;
    float sqi0 = (ir0 < N_) ? g_sq[ir0] : 0.f;
    float sqi1 = (ir1 < N_) ? g_sq[ir1] : 0.f;

    float vv[8][4];
#pragma unroll
    for (int nb = 0; nb < 8; nb++) {
        int c0 = nb * 8 + 2 * tq, c1 = c0 + 1;
        float sj0 = sqB[c0], sj1 = sqB[c1];
        vv[nb][0] = 1.f + tanh_hw((2.f * accG[nb][0] - sqi0 - sj0) * accS[nb][0]);
        vv[nb][1] = 1.f + tanh_hw((2.f * accG[nb][1] - sqi0 - sj1) * accS[nb][1]);
        vv[nb][2] = 1.f + tanh_hw((2.f * accG[nb][2] - sqi1 - sj0) * accS[nb][2]);
        vv[nb][3] = 1.f + tanh_hw((2.f * accG[nb][3] - sqi1 - sj1) * accS[nb][3]);
    }

    bool full = (i0 + 128 <= N_) && (j0 + 64 <= N_);
#pragma unroll
    for (int nb = 0; nb < 8; nb++) {
        int c0 = nb * 8 + 2 * tq;
        if (full) {
            *(float2*)(out + (size_t)ir0 * N_ + j0 + c0) = make_float2(vv[nb][0], vv[nb][1]);
            *(float2*)(out + (size_t)ir1 * N_ + j0 + c0) = make_float2(vv[nb][2], vv[nb][3]);
        } else {
            if (ir0 < N_) {
                if (j0 + c0 < N_)     out[(size_t)ir0 * N_ + j0 + c0] = vv[nb][0];
                if (j0 + c0 + 1 < N_) out[(size_t)ir0 * N_ + j0 + c0 + 1] = vv[nb][1];
            }
            if (ir1 < N_) {
                if (j0 + c0 < N_)     out[(size_t)ir1 * N_ + j0 + c0] = vv[nb][2];
                if (j0 + c0 + 1 < N_) out[(size_t)ir1 * N_ + j0 + c0 + 1] = vv[nb][3];
            }
        }
    }

    // mirror: stage transpose in reused A smem, write (jj, ii) for jj > ii
    __syncthreads();
    float* vT = (float*)(sm + SM_A);  // [64][129]
#pragma unroll
    for (int nb = 0; nb < 8; nb++) {
        int c0 = nb * 8 + 2 * tq, c1 = c0 + 1;
        vT[c0 * 129 + lr0] = vv[nb][0];
        vT[c1 * 129 + lr0] = vv[nb][1];
        vT[c0 * 129 + lr1] = vv[nb][2];
        vT[c1 * 129 + lr1] = vv[nb][3];
    }
    __syncthreads();
    for (int idx = tid; idx < 64 * 128; idx += 256) {
        int r2 = idx >> 7, c2 = idx & 127;
        int jj = j0 + r2, ii = i0 + c2;
        if (jj > ii && jj < N_ && ii < N_) out[(size_t)jj * N_ + ii] = vT[r2 * 129 + c2];
    }
}

// ===== GAT kernels =====
__global__ void alpha_kernel(const float* __restrict__ h, const float* __restrict__ a_s,
                             const float* __restrict__ a_d, int dh) {
    int idx = blockIdx.x * blockDim.x + threadIdx.x;
    if (idx >= T_ * N_ * H_) return;
    int hh = idx & 3, tn = idx >> 2;
    const float* hr = h + (size_t)tn * (H_ * dh) + hh * dh;
    float s = 0.f, d = 0.f;
    for (int k = 0; k < dh; k++) {
        float v = hr[k];
        s += v * a_s[hh * dh + k];
        d += v * a_d[hh * dh + k];
    }
    g_as[idx] = s; g_ad[idx] = d;
}
__global__ void csr_count(const void* ei) {
    int idx = blockIdx.x * blockDim.x + threadIdx.x;
    if (idx >= T_ * E_) return;
    int t = idx / E_, e = idx - t * E_;
    int dst = (int)ld_idx(ei, (size_t)t * 2 * E_ + E_ + e);
    atomicAdd(&g_cnt[t * N_ + dst], 1);
}
__global__ void csr_scan() {
    int t = blockIdx.x, tid = threadIdx.x;
    __shared__ int sh[1024];
    int off = 0;
    for (int chunk = 0; chunk < N_; chunk += 1024) {
        int i = chunk + tid;
        int v = (i < N_) ? g_cnt[t * N_ + i] : 0;
        sh[tid] = v;
        __syncthreads();
        for (int d2 = 1; d2 < 1024; d2 <<= 1) {
            int x = 0;
            if (tid >= d2) x = sh[tid - d2];
            __syncthreads();
            sh[tid] += x;
            __syncthreads();
        }
        if (i < N_) g_rowptr[t * (N_ + 1) + i] = off + sh[tid] - v;
        int tot = sh[1023];
        __syncthreads();
        off += tot;
    }
    if (tid == 0) g_rowptr[t * (N_ + 1) + N_] = off;
}
__global__ void csr_scatter(const void* ei) {
    int idx = blockIdx.x * blockDim.x + threadIdx.x;
    if (idx >= T_ * E_) return;
    int t = idx / E_, e = idx - t * E_;
    int dst = (int)ld_idx(ei, (size_t)t * 2 * E_ + E_ + e);
    int pos = atomicAdd(&g_cursor[t * N_ + dst], 1);
    g_sorted[t * E_ + g_rowptr[t * (N_ + 1) + dst] + pos] = e;
}

// fused gather (ex + den + softmax + elu + bf16 split output)
template <int D, int DH, int L1>
__global__ void gat_gather(const void* ei, const float* __restrict__ ew,
                           const float* __restrict__ hsrc,
                           __nv_bfloat16* __restrict__ oh, __nv_bfloat16* __restrict__ ol,
                           float* __restrict__ ofp) {
    int t = blockIdx.y, n = blockIdx.x, tid = threadIdx.x;
    int start = g_rowptr[t * (N_ + 1) + n];
    int end = g_rowptr[t * (N_ + 1) + n + 1];
    int head = tid / DH;
    __shared__ int s_src[64];
    __shared__ float s_ex[64][4];
    float4 ad4 = *(const float4*)&g_ad[(t * N_ + n) * 4];
    float acc = 0.f, den = 0.f;
    for (int base = start; base < end; base += 64) {
        int cnt = min(64, end - base);
        __syncthreads();
        for (int i = tid; i < cnt; i += D) {
            int eid = g_sorted[t * E_ + base + i];
            int src = (int)ld_idx(ei, (size_t)t * 2 * E_ + eid);
            s_src[i] = src;
            float4 s4 = *(const float4*)&g_as[(t * N_ + src) * 4];
            float wv = ew[(size_t)t * E_ + eid];
            float e0 = s4.x + ad4.x; e0 = e0 > 0.f ? e0 : 0.2f * e0;
            float e1 = s4.y + ad4.y; e1 = e1 > 0.f ? e1 : 0.2f * e1;
            float e2 = s4.z + ad4.z; e2 = e2 > 0.f ? e2 : 0.2f * e2;
            float e3 = s4.w + ad4.w; e3 = e3 > 0.f ? e3 : 0.2f * e3;
            s_ex[i][0] = __expf(e0) * wv;
            s_ex[i][1] = __expf(e1) * wv;
            s_ex[i][2] = __expf(e2) * wv;
            s_ex[i][3] = __expf(e3) * wv;
        }
        __syncthreads();
#pragma unroll 8
        for (int i = 0; i < cnt; i++) {
            float exv = s_ex[i][head];
            den += exv;
            acc += exv * hsrc[((size_t)t * N_ + s_src[i]) * D + tid];
        }
    }
    float v = acc / (den + 1e-16f);
    v = v > 0.f ? v : __expf(v) - 1.f;
    size_t o = ((size_t)t * N_ + n) * 128 + tid;
    __nv_bfloat16 hh = __float2bfloat16_rn(v);
    oh[o] = hh;
    ol[o] = __float2bfloat16_rn(v - __bfloat162float(hh));
    if (!L1) ofp[o] = v;
}

// ===== meso =====
#define MCHUNK 500
__global__ void meso_acc(const void* part, const float* __restrict__ Dw) {
    int t = blockIdx.y, c0 = blockIdx.x * MCHUNK, tid = threadIdx.x;
    __shared__ float sn[NCOM_ * 64];
    __shared__ float sd[NCOM_];
    __shared__ int sp[MCHUNK];
    __shared__ float sD[MCHUNK];
    for (int i = tid; i < NCOM_ * 64; i += blockDim.x) sn[i] = 0.f;
    for (int i = tid; i < NCOM_; i += blockDim.x) sd[i] = 0.f;
    int nmax = min(MCHUNK, N_ - c0);
    for (int i = tid; i < nmax; i += blockDim.x) {
        sp[i] = (int)ld_idx(part, (size_t)t * N_ + c0 + i);
        sD[i] = Dw[(size_t)t * N_ + c0 + i];
    }
    __syncthreads();
    for (int idx = tid; idx < nmax * 64; idx += blockDim.x) {
        int nl = idx >> 6, c = idx & 63;
        float g = g_agg[((size_t)t * N_ + c0 + nl) * 128 + c];
        atomicAdd(&sn[sp[nl] * 64 + c], sD[nl] * g);
        if (c == 0) atomicAdd(&sd[sp[nl]], sD[nl]);
    }
    __syncthreads();
    for (int i = tid; i < NCOM_ * 64; i += blockDim.x)
        atomicAdd(&g_comnum[t * NCOM_ * 64 + i], sn[i]);
    for (int i = tid; i < NCOM_; i += blockDim.x)
        atomicAdd(&g_comden[t * NCOM_ + i], sd[i]);
}
__global__ void meso_scatter(const void* part, __nv_bfloat16* __restrict__ oh,
                             __nv_bfloat16* __restrict__ ol) {
    int idx = blockIdx.x * blockDim.x + threadIdx.x;
    if (idx >= T_ * N_ * 64) return;
    int t = idx / (N_ * 64);
    int r = idx - t * N_ * 64;
    int n = r >> 6, c = r & 63;
    int p = (int)ld_idx(part, (size_t)t * N_ + n);
    float mean = g_comnum[(t * NCOM_ + p) * 64 + c] / (g_comden[t * NCOM_ + p] + 1e-16f);
    size_t o = ((size_t)t * N_ + n) * 128 + 64 + c;
    __nv_bfloat16 hh = __float2bfloat16_rn(mean);
    oh[o] = hh;
    ol[o] = __float2bfloat16_rn(mean - __bfloat162float(hh));
}

// ===== LSTM pointwise =====
__global__ void lstm_pw(const float* __restrict__ b, int t) {
    int idx = blockIdx.x * blockDim.x + threadIdx.x;
    if (idx >= N_ * 128) return;
    int n = idx >> 7, j = idx & 127;
    const float* z = g_Zx + (size_t)t * N_ * 512 + (size_t)n * 512;
    float i_ = z[j] + b[j];
    float f_ = z[128 + j] + b[128 + j];
    float gg = z[256 + j] + b[256 + j];
    float o_ = z[384 + j] + b[384 + j];
    float c = sigf_fast(f_) * g_cbuf[idx] + sigf_fast(i_) * tanh_fast(gg);
    g_cbuf[idx] = c;
    float h = sigf_fast(o_) * tanh_fast(c);
    __nv_bfloat16 hh = __float2bfloat16_rn(h);
    g_hbh[idx] = hh;
    g_hbl[idx] = __float2bfloat16_rn(h - __bfloat162float(hh));
}

// ===== decoder prep =====
__global__ void emb_tanh(const float* __restrict__ emb_b) {
    __shared__ float s[64];
    int tid = threadIdx.x;
    if (tid < 64) s[tid] = 0.f;
    __syncthreads();
    int idx = blockIdx.x * 256 + tid;
    if (idx < N_ * 64) {
        int n = idx >> 6, c = idx & 63;
        float v = tanhf(g_dec[n * 128 + c] + emb_b[c]);
        g_dec[n * 128 + c] = v;
        atomicAdd(&s[c], v * v);
    }
    __syncthreads();
    if (tid < 64) atomicAdd(&g_colsq[tid], s[tid]);
}
__global__ void build_P(const float* __restrict__ scal_b) {
    int n = blockIdx.x, c = threadIdx.x;
    float e = g_dec[n * 128 + c] / sqrtf(g_colsq[c]);
    float s = sigf(g_dec[n * 128 + 64 + c] + scal_b[c]);
    __nv_bfloat16 eh = __float2bfloat16_rn(e);
    g_ph[n * 128 + c] = eh;
    g_pl[n * 128 + c] = __float2bfloat16_rn(e - __bfloat162float(eh));
    __nv_bfloat16 sh2 = __float2bfloat16_rn(s);
    g_ph[n * 128 + 64 + c] = sh2;
    g_pl[n * 128 + 64 + c] = __float2bfloat16_rn(s - __bfloat162float(sh2));
    float v = e * e;
#pragma unroll
    for (int o = 16; o; o >>= 1) v += __shfl_down_sync(0xffffffff, v, o);
    __shared__ float shm[2];
    if ((c & 31) == 0) shm[c >> 5] = v;
    __syncthreads();
    if (c == 0) g_sq[n] = shm[0] + shm[1];
}

// ===== host =====
extern "C" void kernel_launch(void* const* d_in, const int* in_sizes, int n_in,
                              void* d_out, int out_size) {
    const float* feat   = (const float*)d_in[0];
    const float* ew     = (const float*)d_in[1];
    const float* Dw     = (const float*)d_in[2];
    const float* W1     = (const float*)d_in[3];
    const float* a_s1   = (const float*)d_in[4];
    const float* a_d1   = (const float*)d_in[5];
    const float* W2     = (const float*)d_in[6];
    const float* a_s2   = (const float*)d_in[7];
    const float* a_d2   = (const float*)d_in[8];
    const float* Wx     = (const float*)d_in[9];
    const float* Wh     = (const float*)d_in[10];
    const float* b_lstm = (const float*)d_in[11];
    const float* embW   = (const float*)d_in[12];
    const float* embB   = (const float*)d_in[13];
    const float* scalW  = (const float*)d_in[14];
    const float* scalB  = (const float*)d_in[15];
    const void*  ei     = (const void*)d_in[16];
    const void*  part   = (const void*)d_in[17];
    float* out = (float*)d_out;

    cudaFuncSetAttribute(mma_gemm, cudaFuncAttributeMaxDynamicSharedMemorySize, MG_SMEM);
    cudaFuncSetAttribute(pairwise_mma, cudaFuncAttributeMaxDynamicSharedMemorySize, MG_SMEM);

    float *h1, *h2, *agg, *Zx, *cbuf, *dec;
    float *comnum, *comden, *colsq;
    int *cnt, *cursor;
    __nv_bfloat16 *fh, *fl, *hbh, *hbl, *wth, *wtl;
    cudaGetSymbolAddress((void**)&h1, g_h1);
    cudaGetSymbolAddress((void**)&h2, g_h2);
    cudaGetSymbolAddress((void**)&agg, g_agg);
    cudaGetSymbolAddress((void**)&Zx, g_Zx);
    cudaGetSymbolAddress((void**)&cbuf, g_cbuf);
    cudaGetSymbolAddress((void**)&dec, g_dec);
    cudaGetSymbolAddress((void**)&comnum, g_comnum);
    cudaGetSymbolAddress((void**)&comden, g_comden);
    cudaGetSymbolAddress((void**)&colsq, g_colsq);
    cudaGetSymbolAddress((void**)&cnt, g_cnt);
    cudaGetSymbolAddress((void**)&cursor, g_cursor);
    cudaGetSymbolAddress((void**)&fh, g_fh);
    cudaGetSymbolAddress((void**)&fl, g_fl);
    cudaGetSymbolAddress((void**)&hbh, g_hbh);
    cudaGetSymbolAddress((void**)&hbl, g_hbl);
    cudaGetSymbolAddress((void**)&wth, g_wth);
    cudaGetSymbolAddress((void**)&wtl, g_wtl);

    const int MT = 79;   // ceil(10000/128)  (GEMM row tiles)
    const int JT = 157;  // ceil(10000/64)   (pairwise col tiles)
    const int TE = T_ * E_;
    const int TNH = T_ * N_ * H_;
    const int NS8 = T_ * N_ * 128 / 8;

    detect64_kernel<<<1, 1>>>((const int*)ei);

    // GAT layer 1
    split8<<<(NS8 + 255) / 256, 256>>>((const float4*)feat, (uint4*)fh, (uint4*)fl, NS8);
    bsplit<<<(128 * 128 + 255) / 256, 256>>>(W1, wth, wtl, 128);
    mma_gemm<<<dim3(MT, 2, 8), 256, MG_SMEM>>>(fh, fl, wth, wtl, h1, N_, 128,
                                               (long long)N_ * 128, (long long)N_ * 128, 0);
    alpha_kernel<<<(TNH + 255) / 256, 256>>>(h1, a_s1, a_d1, 32);

    fill_i<<<(T_ * N_ + 255) / 256, 256>>>(cnt, 0, T_ * N_);
    csr_count<<<(TE + 255) / 256, 256>>>(ei);
    csr_scan<<<T_, 1024>>>();
    fill_i<<<(T_ * N_ + 255) / 256, 256>>>(cursor, 0, T_ * N_);
    csr_scatter<<<(TE + 255) / 256, 256>>>(ei);

    gat_gather<128, 32, 1><<<dim3(N_, T_), 128>>>(ei, ew, h1, fh, fl, (float*)0);

    // GAT layer 2
    bsplit<<<(64 * 128 + 255) / 256, 256>>>(W2, wth, wtl, 64);
    mma_gemm<<<dim3(MT, 1, 8), 256, MG_SMEM>>>(fh, fl, wth, wtl, h2, N_, 64,
                                               (long long)N_ * 128, (long long)N_ * 64, 0);
    alpha_kernel<<<(TNH + 255) / 256, 256>>>(h2, a_s2, a_d2, 16);
    gat_gather<64, 16, 0><<<dim3(N_, T_), 64>>>(ei, ew, h2, fh, fl, agg);

    // meso
    fill_f<<<(T_ * NCOM_ * 64 + 255) / 256, 256>>>(comnum, 0.f, T_ * NCOM_ * 64);
    fill_f<<<(T_ * NCOM_ + 255) / 256, 256>>>(comden, 0.f, T_ * NCOM_);
    meso_acc<<<dim3((N_ + MCHUNK - 1) / MCHUNK, T_), 256>>>(part, Dw);
    meso_scatter<<<(T_ * N_ * 64 + 255) / 256, 256>>>(part, fh, fl);

    // LSTM
    bsplit<<<(512 * 128 + 255) / 256, 256>>>(Wx, wth, wtl, 512);
    mma_gemm<<<dim3(MT, 8, 8), 256, MG_SMEM>>>(fh, fl, wth, wtl, Zx, N_, 512,
                                               (long long)N_ * 128, (long long)N_ * 512, 0);
    bsplit<<<(512 * 128 + 255) / 256, 256>>>(Wh, wth, wtl, 512);
    fill_f<<<(N_ * 128 + 255) / 256, 256>>>(cbuf, 0.f, N_ * 128);
    for (int t = 0; t < T_; t++) {
        if (t > 0) {
            mma_gemm<<<dim3(MT, 8, 1), 256, MG_SMEM>>>(hbh, hbl, wth, wtl,
                                                       Zx + (size_t)t * N_ * 512, N_, 512, 0, 0, 1);
        }
        lstm_pw<<<(N_ * 128 + 255) / 256, 256>>>(b_lstm, t);
    }

    // decoder: one fused GEMM (emb | scal)
    bsplit<<<(64 * 128 + 255) / 256, 256>>>(embW, wth, wtl, 64);
    bsplit<<<(64 * 128 + 255) / 256, 256>>>(scalW, wth + 64 * 128, wtl + 64 * 128, 64);
    mma_gemm<<<dim3(MT, 2, 1), 256, MG_SMEM>>>(hbh, hbl, wth, wtl, dec, N_, 128, 0, 0, 0);
    fill_f<<<1, 64>>>(colsq, 0.f, 64);
    emb_tanh<<<(N_ * 64 + 255) / 256, 256>>>(embB);
    build_P<<<N_, 64>>>(scalB);
    pairwise_mma<<<dim3(JT, MT), 256, MG_SMEM>>>(out);
}

// round 8
// speedup vs baseline: 2.9003x; 1.0397x over previous
#include <cuda_runtime.h>
#include <cuda_bf16.h>
#include <cuda_fp16.h>
#include <math.h>
#include <stdint.h>

#define T_ 8
#define N_ 10000
#define E_ 320000
#define H_ 4
#define NCOM_ 100

// ===== scratch =====
__device__ int   g_is64;
__device__ __align__(16) __half g_h1h[(size_t)T_ * N_ * 128];
__device__ __align__(16) __half g_h2h[(size_t)T_ * N_ * 64];
__device__ __align__(16) float g_agg[(size_t)T_ * N_ * 128];
__device__ __align__(16) float g_as[T_ * N_ * H_];
__device__ __align__(16) float g_ad[T_ * N_ * H_];
__device__ int   g_cnt[T_ * N_];
__device__ int   g_rowptr[T_ * (N_ + 1)];
__device__ int   g_cursor[T_ * N_];
__device__ int   g_sorted[T_ * E_];
__device__ float g_comnum[T_ * NCOM_ * 64];
__device__ float g_comden[T_ * NCOM_];
__device__ __align__(16) float g_Zx[(size_t)T_ * N_ * 512];
__device__ __align__(16) float g_cbuf[N_ * 128];
__device__ __align__(16) float g_dec[N_ * 128];
__device__ float g_sq[N_];
__device__ float g_colsq[64];
__device__ __align__(16) __nv_bfloat16 g_fh[(size_t)T_ * N_ * 128];
__device__ __align__(16) __nv_bfloat16 g_fl[(size_t)T_ * N_ * 128];
__device__ __align__(16) __nv_bfloat16 g_hbh[N_ * 128];
__device__ __align__(16) __nv_bfloat16 g_hbl[N_ * 128];
__device__ __align__(16) __nv_bfloat16 g_ph[N_ * 128];
__device__ __align__(16) __nv_bfloat16 g_pl[N_ * 128];
__device__ __align__(16) __nv_bfloat16 g_wth[512 * 128];
__device__ __align__(16) __nv_bfloat16 g_wtl[512 * 128];

// ===== helpers =====
__device__ __forceinline__ long long ld_idx(const void* p, size_t i) {
    if (g_is64) return ((const long long*)p)[i];
    return (long long)((const int*)p)[i];
}
__device__ __forceinline__ float sigf(float x) { return 1.f / (1.f + expf(-x)); }
__device__ __forceinline__ float sigf_fast(float x) {
    return __fdividef(1.f, 1.f + __expf(-x));
}
__device__ __forceinline__ float tanh_fast(float x) {
    float e = __expf(2.f * x);
    return 1.f - __fdividef(2.f, e + 1.f);
}
__device__ __forceinline__ float tanh_hw(float x) {
    float y;
    asm("tanh.approx.f32 %0, %1;" : "=f"(y) : "f"(x));
    return y;
}
__device__ __forceinline__ void mma16816(float* c, uint32_t a0, uint32_t a1, uint32_t a2,
                                         uint32_t a3, uint32_t b0, uint32_t b1) {
    asm volatile(
        "mma.sync.aligned.m16n8k16.row.col.f32.bf16.bf16.f32 "
        "{%0,%1,%2,%3}, {%4,%5,%6,%7}, {%8,%9}, {%0,%1,%2,%3};"
        : "+f"(c[0]), "+f"(c[1]), "+f"(c[2]), "+f"(c[3])
        : "r"(a0), "r"(a1), "r"(a2), "r"(a3), "r"(b0), "r"(b1));
}

__global__ void detect64_kernel(const int* ei32) {
    int ok = 1;
    for (int i = 1; i < 64; i += 2)
        if (ei32[i] != 0) ok = 0;
    g_is64 = ok;
}
__global__ void fill_f(float* p, float v, int n) {
    int i = blockIdx.x * blockDim.x + threadIdx.x;
    if (i < n) p[i] = v;
}
__global__ void fill_i(int* p, int v, int n) {
    int i = blockIdx.x * blockDim.x + threadIdx.x;
    if (i < n) p[i] = v;
}
__global__ void split8(const float4* __restrict__ x, uint4* __restrict__ hi,
                       uint4* __restrict__ lo, int n8) {
    int i = blockIdx.x * blockDim.x + threadIdx.x;
    if (i >= n8) return;
    float4 a = x[2 * i], b = x[2 * i + 1];
    float v[8] = {a.x, a.y, a.z, a.w, b.x, b.y, b.z, b.w};
    unsigned ho[4], lo4[4];
#pragma unroll
    for (int j = 0; j < 4; j++) {
        __nv_bfloat162 h2 = __floats2bfloat162_rn(v[2 * j], v[2 * j + 1]);
        __nv_bfloat162 l2 = __floats2bfloat162_rn(v[2 * j] - __low2float(h2),
                                                  v[2 * j + 1] - __high2float(h2));
        ho[j] = *reinterpret_cast<unsigned*>(&h2);
        lo4[j] = *reinterpret_cast<unsigned*>(&l2);
    }
    hi[i] = make_uint4(ho[0], ho[1], ho[2], ho[3]);
    lo[i] = make_uint4(lo4[0], lo4[1], lo4[2], lo4[3]);
}
__global__ void bsplit(const float* __restrict__ B, __nv_bfloat16* __restrict__ bth,
                       __nv_bfloat16* __restrict__ btl, int Dn) {
    int idx = blockIdx.x * blockDim.x + threadIdx.x;
    if (idx >= Dn * 128) return;
    int n = idx >> 7, k = idx & 127;
    float v = B[(size_t)k * Dn + n];
    __nv_bfloat16 h = __float2bfloat16_rn(v);
    bth[idx] = h;
    btl[idx] = __float2bfloat16_rn(v - __bfloat162float(h));
}

// ===== MMA GEMM: CTA tile 128x64, 256 threads, warp grid 4(row)x2(col), warp tile 32x32 =====
#define SM_A 0
#define SM_B 69632
#define SM_SQ 104448
#define MG_SMEM 104960

__device__ __forceinline__ void cp_tile_int(const uint4* __restrict__ Gh,
                                            const uint4* __restrict__ Gl,
                                            char* sm, int off, int base, int Mlim,
                                            int tid, int rows) {
#pragma unroll
    for (int i = 0; i < rows * 16; i += 256) {
        int idx = tid + i;
        int row = idx >> 4, c = idx & 15;
        uint4 vh = make_uint4(0, 0, 0, 0), vl = vh;
        if (base + row < Mlim) {
            vh = Gh[(size_t)(base + row) * 16 + c];
            vl = Gl[(size_t)(base + row) * 16 + c];
        }
        uint4 p0 = make_uint4(vh.x, vl.x, vh.y, vl.y);
        uint4 p1 = make_uint4(vh.z, vl.z, vh.w, vl.w);
        uint4* dst = (uint4*)(sm + off) + ((row * 68 + 4 * c) >> 1);
        dst[0] = p0;
        dst[1] = p1;
    }
}

// mode: 0 = store fp32, 1 = accumulate fp32, 2 = store fp16
__global__ __launch_bounds__(256, 2) void mma_gemm(
    const __nv_bfloat16* __restrict__ Ah, const __nv_bfloat16* __restrict__ Al,
    const __nv_bfloat16* __restrict__ Bh, const __nv_bfloat16* __restrict__ Bl,
    void* __restrict__ Cv, int M, int Dn,
    long long sA, long long sC, int mode)
{
    extern __shared__ char sm[];
    int tid = threadIdx.x, w = tid >> 5, lane = tid & 31;
    int g = lane >> 2, tq = lane & 3;
    int wr = w >> 1, wc = w & 1;
    int m0 = blockIdx.x * 128, n0 = blockIdx.y * 64, t = blockIdx.z;
    Ah += (size_t)t * sA; Al += (size_t)t * sA;

    cp_tile_int((const uint4*)Ah, (const uint4*)Al, sm, SM_A, m0, M, tid, 128);
    cp_tile_int((const uint4*)Bh, (const uint4*)Bl, sm, SM_B, n0, Dn, tid, 64);
    __syncthreads();

    const uint2* SA = (const uint2*)(sm + SM_A);
    const uint2* SB = (const uint2*)(sm + SM_B);

    float acc[2][4][4];
#pragma unroll
    for (int rg = 0; rg < 2; rg++)
#pragma unroll
        for (int nb = 0; nb < 4; nb++)
#pragma unroll
            for (int q = 0; q < 4; q++) acc[rg][nb][q] = 0.f;

    int ra0 = (wr * 32 + g) * 68;
    int rb0 = ra0 + 8 * 68, ra1 = ra0 + 16 * 68, rb1 = ra0 + 24 * 68;
#pragma unroll
    for (int kc = 0; kc < 8; kc++) {
        int ka = kc * 8 + tq;
        uint2 A00 = SA[ra0 + ka], A01 = SA[rb0 + ka];
        uint2 A02 = SA[ra0 + ka + 4], A03 = SA[rb0 + ka + 4];
        uint2 A10 = SA[ra1 + ka], A11 = SA[rb1 + ka];
        uint2 A12 = SA[ra1 + ka + 4], A13 = SA[rb1 + ka + 4];
#pragma unroll
        for (int nb = 0; nb < 4; nb++) {
            int nr = (wc * 32 + nb * 8 + g) * 68;
            uint2 B0 = SB[nr + ka], B1 = SB[nr + ka + 4];
            mma16816(acc[0][nb], A00.x, A01.x, A02.x, A03.x, B0.x, B1.x);
            mma16816(acc[0][nb], A00.x, A01.x, A02.x, A03.x, B0.y, B1.y);
            mma16816(acc[0][nb], A00.y, A01.y, A02.y, A03.y, B0.x, B1.x);
            mma16816(acc[1][nb], A10.x, A11.x, A12.x, A13.x, B0.x, B1.x);
            mma16816(acc[1][nb], A10.x, A11.x, A12.x, A13.x, B0.y, B1.y);
            mma16816(acc[1][nb], A10.y, A11.y, A12.y, A13.y, B0.x, B1.x);
        }
    }

#pragma unroll
    for (int rg = 0; rg < 2; rg++) {
        int r0 = m0 + wr * 32 + rg * 16 + g, r1 = r0 + 8;
#pragma unroll
        for (int nb = 0; nb < 4; nb++) {
            int col = n0 + wc * 32 + nb * 8 + 2 * tq;
            if (mode == 2) {
                __half* Ch = (__half*)Cv + (size_t)t * sC;
                if (r0 < M) {
                    __half2 v = __floats2half2_rn(acc[rg][nb][0], acc[rg][nb][1]);
                    *(__half2*)(Ch + (size_t)r0 * Dn + col) = v;
                }
                if (r1 < M) {
                    __half2 v = __floats2half2_rn(acc[rg][nb][2], acc[rg][nb][3]);
                    *(__half2*)(Ch + (size_t)r1 * Dn + col) = v;
                }
            } else {
                float* C = (float*)Cv + (size_t)t * sC;
                if (r0 < M) {
                    float2* p = (float2*)(C + (size_t)r0 * Dn + col);
                    float2 v = make_float2(acc[rg][nb][0], acc[rg][nb][1]);
                    if (mode == 1) { float2 o = *p; v.x += o.x; v.y += o.y; }
                    *p = v;
                }
                if (r1 < M) {
                    float2* p = (float2*)(C + (size_t)r1 * Dn + col);
                    float2 v = make_float2(acc[rg][nb][2], acc[rg][nb][3]);
                    if (mode == 1) { float2 o = *p; v.x += o.x; v.y += o.y; }
                    *p = v;
                }
            }
        }
    }
}

// ===== pairwise: CTA 128(i) x 64(j), warp tile 32x32, symmetric culling =====
__global__ __launch_bounds__(256, 2) void pairwise_mma(float* __restrict__ out) {
    int i0 = blockIdx.y * 128, j0 = blockIdx.x * 64;
    if (j0 + 64 <= i0) return;
    extern __shared__ char sm[];
    int tid = threadIdx.x, w = tid >> 5, lane = tid & 31;
    int g = lane >> 2, tq = lane & 3;
    int wr = w >> 1, wc = w & 1;
    float* sqB = (float*)(sm + SM_SQ);

    cp_tile_int((const uint4*)g_ph, (const uint4*)g_pl, sm, SM_A, i0, N_, tid, 128);
    cp_tile_int((const uint4*)g_ph, (const uint4*)g_pl, sm, SM_B, j0, N_, tid, 64);
    if (tid < 64) sqB[tid] = (j0 + tid < N_) ? g_sq[j0 + tid] : 0.f;
    __syncthreads();

    const uint2* SA = (const uint2*)(sm + SM_A);
    const uint2* SB = (const uint2*)(sm + SM_B);

    float accG[2][4][4], accS[2][4][4];
#pragma unroll
    for (int rg = 0; rg < 2; rg++)
#pragma unroll
        for (int nb = 0; nb < 4; nb++)
#pragma unroll
            for (int q = 0; q < 4; q++) { accG[rg][nb][q] = 0.f; accS[rg][nb][q] = 0.f; }

    int ra0 = (wr * 32 + g) * 68;
    int rb0 = ra0 + 8 * 68, ra1 = ra0 + 16 * 68, rb1 = ra0 + 24 * 68;
#pragma unroll
    for (int kc = 0; kc < 8; kc++) {
        int ka = kc * 8 + tq;
        uint2 A00 = SA[ra0 + ka], A01 = SA[rb0 + ka];
        uint2 A02 = SA[ra0 + ka + 4], A03 = SA[rb0 + ka + 4];
        uint2 A10 = SA[ra1 + ka], A11 = SA[rb1 + ka];
        uint2 A12 = SA[ra1 + ka + 4], A13 = SA[rb1 + ka + 4];
        float (*a0)[4] = (kc < 4) ? accG[0] : accS[0];
        float (*a1)[4] = (kc < 4) ? accG[1] : accS[1];
#pragma unroll
        for (int nb = 0; nb < 4; nb++) {
            int nr = (wc * 32 + nb * 8 + g) * 68;
            uint2 B0 = SB[nr + ka], B1 = SB[nr + ka + 4];
            mma16816(a0[nb], A00.x, A01.x, A02.x, A03.x, B0.x, B1.x);
            mma16816(a0[nb], A00.x, A01.x, A02.x, A03.x, B0.y, B1.y);
            mma16816(a0[nb], A00.y, A01.y, A02.y, A03.y, B0.x, B1.x);
            mma16816(a1[nb], A10.x, A11.x, A12.x, A13.x, B0.x, B1.x);
            mma16816(a1[nb], A10.x, A11.x, A12.x, A13.x, B0.y, B1.y);
            mma16816(a1[nb], A10.y, A11.y, A12.y, A13.y, B0.x, B1.x);
        }
    }

    bool full = (i0 + 128 <= N_) && (j0 + 64 <= N_);
    float vv[2][4][4];
#pragma unroll
    for (int rg = 0; rg < 2; rg++) {
        int lr0 = wr * 32 + rg * 16 + g, lr1 = lr0 + 8;
        int ir0 = i0 + lr0, ir1 = i0 + lr1;
        float sqi0 = (ir0 < N_) ? g_sq[ir0] : 0.f;
        float sqi1 = (ir1 < N_) ? g_sq[ir1] : 0.f;
#pragma unroll
        for (int nb = 0; nb < 4; nb++) {
            int c0 = wc * 32 + nb * 8 + 2 * tq, c1 = c0 + 1;
            float sj0 = sqB[c0], sj1 = sqB[c1];
            vv[rg][nb][0] = 1.f + tanh_hw((2.f * accG[rg][nb][0] - sqi0 - sj0) * accS[rg][nb][0]);
            vv[rg][nb][1] = 1.f + tanh_hw((2.f * accG[rg][nb][1] - sqi0 - sj1) * accS[rg][nb][1]);
            vv[rg][nb][2] = 1.f + tanh_hw((2.f * accG[rg][nb][2] - sqi1 - sj0) * accS[rg][nb][2]);
            vv[rg][nb][3] = 1.f + tanh_hw((2.f * accG[rg][nb][3] - sqi1 - sj1) * accS[rg][nb][3]);
            if (full) {
                *(float2*)(out + (size_t)ir0 * N_ + j0 + c0) = make_float2(vv[rg][nb][0], vv[rg][nb][1]);
                *(float2*)(out + (size_t)ir1 * N_ + j0 + c0) = make_float2(vv[rg][nb][2], vv[rg][nb][3]);
            } else {
                if (ir0 < N_) {
                    if (j0 + c0 < N_) out[(size_t)ir0 * N_ + j0 + c0] = vv[rg][nb][0];
                    if (j0 + c1 < N_) out[(size_t)ir0 * N_ + j0 + c1] = vv[rg][nb][1];
                }
                if (ir1 < N_) {
                    if (j0 + c0 < N_) out[(size_t)ir1 * N_ + j0 + c0] = vv[rg][nb][2];
                    if (j0 + c1 < N_) out[(size_t)ir1 * N_ + j0 + c1] = vv[rg][nb][3];
                }
            }
        }
    }

    // mirror: stage transpose in reused A smem, write (jj, ii) for jj > ii
    __syncthreads();
    float* vT = (float*)(sm + SM_A);  // [64][129]
#pragma unroll
    for (int rg = 0; rg < 2; rg++) {
        int lr0 = wr * 32 + rg * 16 + g, lr1 = lr0 + 8;
#pragma unroll
        for (int nb = 0; nb < 4; nb++) {
            int c0 = wc * 32 + nb * 8 + 2 * tq, c1 = c0 + 1;
            vT[c0 * 129 + lr0] = vv[rg][nb][0];
            vT[c1 * 129 + lr0] = vv[rg][nb][1];
            vT[c0 * 129 + lr1] = vv[rg][nb][2];
            vT[c1 * 129 + lr1] = vv[rg][nb][3];
        }
    }
    __syncthreads();
    for (int idx = tid; idx < 64 * 128; idx += 256) {
        int r2 = idx >> 7, c2 = idx & 127;
        int jj = j0 + r2, ii = i0 + c2;
        if (jj > ii && jj < N_ && ii < N_) out[(size_t)jj * N_ + ii] = vT[r2 * 129 + c2];
    }
}

// ===== GAT kernels =====
__global__ void alpha_kernel(const __half* __restrict__ h, const float* __restrict__ a_s,
                             const float* __restrict__ a_d, int dh) {
    int idx = blockIdx.x * blockDim.x + threadIdx.x;
    if (idx >= T_ * N_ * H_) return;
    int hh = idx & 3, tn = idx >> 2;
    const __half* hr = h + (size_t)tn * (H_ * dh) + hh * dh;
    float s = 0.f, d = 0.f;
    for (int k = 0; k < dh; k++) {
        float v = __half2float(hr[k]);
        s += v * a_s[hh * dh + k];
        d += v * a_d[hh * dh + k];
    }
    g_as[idx] = s; g_ad[idx] = d;
}
__global__ void csr_count(const void* ei) {
    int idx = blockIdx.x * blockDim.x + threadIdx.x;
    if (idx >= T_ * E_) return;
    int t = idx / E_, e = idx - t * E_;
    int dst = (int)ld_idx(ei, (size_t)t * 2 * E_ + E_ + e);
    atomicAdd(&g_cnt[t * N_ + dst], 1);
}
__global__ void csr_scan() {
    int t = blockIdx.x, tid = threadIdx.x;
    __shared__ int sh[1024];
    int off = 0;
    for (int chunk = 0; chunk < N_; chunk += 1024) {
        int i = chunk + tid;
        int v = (i < N_) ? g_cnt[t * N_ + i] : 0;
        sh[tid] = v;
        __syncthreads();
        for (int d2 = 1; d2 < 1024; d2 <<= 1) {
            int x = 0;
            if (tid >= d2) x = sh[tid - d2];
            __syncthreads();
            sh[tid] += x;
            __syncthreads();
        }
        if (i < N_) g_rowptr[t * (N_ + 1) + i] = off + sh[tid] - v;
        int tot = sh[1023];
        __syncthreads();
        off += tot;
    }
    if (tid == 0) g_rowptr[t * (N_ + 1) + N_] = off;
}
__global__ void csr_scatter(const void* ei) {
    int idx = blockIdx.x * blockDim.x + threadIdx.x;
    if (idx >= T_ * E_) return;
    int t = idx / E_, e = idx - t * E_;
    int dst = (int)ld_idx(ei, (size_t)t * 2 * E_ + E_ + e);
    int pos = atomicAdd(&g_cursor[t * N_ + dst], 1);
    g_sorted[t * E_ + g_rowptr[t * (N_ + 1) + dst] + pos] = e;
}

// fused gather (ex + den + softmax + elu + bf16 split output); hsrc is fp16
template <int D, int DH, int L1>
__global__ void gat_gather(const void* ei, const float* __restrict__ ew,
                           const __half* __restrict__ hsrc,
                           __nv_bfloat16* __restrict__ oh, __nv_bfloat16* __restrict__ ol,
                           float* __restrict__ ofp) {
    int t = blockIdx.y, n = blockIdx.x, tid = threadIdx.x;
    int start = g_rowptr[t * (N_ + 1) + n];
    int end = g_rowptr[t * (N_ + 1) + n + 1];
    int head = tid / DH;
    __shared__ int s_src[64];
    __shared__ float s_ex[64][4];
    float4 ad4 = *(const float4*)&g_ad[(t * N_ + n) * 4];
    float acc = 0.f, den = 0.f;
    for (int base = start; base < end; base += 64) {
        int cnt = min(64, end - base);
        __syncthreads();
        for (int i = tid; i < cnt; i += D) {
            int eid = g_sorted[t * E_ + base + i];
            int src = (int)ld_idx(ei, (size_t)t * 2 * E_ + eid);
            s_src[i] = src;
            float4 s4 = *(const float4*)&g_as[(t * N_ + src) * 4];
            float wv = ew[(size_t)t * E_ + eid];
            float e0 = s4.x + ad4.x; e0 = e0 > 0.f ? e0 : 0.2f * e0;
            float e1 = s4.y + ad4.y; e1 = e1 > 0.f ? e1 : 0.2f * e1;
            float e2 = s4.z + ad4.z; e2 = e2 > 0.f ? e2 : 0.2f * e2;
            float e3 = s4.w + ad4.w; e3 = e3 > 0.f ? e3 : 0.2f * e3;
            s_ex[i][0] = __expf(e0) * wv;
            s_ex[i][1] = __expf(e1) * wv;
            s_ex[i][2] = __expf(e2) * wv;
            s_ex[i][3] = __expf(e3) * wv;
        }
        __syncthreads();
#pragma unroll 8
        for (int i = 0; i < cnt; i++) {
            float exv = s_ex[i][head];
            den += exv;
            acc += exv * __half2float(hsrc[((size_t)t * N_ + s_src[i]) * D + tid]);
        }
    }
    float v = acc / (den + 1e-16f);
    v = v > 0.f ? v : __expf(v) - 1.f;
    size_t o = ((size_t)t * N_ + n) * 128 + tid;
    __nv_bfloat16 hh = __float2bfloat16_rn(v);
    oh[o] = hh;
    ol[o] = __float2bfloat16_rn(v - __bfloat162float(hh));
    if (!L1) ofp[o] = v;
}

// ===== meso =====
#define MCHUNK 500
__global__ void meso_acc(const void* part, const float* __restrict__ Dw) {
    int t = blockIdx.y, c0 = blockIdx.x * MCHUNK, tid = threadIdx.x;
    __shared__ float sn[NCOM_ * 64];
    __shared__ float sd[NCOM_];
    __shared__ int sp[MCHUNK];
    __shared__ float sD[MCHUNK];
    for (int i = tid; i < NCOM_ * 64; i += blockDim.x) sn[i] = 0.f;
    for (int i = tid; i < NCOM_; i += blockDim.x) sd[i] = 0.f;
    int nmax = min(MCHUNK, N_ - c0);
    for (int i = tid; i < nmax; i += blockDim.x) {
        sp[i] = (int)ld_idx(part, (size_t)t * N_ + c0 + i);
        sD[i] = Dw[(size_t)t * N_ + c0 + i];
    }
    __syncthreads();
    for (int idx = tid; idx < nmax * 64; idx += blockDim.x) {
        int nl = idx >> 6, c = idx & 63;
        float g = g_agg[((size_t)t * N_ + c0 + nl) * 128 + c];
        atomicAdd(&sn[sp[nl] * 64 + c], sD[nl] * g);
        if (c == 0) atomicAdd(&sd[sp[nl]], sD[nl]);
    }
    __syncthreads();
    for (int i = tid; i < NCOM_ * 64; i += blockDim.x)
        atomicAdd(&g_comnum[t * NCOM_ * 64 + i], sn[i]);
    for (int i = tid; i < NCOM_; i += blockDim.x)
        atomicAdd(&g_comden[t * NCOM_ + i], sd[i]);
}
__global__ void meso_scatter(const void* part, __nv_bfloat16* __restrict__ oh,
                             __nv_bfloat16* __restrict__ ol) {
    int idx = blockIdx.x * blockDim.x + threadIdx.x;
    if (idx >= T_ * N_ * 64) return;
    int t = idx / (N_ * 64);
    int r = idx - t * N_ * 64;
    int n = r >> 6, c = r & 63;
    int p = (int)ld_idx(part, (size_t)t * N_ + n);
    float mean = g_comnum[(t * NCOM_ + p) * 64 + c] / (g_comden[t * NCOM_ + p] + 1e-16f);
    size_t o = ((size_t)t * N_ + n) * 128 + 64 + c;
    __nv_bfloat16 hh = __float2bfloat16_rn(mean);
    oh[o] = hh;
    ol[o] = __float2bfloat16_rn(mean - __bfloat162float(hh));
}

// ===== LSTM pointwise =====
__global__ void lstm_pw(const float* __restrict__ b, int t) {
    int idx = blockIdx.x * blockDim.x + threadIdx.x;
    if (idx >= N_ * 128) return;
    int n = idx >> 7, j = idx & 127;
    const float* z = g_Zx + (size_t)t * N_ * 512 + (size_t)n * 512;
    float i_ = z[j] + b[j];
    float f_ = z[128 + j] + b[128 + j];
    float gg = z[256 + j] + b[256 + j];
    float o_ = z[384 + j] + b[384 + j];
    float c = sigf_fast(f_) * g_cbuf[idx] + sigf_fast(i_) * tanh_fast(gg);
    g_cbuf[idx] = c;
    float h = sigf_fast(o_) * tanh_fast(c);
    __nv_bfloat16 hh = __float2bfloat16_rn(h);
    g_hbh[idx] = hh;
    g_hbl[idx] = __float2bfloat16_rn(h - __bfloat162float(hh));
}

// ===== decoder prep =====
__global__ void emb_tanh(const float* __restrict__ emb_b) {
    __shared__ float s[64];
    int tid = threadIdx.x;
    if (tid < 64) s[tid] = 0.f;
    __syncthreads();
    int idx = blockIdx.x * 256 + tid;
    if (idx < N_ * 64) {
        int n = idx >> 6, c = idx & 63;
        float v = tanhf(g_dec[n * 128 + c] + emb_b[c]);
        g_dec[n * 128 + c] = v;
        atomicAdd(&s[c], v * v);
    }
    __syncthreads();
    if (tid < 64) atomicAdd(&g_colsq[tid], s[tid]);
}
__global__ void build_P(const float* __restrict__ scal_b) {
    int n = blockIdx.x, c = threadIdx.x;
    float e = g_dec[n * 128 + c] / sqrtf(g_colsq[c]);
    float s = sigf(g_dec[n * 128 + 64 + c] + scal_b[c]);
    __nv_bfloat16 eh = __float2bfloat16_rn(e);
    g_ph[n * 128 + c] = eh;
    g_pl[n * 128 + c] = __float2bfloat16_rn(e - __bfloat162float(eh));
    __nv_bfloat16 sh2 = __float2bfloat16_rn(s);
    g_ph[n * 128 + 64 + c] = sh2;
    g_pl[n * 128 + 64 + c] = __float2bfloat16_rn(s - __bfloat162float(sh2));
    float v = e * e;
#pragma unroll
    for (int o = 16; o; o >>= 1) v += __shfl_down_sync(0xffffffff, v, o);
    __shared__ float shm[2];
    if ((c & 31) == 0) shm[c >> 5] = v;
    __syncthreads();
    if (c == 0) g_sq[n] = shm[0] + shm[1];
}

// ===== host =====
extern "C" void kernel_launch(void* const* d_in, const int* in_sizes, int n_in,
                              void* d_out, int out_size) {
    const float* feat   = (const float*)d_in[0];
    const float* ew     = (const float*)d_in[1];
    const float* Dw     = (const float*)d_in[2];
    const float* W1     = (const float*)d_in[3];
    const float* a_s1   = (const float*)d_in[4];
    const float* a_d1   = (const float*)d_in[5];
    const float* W2     = (const float*)d_in[6];
    const float* a_s2   = (const float*)d_in[7];
    const float* a_d2   = (const float*)d_in[8];
    const float* Wx     = (const float*)d_in[9];
    const float* Wh     = (const float*)d_in[10];
    const float* b_lstm = (const float*)d_in[11];
    const float* embW   = (const float*)d_in[12];
    const float* embB   = (const float*)d_in[13];
    const float* scalW  = (const float*)d_in[14];
    const float* scalB  = (const float*)d_in[15];
    const void*  ei     = (const void*)d_in[16];
    const void*  part   = (const void*)d_in[17];
    float* out = (float*)d_out;

    cudaFuncSetAttribute(mma_gemm, cudaFuncAttributeMaxDynamicSharedMemorySize, MG_SMEM);
    cudaFuncSetAttribute(pairwise_mma, cudaFuncAttributeMaxDynamicSharedMemorySize, MG_SMEM);

    float *agg, *Zx, *cbuf, *dec, *comnum, *comden, *colsq;
    int *cnt, *cursor;
    __half *h1h, *h2h;
    __nv_bfloat16 *fh, *fl, *hbh, *hbl, *wth, *wtl;
    cudaGetSymbolAddress((void**)&h1h, g_h1h);
    cudaGetSymbolAddress((void**)&h2h, g_h2h);
    cudaGetSymbolAddress((void**)&agg, g_agg);
    cudaGetSymbolAddress((void**)&Zx, g_Zx);
    cudaGetSymbolAddress((void**)&cbuf, g_cbuf);
    cudaGetSymbolAddress((void**)&dec, g_dec);
    cudaGetSymbolAddress((void**)&comnum, g_comnum);
    cudaGetSymbolAddress((void**)&comden, g_comden);
    cudaGetSymbolAddress((void**)&colsq, g_colsq);
    cudaGetSymbolAddress((void**)&cnt, g_cnt);
    cudaGetSymbolAddress((void**)&cursor, g_cursor);
    cudaGetSymbolAddress((void**)&fh, g_fh);
    cudaGetSymbolAddress((void**)&fl, g_fl);
    cudaGetSymbolAddress((void**)&hbh, g_hbh);
    cudaGetSymbolAddress((void**)&hbl, g_hbl);
    cudaGetSymbolAddress((void**)&wth, g_wth);
    cudaGetSymbolAddress((void**)&wtl, g_wtl);

    const int MT = 79;   // ceil(10000/128)
    const int JT = 157;  // ceil(10000/64)
    const int TE = T_ * E_;
    const int TNH = T_ * N_ * H_;
    const int NS8 = T_ * N_ * 128 / 8;

    detect64_kernel<<<1, 1>>>((const int*)ei);

    // GAT layer 1
    split8<<<(NS8 + 255) / 256, 256>>>((const float4*)feat, (uint4*)fh, (uint4*)fl, NS8);
    bsplit<<<(128 * 128 + 255) / 256, 256>>>(W1, wth, wtl, 128);
    mma_gemm<<<dim3(MT, 2, 8), 256, MG_SMEM>>>(fh, fl, wth, wtl, h1h, N_, 128,
                                               (long long)N_ * 128, (long long)N_ * 128, 2);
    alpha_kernel<<<(TNH + 255) / 256, 256>>>(h1h, a_s1, a_d1, 32);

    fill_i<<<(T_ * N_ + 255) / 256, 256>>>(cnt, 0, T_ * N_);
    csr_count<<<(TE + 255) / 256, 256>>>(ei);
    csr_scan<<<T_, 1024>>>();
    fill_i<<<(T_ * N_ + 255) / 256, 256>>>(cursor, 0, T_ * N_);
    csr_scatter<<<(TE + 255) / 256, 256>>>(ei);

    gat_gather<128, 32, 1><<<dim3(N_, T_), 128>>>(ei, ew, h1h, fh, fl, (float*)0);

    // GAT layer 2
    bsplit<<<(64 * 128 + 255) / 256, 256>>>(W2, wth, wtl, 64);
    mma_gemm<<<dim3(MT, 1, 8), 256, MG_SMEM>>>(fh, fl, wth, wtl, h2h, N_, 64,
                                               (long long)N_ * 128, (long long)N_ * 64, 2);
    alpha_kernel<<<(TNH + 255) / 256, 256>>>(h2h, a_s2, a_d2, 16);
    gat_gather<64, 16, 0><<<dim3(N_, T_), 64>>>(ei, ew, h2h, fh, fl, agg);

    // meso
    fill_f<<<(T_ * NCOM_ * 64 + 255) / 256, 256>>>(comnum, 0.f, T_ * NCOM_ * 64);
    fill_f<<<(T_ * NCOM_ + 255) / 256, 256>>>(comden, 0.f, T_ * NCOM_);
    meso_acc<<<dim3((N_ + MCHUNK - 1) / MCHUNK, T_), 256>>>(part, Dw);
    meso_scatter<<<(T_ * N_ * 64 + 255) / 256, 256>>>(part, fh, fl);

    // LSTM
    bsplit<<<(512 * 128 + 255) / 256, 256>>>(Wx, wth, wtl, 512);
    mma_gemm<<<dim3(MT, 8, 8), 256, MG_SMEM>>>(fh, fl, wth, wtl, Zx, N_, 512,
                                               (long long)N_ * 128, (long long)N_ * 512, 0);
    bsplit<<<(512 * 128 + 255) / 256, 256>>>(Wh, wth, wtl, 512);
    fill_f<<<(N_ * 128 + 255) / 256, 256>>>(cbuf, 0.f, N_ * 128);
    for (int t = 0; t < T_; t++) {
        if (t > 0) {
            mma_gemm<<<dim3(MT, 8, 1), 256, MG_SMEM>>>(hbh, hbl, wth, wtl,
                                                       Zx + (size_t)t * N_ * 512, N_, 512, 0, 0, 1);
        }
        lstm_pw<<<(N_ * 128 + 255) / 256, 256>>>(b_lstm, t);
    }

    // decoder: one fused GEMM (emb | scal)
    bsplit<<<(64 * 128 + 255) / 256, 256>>>(embW, wth, wtl, 64);
    bsplit<<<(64 * 128 + 255) / 256, 256>>>(scalW, wth + 64 * 128, wtl + 64 * 128, 64);
    mma_gemm<<<dim3(MT, 2, 1), 256, MG_SMEM>>>(hbh, hbl, wth, wtl, dec, N_, 128, 0, 0, 0);
    fill_f<<<1, 64>>>(colsq, 0.f, 64);
    emb_tanh<<<(N_ * 64 + 255) / 256, 256>>>(embB);
    build_P<<<N_, 64>>>(scalB);
    pairwise_mma<<<dim3(JT, MT), 256, MG_SMEM>>>(out);
}

// round 9
// speedup vs baseline: 3.5110x; 1.2105x over previous
#include <cuda_runtime.h>
#include <cuda_fp16.h>
#include <math.h>
#include <stdint.h>

#define T_ 8
#define N_ 10000
#define E_ 320000
#define H_ 4
#define NCOM_ 100

// ===== scratch =====
__device__ int   g_is64;
__device__ __align__(16) __half g_h1h[(size_t)T_ * N_ * 128];
__device__ __align__(16) __half g_h2h[(size_t)T_ * N_ * 64];
__device__ __align__(16) __half g_f[(size_t)T_ * N_ * 128];      // universal fp16 A buffer
__device__ __align__(16) float g_agg[(size_t)T_ * N_ * 128];     // fp32 (meso input, cols 0-63)
__device__ __align__(16) float g_as[T_ * N_ * H_];
__device__ __align__(16) float g_ad[T_ * N_ * H_];
__device__ int   g_cnt[T_ * N_];
__device__ int   g_rowptr[T_ * (N_ + 1)];
__device__ int   g_cursor[T_ * N_];
__device__ int   g_sorted[T_ * E_];
__device__ float g_comnum[T_ * NCOM_ * 64];
__device__ float g_comden[T_ * NCOM_];
__device__ __align__(16) float g_Zx[(size_t)T_ * N_ * 512];
__device__ __align__(16) float g_cbuf[N_ * 128];
__device__ __align__(16) float g_dec[N_ * 128];
__device__ float g_colsq[64];
__device__ __align__(16) __half g_hb[N_ * 128];
__device__ __align__(16) __half g_pa[(size_t)N_ * 160];
__device__ __align__(16) __half g_pb[(size_t)N_ * 160];
__device__ __align__(16) __half g_wt[512 * 128];

// ===== helpers =====
__device__ __forceinline__ long long ld_idx(const void* p, size_t i) {
    if (g_is64) return ((const long long*)p)[i];
    return (long long)((const int*)p)[i];
}
__device__ __forceinline__ float sigf(float x) { return 1.f / (1.f + expf(-x)); }
__device__ __forceinline__ float sigf_fast(float x) {
    return __fdividef(1.f, 1.f + __expf(-x));
}
__device__ __forceinline__ float tanh_fast(float x) {
    float e = __expf(2.f * x);
    return 1.f - __fdividef(2.f, e + 1.f);
}
__device__ __forceinline__ float tanh_hw(float x) {
    float y;
    asm("tanh.approx.f32 %0, %1;" : "=f"(y) : "f"(x));
    return y;
}
// 1 + tanh(x): cubic for small |x| (err<1e-5), MUFU otherwise
__device__ __forceinline__ float one_p_tanh(float x) {
    float ax = fabsf(x);
    if (ax < 0.15f) {
        float x2 = x * x;
        return fmaf(x, fmaf(x2, -0.33333333f, 1.f), 1.f);
    }
    return 1.f + tanh_hw(x);
}
__device__ __forceinline__ void mma_f16(float* c, uint32_t a0, uint32_t a1, uint32_t a2,
                                        uint32_t a3, uint32_t b0, uint32_t b1) {
    asm volatile(
        "mma.sync.aligned.m16n8k16.row.col.f32.f16.f16.f32 "
        "{%0,%1,%2,%3}, {%4,%5,%6,%7}, {%8,%9}, {%0,%1,%2,%3};"
        : "+f"(c[0]), "+f"(c[1]), "+f"(c[2]), "+f"(c[3])
        : "r"(a0), "r"(a1), "r"(a2), "r"(a3), "r"(b0), "r"(b1));
}

__global__ void detect64_kernel(const int* ei32) {
    int ok = 1;
    for (int i = 1; i < 64; i += 2)
        if (ei32[i] != 0) ok = 0;
    g_is64 = ok;
}
__global__ void fill_f(float* p, float v, int n) {
    int i = blockIdx.x * blockDim.x + threadIdx.x;
    if (i < n) p[i] = v;
}
__global__ void fill_i(int* p, int v, int n) {
    int i = blockIdx.x * blockDim.x + threadIdx.x;
    if (i < n) p[i] = v;
}
// fp32 -> fp16 (4 per thread)
__global__ void cvt16(const float4* __restrict__ x, __half2* __restrict__ y, int n4) {
    int i = blockIdx.x * blockDim.x + threadIdx.x;
    if (i >= n4) return;
    float4 v = x[i];
    y[2 * i]     = __floats2half2_rn(v.x, v.y);
    y[2 * i + 1] = __floats2half2_rn(v.z, v.w);
}
// transpose weight B[128 x Dn] -> Bt[Dn x 128] fp16
__global__ void wsplit16(const float* __restrict__ B, __half* __restrict__ bt, int Dn) {
    int idx = blockIdx.x * blockDim.x + threadIdx.x;
    if (idx >= Dn * 128) return;
    int n = idx >> 7, k = idx & 127;
    bt[idx] = __float2half(B[(size_t)k * Dn + n]);
}

// ===== fp16 MMA GEMM: CTA 128x64, 256 threads, warp grid 4x2, warp tile 32x32 =====
#define SM_B 34816                 // A: 128 rows * 68 u32 * 4B
#define MG_SMEM 52736              // + B: 64 * 68 * 4

template <int KU4, int SU4>
__device__ __forceinline__ void cp16(const uint4* __restrict__ G, char* sm, int off,
                                     int base, int Mlim, int tid, int rows) {
    int total = rows * KU4;
    for (int idx = tid; idx < total; idx += 256) {
        int row = idx / KU4, c = idx - row * KU4;
        uint4 v = make_uint4(0, 0, 0, 0);
        if (base + row < Mlim) v = G[(size_t)(base + row) * KU4 + c];
        ((uint4*)(sm + off))[row * SU4 + c] = v;
    }
}

// mode: 0 = store fp32, 1 = accumulate fp32, 2 = store fp16
__global__ __launch_bounds__(256, 3) void mma_gemm(
    const __half* __restrict__ A, const __half* __restrict__ B,
    void* __restrict__ Cv, int M, int Dn,
    long long sA, long long sC, int mode)
{
    extern __shared__ char sm[];
    int tid = threadIdx.x, w = tid >> 5, lane = tid & 31;
    int g = lane >> 2, tq = lane & 3;
    int wr = w >> 1, wc = w & 1;
    int m0 = blockIdx.x * 128, n0 = blockIdx.y * 64, t = blockIdx.z;
    A += (size_t)t * sA;

    cp16<16, 17>((const uint4*)A, sm, 0, m0, M, tid, 128);
    cp16<16, 17>((const uint4*)B, sm, SM_B, n0, Dn, tid, 64);
    __syncthreads();

    const uint32_t* SA = (const uint32_t*)sm;
    const uint32_t* SB = (const uint32_t*)(sm + SM_B);

    float acc[2][4][4];
#pragma unroll
    for (int rg = 0; rg < 2; rg++)
#pragma unroll
        for (int nb = 0; nb < 4; nb++)
#pragma unroll
            for (int q = 0; q < 4; q++) acc[rg][nb][q] = 0.f;

    int ra0 = (wr * 32 + g) * 68;
    int rb0 = ra0 + 8 * 68, ra1 = ra0 + 16 * 68, rb1 = ra0 + 24 * 68;
#pragma unroll
    for (int kc = 0; kc < 8; kc++) {
        int ka = kc * 8 + tq;
        uint32_t a00 = SA[ra0 + ka], a01 = SA[rb0 + ka];
        uint32_t a02 = SA[ra0 + ka + 4], a03 = SA[rb0 + ka + 4];
        uint32_t a10 = SA[ra1 + ka], a11 = SA[rb1 + ka];
        uint32_t a12 = SA[ra1 + ka + 4], a13 = SA[rb1 + ka + 4];
#pragma unroll
        for (int nb = 0; nb < 4; nb++) {
            int nr = (wc * 32 + nb * 8 + g) * 68;
            uint32_t b0 = SB[nr + ka], b1 = SB[nr + ka + 4];
            mma_f16(acc[0][nb], a00, a01, a02, a03, b0, b1);
            mma_f16(acc[1][nb], a10, a11, a12, a13, b0, b1);
        }
    }

#pragma unroll
    for (int rg = 0; rg < 2; rg++) {
        int r0 = m0 + wr * 32 + rg * 16 + g, r1 = r0 + 8;
#pragma unroll
        for (int nb = 0; nb < 4; nb++) {
            int col = n0 + wc * 32 + nb * 8 + 2 * tq;
            if (mode == 2) {
                __half* Ch = (__half*)Cv + (size_t)t * sC;
                if (r0 < M)
                    *(__half2*)(Ch + (size_t)r0 * Dn + col) = __floats2half2_rn(acc[rg][nb][0], acc[rg][nb][1]);
                if (r1 < M)
                    *(__half2*)(Ch + (size_t)r1 * Dn + col) = __floats2half2_rn(acc[rg][nb][2], acc[rg][nb][3]);
            } else {
                float* C = (float*)Cv + (size_t)t * sC;
                if (r0 < M) {
                    float2* p = (float2*)(C + (size_t)r0 * Dn + col);
                    float2 v = make_float2(acc[rg][nb][0], acc[rg][nb][1]);
                    if (mode == 1) { float2 o = *p; v.x += o.x; v.y += o.y; }
                    *p = v;
                }
                if (r1 < M) {
                    float2* p = (float2*)(C + (size_t)r1 * Dn + col);
                    float2 v = make_float2(acc[rg][nb][2], acc[rg][nb][3]);
                    if (mode == 1) { float2 o = *p; v.x += o.x; v.y += o.y; }
                    *p = v;
                }
            }
        }
    }
}

// ===== pairwise: K=160 (d from MMA via correction cols), CTA 128x64, hybrid tanh =====
#define PW_B 43008                 // A: 128 * 84 u32 * 4B
#define PW_SMEM 64768              // + B: 64 * 84 * 4

__global__ __launch_bounds__(256, 2) void pairwise_mma(float* __restrict__ out) {
    int i0 = blockIdx.y * 128, j0 = blockIdx.x * 64;
    if (j0 + 64 <= i0) return;
    extern __shared__ char sm[];
    int tid = threadIdx.x, w = tid >> 5, lane = tid & 31;
    int g = lane >> 2, tq = lane & 3;
    int wr = w >> 1, wc = w & 1;

    cp16<20, 21>((const uint4*)g_pa, sm, 0, i0, N_, tid, 128);
    cp16<20, 21>((const uint4*)g_pb, sm, PW_B, j0, N_, tid, 64);
    __syncthreads();

    const uint32_t* SA = (const uint32_t*)sm;
    const uint32_t* SB = (const uint32_t*)(sm + PW_B);

    float accG[2][4][4], accS[2][4][4];
#pragma unroll
    for (int rg = 0; rg < 2; rg++)
#pragma unroll
        for (int nb = 0; nb < 4; nb++)
#pragma unroll
            for (int q = 0; q < 4; q++) { accG[rg][nb][q] = 0.f; accS[rg][nb][q] = 0.f; }

    int ra0 = (wr * 32 + g) * 84;
    int rb0 = ra0 + 8 * 84, ra1 = ra0 + 16 * 84, rb1 = ra0 + 24 * 84;
#pragma unroll
    for (int kc = 0; kc < 9; kc++) {       // k words 0..71 (G: 0..39, S: 40..71)
        int ka = kc * 8 + tq;
        uint32_t a00 = SA[ra0 + ka], a01 = SA[rb0 + ka];
        uint32_t a02 = SA[ra0 + ka + 4], a03 = SA[rb0 + ka + 4];
        uint32_t a10 = SA[ra1 + ka], a11 = SA[rb1 + ka];
        uint32_t a12 = SA[ra1 + ka + 4], a13 = SA[rb1 + ka + 4];
        float (*a0)[4] = (kc < 5) ? accG[0] : accS[0];
        float (*a1)[4] = (kc < 5) ? accG[1] : accS[1];
#pragma unroll
        for (int nb = 0; nb < 4; nb++) {
            int nr = (wc * 32 + nb * 8 + g) * 84;
            uint32_t b0 = SB[nr + ka], b1 = SB[nr + ka + 4];
            mma_f16(a0[nb], a00, a01, a02, a03, b0, b1);
            mma_f16(a1[nb], a10, a11, a12, a13, b0, b1);
        }
    }

    bool full = (i0 + 128 <= N_) && (j0 + 64 <= N_);
    float vv[2][4][4];
#pragma unroll
    for (int rg = 0; rg < 2; rg++) {
        int lr0 = wr * 32 + rg * 16 + g, lr1 = lr0 + 8;
        int ir0 = i0 + lr0, ir1 = i0 + lr1;
#pragma unroll
        for (int nb = 0; nb < 4; nb++) {
            int c0 = wc * 32 + nb * 8 + 2 * tq;
            vv[rg][nb][0] = one_p_tanh(accG[rg][nb][0] * accS[rg][nb][0]);
            vv[rg][nb][1] = one_p_tanh(accG[rg][nb][1] * accS[rg][nb][1]);
            vv[rg][nb][2] = one_p_tanh(accG[rg][nb][2] * accS[rg][nb][2]);
            vv[rg][nb][3] = one_p_tanh(accG[rg][nb][3] * accS[rg][nb][3]);
            if (full) {
                *(float2*)(out + (size_t)ir0 * N_ + j0 + c0) = make_float2(vv[rg][nb][0], vv[rg][nb][1]);
                *(float2*)(out + (size_t)ir1 * N_ + j0 + c0) = make_float2(vv[rg][nb][2], vv[rg][nb][3]);
            } else {
                if (ir0 < N_) {
                    if (j0 + c0 < N_)     out[(size_t)ir0 * N_ + j0 + c0] = vv[rg][nb][0];
                    if (j0 + c0 + 1 < N_) out[(size_t)ir0 * N_ + j0 + c0 + 1] = vv[rg][nb][1];
                }
                if (ir1 < N_) {
                    if (j0 + c0 < N_)     out[(size_t)ir1 * N_ + j0 + c0] = vv[rg][nb][2];
                    if (j0 + c0 + 1 < N_) out[(size_t)ir1 * N_ + j0 + c0 + 1] = vv[rg][nb][3];
                }
            }
        }
    }

    // mirror: stage transpose in reused A smem, write (jj, ii) for jj > ii
    __syncthreads();
    float* vT = (float*)sm;  // [64][129] = 33024 B < PW_B
#pragma unroll
    for (int rg = 0; rg < 2; rg++) {
        int lr0 = wr * 32 + rg * 16 + g, lr1 = lr0 + 8;
#pragma unroll
        for (int nb = 0; nb < 4; nb++) {
            int c0 = wc * 32 + nb * 8 + 2 * tq, c1 = c0 + 1;
            vT[c0 * 129 + lr0] = vv[rg][nb][0];
            vT[c1 * 129 + lr0] = vv[rg][nb][1];
            vT[c0 * 129 + lr1] = vv[rg][nb][2];
            vT[c1 * 129 + lr1] = vv[rg][nb][3];
        }
    }
    __syncthreads();
    for (int idx = tid; idx < 64 * 128; idx += 256) {
        int r2 = idx >> 7, c2 = idx & 127;
        int jj = j0 + r2, ii = i0 + c2;
        if (jj > ii && jj < N_ && ii < N_) out[(size_t)jj * N_ + ii] = vT[r2 * 129 + c2];
    }
}

// ===== GAT kernels =====
__global__ void alpha_kernel(const __half* __restrict__ h, const float* __restrict__ a_s,
                             const float* __restrict__ a_d, int dh) {
    int idx = blockIdx.x * blockDim.x + threadIdx.x;
    if (idx >= T_ * N_ * H_) return;
    int hh = idx & 3, tn = idx >> 2;
    const __half* hr = h + (size_t)tn * (H_ * dh) + hh * dh;
    float s = 0.f, d = 0.f;
    for (int k = 0; k < dh; k++) {
        float v = __half2float(hr[k]);
        s += v * a_s[hh * dh + k];
        d += v * a_d[hh * dh + k];
    }
    g_as[idx] = s; g_ad[idx] = d;
}
__global__ void csr_count(const void* ei) {
    int idx = blockIdx.x * blockDim.x + threadIdx.x;
    if (idx >= T_ * E_) return;
    int t = idx / E_, e = idx - t * E_;
    int dst = (int)ld_idx(ei, (size_t)t * 2 * E_ + E_ + e);
    atomicAdd(&g_cnt[t * N_ + dst], 1);
}
__global__ void csr_scan() {
    int t = blockIdx.x, tid = threadIdx.x;
    __shared__ int sh[1024];
    int off = 0;
    for (int chunk = 0; chunk < N_; chunk += 1024) {
        int i = chunk + tid;
        int v = (i < N_) ? g_cnt[t * N_ + i] : 0;
        sh[tid] = v;
        __syncthreads();
        for (int d2 = 1; d2 < 1024; d2 <<= 1) {
            int x = 0;
            if (tid >= d2) x = sh[tid - d2];
            __syncthreads();
            sh[tid] += x;
            __syncthreads();
        }
        if (i < N_) g_rowptr[t * (N_ + 1) + i] = off + sh[tid] - v;
        int tot = sh[1023];
        __syncthreads();
        off += tot;
    }
    if (tid == 0) g_rowptr[t * (N_ + 1) + N_] = off;
}
__global__ void csr_scatter(const void* ei) {
    int idx = blockIdx.x * blockDim.x + threadIdx.x;
    if (idx >= T_ * E_) return;
    int t = idx / E_, e = idx - t * E_;
    int dst = (int)ld_idx(ei, (size_t)t * 2 * E_ + E_ + e);
    int pos = atomicAdd(&g_cursor[t * N_ + dst], 1);
    g_sorted[t * E_ + g_rowptr[t * (N_ + 1) + dst] + pos] = e;
}

// fused gather; hsrc fp16, out fp16 (+ fp32 for meso at L2)
template <int D, int DH, int L1>
__global__ void gat_gather(const void* ei, const float* __restrict__ ew,
                           const __half* __restrict__ hsrc,
                           __half* __restrict__ oh, float* __restrict__ ofp) {
    int t = blockIdx.y, n = blockIdx.x, tid = threadIdx.x;
    int start = g_rowptr[t * (N_ + 1) + n];
    int end = g_rowptr[t * (N_ + 1) + n + 1];
    int head = tid / DH;
    __shared__ int s_src[64];
    __shared__ float s_ex[64][4];
    float4 ad4 = *(const float4*)&g_ad[(t * N_ + n) * 4];
    float acc = 0.f, den = 0.f;
    for (int base = start; base < end; base += 64) {
        int cnt = min(64, end - base);
        __syncthreads();
        for (int i = tid; i < cnt; i += D) {
            int eid = g_sorted[t * E_ + base + i];
            int src = (int)ld_idx(ei, (size_t)t * 2 * E_ + eid);
            s_src[i] = src;
            float4 s4 = *(const float4*)&g_as[(t * N_ + src) * 4];
            float wv = ew[(size_t)t * E_ + eid];
            float e0 = s4.x + ad4.x; e0 = e0 > 0.f ? e0 : 0.2f * e0;
            float e1 = s4.y + ad4.y; e1 = e1 > 0.f ? e1 : 0.2f * e1;
            float e2 = s4.z + ad4.z; e2 = e2 > 0.f ? e2 : 0.2f * e2;
            float e3 = s4.w + ad4.w; e3 = e3 > 0.f ? e3 : 0.2f * e3;
            s_ex[i][0] = __expf(e0) * wv;
            s_ex[i][1] = __expf(e1) * wv;
            s_ex[i][2] = __expf(e2) * wv;
            s_ex[i][3] = __expf(e3) * wv;
        }
        __syncthreads();
#pragma unroll 8
        for (int i = 0; i < cnt; i++) {
            float exv = s_ex[i][head];
            den += exv;
            acc += exv * __half2float(hsrc[((size_t)t * N_ + s_src[i]) * D + tid]);
        }
    }
    float v = acc / (den + 1e-16f);
    v = v > 0.f ? v : __expf(v) - 1.f;
    size_t o = ((size_t)t * N_ + n) * 128 + tid;
    oh[o] = __float2half(v);
    if (!L1) ofp[o] = v;
}

// ===== meso =====
#define MCHUNK 500
__global__ void meso_acc(const void* part, const float* __restrict__ Dw) {
    int t = blockIdx.y, c0 = blockIdx.x * MCHUNK, tid = threadIdx.x;
    __shared__ float sn[NCOM_ * 64];
    __shared__ float sd[NCOM_];
    __shared__ int sp[MCHUNK];
    __shared__ float sD[MCHUNK];
    for (int i = tid; i < NCOM_ * 64; i += blockDim.x) sn[i] = 0.f;
    for (int i = tid; i < NCOM_; i += blockDim.x) sd[i] = 0.f;
    int nmax = min(MCHUNK, N_ - c0);
    for (int i = tid; i < nmax; i += blockDim.x) {
        sp[i] = (int)ld_idx(part, (size_t)t * N_ + c0 + i);
        sD[i] = Dw[(size_t)t * N_ + c0 + i];
    }
    __syncthreads();
    for (int idx = tid; idx < nmax * 64; idx += blockDim.x) {
        int nl = idx >> 6, c = idx & 63;
        float g = g_agg[((size_t)t * N_ + c0 + nl) * 128 + c];
        atomicAdd(&sn[sp[nl] * 64 + c], sD[nl] * g);
        if (c == 0) atomicAdd(&sd[sp[nl]], sD[nl]);
    }
    __syncthreads();
    for (int i = tid; i < NCOM_ * 64; i += blockDim.x)
        atomicAdd(&g_comnum[t * NCOM_ * 64 + i], sn[i]);
    for (int i = tid; i < NCOM_; i += blockDim.x)
        atomicAdd(&g_comden[t * NCOM_ + i], sd[i]);
}
__global__ void meso_scatter(const void* part, __half* __restrict__ oh) {
    int idx = blockIdx.x * blockDim.x + threadIdx.x;
    if (idx >= T_ * N_ * 64) return;
    int t = idx / (N_ * 64);
    int r = idx - t * N_ * 64;
    int n = r >> 6, c = r & 63;
    int p = (int)ld_idx(part, (size_t)t * N_ + n);
    float mean = g_comnum[(t * NCOM_ + p) * 64 + c] / (g_comden[t * NCOM_ + p] + 1e-16f);
    oh[((size_t)t * N_ + n) * 128 + 64 + c] = __float2half(mean);
}

// ===== LSTM pointwise =====
__global__ void lstm_pw(const float* __restrict__ b, int t) {
    int idx = blockIdx.x * blockDim.x + threadIdx.x;
    if (idx >= N_ * 128) return;
    int n = idx >> 7, j = idx & 127;
    const float* z = g_Zx + (size_t)t * N_ * 512 + (size_t)n * 512;
    float i_ = z[j] + b[j];
    float f_ = z[128 + j] + b[128 + j];
    float gg = z[256 + j] + b[256 + j];
    float o_ = z[384 + j] + b[384 + j];
    float c = sigf_fast(f_) * g_cbuf[idx] + sigf_fast(i_) * tanh_fast(gg);
    g_cbuf[idx] = c;
    g_hb[idx] = __float2half(sigf_fast(o_) * tanh_fast(c));
}

// ===== decoder prep =====
__global__ void emb_tanh(const float* __restrict__ emb_b) {
    __shared__ float s[64];
    int tid = threadIdx.x;
    if (tid < 64) s[tid] = 0.f;
    __syncthreads();
    int idx = blockIdx.x * 256 + tid;
    if (idx < N_ * 64) {
        int n = idx >> 6, c = idx & 63;
        float v = tanhf(g_dec[n * 128 + c] + emb_b[c]);
        g_dec[n * 128 + c] = v;
        atomicAdd(&s[c], v * v);
    }
    __syncthreads();
    if (tid < 64) atomicAdd(&g_colsq[tid], s[tid]);
}
// build PA/PB: [sqrt2*e (64) | corr (16) | scal (64) | 0 (16)], K=160
__global__ void build_P(const float* __restrict__ scal_b) {
    int n = blockIdx.x, c = threadIdx.x;  // 64 threads
    float e = g_dec[n * 128 + c] * rsqrtf(g_colsq[c]);
    float s = sigf(g_dec[n * 128 + 64 + c] + scal_b[c]);
    float v = e * e;
#pragma unroll
    for (int o = 16; o; o >>= 1) v += __shfl_down_sync(0xffffffff, v, o);
    __shared__ float shm[2];
    if ((c & 31) == 0) shm[c >> 5] = v;
    __syncthreads();
    float sq = shm[0] + shm[1];
    size_t base = (size_t)n * 160;
    __half he = __float2half(1.41421356f * e);
    __half hs = __float2half(s);
    g_pa[base + c] = he;        g_pb[base + c] = he;
    g_pa[base + 80 + c] = hs;   g_pb[base + 80 + c] = hs;
    if (c < 16) {
        __half za = __float2half(0.f), zb = za;
        if (c == 0) { za = __float2half(sq);   zb = __float2half(-1.f); }
        if (c == 1) { za = __float2half(1.f);  zb = __float2half(-sq); }
        g_pa[base + 64 + c] = za;
        g_pb[base + 64 + c] = zb;
        g_pa[base + 144 + c] = __float2half(0.f);
        g_pb[base + 144 + c] = __float2half(0.f);
    }
}

// ===== host =====
extern "C" void kernel_launch(void* const* d_in, const int* in_sizes, int n_in,
                              void* d_out, int out_size) {
    const float* feat   = (const float*)d_in[0];
    const float* ew     = (const float*)d_in[1];
    const float* Dw     = (const float*)d_in[2];
    const float* W1     = (const float*)d_in[3];
    const float* a_s1   = (const float*)d_in[4];
    const float* a_d1   = (const float*)d_in[5];
    const float* W2     = (const float*)d_in[6];
    const float* a_s2   = (const float*)d_in[7];
    const float* a_d2   = (const float*)d_in[8];
    const float* Wx     = (const float*)d_in[9];
    const float* Wh     = (const float*)d_in[10];
    const float* b_lstm = (const float*)d_in[11];
    const float* embW   = (const float*)d_in[12];
    const float* embB   = (const float*)d_in[13];
    const float* scalW  = (const float*)d_in[14];
    const float* scalB  = (const float*)d_in[15];
    const void*  ei     = (const void*)d_in[16];
    const void*  part   = (const void*)d_in[17];
    float* out = (float*)d_out;

    cudaFuncSetAttribute(mma_gemm, cudaFuncAttributeMaxDynamicSharedMemorySize, MG_SMEM);
    cudaFuncSetAttribute(pairwise_mma, cudaFuncAttributeMaxDynamicSharedMemorySize, PW_SMEM);

    float *agg, *Zx, *cbuf, *dec, *comnum, *comden, *colsq;
    int *cnt, *cursor;
    __half *h1h, *h2h, *f16, *hb, *wt;
    cudaGetSymbolAddress((void**)&h1h, g_h1h);
    cudaGetSymbolAddress((void**)&h2h, g_h2h);
    cudaGetSymbolAddress((void**)&f16, g_f);
    cudaGetSymbolAddress((void**)&agg, g_agg);
    cudaGetSymbolAddress((void**)&Zx, g_Zx);
    cudaGetSymbolAddress((void**)&cbuf, g_cbuf);
    cudaGetSymbolAddress((void**)&dec, g_dec);
    cudaGetSymbolAddress((void**)&comnum, g_comnum);
    cudaGetSymbolAddress((void**)&comden, g_comden);
    cudaGetSymbolAddress((void**)&colsq, g_colsq);
    cudaGetSymbolAddress((void**)&cnt, g_cnt);
    cudaGetSymbolAddress((void**)&cursor, g_cursor);
    cudaGetSymbolAddress((void**)&hb, g_hb);
    cudaGetSymbolAddress((void**)&wt, g_wt);

    const int MT = 79;   // ceil(10000/128)
    const int JT = 157;  // ceil(10000/64)
    const int TE = T_ * E_;
    const int TNH = T_ * N_ * H_;
    const int NS4 = T_ * N_ * 128 / 4;

    detect64_kernel<<<1, 1>>>((const int*)ei);

    // GAT layer 1
    cvt16<<<(NS4 + 255) / 256, 256>>>((const float4*)feat, (__half2*)f16, NS4);
    wsplit16<<<(128 * 128 + 255) / 256, 256>>>(W1, wt, 128);
    mma_gemm<<<dim3(MT, 2, 8), 256, MG_SMEM>>>(f16, wt, h1h, N_, 128,
                                               (long long)N_ * 128, (long long)N_ * 128, 2);
    alpha_kernel<<<(TNH + 255) / 256, 256>>>(h1h, a_s1, a_d1, 32);

    fill_i<<<(T_ * N_ + 255) / 256, 256>>>(cnt, 0, T_ * N_);
    csr_count<<<(TE + 255) / 256, 256>>>(ei);
    csr_scan<<<T_, 1024>>>();
    fill_i<<<(T_ * N_ + 255) / 256, 256>>>(cursor, 0, T_ * N_);
    csr_scatter<<<(TE + 255) / 256, 256>>>(ei);

    gat_gather<128, 32, 1><<<dim3(N_, T_), 128>>>(ei, ew, h1h, f16, (float*)0);

    // GAT layer 2
    wsplit16<<<(64 * 128 + 255) / 256, 256>>>(W2, wt, 64);
    mma_gemm<<<dim3(MT, 1, 8), 256, MG_SMEM>>>(f16, wt, h2h, N_, 64,
                                               (long long)N_ * 128, (long long)N_ * 64, 2);
    alpha_kernel<<<(TNH + 255) / 256, 256>>>(h2h, a_s2, a_d2, 16);
    gat_gather<64, 16, 0><<<dim3(N_, T_), 64>>>(ei, ew, h2h, f16, agg);

    // meso
    fill_f<<<(T_ * NCOM_ * 64 + 255) / 256, 256>>>(comnum, 0.f, T_ * NCOM_ * 64);
    fill_f<<<(T_ * NCOM_ + 255) / 256, 256>>>(comden, 0.f, T_ * NCOM_);
    meso_acc<<<dim3((N_ + MCHUNK - 1) / MCHUNK, T_), 256>>>(part, Dw);
    meso_scatter<<<(T_ * N_ * 64 + 255) / 256, 256>>>(part, f16);

    // LSTM
    wsplit16<<<(512 * 128 + 255) / 256, 256>>>(Wx, wt, 512);
    mma_gemm<<<dim3(MT, 8, 8), 256, MG_SMEM>>>(f16, wt, Zx, N_, 512,
                                               (long long)N_ * 128, (long long)N_ * 512, 0);
    wsplit16<<<(512 * 128 + 255) / 256, 256>>>(Wh, wt, 512);
    fill_f<<<(N_ * 128 + 255) / 256, 256>>>(cbuf, 0.f, N_ * 128);
    for (int t = 0; t < T_; t++) {
        if (t > 0) {
            mma_gemm<<<dim3(MT, 8, 1), 256, MG_SMEM>>>(hb, wt, Zx + (size_t)t * N_ * 512,
                                                       N_, 512, 0, 0, 1);
        }
        lstm_pw<<<(N_ * 128 + 255) / 256, 256>>>(b_lstm, t);
    }

    // decoder: fused (emb | scal) GEMM -> dec fp32
    wsplit16<<<(64 * 128 + 255) / 256, 256>>>(embW, wt, 64);
    wsplit16<<<(64 * 128 + 255) / 256, 256>>>(scalW, wt + 64 * 128, 64);
    mma_gemm<<<dim3(MT, 2, 1), 256, MG_SMEM>>>(hb, wt, dec, N_, 128, 0, 0, 0);
    fill_f<<<1, 64>>>(colsq, 0.f, 64);
    emb_tanh<<<(N_ * 64 + 255) / 256, 256>>>(embB);
    build_P<<<N_, 64>>>(scalB);
    pairwise_mma<<<dim3(JT, MT), 256, PW_SMEM>>>(out);
}

// round 10
// speedup vs baseline: 3.7060x; 1.0555x over previous
#include <cuda_runtime.h>
#include <cuda_fp16.h>
#include <math.h>
#include <stdint.h>

#define T_ 8
#define N_ 10000
#define E_ 320000
#define H_ 4
#define NCOM_ 100

// ===== scratch =====
__device__ int   g_is64;
__device__ __align__(16) __half g_h1h[(size_t)T_ * N_ * 128];
__device__ __align__(16) __half g_h2h[(size_t)T_ * N_ * 64];
__device__ __align__(16) __half g_f[(size_t)T_ * N_ * 128];
__device__ __align__(16) float g_agg[(size_t)T_ * N_ * 128];
__device__ __align__(16) float g_as[T_ * N_ * H_];
__device__ __align__(16) float g_ad[T_ * N_ * H_];
__device__ int   g_cnt[T_ * N_];
__device__ int   g_rowptr[T_ * (N_ + 1)];
__device__ int   g_cursor[T_ * N_];
__device__ int   g_sorted[T_ * E_];
__device__ float g_comnum[T_ * NCOM_ * 64];
__device__ float g_comden[T_ * NCOM_];
__device__ __align__(16) float g_Zx[(size_t)T_ * N_ * 512];
__device__ __align__(16) float g_cbuf[N_ * 128];
__device__ __align__(16) float g_dec[N_ * 128];
__device__ float g_colsq[64];
__device__ __align__(16) __half g_hb[N_ * 128];
__device__ __align__(16) __half g_pa[(size_t)N_ * 160];
__device__ __align__(16) __half g_pb[(size_t)N_ * 160];
__device__ __align__(16) __half g_wt[512 * 128];

// ===== helpers =====
__device__ __forceinline__ long long ld_idx(const void* p, size_t i) {
    if (g_is64) return ((const long long*)p)[i];
    return (long long)((const int*)p)[i];
}
__device__ __forceinline__ float sigf(float x) { return 1.f / (1.f + expf(-x)); }
__device__ __forceinline__ float sigf_fast(float x) {
    return __fdividef(1.f, 1.f + __expf(-x));
}
__device__ __forceinline__ float tanh_fast(float x) {
    float e = __expf(2.f * x);
    return 1.f - __fdividef(2.f, e + 1.f);
}
__device__ __forceinline__ float tanh_hw(float x) {
    float y;
    asm("tanh.approx.f32 %0, %1;" : "=f"(y) : "f"(x));
    return y;
}
__device__ __forceinline__ float one_p_tanh(float x) {
    float ax = fabsf(x);
    if (ax < 0.15f) {
        float x2 = x * x;
        return fmaf(x, fmaf(x2, -0.33333333f, 1.f), 1.f);
    }
    return 1.f + tanh_hw(x);
}
__device__ __forceinline__ void mma_f16(float* c, uint32_t a0, uint32_t a1, uint32_t a2,
                                        uint32_t a3, uint32_t b0, uint32_t b1) {
    asm volatile(
        "mma.sync.aligned.m16n8k16.row.col.f32.f16.f16.f32 "
        "{%0,%1,%2,%3}, {%4,%5,%6,%7}, {%8,%9}, {%0,%1,%2,%3};"
        : "+f"(c[0]), "+f"(c[1]), "+f"(c[2]), "+f"(c[3])
        : "r"(a0), "r"(a1), "r"(a2), "r"(a3), "r"(b0), "r"(b1));
}

__global__ void detect64_kernel(const int* ei32) {
    int ok = 1;
    for (int i = 1; i < 64; i += 2)
        if (ei32[i] != 0) ok = 0;
    g_is64 = ok;
}
__global__ void fill_f(float* p, float v, int n) {
    int i = blockIdx.x * blockDim.x + threadIdx.x;
    if (i < n) p[i] = v;
}
__global__ void fill_i(int* p, int v, int n) {
    int i = blockIdx.x * blockDim.x + threadIdx.x;
    if (i < n) p[i] = v;
}
__global__ void cvt16(const float4* __restrict__ x, __half2* __restrict__ y, int n4) {
    int i = blockIdx.x * blockDim.x + threadIdx.x;
    if (i >= n4) return;
    float4 v = x[i];
    y[2 * i]     = __floats2half2_rn(v.x, v.y);
    y[2 * i + 1] = __floats2half2_rn(v.z, v.w);
}
__global__ void wsplit16(const float* __restrict__ B, __half* __restrict__ bt, int Dn) {
    int idx = blockIdx.x * blockDim.x + threadIdx.x;
    if (idx >= Dn * 128) return;
    int n = idx >> 7, k = idx & 127;
    bt[idx] = __float2half(B[(size_t)k * Dn + n]);
}

// ===== smem tile copy =====
template <int KU4, int SU4, int THREADS>
__device__ __forceinline__ void cp16(const uint4* __restrict__ G, char* sm, int off,
                                     int base, int Mlim, int tid, int rows) {
    int total = rows * KU4;
    for (int idx = tid; idx < total; idx += THREADS) {
        int row = idx / KU4, c = idx - row * KU4;
        uint4 v = make_uint4(0, 0, 0, 0);
        if (base + row < Mlim) v = G[(size_t)(base + row) * KU4 + c];
        ((uint4*)(sm + off))[row * SU4 + c] = v;
    }
}

// ===== fp16 MMA GEMM: CTA 128x64, 256 threads, warp grid 4x2, warp tile 32x32 =====
#define SM_B 34816
#define MG_SMEM 52736

// mode: 0 = store fp32, 1 = accumulate fp32, 2 = store fp16
__global__ __launch_bounds__(256, 3) void mma_gemm(
    const __half* __restrict__ A, const __half* __restrict__ B,
    void* __restrict__ Cv, int M, int Dn,
    long long sA, long long sC, int mode)
{
    extern __shared__ char sm[];
    int tid = threadIdx.x, w = tid >> 5, lane = tid & 31;
    int g = lane >> 2, tq = lane & 3;
    int wr = w >> 1, wc = w & 1;
    int m0 = blockIdx.x * 128, n0 = blockIdx.y * 64, t = blockIdx.z;
    A += (size_t)t * sA;

    cp16<16, 17, 256>((const uint4*)A, sm, 0, m0, M, tid, 128);
    cp16<16, 17, 256>((const uint4*)B, sm, SM_B, n0, Dn, tid, 64);
    __syncthreads();

    const uint32_t* SA = (const uint32_t*)sm;
    const uint32_t* SB = (const uint32_t*)(sm + SM_B);

    float acc[2][4][4];
#pragma unroll
    for (int rg = 0; rg < 2; rg++)
#pragma unroll
        for (int nb = 0; nb < 4; nb++)
#pragma unroll
            for (int q = 0; q < 4; q++) acc[rg][nb][q] = 0.f;

    int ra0 = (wr * 32 + g) * 68;
    int rb0 = ra0 + 8 * 68, ra1 = ra0 + 16 * 68, rb1 = ra0 + 24 * 68;
#pragma unroll
    for (int kc = 0; kc < 8; kc++) {
        int ka = kc * 8 + tq;
        uint32_t a00 = SA[ra0 + ka], a01 = SA[rb0 + ka];
        uint32_t a02 = SA[ra0 + ka + 4], a03 = SA[rb0 + ka + 4];
        uint32_t a10 = SA[ra1 + ka], a11 = SA[rb1 + ka];
        uint32_t a12 = SA[ra1 + ka + 4], a13 = SA[rb1 + ka + 4];
#pragma unroll
        for (int nb = 0; nb < 4; nb++) {
            int nr = (wc * 32 + nb * 8 + g) * 68;
            uint32_t b0 = SB[nr + ka], b1 = SB[nr + ka + 4];
            mma_f16(acc[0][nb], a00, a01, a02, a03, b0, b1);
            mma_f16(acc[1][nb], a10, a11, a12, a13, b0, b1);
        }
    }

#pragma unroll
    for (int rg = 0; rg < 2; rg++) {
        int r0 = m0 + wr * 32 + rg * 16 + g, r1 = r0 + 8;
#pragma unroll
        for (int nb = 0; nb < 4; nb++) {
            int col = n0 + wc * 32 + nb * 8 + 2 * tq;
            if (mode == 2) {
                __half* Ch = (__half*)Cv + (size_t)t * sC;
                if (r0 < M)
                    *(__half2*)(Ch + (size_t)r0 * Dn + col) = __floats2half2_rn(acc[rg][nb][0], acc[rg][nb][1]);
                if (r1 < M)
                    *(__half2*)(Ch + (size_t)r1 * Dn + col) = __floats2half2_rn(acc[rg][nb][2], acc[rg][nb][3]);
            } else {
                float* C = (float*)Cv + (size_t)t * sC;
                if (r0 < M) {
                    float2* p = (float2*)(C + (size_t)r0 * Dn + col);
                    float2 v = make_float2(acc[rg][nb][0], acc[rg][nb][1]);
                    if (mode == 1) { float2 o = *p; v.x += o.x; v.y += o.y; }
                    *p = v;
                }
                if (r1 < M) {
                    float2* p = (float2*)(C + (size_t)r1 * Dn + col);
                    float2 v = make_float2(acc[rg][nb][2], acc[rg][nb][3]);
                    if (mode == 1) { float2 o = *p; v.x += o.x; v.y += o.y; }
                    *p = v;
                }
            }
        }
    }
}

// ===== pairwise: CTA 128x128, 512 threads (warp grid 4x4), K=160, streaming stores =====
#define PW_B 43008                 // A: 128 * 84 u32 * 4B
#define PW_SMEM 86016              // + B: 128 * 84 * 4

__global__ __launch_bounds__(512, 2) void pairwise_mma(float* __restrict__ out) {
    int bi = blockIdx.y, bj = blockIdx.x;
    if (bj < bi) return;           // keep upper triangle of tiles
    int i0 = bi * 128, j0 = bj * 128;
    extern __shared__ char sm[];
    int tid = threadIdx.x, w = tid >> 5, lane = tid & 31;
    int g = lane >> 2, tq = lane & 3;
    int wr = w >> 2, wc = w & 3;

    cp16<20, 21, 512>((const uint4*)g_pa, sm, 0, i0, N_, tid, 128);
    cp16<20, 21, 512>((const uint4*)g_pb, sm, PW_B, j0, N_, tid, 128);
    __syncthreads();

    const uint32_t* SA = (const uint32_t*)sm;
    const uint32_t* SB = (const uint32_t*)(sm + PW_B);

    float accG[2][4][4], accS[2][4][4];
#pragma unroll
    for (int rg = 0; rg < 2; rg++)
#pragma unroll
        for (int nb = 0; nb < 4; nb++)
#pragma unroll
            for (int q = 0; q < 4; q++) { accG[rg][nb][q] = 0.f; accS[rg][nb][q] = 0.f; }

    int ra0 = (wr * 32 + g) * 84;
    int rb0 = ra0 + 8 * 84, ra1 = ra0 + 16 * 84, rb1 = ra0 + 24 * 84;
#pragma unroll
    for (int kc = 0; kc < 9; kc++) {
        int ka = kc * 8 + tq;
        uint32_t a00 = SA[ra0 + ka], a01 = SA[rb0 + ka];
        uint32_t a02 = SA[ra0 + ka + 4], a03 = SA[rb0 + ka + 4];
        uint32_t a10 = SA[ra1 + ka], a11 = SA[rb1 + ka];
        uint32_t a12 = SA[ra1 + ka + 4], a13 = SA[rb1 + ka + 4];
        float (*a0)[4] = (kc < 5) ? accG[0] : accS[0];
        float (*a1)[4] = (kc < 5) ? accG[1] : accS[1];
#pragma unroll
        for (int nb = 0; nb < 4; nb++) {
            int nr = (wc * 32 + nb * 8 + g) * 84;
            uint32_t b0 = SB[nr + ka], b1 = SB[nr + ka + 4];
            mma_f16(a0[nb], a00, a01, a02, a03, b0, b1);
            mma_f16(a1[nb], a10, a11, a12, a13, b0, b1);
        }
    }

    bool full = (i0 + 128 <= N_) && (j0 + 128 <= N_);
    float vv[2][4][4];
#pragma unroll
    for (int rg = 0; rg < 2; rg++) {
        int lr0 = wr * 32 + rg * 16 + g, lr1 = lr0 + 8;
        int ir0 = i0 + lr0, ir1 = i0 + lr1;
#pragma unroll
        for (int nb = 0; nb < 4; nb++) {
            int c0 = wc * 32 + nb * 8 + 2 * tq;
            vv[rg][nb][0] = one_p_tanh(accG[rg][nb][0] * accS[rg][nb][0]);
            vv[rg][nb][1] = one_p_tanh(accG[rg][nb][1] * accS[rg][nb][1]);
            vv[rg][nb][2] = one_p_tanh(accG[rg][nb][2] * accS[rg][nb][2]);
            vv[rg][nb][3] = one_p_tanh(accG[rg][nb][3] * accS[rg][nb][3]);
            if (full) {
                __stcs((float2*)(out + (size_t)ir0 * N_ + j0 + c0),
                       make_float2(vv[rg][nb][0], vv[rg][nb][1]));
                __stcs((float2*)(out + (size_t)ir1 * N_ + j0 + c0),
                       make_float2(vv[rg][nb][2], vv[rg][nb][3]));
            } else {
                if (ir0 < N_) {
                    if (j0 + c0 < N_)     __stcs(out + (size_t)ir0 * N_ + j0 + c0, vv[rg][nb][0]);
                    if (j0 + c0 + 1 < N_) __stcs(out + (size_t)ir0 * N_ + j0 + c0 + 1, vv[rg][nb][1]);
                }
                if (ir1 < N_) {
                    if (j0 + c0 < N_)     __stcs(out + (size_t)ir1 * N_ + j0 + c0, vv[rg][nb][2]);
                    if (j0 + c0 + 1 < N_) __stcs(out + (size_t)ir1 * N_ + j0 + c0 + 1, vv[rg][nb][3]);
                }
            }
        }
    }

    // mirror: stage transpose in reused smem, write (jj, ii) for jj > ii
    __syncthreads();
    float* vT = (float*)sm;  // [128][129] = 66048 B < 86016
#pragma unroll
    for (int rg = 0; rg < 2; rg++) {
        int lr0 = wr * 32 + rg * 16 + g, lr1 = lr0 + 8;
#pragma unroll
        for (int nb = 0; nb < 4; nb++) {
            int c0 = wc * 32 + nb * 8 + 2 * tq, c1 = c0 + 1;
            vT[c0 * 129 + lr0] = vv[rg][nb][0];
            vT[c1 * 129 + lr0] = vv[rg][nb][1];
            vT[c0 * 129 + lr1] = vv[rg][nb][2];
            vT[c1 * 129 + lr1] = vv[rg][nb][3];
        }
    }
    __syncthreads();
    for (int idx = tid; idx < 128 * 128; idx += 512) {
        int r2 = idx >> 7, c2 = idx & 127;
        int jj = j0 + r2, ii = i0 + c2;
        if (jj > ii && jj < N_ && ii < N_) __stcs(out + (size_t)jj * N_ + ii, vT[r2 * 129 + c2]);
    }
}

// ===== GAT kernels =====
__global__ void alpha_kernel(const __half* __restrict__ h, const float* __restrict__ a_s,
                             const float* __restrict__ a_d, int dh) {
    int idx = blockIdx.x * blockDim.x + threadIdx.x;
    if (idx >= T_ * N_ * H_) return;
    int hh = idx & 3, tn = idx >> 2;
    const __half* hr = h + (size_t)tn * (H_ * dh) + hh * dh;
    float s = 0.f, d = 0.f;
    for (int k = 0; k < dh; k++) {
        float v = __half2float(hr[k]);
        s += v * a_s[hh * dh + k];
        d += v * a_d[hh * dh + k];
    }
    g_as[idx] = s; g_ad[idx] = d;
}
__global__ void csr_count(const void* ei) {
    int idx = blockIdx.x * blockDim.x + threadIdx.x;
    if (idx >= T_ * E_) return;
    int t = idx / E_, e = idx - t * E_;
    int dst = (int)ld_idx(ei, (size_t)t * 2 * E_ + E_ + e);
    atomicAdd(&g_cnt[t * N_ + dst], 1);
}
__global__ void csr_scan() {
    int t = blockIdx.x, tid = threadIdx.x;
    __shared__ int sh[1024];
    int off = 0;
    for (int chunk = 0; chunk < N_; chunk += 1024) {
        int i = chunk + tid;
        int v = (i < N_) ? g_cnt[t * N_ + i] : 0;
        sh[tid] = v;
        __syncthreads();
        for (int d2 = 1; d2 < 1024; d2 <<= 1) {
            int x = 0;
            if (tid >= d2) x = sh[tid - d2];
            __syncthreads();
            sh[tid] += x;
            __syncthreads();
        }
        if (i < N_) g_rowptr[t * (N_ + 1) + i] = off + sh[tid] - v;
        int tot = sh[1023];
        __syncthreads();
        off += tot;
    }
    if (tid == 0) g_rowptr[t * (N_ + 1) + N_] = off;
}
__global__ void csr_scatter(const void* ei) {
    int idx = blockIdx.x * blockDim.x + threadIdx.x;
    if (idx >= T_ * E_) return;
    int t = idx / E_, e = idx - t * E_;
    int dst = (int)ld_idx(ei, (size_t)t * 2 * E_ + E_ + e);
    int pos = atomicAdd(&g_cursor[t * N_ + dst], 1);
    g_sorted[t * E_ + g_rowptr[t * (N_ + 1) + dst] + pos] = e;
}

template <int D, int DH, int L1>
__global__ void gat_gather(const void* ei, const float* __restrict__ ew,
                           const __half* __restrict__ hsrc,
                           __half* __restrict__ oh, float* __restrict__ ofp) {
    int t = blockIdx.y, n = blockIdx.x, tid = threadIdx.x;
    int start = g_rowptr[t * (N_ + 1) + n];
    int end = g_rowptr[t * (N_ + 1) + n + 1];
    int head = tid / DH;
    __shared__ int s_src[64];
    __shared__ float s_ex[64][4];
    float4 ad4 = *(const float4*)&g_ad[(t * N_ + n) * 4];
    float acc = 0.f, den = 0.f;
    for (int base = start; base < end; base += 64) {
        int cnt = min(64, end - base);
        __syncthreads();
        for (int i = tid; i < cnt; i += D) {
            int eid = g_sorted[t * E_ + base + i];
            int src = (int)ld_idx(ei, (size_t)t * 2 * E_ + eid);
            s_src[i] = src;
            float4 s4 = *(const float4*)&g_as[(t * N_ + src) * 4];
            float wv = ew[(size_t)t * E_ + eid];
            float e0 = s4.x + ad4.x; e0 = e0 > 0.f ? e0 : 0.2f * e0;
            float e1 = s4.y + ad4.y; e1 = e1 > 0.f ? e1 : 0.2f * e1;
            float e2 = s4.z + ad4.z; e2 = e2 > 0.f ? e2 : 0.2f * e2;
            float e3 = s4.w + ad4.w; e3 = e3 > 0.f ? e3 : 0.2f * e3;
            s_ex[i][0] = __expf(e0) * wv;
            s_ex[i][1] = __expf(e1) * wv;
            s_ex[i][2] = __expf(e2) * wv;
            s_ex[i][3] = __expf(e3) * wv;
        }
        __syncthreads();
#pragma unroll 8
        for (int i = 0; i < cnt; i++) {
            float exv = s_ex[i][head];
            den += exv;
            acc += exv * __half2float(hsrc[((size_t)t * N_ + s_src[i]) * D + tid]);
        }
    }
    float v = acc / (den + 1e-16f);
    v = v > 0.f ? v : __expf(v) - 1.f;
    size_t o = ((size_t)t * N_ + n) * 128 + tid;
    oh[o] = __float2half(v);
    if (!L1) ofp[o] = v;
}

// ===== meso =====
#define MCHUNK 500
__global__ void meso_acc(const void* part, const float* __restrict__ Dw) {
    int t = blockIdx.y, c0 = blockIdx.x * MCHUNK, tid = threadIdx.x;
    __shared__ float sn[NCOM_ * 64];
    __shared__ float sd[NCOM_];
    __shared__ int sp[MCHUNK];
    __shared__ float sD[MCHUNK];
    for (int i = tid; i < NCOM_ * 64; i += blockDim.x) sn[i] = 0.f;
    for (int i = tid; i < NCOM_; i += blockDim.x) sd[i] = 0.f;
    int nmax = min(MCHUNK, N_ - c0);
    for (int i = tid; i < nmax; i += blockDim.x) {
        sp[i] = (int)ld_idx(part, (size_t)t * N_ + c0 + i);
        sD[i] = Dw[(size_t)t * N_ + c0 + i];
    }
    __syncthreads();
    for (int idx = tid; idx < nmax * 64; idx += blockDim.x) {
        int nl = idx >> 6, c = idx & 63;
        float g = g_agg[((size_t)t * N_ + c0 + nl) * 128 + c];
        atomicAdd(&sn[sp[nl] * 64 + c], sD[nl] * g);
        if (c == 0) atomicAdd(&sd[sp[nl]], sD[nl]);
    }
    __syncthreads();
    for (int i = tid; i < NCOM_ * 64; i += blockDim.x)
        atomicAdd(&g_comnum[t * NCOM_ * 64 + i], sn[i]);
    for (int i = tid; i < NCOM_; i += blockDim.x)
        atomicAdd(&g_comden[t * NCOM_ + i], sd[i]);
}
__global__ void meso_scatter(const void* part, __half* __restrict__ oh) {
    int idx = blockIdx.x * blockDim.x + threadIdx.x;
    if (idx >= T_ * N_ * 64) return;
    int t = idx / (N_ * 64);
    int r = idx - t * N_ * 64;
    int n = r >> 6, c = r & 63;
    int p = (int)ld_idx(part, (size_t)t * N_ + n);
    float mean = g_comnum[(t * NCOM_ + p) * 64 + c] / (g_comden[t * NCOM_ + p] + 1e-16f);
    oh[((size_t)t * N_ + n) * 128 + 64 + c] = __float2half(mean);
}

// ===== LSTM pointwise =====
__global__ void lstm_pw(const float* __restrict__ b, int t) {
    int idx = blockIdx.x * blockDim.x + threadIdx.x;
    if (idx >= N_ * 128) return;
    int n = idx >> 7, j = idx & 127;
    const float* z = g_Zx + (size_t)t * N_ * 512 + (size_t)n * 512;
    float i_ = z[j] + b[j];
    float f_ = z[128 + j] + b[128 + j];
    float gg = z[256 + j] + b[256 + j];
    float o_ = z[384 + j] + b[384 + j];
    float c = sigf_fast(f_) * g_cbuf[idx] + sigf_fast(i_) * tanh_fast(gg);
    g_cbuf[idx] = c;
    g_hb[idx] = __float2half(sigf_fast(o_) * tanh_fast(c));
}

// ===== decoder prep =====
__global__ void emb_tanh(const float* __restrict__ emb_b) {
    __shared__ float s[64];
    int tid = threadIdx.x;
    if (tid < 64) s[tid] = 0.f;
    __syncthreads();
    int idx = blockIdx.x * 256 + tid;
    if (idx < N_ * 64) {
        int n = idx >> 6, c = idx & 63;
        float v = tanhf(g_dec[n * 128 + c] + emb_b[c]);
        g_dec[n * 128 + c] = v;
        atomicAdd(&s[c], v * v);
    }
    __syncthreads();
    if (tid < 64) atomicAdd(&g_colsq[tid], s[tid]);
}
// build PA/PB: [sqrt2*e (64) | corr (16) | scal (64) | 0 (16)], K=160
__global__ void build_P(const float* __restrict__ scal_b) {
    int n = blockIdx.x, c = threadIdx.x;  // 64 threads
    float e = g_dec[n * 128 + c] * rsqrtf(g_colsq[c]);
    float s = sigf(g_dec[n * 128 + 64 + c] + scal_b[c]);
    float v = e * e;
#pragma unroll
    for (int o = 16; o; o >>= 1) v += __shfl_down_sync(0xffffffff, v, o);
    __shared__ float shm[2];
    if ((c & 31) == 0) shm[c >> 5] = v;
    __syncthreads();
    float sq = shm[0] + shm[1];
    size_t base = (size_t)n * 160;
    __half he = __float2half(1.41421356f * e);
    __half hs = __float2half(s);
    g_pa[base + c] = he;        g_pb[base + c] = he;
    g_pa[base + 80 + c] = hs;   g_pb[base + 80 + c] = hs;
    if (c < 16) {
        __half za = __float2half(0.f), zb = za;
        if (c == 0) { za = __float2half(sq);   zb = __float2half(-1.f); }
        if (c == 1) { za = __float2half(1.f);  zb = __float2half(-sq); }
        g_pa[base + 64 + c] = za;
        g_pb[base + 64 + c] = zb;
        g_pa[base + 144 + c] = __float2half(0.f);
        g_pb[base + 144 + c] = __float2half(0.f);
    }
}

// ===== host =====
extern "C" void kernel_launch(void* const* d_in, const int* in_sizes, int n_in,
                              void* d_out, int out_size) {
    const float* feat   = (const float*)d_in[0];
    const float* ew     = (const float*)d_in[1];
    const float* Dw     = (const float*)d_in[2];
    const float* W1     = (const float*)d_in[3];
    const float* a_s1   = (const float*)d_in[4];
    const float* a_d1   = (const float*)d_in[5];
    const float* W2     = (const float*)d_in[6];
    const float* a_s2   = (const float*)d_in[7];
    const float* a_d2   = (const float*)d_in[8];
    const float* Wx     = (const float*)d_in[9];
    const float* Wh     = (const float*)d_in[10];
    const float* b_lstm = (const float*)d_in[11];
    const float* embW   = (const float*)d_in[12];
    const float* embB   = (const float*)d_in[13];
    const float* scalW  = (const float*)d_in[14];
    const float* scalB  = (const float*)d_in[15];
    const void*  ei     = (const void*)d_in[16];
    const void*  part   = (const void*)d_in[17];
    float* out = (float*)d_out;

    cudaFuncSetAttribute(mma_gemm, cudaFuncAttributeMaxDynamicSharedMemorySize, MG_SMEM);
    cudaFuncSetAttribute(pairwise_mma, cudaFuncAttributeMaxDynamicSharedMemorySize, PW_SMEM);

    float *agg, *Zx, *cbuf, *dec, *comnum, *comden, *colsq;
    int *cnt, *cursor;
    __half *h1h, *h2h, *f16, *hb, *wt;
    cudaGetSymbolAddress((void**)&h1h, g_h1h);
    cudaGetSymbolAddress((void**)&h2h, g_h2h);
    cudaGetSymbolAddress((void**)&f16, g_f);
    cudaGetSymbolAddress((void**)&agg, g_agg);
    cudaGetSymbolAddress((void**)&Zx, g_Zx);
    cudaGetSymbolAddress((void**)&cbuf, g_cbuf);
    cudaGetSymbolAddress((void**)&dec, g_dec);
    cudaGetSymbolAddress((void**)&comnum, g_comnum);
    cudaGetSymbolAddress((void**)&comden, g_comden);
    cudaGetSymbolAddress((void**)&colsq, g_colsq);
    cudaGetSymbolAddress((void**)&cnt, g_cnt);
    cudaGetSymbolAddress((void**)&cursor, g_cursor);
    cudaGetSymbolAddress((void**)&hb, g_hb);
    cudaGetSymbolAddress((void**)&wt, g_wt);

    const int MT = 79;   // ceil(10000/128)
    const int TE = T_ * E_;
    const int TNH = T_ * N_ * H_;
    const int NS4 = T_ * N_ * 128 / 4;

    detect64_kernel<<<1, 1>>>((const int*)ei);

    // GAT layer 1
    cvt16<<<(NS4 + 255) / 256, 256>>>((const float4*)feat, (__half2*)f16, NS4);
    wsplit16<<<(128 * 128 + 255) / 256, 256>>>(W1, wt, 128);
    mma_gemm<<<dim3(MT, 2, 8), 256, MG_SMEM>>>(f16, wt, h1h, N_, 128,
                                               (long long)N_ * 128, (long long)N_ * 128, 2);
    alpha_kernel<<<(TNH + 255) / 256, 256>>>(h1h, a_s1, a_d1, 32);

    fill_i<<<(T_ * N_ + 255) / 256, 256>>>(cnt, 0, T_ * N_);
    csr_count<<<(TE + 255) / 256, 256>>>(ei);
    csr_scan<<<T_, 1024>>>();
    fill_i<<<(T_ * N_ + 255) / 256, 256>>>(cursor, 0, T_ * N_);
    csr_scatter<<<(TE + 255) / 256, 256>>>(ei);

    gat_gather<128, 32, 1><<<dim3(N_, T_), 128>>>(ei, ew, h1h, f16, (float*)0);

    // GAT layer 2
    wsplit16<<<(64 * 128 + 255) / 256, 256>>>(W2, wt, 64);
    mma_gemm<<<dim3(MT, 1, 8), 256, MG_SMEM>>>(f16, wt, h2h, N_, 64,
                                               (long long)N_ * 128, (long long)N_ * 64, 2);
    alpha_kernel<<<(TNH + 255) / 256, 256>>>(h2h, a_s2, a_d2, 16);
    gat_gather<64, 16, 0><<<dim3(N_, T_), 64>>>(ei, ew, h2h, f16, agg);

    // meso
    fill_f<<<(T_ * NCOM_ * 64 + 255) / 256, 256>>>(comnum, 0.f, T_ * NCOM_ * 64);
    fill_f<<<(T_ * NCOM_ + 255) / 256, 256>>>(comden, 0.f, T_ * NCOM_);
    meso_acc<<<dim3((N_ + MCHUNK - 1) / MCHUNK, T_), 256>>>(part, Dw);
    meso_scatter<<<(T_ * N_ * 64 + 255) / 256, 256>>>(part, f16);

    // LSTM
    wsplit16<<<(512 * 128 + 255) / 256, 256>>>(Wx, wt, 512);
    mma_gemm<<<dim3(MT, 8, 8), 256, MG_SMEM>>>(f16, wt, Zx, N_, 512,
                                               (long long)N_ * 128, (long long)N_ * 512, 0);
    wsplit16<<<(512 * 128 + 255) / 256, 256>>>(Wh, wt, 512);
    fill_f<<<(N_ * 128 + 255) / 256, 256>>>(cbuf, 0.f, N_ * 128);
    for (int t = 0; t < T_; t++) {
        if (t > 0) {
            mma_gemm<<<dim3(MT, 8, 1), 256, MG_SMEM>>>(hb, wt, Zx + (size_t)t * N_ * 512,
                                                       N_, 512, 0, 0, 1);
        }
        lstm_pw<<<(N_ * 128 + 255) / 256, 256>>>(b_lstm, t);
    }

    // decoder
    wsplit16<<<(64 * 128 + 255) / 256, 256>>>(embW, wt, 64);
    wsplit16<<<(64 * 128 + 255) / 256, 256>>>(scalW, wt + 64 * 128, 64);
    mma_gemm<<<dim3(MT, 2, 1), 256, MG_SMEM>>>(hb, wt, dec, N_, 128, 0, 0, 0);
    fill_f<<<1, 64>>>(colsq, 0.f, 64);
    emb_tanh<<<(N_ * 64 + 255) / 256, 256>>>(embB);
    build_P<<<N_, 64>>>(scalB);
    pairwise_mma<<<dim3(MT, MT), 512, PW_SMEM>>>(out);
}

// round 12
// speedup vs baseline: 3.9947x; 1.0779x over previous
#include <cuda_runtime.h>
#include <cuda_fp16.h>
#include <math.h>
#include <stdint.h>

#define T_ 8
#define N_ 10000
#define E_ 320000
#define H_ 4
#define NCOM_ 100

// ===== scratch =====
__device__ int   g_is64;
__device__ __align__(16) __half g_h1h[(size_t)T_ * N_ * 128];
__device__ __align__(16) __half g_h2h[(size_t)T_ * N_ * 64];
__device__ __align__(16) __half g_f[(size_t)T_ * N_ * 128];
__device__ __align__(16) float g_as[T_ * N_ * H_];
__device__ __align__(16) float g_ad[T_ * N_ * H_];
__device__ int   g_cnt[T_ * N_];
__device__ int   g_rowptr[T_ * (N_ + 1)];
__device__ int   g_cursor[T_ * N_];
__device__ int   g_sorted[T_ * E_];
__device__ float g_comnum[T_ * NCOM_ * 64];
__device__ float g_comden[T_ * NCOM_];
__device__ __align__(16) float g_Zx[(size_t)T_ * N_ * 512];
__device__ __align__(16) float g_cbuf[N_ * 128];
__device__ __align__(16) float g_dec[N_ * 128];
__device__ float g_colsq[64];
__device__ __align__(16) __half g_hb0[N_ * 128];
__device__ __align__(16) __half g_hb1[N_ * 128];
__device__ __align__(16) __half g_pa[(size_t)N_ * 160];
__device__ __align__(16) __half g_pb[(size_t)N_ * 160];
__device__ __align__(16) __half g_wt[512 * 128];

// ===== helpers =====
__device__ __forceinline__ long long ld_idx(const void* p, size_t i) {
    if (g_is64) return ((const long long*)p)[i];
    return (long long)((const int*)p)[i];
}
__device__ __forceinline__ float sigf(float x) { return 1.f / (1.f + expf(-x)); }
__device__ __forceinline__ float sigf_fast(float x) {
    return __fdividef(1.f, 1.f + __expf(-x));
}
__device__ __forceinline__ float tanh_fast(float x) {
    float e = __expf(2.f * x);
    return 1.f - __fdividef(2.f, e + 1.f);
}
__device__ __forceinline__ float tanh_hw(float x) {
    float y;
    asm("tanh.approx.f32 %0, %1;" : "=f"(y) : "f"(x));
    return y;
}
__device__ __forceinline__ float one_p_tanh(float x) {
    float ax = fabsf(x);
    if (ax < 0.15f) {
        float x2 = x * x;
        return fmaf(x, fmaf(x2, -0.33333333f, 1.f), 1.f);
    }
    return 1.f + tanh_hw(x);
}
__device__ __forceinline__ void mma_f16(float* c, uint32_t a0, uint32_t a1, uint32_t a2,
                                        uint32_t a3, uint32_t b0, uint32_t b1) {
    asm volatile(
        "mma.sync.aligned.m16n8k16.row.col.f32.f16.f16.f32 "
        "{%0,%1,%2,%3}, {%4,%5,%6,%7}, {%8,%9}, {%0,%1,%2,%3};"
        : "+f"(c[0]), "+f"(c[1]), "+f"(c[2]), "+f"(c[3])
        : "r"(a0), "r"(a1), "r"(a2), "r"(a3), "r"(b0), "r"(b1));
}

__global__ void detect64_kernel(const int* ei32) {
    int ok = 1;
    for (int i = 1; i < 64; i += 2)
        if (ei32[i] != 0) ok = 0;
    g_is64 = ok;
}
__global__ void fill_f(float* p, float v, int n) {
    int i = blockIdx.x * blockDim.x + threadIdx.x;
    if (i < n) p[i] = v;
}
__global__ void fill_i(int* p, int v, int n) {
    int i = blockIdx.x * blockDim.x + threadIdx.x;
    if (i < n) p[i] = v;
}
__global__ void cvt16(const float4* __restrict__ x, __half2* __restrict__ y, int n4) {
    int i = blockIdx.x * blockDim.x + threadIdx.x;
    if (i >= n4) return;
    float4 v = x[i];
    y[2 * i]     = __floats2half2_rn(v.x, v.y);
    y[2 * i + 1] = __floats2half2_rn(v.z, v.w);
}
__global__ void wsplit16(const float* __restrict__ B, __half* __restrict__ bt, int Dn) {
    int idx = blockIdx.x * blockDim.x + threadIdx.x;
    if (idx >= Dn * 128) return;
    int n = idx >> 7, k = idx & 127;
    bt[idx] = __float2half(B[(size_t)k * Dn + n]);
}
// gate-interleaved permute for LSTM weights: p = (j/8)*32 + gate*8 + j%8
__global__ void wsplit16_lstm(const float* __restrict__ B, __half* __restrict__ bt) {
    int idx = blockIdx.x * blockDim.x + threadIdx.x;
    if (idx >= 512 * 128) return;
    int p = idx >> 7, k = idx & 127;
    int blk = p >> 5, r = p & 31, gate = r >> 3, jl = r & 7;
    int o = gate * 128 + blk * 8 + jl;
    bt[idx] = __float2half(B[(size_t)k * 512 + o]);
}

// ===== smem tile copy =====
template <int KU4, int SU4, int THREADS>
__device__ __forceinline__ void cp16(const uint4* __restrict__ G, char* sm, int off,
                                     int base, int Mlim, int tid, int rows) {
    int total = rows * KU4;
    for (int idx = tid; idx < total; idx += THREADS) {
        int row = idx / KU4, c = idx - row * KU4;
        uint4 v = make_uint4(0, 0, 0, 0);
        if (base + row < Mlim) v = G[(size_t)(base + row) * KU4 + c];
        ((uint4*)(sm + off))[row * SU4 + c] = v;
    }
}

// ===== fp16 MMA GEMM: CTA 128x64, 256 threads, warp grid 4x2, warp tile 32x32 =====
#define SM_B 34816
#define MG_SMEM 52736

#define GEMM_MAINLOOP(ACC)                                                         \
    int ra0 = (wr * 32 + g) * 68;                                                  \
    int rb0 = ra0 + 8 * 68, ra1 = ra0 + 16 * 68, rb1 = ra0 + 24 * 68;              \
    _Pragma("unroll")                                                              \
    for (int kc = 0; kc < 8; kc++) {                                               \
        int ka = kc * 8 + tq;                                                      \
        uint32_t a00 = SA[ra0 + ka], a01 = SA[rb0 + ka];                           \
        uint32_t a02 = SA[ra0 + ka + 4], a03 = SA[rb0 + ka + 4];                   \
        uint32_t a10 = SA[ra1 + ka], a11 = SA[rb1 + ka];                           \
        uint32_t a12 = SA[ra1 + ka + 4], a13 = SA[rb1 + ka + 4];                   \
        _Pragma("unroll")                                                          \
        for (int nb = 0; nb < 4; nb++) {                                           \
            int nr = (wc * 32 + nb * 8 + g) * 68;                                  \
            uint32_t b0 = SB[nr + ka], b1 = SB[nr + ka + 4];                       \
            mma_f16(ACC[0][nb], a00, a01, a02, a03, b0, b1);                       \
            mma_f16(ACC[1][nb], a10, a11, a12, a13, b0, b1);                       \
        }                                                                          \
    }

// mode: 0 = store fp32, 2 = store fp16
__global__ __launch_bounds__(256, 3) void mma_gemm(
    const __half* __restrict__ A, const __half* __restrict__ B,
    void* __restrict__ Cv, int M, int Dn,
    long long sA, long long sC, int mode)
{
    extern __shared__ char sm[];
    int tid = threadIdx.x, w = tid >> 5, lane = tid & 31;
    int g = lane >> 2, tq = lane & 3;
    int wr = w >> 1, wc = w & 1;
    int m0 = blockIdx.x * 128, n0 = blockIdx.y * 64, t = blockIdx.z;
    A += (size_t)t * sA;

    cp16<16, 17, 256>((const uint4*)A, sm, 0, m0, M, tid, 128);
    cp16<16, 17, 256>((const uint4*)B, sm, SM_B, n0, Dn, tid, 64);
    __syncthreads();

    const uint32_t* SA = (const uint32_t*)sm;
    const uint32_t* SB = (const uint32_t*)(sm + SM_B);

    float acc[2][4][4];
#pragma unroll
    for (int rg = 0; rg < 2; rg++)
#pragma unroll
        for (int nb = 0; nb < 4; nb++)
#pragma unroll
            for (int q = 0; q < 4; q++) acc[rg][nb][q] = 0.f;

    GEMM_MAINLOOP(acc)

#pragma unroll
    for (int rg = 0; rg < 2; rg++) {
        int r0 = m0 + wr * 32 + rg * 16 + g, r1 = r0 + 8;
#pragma unroll
        for (int nb = 0; nb < 4; nb++) {
            int col = n0 + wc * 32 + nb * 8 + 2 * tq;
            if (mode == 2) {
                __half* Ch = (__half*)Cv + (size_t)t * sC;
                if (r0 < M)
                    *(__half2*)(Ch + (size_t)r0 * Dn + col) = __floats2half2_rn(acc[rg][nb][0], acc[rg][nb][1]);
                if (r1 < M)
                    *(__half2*)(Ch + (size_t)r1 * Dn + col) = __floats2half2_rn(acc[rg][nb][2], acc[rg][nb][3]);
            } else {
                float* C = (float*)Cv + (size_t)t * sC;
                if (r0 < M)
                    *(float2*)(C + (size_t)r0 * Dn + col) = make_float2(acc[rg][nb][0], acc[rg][nb][1]);
                if (r1 < M)
                    *(float2*)(C + (size_t)r1 * Dn + col) = make_float2(acc[rg][nb][2], acc[rg][nb][3]);
            }
        }
    }
}

// ===== fused LSTM GEMM: z = Zx + Wh*h (+b); gate-interleaved; double-buffered h =====
__global__ __launch_bounds__(256, 3) void mma_gemm_lstm(
    const __half* __restrict__ A, const __half* __restrict__ B,
    const float* __restrict__ Zt, const float* __restrict__ bias,
    __half* __restrict__ hout)
{
    extern __shared__ char sm[];
    int tid = threadIdx.x, w = tid >> 5, lane = tid & 31;
    int g = lane >> 2, tq = lane & 3;
    int wr = w >> 1, wc = w & 1;
    int m0 = blockIdx.x * 128, n0 = blockIdx.y * 64;

    cp16<16, 17, 256>((const uint4*)A, sm, 0, m0, N_, tid, 128);
    cp16<16, 17, 256>((const uint4*)B, sm, SM_B, n0, 512, tid, 64);
    __syncthreads();

    const uint32_t* SA = (const uint32_t*)sm;
    const uint32_t* SB = (const uint32_t*)(sm + SM_B);

    float acc[2][4][4];
#pragma unroll
    for (int rg = 0; rg < 2; rg++)
#pragma unroll
        for (int nb = 0; nb < 4; nb++)
#pragma unroll
            for (int q = 0; q < 4; q++) acc[rg][nb][q] = 0.f;

    GEMM_MAINLOOP(acc)

    int pbase = n0 + wc * 32;
    int jb8 = (pbase >> 5) * 8;
    float bi[2], bf[2], bg[2], bo[2];
#pragma unroll
    for (int q01 = 0; q01 < 2; q01++) {
        int j = jb8 + 2 * tq + q01;
        bi[q01] = bias[j];
        bf[q01] = bias[128 + j];
        bg[q01] = bias[256 + j];
        bo[q01] = bias[384 + j];
    }
#pragma unroll
    for (int rg = 0; rg < 2; rg++) {
#pragma unroll
        for (int rr = 0; rr < 2; rr++) {
            int row = m0 + wr * 32 + rg * 16 + g + rr * 8;
            if (row >= N_) continue;
            int qoff = rr * 2;
            float hv[2], cv[2];
#pragma unroll
            for (int q01 = 0; q01 < 2; q01++) {
                int j = jb8 + 2 * tq + q01;
                const float* zr = Zt + (size_t)row * 512 + pbase + 2 * tq + q01;
                float zi = acc[rg][0][qoff + q01] + zr[0]  + bi[q01];
                float zf = acc[rg][1][qoff + q01] + zr[8]  + bf[q01];
                float zg = acc[rg][2][qoff + q01] + zr[16] + bg[q01];
                float zo = acc[rg][3][qoff + q01] + zr[24] + bo[q01];
                float c = sigf_fast(zf) * g_cbuf[row * 128 + j] + sigf_fast(zi) * tanh_fast(zg);
                cv[q01] = c;
                hv[q01] = sigf_fast(zo) * tanh_fast(c);
            }
            int j0 = jb8 + 2 * tq;
            *(float2*)&g_cbuf[row * 128 + j0] = make_float2(cv[0], cv[1]);
            *(__half2*)&hout[row * 128 + j0] = __floats2half2_rn(hv[0], hv[1]);
        }
    }
}

// t=0 LSTM (c0 = 0): read permuted Zx + bias only
__global__ void lstm_pw0(const float* __restrict__ b, __half* __restrict__ hout) {
    int idx = blockIdx.x * blockDim.x + threadIdx.x;
    if (idx >= N_ * 128) return;
    int n = idx >> 7, j = idx & 127;
    const float* z = g_Zx + (size_t)n * 512 + (j >> 3) * 32 + (j & 7);
    float zi = z[0] + b[j];
    float zg = z[16] + b[256 + j];
    float zo = z[24] + b[384 + j];
    float c = sigf_fast(zi) * tanh_fast(zg);
    g_cbuf[idx] = c;
    hout[idx] = __float2half(sigf_fast(zo) * tanh_fast(c));
}

// ===== pairwise: CTA 128x128, 512 threads, K=160, streaming stores =====
#define PW_B 43008
#define PW_SMEM 86016

__global__ __launch_bounds__(512, 2) void pairwise_mma(float* __restrict__ out) {
    int bi = blockIdx.y, bj = blockIdx.x;
    if (bj < bi) return;
    int i0 = bi * 128, j0 = bj * 128;
    extern __shared__ char sm[];
    int tid = threadIdx.x, w = tid >> 5, lane = tid & 31;
    int g = lane >> 2, tq = lane & 3;
    int wr = w >> 2, wc = w & 3;

    cp16<20, 21, 512>((const uint4*)g_pa, sm, 0, i0, N_, tid, 128);
    cp16<20, 21, 512>((const uint4*)g_pb, sm, PW_B, j0, N_, tid, 128);
    __syncthreads();

    const uint32_t* SA = (const uint32_t*)sm;
    const uint32_t* SB = (const uint32_t*)(sm + PW_B);

    float accG[2][4][4], accS[2][4][4];
#pragma unroll
    for (int rg = 0; rg < 2; rg++)
#pragma unroll
        for (int nb = 0; nb < 4; nb++)
#pragma unroll
            for (int q = 0; q < 4; q++) { accG[rg][nb][q] = 0.f; accS[rg][nb][q] = 0.f; }

    int ra0 = (wr * 32 + g) * 84;
    int rb0 = ra0 + 8 * 84, ra1 = ra0 + 16 * 84, rb1 = ra0 + 24 * 84;
#pragma unroll
    for (int kc = 0; kc < 9; kc++) {
        int ka = kc * 8 + tq;
        uint32_t a00 = SA[ra0 + ka], a01 = SA[rb0 + ka];
        uint32_t a02 = SA[ra0 + ka + 4], a03 = SA[rb0 + ka + 4];
        uint32_t a10 = SA[ra1 + ka], a11 = SA[rb1 + ka];
        uint32_t a12 = SA[ra1 + ka + 4], a13 = SA[rb1 + ka + 4];
        float (*a0)[4] = (kc < 5) ? accG[0] : accS[0];
        float (*a1)[4] = (kc < 5) ? accG[1] : accS[1];
#pragma unroll
        for (int nb = 0; nb < 4; nb++) {
            int nr = (wc * 32 + nb * 8 + g) * 84;
            uint32_t b0 = SB[nr + ka], b1 = SB[nr + ka + 4];
            mma_f16(a0[nb], a00, a01, a02, a03, b0, b1);
            mma_f16(a1[nb], a10, a11, a12, a13, b0, b1);
        }
    }

    bool full = (i0 + 128 <= N_) && (j0 + 128 <= N_);
    float vv[2][4][4];
#pragma unroll
    for (int rg = 0; rg < 2; rg++) {
        int lr0 = wr * 32 + rg * 16 + g, lr1 = lr0 + 8;
        int ir0 = i0 + lr0, ir1 = i0 + lr1;
#pragma unroll
        for (int nb = 0; nb < 4; nb++) {
            int c0 = wc * 32 + nb * 8 + 2 * tq;
            vv[rg][nb][0] = one_p_tanh(accG[rg][nb][0] * accS[rg][nb][0]);
            vv[rg][nb][1] = one_p_tanh(accG[rg][nb][1] * accS[rg][nb][1]);
            vv[rg][nb][2] = one_p_tanh(accG[rg][nb][2] * accS[rg][nb][2]);
            vv[rg][nb][3] = one_p_tanh(accG[rg][nb][3] * accS[rg][nb][3]);
            if (full) {
                __stcs((float2*)(out + (size_t)ir0 * N_ + j0 + c0),
                       make_float2(vv[rg][nb][0], vv[rg][nb][1]));
                __stcs((float2*)(out + (size_t)ir1 * N_ + j0 + c0),
                       make_float2(vv[rg][nb][2], vv[rg][nb][3]));
            } else {
                if (ir0 < N_) {
                    if (j0 + c0 < N_)     __stcs(out + (size_t)ir0 * N_ + j0 + c0, vv[rg][nb][0]);
                    if (j0 + c0 + 1 < N_) __stcs(out + (size_t)ir0 * N_ + j0 + c0 + 1, vv[rg][nb][1]);
                }
                if (ir1 < N_) {
                    if (j0 + c0 < N_)     __stcs(out + (size_t)ir1 * N_ + j0 + c0, vv[rg][nb][2]);
                    if (j0 + c0 + 1 < N_) __stcs(out + (size_t)ir1 * N_ + j0 + c0 + 1, vv[rg][nb][3]);
                }
            }
        }
    }

    __syncthreads();
    float* vT = (float*)sm;  // [128][129]
#pragma unroll
    for (int rg = 0; rg < 2; rg++) {
        int lr0 = wr * 32 + rg * 16 + g, lr1 = lr0 + 8;
#pragma unroll
        for (int nb = 0; nb < 4; nb++) {
            int c0 = wc * 32 + nb * 8 + 2 * tq, c1 = c0 + 1;
            vT[c0 * 129 + lr0] = vv[rg][nb][0];
            vT[c1 * 129 + lr0] = vv[rg][nb][1];
            vT[c0 * 129 + lr1] = vv[rg][nb][2];
            vT[c1 * 129 + lr1] = vv[rg][nb][3];
        }
    }
    __syncthreads();
    for (int idx = tid; idx < 128 * 128; idx += 512) {
        int r2 = idx >> 7, c2 = idx & 127;
        int jj = j0 + r2, ii = i0 + c2;
        if (jj > ii && jj < N_ && ii < N_) __stcs(out + (size_t)jj * N_ + ii, vT[r2 * 129 + c2]);
    }
}

// ===== GAT kernels =====
__global__ void alpha_kernel(const __half* __restrict__ h, const float* __restrict__ a_s,
                             const float* __restrict__ a_d, int dh) {
    int idx = blockIdx.x * blockDim.x + threadIdx.x;
    if (idx >= T_ * N_ * H_) return;
    int hh = idx & 3, tn = idx >> 2;
    const __half* hr = h + (size_t)tn * (H_ * dh) + hh * dh;
    float s = 0.f, d = 0.f;
    for (int k = 0; k < dh; k++) {
        float v = __half2float(hr[k]);
        s += v * a_s[hh * dh + k];
        d += v * a_d[hh * dh + k];
    }
    g_as[idx] = s; g_ad[idx] = d;
}
__global__ void csr_count(const void* ei) {
    int idx = blockIdx.x * blockDim.x + threadIdx.x;
    if (idx >= T_ * E_) return;
    int t = idx / E_, e = idx - t * E_;
    int dst = (int)ld_idx(ei, (size_t)t * 2 * E_ + E_ + e);
    atomicAdd(&g_cnt[t * N_ + dst], 1);
}
__global__ void csr_scan() {
    int t = blockIdx.x, tid = threadIdx.x;
    __shared__ int sh[1024];
    int off = 0;
    for (int chunk = 0; chunk < N_; chunk += 1024) {
        int i = chunk + tid;
        int v = (i < N_) ? g_cnt[t * N_ + i] : 0;
        sh[tid] = v;
        __syncthreads();
        for (int d2 = 1; d2 < 1024; d2 <<= 1) {
            int x = 0;
            if (tid >= d2) x = sh[tid - d2];
            __syncthreads();
            sh[tid] += x;
            __syncthreads();
        }
        if (i < N_) g_rowptr[t * (N_ + 1) + i] = off + sh[tid] - v;
        int tot = sh[1023];
        __syncthreads();
        off += tot;
    }
    if (tid == 0) g_rowptr[t * (N_ + 1) + N_] = off;
}
__global__ void csr_scatter(const void* ei) {
    int idx = blockIdx.x * blockDim.x + threadIdx.x;
    if (idx >= T_ * E_) return;
    int t = idx / E_, e = idx - t * E_;
    int dst = (int)ld_idx(ei, (size_t)t * 2 * E_ + E_ + e);
    int pos = atomicAdd(&g_cursor[t * N_ + dst], 1);
    g_sorted[t * E_ + g_rowptr[t * (N_ + 1) + dst] + pos] = e;
}

template <int D, int DH>
__global__ void gat_gather(const void* ei, const float* __restrict__ ew,
                           const __half* __restrict__ hsrc, __half* __restrict__ oh) {
    int t = blockIdx.y, n = blockIdx.x, tid = threadIdx.x;
    int start = g_rowptr[t * (N_ + 1) + n];
    int end = g_rowptr[t * (N_ + 1) + n + 1];
    int head = tid / DH;
    __shared__ int s_src[64];
    __shared__ float s_ex[64][4];
    float4 ad4 = *(const float4*)&g_ad[(t * N_ + n) * 4];
    float acc = 0.f, den = 0.f;
    for (int base = start; base < end; base += 64) {
        int cnt = min(64, end - base);
        __syncthreads();
        for (int i = tid; i < cnt; i += D) {
            int eid = g_sorted[t * E_ + base + i];
            int src = (int)ld_idx(ei, (size_t)t * 2 * E_ + eid);
            s_src[i] = src;
            float4 s4 = *(const float4*)&g_as[(t * N_ + src) * 4];
            float wv = ew[(size_t)t * E_ + eid];
            float e0 = s4.x + ad4.x; e0 = e0 > 0.f ? e0 : 0.2f * e0;
            float e1 = s4.y + ad4.y; e1 = e1 > 0.f ? e1 : 0.2f * e1;
            float e2 = s4.z + ad4.z; e2 = e2 > 0.f ? e2 : 0.2f * e2;
            float e3 = s4.w + ad4.w; e3 = e3 > 0.f ? e3 : 0.2f * e3;
            s_ex[i][0] = __expf(e0) * wv;
            s_ex[i][1] = __expf(e1) * wv;
            s_ex[i][2] = __expf(e2) * wv;
            s_ex[i][3] = __expf(e3) * wv;
        }
        __syncthreads();
#pragma unroll 8
        for (int i = 0; i < cnt; i++) {
            float exv = s_ex[i][head];
            den += exv;
            acc += exv * __half2float(hsrc[((size_t)t * N_ + s_src[i]) * D + tid]);
        }
    }
    float v = acc / (den + 1e-16f);
    v = v > 0.f ? v : __expf(v) - 1.f;
    oh[((size_t)t * N_ + n) * 128 + tid] = __float2half(v);
}

// ===== meso (reads fp16 gather output directly) =====
#define MCHUNK 500
__global__ void meso_acc(const void* part, const float* __restrict__ Dw) {
    int t = blockIdx.y, c0 = blockIdx.x * MCHUNK, tid = threadIdx.x;
    __shared__ float sn[NCOM_ * 64];
    __shared__ float sd[NCOM_];
    __shared__ int sp[MCHUNK];
    __shared__ float sD[MCHUNK];
    for (int i = tid; i < NCOM_ * 64; i += blockDim.x) sn[i] = 0.f;
    for (int i = tid; i < NCOM_; i += blockDim.x) sd[i] = 0.f;
    int nmax = min(MCHUNK, N_ - c0);
    for (int i = tid; i < nmax; i += blockDim.x) {
        sp[i] = (int)ld_idx(part, (size_t)t * N_ + c0 + i);
        sD[i] = Dw[(size_t)t * N_ + c0 + i];
    }
    __syncthreads();
    for (int idx = tid; idx < nmax * 64; idx += blockDim.x) {
        int nl = idx >> 6, c = idx & 63;
        float g = __half2float(g_f[((size_t)t * N_ + c0 + nl) * 128 + c]);
        atomicAdd(&sn[sp[nl] * 64 + c], sD[nl] * g);
        if (c == 0) atomicAdd(&sd[sp[nl]], sD[nl]);
    }
    __syncthreads();
    for (int i = tid; i < NCOM_ * 64; i += blockDim.x)
        atomicAdd(&g_comnum[t * NCOM_ * 64 + i], sn[i]);
    for (int i = tid; i < NCOM_; i += blockDim.x)
        atomicAdd(&g_comden[t * NCOM_ + i], sd[i]);
}
__global__ void meso_scatter(const void* part, __half* __restrict__ oh) {
    int idx = blockIdx.x * blockDim.x + threadIdx.x;
    if (idx >= T_ * N_ * 64) return;
    int t = idx / (N_ * 64);
    int r = idx - t * N_ * 64;
    int n = r >> 6, c = r & 63;
    int p = (int)ld_idx(part, (size_t)t * N_ + n);
    float mean = g_comnum[(t * NCOM_ + p) * 64 + c] / (g_comden[t * NCOM_ + p] + 1e-16f);
    oh[((size_t)t * N_ + n) * 128 + 64 + c] = __float2half(mean);
}

// ===== decoder prep =====
__global__ void emb_tanh(const float* __restrict__ emb_b) {
    __shared__ float s[64];
    int tid = threadIdx.x;
    if (tid < 64) s[tid] = 0.f;
    __syncthreads();
    int idx = blockIdx.x * 256 + tid;
    if (idx < N_ * 64) {
        int n = idx >> 6, c = idx & 63;
        float v = tanhf(g_dec[n * 128 + c] + emb_b[c]);
        g_dec[n * 128 + c] = v;
        atomicAdd(&s[c], v * v);
    }
    __syncthreads();
    if (tid < 64) atomicAdd(&g_colsq[tid], s[tid]);
}
__global__ void build_P(const float* __restrict__ scal_b) {
    int n = blockIdx.x, c = threadIdx.x;
    float e = g_dec[n * 128 + c] * rsqrtf(g_colsq[c]);
    float s = sigf(g_dec[n * 128 + 64 + c] + scal_b[c]);
    float v = e * e;
#pragma unroll
    for (int o = 16; o; o >>= 1) v += __shfl_down_sync(0xffffffff, v, o);
    __shared__ float shm[2];
    if ((c & 31) == 0) shm[c >> 5] = v;
    __syncthreads();
    float sq = shm[0] + shm[1];
    size_t base = (size_t)n * 160;
    __half he = __float2half(1.41421356f * e);
    __half hs = __float2half(s);
    g_pa[base + c] = he;        g_pb[base + c] = he;
    g_pa[base + 80 + c] = hs;   g_pb[base + 80 + c] = hs;
    if (c < 16) {
        __half za = __float2half(0.f), zb = za;
        if (c == 0) { za = __float2half(sq);   zb = __float2half(-1.f); }
        if (c == 1) { za = __float2half(1.f);  zb = __float2half(-sq); }
        g_pa[base + 64 + c] = za;
        g_pb[base + 64 + c] = zb;
        g_pa[base + 144 + c] = __float2half(0.f);
        g_pb[base + 144 + c] = __float2half(0.f);
    }
}

// ===== host =====
extern "C" void kernel_launch(void* const* d_in, const int* in_sizes, int n_in,
                              void* d_out, int out_size) {
    const float* feat   = (const float*)d_in[0];
    const float* ew     = (const float*)d_in[1];
    const float* Dw     = (const float*)d_in[2];
    const float* W1     = (const float*)d_in[3];
    const float* a_s1   = (const float*)d_in[4];
    const float* a_d1   = (const float*)d_in[5];
    const float* W2     = (const float*)d_in[6];
    const float* a_s2   = (const float*)d_in[7];
    const float* a_d2   = (const float*)d_in[8];
    const float* Wx     = (const float*)d_in[9];
    const float* Wh     = (const float*)d_in[10];
    const float* b_lstm = (const float*)d_in[11];
    const float* embW   = (const float*)d_in[12];
    const float* embB   = (const float*)d_in[13];
    const float* scalW  = (const float*)d_in[14];
    const float* scalB  = (const float*)d_in[15];
    const void*  ei     = (const void*)d_in[16];
    const void*  part   = (const void*)d_in[17];
    float* out = (float*)d_out;

    cudaFuncSetAttribute(mma_gemm, cudaFuncAttributeMaxDynamicSharedMemorySize, MG_SMEM);
    cudaFuncSetAttribute(mma_gemm_lstm, cudaFuncAttributeMaxDynamicSharedMemorySize, MG_SMEM);
    cudaFuncSetAttribute(pairwise_mma, cudaFuncAttributeMaxDynamicSharedMemorySize, PW_SMEM);

    float *Zx, *dec, *comnum, *comden, *colsq;
    int *cnt, *cursor;
    __half *h1h, *h2h, *f16, *hb0, *hb1, *wt;
    cudaGetSymbolAddress((void**)&h1h, g_h1h);
    cudaGetSymbolAddress((void**)&h2h, g_h2h);
    cudaGetSymbolAddress((void**)&f16, g_f);
    cudaGetSymbolAddress((void**)&Zx, g_Zx);
    cudaGetSymbolAddress((void**)&dec, g_dec);
    cudaGetSymbolAddress((void**)&comnum, g_comnum);
    cudaGetSymbolAddress((void**)&comden, g_comden);
    cudaGetSymbolAddress((void**)&colsq, g_colsq);
    cudaGetSymbolAddress((void**)&cnt, g_cnt);
    cudaGetSymbolAddress((void**)&cursor, g_cursor);
    cudaGetSymbolAddress((void**)&hb0, g_hb0);
    cudaGetSymbolAddress((void**)&hb1, g_hb1);
    cudaGetSymbolAddress((void**)&wt, g_wt);
    __half* hbuf[2] = {hb0, hb1};

    const int MT = 79;
    const int TE = T_ * E_;
    const int TNH = T_ * N_ * H_;
    const int NS4 = T_ * N_ * 128 / 4;

    detect64_kernel<<<1, 1>>>((const int*)ei);

    // GAT layer 1
    cvt16<<<(NS4 + 255) / 256, 256>>>((const float4*)feat, (__half2*)f16, NS4);
    wsplit16<<<(128 * 128 + 255) / 256, 256>>>(W1, wt, 128);
    mma_gemm<<<dim3(MT, 2, 8), 256, MG_SMEM>>>(f16, wt, h1h, N_, 128,
                                               (long long)N_ * 128, (long long)N_ * 128, 2);
    alpha_kernel<<<(TNH + 255) / 256, 256>>>(h1h, a_s1, a_d1, 32);

    fill_i<<<(T_ * N_ + 255) / 256, 256>>>(cnt, 0, T_ * N_);
    csr_count<<<(TE + 255) / 256, 256>>>(ei);
    csr_scan<<<T_, 1024>>>();
    fill_i<<<(T_ * N_ + 255) / 256, 256>>>(cursor, 0, T_ * N_);
    csr_scatter<<<(TE + 255) / 256, 256>>>(ei);

    gat_gather<128, 32><<<dim3(N_, T_), 128>>>(ei, ew, h1h, f16);

    // GAT layer 2
    wsplit16<<<(64 * 128 + 255) / 256, 256>>>(W2, wt, 64);
    mma_gemm<<<dim3(MT, 1, 8), 256, MG_SMEM>>>(f16, wt, h2h, N_, 64,
                                               (long long)N_ * 128, (long long)N_ * 64, 2);
    alpha_kernel<<<(TNH + 255) / 256, 256>>>(h2h, a_s2, a_d2, 16);
    gat_gather<64, 16><<<dim3(N_, T_), 64>>>(ei, ew, h2h, f16);

    // meso
    fill_f<<<(T_ * NCOM_ * 64 + 255) / 256, 256>>>(comnum, 0.f, T_ * NCOM_ * 64);
    fill_f<<<(T_ * NCOM_ + 255) / 256, 256>>>(comden, 0.f, T_ * NCOM_);
    meso_acc<<<dim3((N_ + MCHUNK - 1) / MCHUNK, T_), 256>>>(part, Dw);
    meso_scatter<<<(T_ * N_ * 64 + 255) / 256, 256>>>(part, f16);

    // LSTM: Wx (permuted) for all t, then fused Wh+gates per step (double-buffered h)
    wsplit16_lstm<<<(512 * 128 + 255) / 256, 256>>>(Wx, wt);
    mma_gemm<<<dim3(MT, 8, 8), 256, MG_SMEM>>>(f16, wt, Zx, N_, 512,
                                               (long long)N_ * 128, (long long)N_ * 512, 0);
    wsplit16_lstm<<<(512 * 128 + 255) / 256, 256>>>(Wh, wt);
    lstm_pw0<<<(N_ * 128 + 255) / 256, 256>>>(b_lstm, hbuf[0]);
    for (int t = 1; t < T_; t++) {
        mma_gemm_lstm<<<dim3(MT, 8, 1), 256, MG_SMEM>>>(hbuf[(t - 1) & 1], wt,
                                                        Zx + (size_t)t * N_ * 512, b_lstm,
                                                        hbuf[t & 1]);
    }
    __half* hlast = hbuf[(T_ - 1) & 1];

    // decoder
    wsplit16<<<(64 * 128 + 255) / 256, 256>>>(embW, wt, 64);
    wsplit16<<<(64 * 128 + 255) / 256, 256>>>(scalW, wt + 64 * 128, 64);
    mma_gemm<<<dim3(MT, 2, 1), 256, MG_SMEM>>>(hlast, wt, dec, N_, 128, 0, 0, 0);
    fill_f<<<1, 64>>>(colsq, 0.f, 64);
    emb_tanh<<<(N_ * 64 + 255) / 256, 256>>>(embB);
    build_P<<<N_, 64>>>(scalB);
    pairwise_mma<<<dim3(MT, MT), 512, PW_SMEM>>>(out);
}

// round 13
// speedup vs baseline: 4.0400x; 1.0113x over previous
#include <cuda_runtime.h>
#include <cuda_fp16.h>
#include <math.h>
#include <stdint.h>

#define T_ 8
#define N_ 10000
#define E_ 320000
#define H_ 4
#define NCOM_ 100

// ===== scratch =====
__device__ int   g_is64;
__device__ __align__(16) __half g_h1h[(size_t)T_ * N_ * 128];
__device__ __align__(16) __half g_h2h[(size_t)T_ * N_ * 64];
__device__ __align__(16) __half g_f[(size_t)T_ * N_ * 128];
__device__ __align__(16) float g_as[T_ * N_ * H_];
__device__ __align__(16) float g_ad[T_ * N_ * H_];
__device__ int   g_cnt[T_ * N_];
__device__ int   g_rowptr[T_ * (N_ + 1)];
__device__ int   g_cursor[T_ * N_];
__device__ int   g_sorted[T_ * E_];
__device__ float g_comnum[T_ * NCOM_ * 64];
__device__ float g_comden[T_ * NCOM_];
__device__ __align__(16) float g_Zx[(size_t)T_ * N_ * 512];
__device__ __align__(16) float g_cbuf[N_ * 128];
__device__ __align__(16) float g_dec[N_ * 128];
__device__ float g_colsq[64];
__device__ __align__(16) __half g_hb0[N_ * 128];
__device__ __align__(16) __half g_hb1[N_ * 128];
__device__ __align__(16) __half g_pa[(size_t)N_ * 160];
__device__ __align__(16) __half g_pb[(size_t)N_ * 160];
__device__ __align__(16) __half g_wt[512 * 128];

// ===== helpers =====
__device__ __forceinline__ long long ld_idx(const void* p, size_t i) {
    if (g_is64) return ((const long long*)p)[i];
    return (long long)((const int*)p)[i];
}
__device__ __forceinline__ float sigf(float x) { return 1.f / (1.f + expf(-x)); }
__device__ __forceinline__ float sigf_fast(float x) {
    return __fdividef(1.f, 1.f + __expf(-x));
}
__device__ __forceinline__ float tanh_fast(float x) {
    float e = __expf(2.f * x);
    return 1.f - __fdividef(2.f, e + 1.f);
}
__device__ __forceinline__ float tanh_hw(float x) {
    float y;
    asm("tanh.approx.f32 %0, %1;" : "=f"(y) : "f"(x));
    return y;
}
__device__ __forceinline__ float one_p_tanh(float x) {
    float ax = fabsf(x);
    if (ax < 0.15f) {
        float x2 = x * x;
        return fmaf(x, fmaf(x2, -0.33333333f, 1.f), 1.f);
    }
    return 1.f + tanh_hw(x);
}
__device__ __forceinline__ void mma_f16(float* c, uint32_t a0, uint32_t a1, uint32_t a2,
                                        uint32_t a3, uint32_t b0, uint32_t b1) {
    asm volatile(
        "mma.sync.aligned.m16n8k16.row.col.f32.f16.f16.f32 "
        "{%0,%1,%2,%3}, {%4,%5,%6,%7}, {%8,%9}, {%0,%1,%2,%3};"
        : "+f"(c[0]), "+f"(c[1]), "+f"(c[2]), "+f"(c[3])
        : "r"(a0), "r"(a1), "r"(a2), "r"(a3), "r"(b0), "r"(b1));
}

__global__ void detect64_kernel(const int* ei32) {
    int ok = 1;
    for (int i = 1; i < 64; i += 2)
        if (ei32[i] != 0) ok = 0;
    g_is64 = ok;
}
__global__ void fill_f(float* p, float v, int n) {
    int i = blockIdx.x * blockDim.x + threadIdx.x;
    if (i < n) p[i] = v;
}
__global__ void fill_i(int* p, int v, int n) {
    int i = blockIdx.x * blockDim.x + threadIdx.x;
    if (i < n) p[i] = v;
}
__global__ void cvt16(const float4* __restrict__ x, __half2* __restrict__ y, int n4) {
    int i = blockIdx.x * blockDim.x + threadIdx.x;
    if (i >= n4) return;
    float4 v = x[i];
    y[2 * i]     = __floats2half2_rn(v.x, v.y);
    y[2 * i + 1] = __floats2half2_rn(v.z, v.w);
}
__global__ void wsplit16(const float* __restrict__ B, __half* __restrict__ bt, int Dn) {
    int idx = blockIdx.x * blockDim.x + threadIdx.x;
    if (idx >= Dn * 128) return;
    int n = idx >> 7, k = idx & 127;
    bt[idx] = __float2half(B[(size_t)k * Dn + n]);
}
// gate-interleaved permute for LSTM weights: p = (j/8)*32 + gate*8 + j%8
__global__ void wsplit16_lstm(const float* __restrict__ B, __half* __restrict__ bt) {
    int idx = blockIdx.x * blockDim.x + threadIdx.x;
    if (idx >= 512 * 128) return;
    int p = idx >> 7, k = idx & 127;
    int blk = p >> 5, r = p & 31, gate = r >> 3, jl = r & 7;
    int o = gate * 128 + blk * 8 + jl;
    bt[idx] = __float2half(B[(size_t)k * 512 + o]);
}

// ===== smem tile copy =====
template <int KU4, int SU4, int THREADS>
__device__ __forceinline__ void cp16(const uint4* __restrict__ G, char* sm, int off,
                                     int base, int Mlim, int tid, int rows) {
    int total = rows * KU4;
    for (int idx = tid; idx < total; idx += THREADS) {
        int row = idx / KU4, c = idx - row * KU4;
        uint4 v = make_uint4(0, 0, 0, 0);
        if (base + row < Mlim) v = G[(size_t)(base + row) * KU4 + c];
        ((uint4*)(sm + off))[row * SU4 + c] = v;
    }
}

// ===== fp16 MMA GEMM: CTA 128x64, 256 threads, warp grid 4x2, warp tile 32x32 =====
#define SM_B 34816
#define MG_SMEM 52736

#define GEMM_MAINLOOP(ACC)                                                         \
    int ra0 = (wr * 32 + g) * 68;                                                  \
    int rb0 = ra0 + 8 * 68, ra1 = ra0 + 16 * 68, rb1 = ra0 + 24 * 68;              \
    _Pragma("unroll")                                                              \
    for (int kc = 0; kc < 8; kc++) {                                               \
        int ka = kc * 8 + tq;                                                      \
        uint32_t a00 = SA[ra0 + ka], a01 = SA[rb0 + ka];                           \
        uint32_t a02 = SA[ra0 + ka + 4], a03 = SA[rb0 + ka + 4];                   \
        uint32_t a10 = SA[ra1 + ka], a11 = SA[rb1 + ka];                           \
        uint32_t a12 = SA[ra1 + ka + 4], a13 = SA[rb1 + ka + 4];                   \
        _Pragma("unroll")                                                          \
        for (int nb = 0; nb < 4; nb++) {                                           \
            int nr = (wc * 32 + nb * 8 + g) * 68;                                  \
            uint32_t b0 = SB[nr + ka], b1 = SB[nr + ka + 4];                       \
            mma_f16(ACC[0][nb], a00, a01, a02, a03, b0, b1);                       \
            mma_f16(ACC[1][nb], a10, a11, a12, a13, b0, b1);                       \
        }                                                                          \
    }

// mode: 0 = store fp32, 2 = store fp16
__global__ __launch_bounds__(256, 3) void mma_gemm(
    const __half* __restrict__ A, const __half* __restrict__ B,
    void* __restrict__ Cv, int M, int Dn,
    long long sA, long long sC, int mode)
{
    extern __shared__ char sm[];
    int tid = threadIdx.x, w = tid >> 5, lane = tid & 31;
    int g = lane >> 2, tq = lane & 3;
    int wr = w >> 1, wc = w & 1;
    int m0 = blockIdx.x * 128, n0 = blockIdx.y * 64, t = blockIdx.z;
    A += (size_t)t * sA;

    cp16<16, 17, 256>((const uint4*)A, sm, 0, m0, M, tid, 128);
    cp16<16, 17, 256>((const uint4*)B, sm, SM_B, n0, Dn, tid, 64);
    __syncthreads();

    const uint32_t* SA = (const uint32_t*)sm;
    const uint32_t* SB = (const uint32_t*)(sm + SM_B);

    float acc[2][4][4];
#pragma unroll
    for (int rg = 0; rg < 2; rg++)
#pragma unroll
        for (int nb = 0; nb < 4; nb++)
#pragma unroll
            for (int q = 0; q < 4; q++) acc[rg][nb][q] = 0.f;

    GEMM_MAINLOOP(acc)

#pragma unroll
    for (int rg = 0; rg < 2; rg++) {
        int r0 = m0 + wr * 32 + rg * 16 + g, r1 = r0 + 8;
#pragma unroll
        for (int nb = 0; nb < 4; nb++) {
            int col = n0 + wc * 32 + nb * 8 + 2 * tq;
            if (mode == 2) {
                __half* Ch = (__half*)Cv + (size_t)t * sC;
                if (r0 < M)
                    *(__half2*)(Ch + (size_t)r0 * Dn + col) = __floats2half2_rn(acc[rg][nb][0], acc[rg][nb][1]);
                if (r1 < M)
                    *(__half2*)(Ch + (size_t)r1 * Dn + col) = __floats2half2_rn(acc[rg][nb][2], acc[rg][nb][3]);
            } else {
                float* C = (float*)Cv + (size_t)t * sC;
                if (r0 < M)
                    *(float2*)(C + (size_t)r0 * Dn + col) = make_float2(acc[rg][nb][0], acc[rg][nb][1]);
                if (r1 < M)
                    *(float2*)(C + (size_t)r1 * Dn + col) = make_float2(acc[rg][nb][2], acc[rg][nb][3]);
            }
        }
    }
}

// ===== fp16 MMA GEMM: CTA 128x128, 512 threads, warp grid 4x4 (for Dn >= 128) =====
#define SM_B2 34816
#define MG2_SMEM 69632

__global__ __launch_bounds__(512, 2) void mma_gemm_128(
    const __half* __restrict__ A, const __half* __restrict__ B,
    void* __restrict__ Cv, int M, int Dn,
    long long sA, long long sC, int mode)
{
    extern __shared__ char sm[];
    int tid = threadIdx.x, w = tid >> 5, lane = tid & 31;
    int g = lane >> 2, tq = lane & 3;
    int wr = w >> 2, wc = w & 3;
    int m0 = blockIdx.x * 128, n0 = blockIdx.y * 128, t = blockIdx.z;
    A += (size_t)t * sA;

    cp16<16, 17, 512>((const uint4*)A, sm, 0, m0, M, tid, 128);
    cp16<16, 17, 512>((const uint4*)B, sm, SM_B2, n0, Dn, tid, 128);
    __syncthreads();

    const uint32_t* SA = (const uint32_t*)sm;
    const uint32_t* SB = (const uint32_t*)(sm + SM_B2);

    float acc[2][4][4];
#pragma unroll
    for (int rg = 0; rg < 2; rg++)
#pragma unroll
        for (int nb = 0; nb < 4; nb++)
#pragma unroll
            for (int q = 0; q < 4; q++) acc[rg][nb][q] = 0.f;

    GEMM_MAINLOOP(acc)

#pragma unroll
    for (int rg = 0; rg < 2; rg++) {
        int r0 = m0 + wr * 32 + rg * 16 + g, r1 = r0 + 8;
#pragma unroll
        for (int nb = 0; nb < 4; nb++) {
            int col = n0 + wc * 32 + nb * 8 + 2 * tq;
            if (mode == 2) {
                __half* Ch = (__half*)Cv + (size_t)t * sC;
                if (r0 < M)
                    *(__half2*)(Ch + (size_t)r0 * Dn + col) = __floats2half2_rn(acc[rg][nb][0], acc[rg][nb][1]);
                if (r1 < M)
                    *(__half2*)(Ch + (size_t)r1 * Dn + col) = __floats2half2_rn(acc[rg][nb][2], acc[rg][nb][3]);
            } else {
                float* C = (float*)Cv + (size_t)t * sC;
                if (r0 < M)
                    *(float2*)(C + (size_t)r0 * Dn + col) = make_float2(acc[rg][nb][0], acc[rg][nb][1]);
                if (r1 < M)
                    *(float2*)(C + (size_t)r1 * Dn + col) = make_float2(acc[rg][nb][2], acc[rg][nb][3]);
            }
        }
    }
}

// ===== fused LSTM GEMM: z = Zx + Wh*h (+b); gate-interleaved; double-buffered h =====
__global__ __launch_bounds__(256, 3) void mma_gemm_lstm(
    const __half* __restrict__ A, const __half* __restrict__ B,
    const float* __restrict__ Zt, const float* __restrict__ bias,
    __half* __restrict__ hout)
{
    extern __shared__ char sm[];
    int tid = threadIdx.x, w = tid >> 5, lane = tid & 31;
    int g = lane >> 2, tq = lane & 3;
    int wr = w >> 1, wc = w & 1;
    int m0 = blockIdx.x * 128, n0 = blockIdx.y * 64;

    cp16<16, 17, 256>((const uint4*)A, sm, 0, m0, N_, tid, 128);
    cp16<16, 17, 256>((const uint4*)B, sm, SM_B, n0, 512, tid, 64);
    __syncthreads();

    const uint32_t* SA = (const uint32_t*)sm;
    const uint32_t* SB = (const uint32_t*)(sm + SM_B);

    float acc[2][4][4];
#pragma unroll
    for (int rg = 0; rg < 2; rg++)
#pragma unroll
        for (int nb = 0; nb < 4; nb++)
#pragma unroll
            for (int q = 0; q < 4; q++) acc[rg][nb][q] = 0.f;

    GEMM_MAINLOOP(acc)

    int pbase = n0 + wc * 32;
    int jb8 = (pbase >> 5) * 8;
    float bi[2], bf[2], bg[2], bo[2];
#pragma unroll
    for (int q01 = 0; q01 < 2; q01++) {
        int j = jb8 + 2 * tq + q01;
        bi[q01] = bias[j];
        bf[q01] = bias[128 + j];
        bg[q01] = bias[256 + j];
        bo[q01] = bias[384 + j];
    }
#pragma unroll
    for (int rg = 0; rg < 2; rg++) {
#pragma unroll
        for (int rr = 0; rr < 2; rr++) {
            int row = m0 + wr * 32 + rg * 16 + g + rr * 8;
            if (row >= N_) continue;
            int qoff = rr * 2;
            float hv[2], cv[2];
#pragma unroll
            for (int q01 = 0; q01 < 2; q01++) {
                int j = jb8 + 2 * tq + q01;
                const float* zr = Zt + (size_t)row * 512 + pbase + 2 * tq + q01;
                float zi = acc[rg][0][qoff + q01] + zr[0]  + bi[q01];
                float zf = acc[rg][1][qoff + q01] + zr[8]  + bf[q01];
                float zg = acc[rg][2][qoff + q01] + zr[16] + bg[q01];
                float zo = acc[rg][3][qoff + q01] + zr[24] + bo[q01];
                float c = sigf_fast(zf) * g_cbuf[row * 128 + j] + sigf_fast(zi) * tanh_fast(zg);
                cv[q01] = c;
                hv[q01] = sigf_fast(zo) * tanh_fast(c);
            }
            int j0 = jb8 + 2 * tq;
            *(float2*)&g_cbuf[row * 128 + j0] = make_float2(cv[0], cv[1]);
            *(__half2*)&hout[row * 128 + j0] = __floats2half2_rn(hv[0], hv[1]);
        }
    }
}

// t=0 LSTM (c0 = 0): read permuted Zx + bias only
__global__ void lstm_pw0(const float* __restrict__ b, __half* __restrict__ hout) {
    int idx = blockIdx.x * blockDim.x + threadIdx.x;
    if (idx >= N_ * 128) return;
    int n = idx >> 7, j = idx & 127;
    const float* z = g_Zx + (size_t)n * 512 + (j >> 3) * 32 + (j & 7);
    float zi = z[0] + b[j];
    float zg = z[16] + b[256 + j];
    float zo = z[24] + b[384 + j];
    float c = sigf_fast(zi) * tanh_fast(zg);
    g_cbuf[idx] = c;
    hout[idx] = __float2half(sigf_fast(zo) * tanh_fast(c));
}

// ===== pairwise: CTA 128x128, 512 threads, K=160, streaming stores =====
#define PW_B 43008
#define PW_SMEM 86016

__global__ __launch_bounds__(512, 2) void pairwise_mma(float* __restrict__ out) {
    int bi = blockIdx.y, bj = blockIdx.x;
    if (bj < bi) return;
    int i0 = bi * 128, j0 = bj * 128;
    extern __shared__ char sm[];
    int tid = threadIdx.x, w = tid >> 5, lane = tid & 31;
    int g = lane >> 2, tq = lane & 3;
    int wr = w >> 2, wc = w & 3;

    cp16<20, 21, 512>((const uint4*)g_pa, sm, 0, i0, N_, tid, 128);
    cp16<20, 21, 512>((const uint4*)g_pb, sm, PW_B, j0, N_, tid, 128);
    __syncthreads();

    const uint32_t* SA = (const uint32_t*)sm;
    const uint32_t* SB = (const uint32_t*)(sm + PW_B);

    float accG[2][4][4], accS[2][4][4];
#pragma unroll
    for (int rg = 0; rg < 2; rg++)
#pragma unroll
        for (int nb = 0; nb < 4; nb++)
#pragma unroll
            for (int q = 0; q < 4; q++) { accG[rg][nb][q] = 0.f; accS[rg][nb][q] = 0.f; }

    int ra0 = (wr * 32 + g) * 84;
    int rb0 = ra0 + 8 * 84, ra1 = ra0 + 16 * 84, rb1 = ra0 + 24 * 84;
#pragma unroll
    for (int kc = 0; kc < 9; kc++) {
        int ka = kc * 8 + tq;
        uint32_t a00 = SA[ra0 + ka], a01 = SA[rb0 + ka];
        uint32_t a02 = SA[ra0 + ka + 4], a03 = SA[rb0 + ka + 4];
        uint32_t a10 = SA[ra1 + ka], a11 = SA[rb1 + ka];
        uint32_t a12 = SA[ra1 + ka + 4], a13 = SA[rb1 + ka + 4];
        float (*a0)[4] = (kc < 5) ? accG[0] : accS[0];
        float (*a1)[4] = (kc < 5) ? accG[1] : accS[1];
#pragma unroll
        for (int nb = 0; nb < 4; nb++) {
            int nr = (wc * 32 + nb * 8 + g) * 84;
            uint32_t b0 = SB[nr + ka], b1 = SB[nr + ka + 4];
            mma_f16(a0[nb], a00, a01, a02, a03, b0, b1);
            mma_f16(a1[nb], a10, a11, a12, a13, b0, b1);
        }
    }

    bool full = (i0 + 128 <= N_) && (j0 + 128 <= N_);
    float vv[2][4][4];
#pragma unroll
    for (int rg = 0; rg < 2; rg++) {
        int lr0 = wr * 32 + rg * 16 + g, lr1 = lr0 + 8;
        int ir0 = i0 + lr0, ir1 = i0 + lr1;
#pragma unroll
        for (int nb = 0; nb < 4; nb++) {
            int c0 = wc * 32 + nb * 8 + 2 * tq;
            vv[rg][nb][0] = one_p_tanh(accG[rg][nb][0] * accS[rg][nb][0]);
            vv[rg][nb][1] = one_p_tanh(accG[rg][nb][1] * accS[rg][nb][1]);
            vv[rg][nb][2] = one_p_tanh(accG[rg][nb][2] * accS[rg][nb][2]);
            vv[rg][nb][3] = one_p_tanh(accG[rg][nb][3] * accS[rg][nb][3]);
            if (full) {
                __stcs((float2*)(out + (size_t)ir0 * N_ + j0 + c0),
                       make_float2(vv[rg][nb][0], vv[rg][nb][1]));
                __stcs((float2*)(out + (size_t)ir1 * N_ + j0 + c0),
                       make_float2(vv[rg][nb][2], vv[rg][nb][3]));
            } else {
                if (ir0 < N_) {
                    if (j0 + c0 < N_)     __stcs(out + (size_t)ir0 * N_ + j0 + c0, vv[rg][nb][0]);
                    if (j0 + c0 + 1 < N_) __stcs(out + (size_t)ir0 * N_ + j0 + c0 + 1, vv[rg][nb][1]);
                }
                if (ir1 < N_) {
                    if (j0 + c0 < N_)     __stcs(out + (size_t)ir1 * N_ + j0 + c0, vv[rg][nb][2]);
                    if (j0 + c0 + 1 < N_) __stcs(out + (size_t)ir1 * N_ + j0 + c0 + 1, vv[rg][nb][3]);
                }
            }
        }
    }

    __syncthreads();
    float* vT = (float*)sm;  // [128][129]
#pragma unroll
    for (int rg = 0; rg < 2; rg++) {
        int lr0 = wr * 32 + rg * 16 + g, lr1 = lr0 + 8;
#pragma unroll
        for (int nb = 0; nb < 4; nb++) {
            int c0 = wc * 32 + nb * 8 + 2 * tq, c1 = c0 + 1;
            vT[c0 * 129 + lr0] = vv[rg][nb][0];
            vT[c1 * 129 + lr0] = vv[rg][nb][1];
            vT[c0 * 129 + lr1] = vv[rg][nb][2];
            vT[c1 * 129 + lr1] = vv[rg][nb][3];
        }
    }
    __syncthreads();
    for (int idx = tid; idx < 128 * 128; idx += 512) {
        int r2 = idx >> 7, c2 = idx & 127;
        int jj = j0 + r2, ii = i0 + c2;
        if (jj > ii && jj < N_ && ii < N_) __stcs(out + (size_t)jj * N_ + ii, vT[r2 * 129 + c2]);
    }
}

// ===== GAT kernels =====
__global__ void alpha_kernel(const __half* __restrict__ h, const float* __restrict__ a_s,
                             const float* __restrict__ a_d, int dh) {
    int idx = blockIdx.x * blockDim.x + threadIdx.x;
    if (idx >= T_ * N_ * H_) return;
    int hh = idx & 3, tn = idx >> 2;
    const __half* hr = h + (size_t)tn * (H_ * dh) + hh * dh;
    float s = 0.f, d = 0.f;
    for (int k = 0; k < dh; k++) {
        float v = __half2float(hr[k]);
        s += v * a_s[hh * dh + k];
        d += v * a_d[hh * dh + k];
    }
    g_as[idx] = s; g_ad[idx] = d;
}
__global__ void csr_count(const void* ei) {
    int idx = blockIdx.x * blockDim.x + threadIdx.x;
    if (idx >= T_ * E_) return;
    int t = idx / E_, e = idx - t * E_;
    int dst = (int)ld_idx(ei, (size_t)t * 2 * E_ + E_ + e);
    atomicAdd(&g_cnt[t * N_ + dst], 1);
}
__global__ void csr_scan() {
    int t = blockIdx.x, tid = threadIdx.x;
    __shared__ int sh[1024];
    int off = 0;
    for (int chunk = 0; chunk < N_; chunk += 1024) {
        int i = chunk + tid;
        int v = (i < N_) ? g_cnt[t * N_ + i] : 0;
        sh[tid] = v;
        __syncthreads();
        for (int d2 = 1; d2 < 1024; d2 <<= 1) {
            int x = 0;
            if (tid >= d2) x = sh[tid - d2];
            __syncthreads();
            sh[tid] += x;
            __syncthreads();
        }
        if (i < N_) g_rowptr[t * (N_ + 1) + i] = off + sh[tid] - v;
        int tot = sh[1023];
        __syncthreads();
        off += tot;
    }
    if (tid == 0) g_rowptr[t * (N_ + 1) + N_] = off;
}
__global__ void csr_scatter(const void* ei) {
    int idx = blockIdx.x * blockDim.x + threadIdx.x;
    if (idx >= T_ * E_) return;
    int t = idx / E_, e = idx - t * E_;
    int dst = (int)ld_idx(ei, (size_t)t * 2 * E_ + E_ + e);
    int pos = atomicAdd(&g_cursor[t * N_ + dst], 1);
    g_sorted[t * E_ + g_rowptr[t * (N_ + 1) + dst] + pos] = e;
}

template <int D, int DH>
__global__ void gat_gather(const void* ei, const float* __restrict__ ew,
                           const __half* __restrict__ hsrc, __half* __restrict__ oh) {
    int t = blockIdx.y, n = blockIdx.x, tid = threadIdx.x;
    int start = g_rowptr[t * (N_ + 1) + n];
    int end = g_rowptr[t * (N_ + 1) + n + 1];
    int head = tid / DH;
    __shared__ int s_src[64];
    __shared__ float s_ex[64][4];
    float4 ad4 = *(const float4*)&g_ad[(t * N_ + n) * 4];
    float acc = 0.f, den = 0.f;
    for (int base = start; base < end; base += 64) {
        int cnt = min(64, end - base);
        __syncthreads();
        for (int i = tid; i < cnt; i += D) {
            int eid = g_sorted[t * E_ + base + i];
            int src = (int)ld_idx(ei, (size_t)t * 2 * E_ + eid);
            s_src[i] = src;
            float4 s4 = *(const float4*)&g_as[(t * N_ + src) * 4];
            float wv = ew[(size_t)t * E_ + eid];
            float e0 = s4.x + ad4.x; e0 = e0 > 0.f ? e0 : 0.2f * e0;
            float e1 = s4.y + ad4.y; e1 = e1 > 0.f ? e1 : 0.2f * e1;
            float e2 = s4.z + ad4.z; e2 = e2 > 0.f ? e2 : 0.2f * e2;
            float e3 = s4.w + ad4.w; e3 = e3 > 0.f ? e3 : 0.2f * e3;
            s_ex[i][0] = __expf(e0) * wv;
            s_ex[i][1] = __expf(e1) * wv;
            s_ex[i][2] = __expf(e2) * wv;
            s_ex[i][3] = __expf(e3) * wv;
        }
        __syncthreads();
#pragma unroll 8
        for (int i = 0; i < cnt; i++) {
            float exv = s_ex[i][head];
            den += exv;
            acc += exv * __half2float(hsrc[((size_t)t * N_ + s_src[i]) * D + tid]);
        }
    }
    float v = acc / (den + 1e-16f);
    v = v > 0.f ? v : __expf(v) - 1.f;
    oh[((size_t)t * N_ + n) * 128 + tid] = __float2half(v);
}

// ===== meso (reads fp16 gather output directly) =====
#define MCHUNK 500
__global__ void meso_acc(const void* part, const float* __restrict__ Dw) {
    int t = blockIdx.y, c0 = blockIdx.x * MCHUNK, tid = threadIdx.x;
    __shared__ float sn[NCOM_ * 64];
    __shared__ float sd[NCOM_];
    __shared__ int sp[MCHUNK];
    __shared__ float sD[MCHUNK];
    for (int i = tid; i < NCOM_ * 64; i += blockDim.x) sn[i] = 0.f;
    for (int i = tid; i < NCOM_; i += blockDim.x) sd[i] = 0.f;
    int nmax = min(MCHUNK, N_ - c0);
    for (int i = tid; i < nmax; i += blockDim.x) {
        sp[i] = (int)ld_idx(part, (size_t)t * N_ + c0 + i);
        sD[i] = Dw[(size_t)t * N_ + c0 + i];
    }
    __syncthreads();
    for (int idx = tid; idx < nmax * 64; idx += blockDim.x) {
        int nl = idx >> 6, c = idx & 63;
        float g = __half2float(g_f[((size_t)t * N_ + c0 + nl) * 128 + c]);
        atomicAdd(&sn[sp[nl] * 64 + c], sD[nl] * g);
        if (c == 0) atomicAdd(&sd[sp[nl]], sD[nl]);
    }
    __syncthreads();
    for (int i = tid; i < NCOM_ * 64; i += blockDim.x)
        atomicAdd(&g_comnum[t * NCOM_ * 64 + i], sn[i]);
    for (int i = tid; i < NCOM_; i += blockDim.x)
        atomicAdd(&g_comden[t * NCOM_ + i], sd[i]);
}
__global__ void meso_scatter(const void* part, __half* __restrict__ oh) {
    int idx = blockIdx.x * blockDim.x + threadIdx.x;
    if (idx >= T_ * N_ * 64) return;
    int t = idx / (N_ * 64);
    int r = idx - t * N_ * 64;
    int n = r >> 6, c = r & 63;
    int p = (int)ld_idx(part, (size_t)t * N_ + n);
    float mean = g_comnum[(t * NCOM_ + p) * 64 + c] / (g_comden[t * NCOM_ + p] + 1e-16f);
    oh[((size_t)t * N_ + n) * 128 + 64 + c] = __float2half(mean);
}

// ===== decoder prep =====
__global__ void emb_tanh(const float* __restrict__ emb_b) {
    __shared__ float s[64];
    int tid = threadIdx.x;
    if (tid < 64) s[tid] = 0.f;
    __syncthreads();
    int idx = blockIdx.x * 256 + tid;
    if (idx < N_ * 64) {
        int n = idx >> 6, c = idx & 63;
        float v = tanhf(g_dec[n * 128 + c] + emb_b[c]);
        g_dec[n * 128 + c] = v;
        atomicAdd(&s[c], v * v);
    }
    __syncthreads();
    if (tid < 64) atomicAdd(&g_colsq[tid], s[tid]);
}
__global__ void build_P(const float* __restrict__ scal_b) {
    int n = blockIdx.x, c = threadIdx.x;
    float e = g_dec[n * 128 + c] * rsqrtf(g_colsq[c]);
    float s = sigf(g_dec[n * 128 + 64 + c] + scal_b[c]);
    float v = e * e;
#pragma unroll
    for (int o = 16; o; o >>= 1) v += __shfl_down_sync(0xffffffff, v, o);
    __shared__ float shm[2];
    if ((c & 31) == 0) shm[c >> 5] = v;
    __syncthreads();
    float sq = shm[0] + shm[1];
    size_t base = (size_t)n * 160;
    __half he = __float2half(1.41421356f * e);
    __half hs = __float2half(s);
    g_pa[base + c] = he;        g_pb[base + c] = he;
    g_pa[base + 80 + c] = hs;   g_pb[base + 80 + c] = hs;
    if (c < 16) {
        __half za = __float2half(0.f), zb = za;
        if (c == 0) { za = __float2half(sq);   zb = __float2half(-1.f); }
        if (c == 1) { za = __float2half(1.f);  zb = __float2half(-sq); }
        g_pa[base + 64 + c] = za;
        g_pb[base + 64 + c] = zb;
        g_pa[base + 144 + c] = __float2half(0.f);
        g_pb[base + 144 + c] = __float2half(0.f);
    }
}

// ===== host =====
extern "C" void kernel_launch(void* const* d_in, const int* in_sizes, int n_in,
                              void* d_out, int out_size) {
    const float* feat   = (const float*)d_in[0];
    const float* ew     = (const float*)d_in[1];
    const float* Dw     = (const float*)d_in[2];
    const float* W1     = (const float*)d_in[3];
    const float* a_s1   = (const float*)d_in[4];
    const float* a_d1   = (const float*)d_in[5];
    const float* W2     = (const float*)d_in[6];
    const float* a_s2   = (const float*)d_in[7];
    const float* a_d2   = (const float*)d_in[8];
    const float* Wx     = (const float*)d_in[9];
    const float* Wh     = (const float*)d_in[10];
    const float* b_lstm = (const float*)d_in[11];
    const float* embW   = (const float*)d_in[12];
    const float* embB   = (const float*)d_in[13];
    const float* scalW  = (const float*)d_in[14];
    const float* scalB  = (const float*)d_in[15];
    const void*  ei     = (const void*)d_in[16];
    const void*  part   = (const void*)d_in[17];
    float* out = (float*)d_out;

    cudaFuncSetAttribute(mma_gemm, cudaFuncAttributeMaxDynamicSharedMemorySize, MG_SMEM);
    cudaFuncSetAttribute(mma_gemm_128, cudaFuncAttributeMaxDynamicSharedMemorySize, MG2_SMEM);
    cudaFuncSetAttribute(mma_gemm_lstm, cudaFuncAttributeMaxDynamicSharedMemorySize, MG_SMEM);
    cudaFuncSetAttribute(pairwise_mma, cudaFuncAttributeMaxDynamicSharedMemorySize, PW_SMEM);

    float *Zx, *dec, *comnum, *comden, *colsq;
    int *cnt, *cursor;
    __half *h1h, *h2h, *f16, *hb0, *hb1, *wt;
    cudaGetSymbolAddress((void**)&h1h, g_h1h);
    cudaGetSymbolAddress((void**)&h2h, g_h2h);
    cudaGetSymbolAddress((void**)&f16, g_f);
    cudaGetSymbolAddress((void**)&Zx, g_Zx);
    cudaGetSymbolAddress((void**)&dec, g_dec);
    cudaGetSymbolAddress((void**)&comnum, g_comnum);
    cudaGetSymbolAddress((void**)&comden, g_comden);
    cudaGetSymbolAddress((void**)&colsq, g_colsq);
    cudaGetSymbolAddress((void**)&cnt, g_cnt);
    cudaGetSymbolAddress((void**)&cursor, g_cursor);
    cudaGetSymbolAddress((void**)&hb0, g_hb0);
    cudaGetSymbolAddress((void**)&hb1, g_hb1);
    cudaGetSymbolAddress((void**)&wt, g_wt);
    __half* hbuf[2] = {hb0, hb1};

    const int MT = 79;
    const int TE = T_ * E_;
    const int TNH = T_ * N_ * H_;
    const int NS4 = T_ * N_ * 128 / 4;

    detect64_kernel<<<1, 1>>>((const int*)ei);

    // GAT layer 1 (Dn=128 -> 128x128 tile kernel)
    cvt16<<<(NS4 + 255) / 256, 256>>>((const float4*)feat, (__half2*)f16, NS4);
    wsplit16<<<(128 * 128 + 255) / 256, 256>>>(W1, wt, 128);
    mma_gemm_128<<<dim3(MT, 1, 8), 512, MG2_SMEM>>>(f16, wt, h1h, N_, 128,
                                                    (long long)N_ * 128, (long long)N_ * 128, 2);
    alpha_kernel<<<(TNH + 255) / 256, 256>>>(h1h, a_s1, a_d1, 32);

    fill_i<<<(T_ * N_ + 255) / 256, 256>>>(cnt, 0, T_ * N_);
    csr_count<<<(TE + 255) / 256, 256>>>(ei);
    csr_scan<<<T_, 1024>>>();
    fill_i<<<(T_ * N_ + 255) / 256, 256>>>(cursor, 0, T_ * N_);
    csr_scatter<<<(TE + 255) / 256, 256>>>(ei);

    gat_gather<128, 32><<<dim3(N_, T_), 128>>>(ei, ew, h1h, f16);

    // GAT layer 2 (Dn=64 -> 128x64 kernel)
    wsplit16<<<(64 * 128 + 255) / 256, 256>>>(W2, wt, 64);
    mma_gemm<<<dim3(MT, 1, 8), 256, MG_SMEM>>>(f16, wt, h2h, N_, 64,
                                               (long long)N_ * 128, (long long)N_ * 64, 2);
    alpha_kernel<<<(TNH + 255) / 256, 256>>>(h2h, a_s2, a_d2, 16);
    gat_gather<64, 16><<<dim3(N_, T_), 64>>>(ei, ew, h2h, f16);

    // meso
    fill_f<<<(T_ * NCOM_ * 64 + 255) / 256, 256>>>(comnum, 0.f, T_ * NCOM_ * 64);
    fill_f<<<(T_ * NCOM_ + 255) / 256, 256>>>(comden, 0.f, T_ * NCOM_);
    meso_acc<<<dim3((N_ + MCHUNK - 1) / MCHUNK, T_), 256>>>(part, Dw);
    meso_scatter<<<(T_ * N_ * 64 + 255) / 256, 256>>>(part, f16);

    // LSTM: Wx (permuted, Dn=512 -> 128x128 kernel), then fused Wh+gates per step
    wsplit16_lstm<<<(512 * 128 + 255) / 256, 256>>>(Wx, wt);
    mma_gemm_128<<<dim3(MT, 4, 8), 512, MG2_SMEM>>>(f16, wt, Zx, N_, 512,
                                                    (long long)N_ * 128, (long long)N_ * 512, 0);
    wsplit16_lstm<<<(512 * 128 + 255) / 256, 256>>>(Wh, wt);
    lstm_pw0<<<(N_ * 128 + 255) / 256, 256>>>(b_lstm, hbuf[0]);
    for (int t = 1; t < T_; t++) {
        mma_gemm_lstm<<<dim3(MT, 8, 1), 256, MG_SMEM>>>(hbuf[(t - 1) & 1], wt,
                                                        Zx + (size_t)t * N_ * 512, b_lstm,
                                                        hbuf[t & 1]);
    }
    __half* hlast = hbuf[(T_ - 1) & 1];

    // decoder (Dn=128 -> 128x128 kernel)
    wsplit16<<<(64 * 128 + 255) / 256, 256>>>(embW, wt, 64);
    wsplit16<<<(64 * 128 + 255) / 256, 256>>>(scalW, wt + 64 * 128, 64);
    mma_gemm_128<<<dim3(MT, 1, 1), 512, MG2_SMEM>>>(hlast, wt, dec, N_, 128, 0, 0, 0);
    fill_f<<<1, 64>>>(colsq, 0.f, 64);
    emb_tanh<<<(N_ * 64 + 255) / 256, 256>>>(embB);
    build_P<<<N_, 64>>>(scalB);
    pairwise_mma<<<dim3(MT, MT), 512, PW_SMEM>>>(out);
}

// round 14
// speedup vs baseline: 4.1796x; 1.0346x over previous
#include <cuda_runtime.h>
#include <cuda_fp16.h>
#include <math.h>
#include <stdint.h>

#define T_ 8
#define N_ 10000
#define E_ 320000
#define H_ 4
#define NCOM_ 100

// ===== scratch =====
__device__ int   g_is64;
__device__ __align__(16) __half g_h1h[(size_t)T_ * N_ * 128];
__device__ __align__(16) __half g_h2h[(size_t)T_ * N_ * 64];
__device__ __align__(16) __half g_f[(size_t)T_ * N_ * 128];
__device__ __align__(16) float g_as[T_ * N_ * H_];
__device__ __align__(16) float g_ad[T_ * N_ * H_];
__device__ int   g_cnt[T_ * N_];
__device__ int   g_rowptr[T_ * (N_ + 1)];
__device__ int   g_cursor[T_ * N_];
__device__ int   g_sorted[T_ * E_];
__device__ float g_comnum[T_ * NCOM_ * 64];
__device__ float g_comden[T_ * NCOM_];
__device__ __align__(16) __half g_Zx[(size_t)T_ * N_ * 512];
__device__ __align__(16) float g_cbuf[N_ * 128];
__device__ __align__(16) float g_dec[N_ * 128];
__device__ float g_colsq[64];
__device__ __align__(16) __half g_hb0[N_ * 128];
__device__ __align__(16) __half g_hb1[N_ * 128];
__device__ __align__(16) __half g_pa[(size_t)N_ * 160];
__device__ __align__(16) __half g_pb[(size_t)N_ * 160];
__device__ __align__(16) __half g_wt[512 * 128];

// ===== helpers =====
__device__ __forceinline__ long long ld_idx(const void* p, size_t i) {
    if (g_is64) return ((const long long*)p)[i];
    return (long long)((const int*)p)[i];
}
__device__ __forceinline__ float sigf(float x) { return 1.f / (1.f + expf(-x)); }
__device__ __forceinline__ float sigf_fast(float x) {
    return __fdividef(1.f, 1.f + __expf(-x));
}
__device__ __forceinline__ float tanh_fast(float x) {
    float e = __expf(2.f * x);
    return 1.f - __fdividef(2.f, e + 1.f);
}
__device__ __forceinline__ float tanh_hw(float x) {
    float y;
    asm("tanh.approx.f32 %0, %1;" : "=f"(y) : "f"(x));
    return y;
}
__device__ __forceinline__ float one_p_tanh(float x) {
    float ax = fabsf(x);
    if (ax < 0.15f) {
        float x2 = x * x;
        return fmaf(x, fmaf(x2, -0.33333333f, 1.f), 1.f);
    }
    return 1.f + tanh_hw(x);
}
__device__ __forceinline__ void mma_f16(float* c, uint32_t a0, uint32_t a1, uint32_t a2,
                                        uint32_t a3, uint32_t b0, uint32_t b1) {
    asm volatile(
        "mma.sync.aligned.m16n8k16.row.col.f32.f16.f16.f32 "
        "{%0,%1,%2,%3}, {%4,%5,%6,%7}, {%8,%9}, {%0,%1,%2,%3};"
        : "+f"(c[0]), "+f"(c[1]), "+f"(c[2]), "+f"(c[3])
        : "r"(a0), "r"(a1), "r"(a2), "r"(a3), "r"(b0), "r"(b1));
}

__global__ void detect64_kernel(const int* ei32) {
    int ok = 1;
    for (int i = 1; i < 64; i += 2)
        if (ei32[i] != 0) ok = 0;
    g_is64 = ok;
}
__global__ void fill_f(float* p, float v, int n) {
    int i = blockIdx.x * blockDim.x + threadIdx.x;
    if (i < n) p[i] = v;
}
__global__ void fill_i(int* p, int v, int n) {
    int i = blockIdx.x * blockDim.x + threadIdx.x;
    if (i < n) p[i] = v;
}
__global__ void cvt16(const float4* __restrict__ x, __half2* __restrict__ y, int n4) {
    int i = blockIdx.x * blockDim.x + threadIdx.x;
    if (i >= n4) return;
    float4 v = x[i];
    y[2 * i]     = __floats2half2_rn(v.x, v.y);
    y[2 * i + 1] = __floats2half2_rn(v.z, v.w);
}
__global__ void wsplit16(const float* __restrict__ B, __half* __restrict__ bt, int Dn) {
    int idx = blockIdx.x * blockDim.x + threadIdx.x;
    if (idx >= Dn * 128) return;
    int n = idx >> 7, k = idx & 127;
    bt[idx] = __float2half(B[(size_t)k * Dn + n]);
}
// gate-interleaved permute for LSTM weights: p = (j/8)*32 + gate*8 + j%8
__global__ void wsplit16_lstm(const float* __restrict__ B, __half* __restrict__ bt) {
    int idx = blockIdx.x * blockDim.x + threadIdx.x;
    if (idx >= 512 * 128) return;
    int p = idx >> 7, k = idx & 127;
    int blk = p >> 5, r = p & 31, gate = r >> 3, jl = r & 7;
    int o = gate * 128 + blk * 8 + jl;
    bt[idx] = __float2half(B[(size_t)k * 512 + o]);
}

// ===== smem tile copy =====
template <int KU4, int SU4, int THREADS>
__device__ __forceinline__ void cp16(const uint4* __restrict__ G, char* sm, int off,
                                     int base, int Mlim, int tid, int rows) {
    int total = rows * KU4;
    for (int idx = tid; idx < total; idx += THREADS) {
        int row = idx / KU4, c = idx - row * KU4;
        uint4 v = make_uint4(0, 0, 0, 0);
        if (base + row < Mlim) v = G[(size_t)(base + row) * KU4 + c];
        ((uint4*)(sm + off))[row * SU4 + c] = v;
    }
}

// ===== fp16 MMA GEMM: CTA 128x64, 256 threads, warp grid 4x2, warp tile 32x32 =====
#define SM_B 34816
#define MG_SMEM 52736

#define GEMM_MAINLOOP(ACC)                                                         \
    int ra0 = (wr * 32 + g) * 68;                                                  \
    int rb0 = ra0 + 8 * 68, ra1 = ra0 + 16 * 68, rb1 = ra0 + 24 * 68;              \
    _Pragma("unroll")                                                              \
    for (int kc = 0; kc < 8; kc++) {                                               \
        int ka = kc * 8 + tq;                                                      \
        uint32_t a00 = SA[ra0 + ka], a01 = SA[rb0 + ka];                           \
        uint32_t a02 = SA[ra0 + ka + 4], a03 = SA[rb0 + ka + 4];                   \
        uint32_t a10 = SA[ra1 + ka], a11 = SA[rb1 + ka];                           \
        uint32_t a12 = SA[ra1 + ka + 4], a13 = SA[rb1 + ka + 4];                   \
        _Pragma("unroll")                                                          \
        for (int nb = 0; nb < 4; nb++) {                                           \
            int nr = (wc * 32 + nb * 8 + g) * 68;                                  \
            uint32_t b0 = SB[nr + ka], b1 = SB[nr + ka + 4];                       \
            mma_f16(ACC[0][nb], a00, a01, a02, a03, b0, b1);                       \
            mma_f16(ACC[1][nb], a10, a11, a12, a13, b0, b1);                       \
        }                                                                          \
    }

// mode: 0 = store fp32, 2 = store fp16
__global__ __launch_bounds__(256, 3) void mma_gemm(
    const __half* __restrict__ A, const __half* __restrict__ B,
    void* __restrict__ Cv, int M, int Dn,
    long long sA, long long sC, int mode)
{
    extern __shared__ char sm[];
    int tid = threadIdx.x, w = tid >> 5, lane = tid & 31;
    int g = lane >> 2, tq = lane & 3;
    int wr = w >> 1, wc = w & 1;
    int m0 = blockIdx.x * 128, n0 = blockIdx.y * 64, t = blockIdx.z;
    A += (size_t)t * sA;

    cp16<16, 17, 256>((const uint4*)A, sm, 0, m0, M, tid, 128);
    cp16<16, 17, 256>((const uint4*)B, sm, SM_B, n0, Dn, tid, 64);
    __syncthreads();

    const uint32_t* SA = (const uint32_t*)sm;
    const uint32_t* SB = (const uint32_t*)(sm + SM_B);

    float acc[2][4][4];
#pragma unroll
    for (int rg = 0; rg < 2; rg++)
#pragma unroll
        for (int nb = 0; nb < 4; nb++)
#pragma unroll
            for (int q = 0; q < 4; q++) acc[rg][nb][q] = 0.f;

    GEMM_MAINLOOP(acc)

#pragma unroll
    for (int rg = 0; rg < 2; rg++) {
        int r0 = m0 + wr * 32 + rg * 16 + g, r1 = r0 + 8;
#pragma unroll
        for (int nb = 0; nb < 4; nb++) {
            int col = n0 + wc * 32 + nb * 8 + 2 * tq;
            if (mode == 2) {
                __half* Ch = (__half*)Cv + (size_t)t * sC;
                if (r0 < M)
                    *(__half2*)(Ch + (size_t)r0 * Dn + col) = __floats2half2_rn(acc[rg][nb][0], acc[rg][nb][1]);
                if (r1 < M)
                    *(__half2*)(Ch + (size_t)r1 * Dn + col) = __floats2half2_rn(acc[rg][nb][2], acc[rg][nb][3]);
            } else {
                float* C = (float*)Cv + (size_t)t * sC;
                if (r0 < M)
                    *(float2*)(C + (size_t)r0 * Dn + col) = make_float2(acc[rg][nb][0], acc[rg][nb][1]);
                if (r1 < M)
                    *(float2*)(C + (size_t)r1 * Dn + col) = make_float2(acc[rg][nb][2], acc[rg][nb][3]);
            }
        }
    }
}

// ===== fp16 MMA GEMM: CTA 128x128, 512 threads, warp grid 4x4 (Dn >= 128) =====
#define SM_B2 34816
#define MG2_SMEM 69632

__global__ __launch_bounds__(512, 2) void mma_gemm_128(
    const __half* __restrict__ A, const __half* __restrict__ B,
    void* __restrict__ Cv, int M, int Dn,
    long long sA, long long sC, int mode)
{
    extern __shared__ char sm[];
    int tid = threadIdx.x, w = tid >> 5, lane = tid & 31;
    int g = lane >> 2, tq = lane & 3;
    int wr = w >> 2, wc = w & 3;
    int m0 = blockIdx.x * 128, n0 = blockIdx.y * 128, t = blockIdx.z;
    A += (size_t)t * sA;

    cp16<16, 17, 512>((const uint4*)A, sm, 0, m0, M, tid, 128);
    cp16<16, 17, 512>((const uint4*)B, sm, SM_B2, n0, Dn, tid, 128);
    __syncthreads();

    const uint32_t* SA = (const uint32_t*)sm;
    const uint32_t* SB = (const uint32_t*)(sm + SM_B2);

    float acc[2][4][4];
#pragma unroll
    for (int rg = 0; rg < 2; rg++)
#pragma unroll
        for (int nb = 0; nb < 4; nb++)
#pragma unroll
            for (int q = 0; q < 4; q++) acc[rg][nb][q] = 0.f;

    GEMM_MAINLOOP(acc)

#pragma unroll
    for (int rg = 0; rg < 2; rg++) {
        int r0 = m0 + wr * 32 + rg * 16 + g, r1 = r0 + 8;
#pragma unroll
        for (int nb = 0; nb < 4; nb++) {
            int col = n0 + wc * 32 + nb * 8 + 2 * tq;
            if (mode == 2) {
                __half* Ch = (__half*)Cv + (size_t)t * sC;
                if (r0 < M)
                    *(__half2*)(Ch + (size_t)r0 * Dn + col) = __floats2half2_rn(acc[rg][nb][0], acc[rg][nb][1]);
                if (r1 < M)
                    *(__half2*)(Ch + (size_t)r1 * Dn + col) = __floats2half2_rn(acc[rg][nb][2], acc[rg][nb][3]);
            } else {
                float* C = (float*)Cv + (size_t)t * sC;
                if (r0 < M)
                    *(float2*)(C + (size_t)r0 * Dn + col) = make_float2(acc[rg][nb][0], acc[rg][nb][1]);
                if (r1 < M)
                    *(float2*)(C + (size_t)r1 * Dn + col) = make_float2(acc[rg][nb][2], acc[rg][nb][3]);
            }
        }
    }
}

// ===== fused LSTM GEMM (128x128 tile, 512 threads): z = Zx(fp16) + Wh*h (+b) =====
__global__ __launch_bounds__(512, 2) void mma_gemm_lstm(
    const __half* __restrict__ A, const __half* __restrict__ B,
    const __half* __restrict__ Zt, const float* __restrict__ bias,
    __half* __restrict__ hout)
{
    extern __shared__ char sm[];
    int tid = threadIdx.x, w = tid >> 5, lane = tid & 31;
    int g = lane >> 2, tq = lane & 3;
    int wr = w >> 2, wc = w & 3;
    int m0 = blockIdx.x * 128, n0 = blockIdx.y * 128;

    cp16<16, 17, 512>((const uint4*)A, sm, 0, m0, N_, tid, 128);
    cp16<16, 17, 512>((const uint4*)B, sm, SM_B2, n0, 512, tid, 128);
    __syncthreads();

    const uint32_t* SA = (const uint32_t*)sm;
    const uint32_t* SB = (const uint32_t*)(sm + SM_B2);

    float acc[2][4][4];
#pragma unroll
    for (int rg = 0; rg < 2; rg++)
#pragma unroll
        for (int nb = 0; nb < 4; nb++)
#pragma unroll
            for (int q = 0; q < 4; q++) acc[rg][nb][q] = 0.f;

    GEMM_MAINLOOP(acc)

    int pbase = n0 + wc * 32;
    int jb8 = (pbase >> 5) * 8;
    float bi[2], bf[2], bg[2], bo[2];
#pragma unroll
    for (int q01 = 0; q01 < 2; q01++) {
        int j = jb8 + 2 * tq + q01;
        bi[q01] = bias[j];
        bf[q01] = bias[128 + j];
        bg[q01] = bias[256 + j];
        bo[q01] = bias[384 + j];
    }
#pragma unroll
    for (int rg = 0; rg < 2; rg++) {
#pragma unroll
        for (int rr = 0; rr < 2; rr++) {
            int row = m0 + wr * 32 + rg * 16 + g + rr * 8;
            if (row >= N_) continue;
            int qoff = rr * 2;
            float hv[2], cv[2];
#pragma unroll
            for (int q01 = 0; q01 < 2; q01++) {
                int j = jb8 + 2 * tq + q01;
                const __half* zr = Zt + (size_t)row * 512 + pbase + 2 * tq + q01;
                float zi = acc[rg][0][qoff + q01] + __half2float(zr[0])  + bi[q01];
                float zf = acc[rg][1][qoff + q01] + __half2float(zr[8])  + bf[q01];
                float zg = acc[rg][2][qoff + q01] + __half2float(zr[16]) + bg[q01];
                float zo = acc[rg][3][qoff + q01] + __half2float(zr[24]) + bo[q01];
                float c = sigf_fast(zf) * g_cbuf[row * 128 + j] + sigf_fast(zi) * tanh_fast(zg);
                cv[q01] = c;
                hv[q01] = sigf_fast(zo) * tanh_fast(c);
            }
            int j0 = jb8 + 2 * tq;
            *(float2*)&g_cbuf[row * 128 + j0] = make_float2(cv[0], cv[1]);
            *(__half2*)&hout[row * 128 + j0] = __floats2half2_rn(hv[0], hv[1]);
        }
    }
}

// t=0 LSTM (c0 = 0): read permuted fp16 Zx + bias only
__global__ void lstm_pw0(const float* __restrict__ b, __half* __restrict__ hout) {
    int idx = blockIdx.x * blockDim.x + threadIdx.x;
    if (idx >= N_ * 128) return;
    int n = idx >> 7, j = idx & 127;
    const __half* z = g_Zx + (size_t)n * 512 + (j >> 3) * 32 + (j & 7);
    float zi = __half2float(z[0]) + b[j];
    float zg = __half2float(z[16]) + b[256 + j];
    float zo = __half2float(z[24]) + b[384 + j];
    float c = sigf_fast(zi) * tanh_fast(zg);
    g_cbuf[idx] = c;
    hout[idx] = __float2half(sigf_fast(zo) * tanh_fast(c));
}

// ===== pairwise: CTA 128x128, 512 threads, K=160, streaming stores =====
#define PW_B 43008
#define PW_SMEM 86016

__global__ __launch_bounds__(512, 2) void pairwise_mma(float* __restrict__ out) {
    int bi = blockIdx.y, bj = blockIdx.x;
    if (bj < bi) return;
    int i0 = bi * 128, j0 = bj * 128;
    extern __shared__ char sm[];
    int tid = threadIdx.x, w = tid >> 5, lane = tid & 31;
    int g = lane >> 2, tq = lane & 3;
    int wr = w >> 2, wc = w & 3;

    cp16<20, 21, 512>((const uint4*)g_pa, sm, 0, i0, N_, tid, 128);
    cp16<20, 21, 512>((const uint4*)g_pb, sm, PW_B, j0, N_, tid, 128);
    __syncthreads();

    const uint32_t* SA = (const uint32_t*)sm;
    const uint32_t* SB = (const uint32_t*)(sm + PW_B);

    float accG[2][4][4], accS[2][4][4];
#pragma unroll
    for (int rg = 0; rg < 2; rg++)
#pragma unroll
        for (int nb = 0; nb < 4; nb++)
#pragma unroll
            for (int q = 0; q < 4; q++) { accG[rg][nb][q] = 0.f; accS[rg][nb][q] = 0.f; }

    int ra0 = (wr * 32 + g) * 84;
    int rb0 = ra0 + 8 * 84, ra1 = ra0 + 16 * 84, rb1 = ra0 + 24 * 84;
#pragma unroll
    for (int kc = 0; kc < 9; kc++) {
        int ka = kc * 8 + tq;
        uint32_t a00 = SA[ra0 + ka], a01 = SA[rb0 + ka];
        uint32_t a02 = SA[ra0 + ka + 4], a03 = SA[rb0 + ka + 4];
        uint32_t a10 = SA[ra1 + ka], a11 = SA[rb1 + ka];
        uint32_t a12 = SA[ra1 + ka + 4], a13 = SA[rb1 + ka + 4];
        float (*a0)[4] = (kc < 5) ? accG[0] : accS[0];
        float (*a1)[4] = (kc < 5) ? accG[1] : accS[1];
#pragma unroll
        for (int nb = 0; nb < 4; nb++) {
            int nr = (wc * 32 + nb * 8 + g) * 84;
            uint32_t b0 = SB[nr + ka], b1 = SB[nr + ka + 4];
            mma_f16(a0[nb], a00, a01, a02, a03, b0, b1);
            mma_f16(a1[nb], a10, a11, a12, a13, b0, b1);
        }
    }

    bool full = (i0 + 128 <= N_) && (j0 + 128 <= N_);
    float vv[2][4][4];
#pragma unroll
    for (int rg = 0; rg < 2; rg++) {
        int lr0 = wr * 32 + rg * 16 + g, lr1 = lr0 + 8;
        int ir0 = i0 + lr0, ir1 = i0 + lr1;
#pragma unroll
        for (int nb = 0; nb < 4; nb++) {
            int c0 = wc * 32 + nb * 8 + 2 * tq;
            vv[rg][nb][0] = one_p_tanh(accG[rg][nb][0] * accS[rg][nb][0]);
            vv[rg][nb][1] = one_p_tanh(accG[rg][nb][1] * accS[rg][nb][1]);
            vv[rg][nb][2] = one_p_tanh(accG[rg][nb][2] * accS[rg][nb][2]);
            vv[rg][nb][3] = one_p_tanh(accG[rg][nb][3] * accS[rg][nb][3]);
            if (full) {
                __stcs((float2*)(out + (size_t)ir0 * N_ + j0 + c0),
                       make_float2(vv[rg][nb][0], vv[rg][nb][1]));
                __stcs((float2*)(out + (size_t)ir1 * N_ + j0 + c0),
                       make_float2(vv[rg][nb][2], vv[rg][nb][3]));
            } else {
                if (ir0 < N_) {
                    if (j0 + c0 < N_)     __stcs(out + (size_t)ir0 * N_ + j0 + c0, vv[rg][nb][0]);
                    if (j0 + c0 + 1 < N_) __stcs(out + (size_t)ir0 * N_ + j0 + c0 + 1, vv[rg][nb][1]);
                }
                if (ir1 < N_) {
                    if (j0 + c0 < N_)     __stcs(out + (size_t)ir1 * N_ + j0 + c0, vv[rg][nb][2]);
                    if (j0 + c0 + 1 < N_) __stcs(out + (size_t)ir1 * N_ + j0 + c0 + 1, vv[rg][nb][3]);
                }
            }
        }
    }

    __syncthreads();
    float* vT = (float*)sm;  // [128][129]
#pragma unroll
    for (int rg = 0; rg < 2; rg++) {
        int lr0 = wr * 32 + rg * 16 + g, lr1 = lr0 + 8;
#pragma unroll
        for (int nb = 0; nb < 4; nb++) {
            int c0 = wc * 32 + nb * 8 + 2 * tq, c1 = c0 + 1;
            vT[c0 * 129 + lr0] = vv[rg][nb][0];
            vT[c1 * 129 + lr0] = vv[rg][nb][1];
            vT[c0 * 129 + lr1] = vv[rg][nb][2];
            vT[c1 * 129 + lr1] = vv[rg][nb][3];
        }
    }
    __syncthreads();
    for (int idx = tid; idx < 128 * 128; idx += 512) {
        int r2 = idx >> 7, c2 = idx & 127;
        int jj = j0 + r2, ii = i0 + c2;
        if (jj > ii && jj < N_ && ii < N_) __stcs(out + (size_t)jj * N_ + ii, vT[r2 * 129 + c2]);
    }
}

// ===== GAT kernels =====
__global__ void alpha_kernel(const __half* __restrict__ h, const float* __restrict__ a_s,
                             const float* __restrict__ a_d, int dh) {
    int idx = blockIdx.x * blockDim.x + threadIdx.x;
    if (idx >= T_ * N_ * H_) return;
    int hh = idx & 3, tn = idx >> 2;
    const __half2* hr = (const __half2*)(h + (size_t)tn * (H_ * dh) + hh * dh);
    float s = 0.f, d = 0.f;
    for (int k = 0; k < dh / 2; k++) {
        float2 v = __half22float2(hr[k]);
        s += v.x * a_s[hh * dh + 2 * k] + v.y * a_s[hh * dh + 2 * k + 1];
        d += v.x * a_d[hh * dh + 2 * k] + v.y * a_d[hh * dh + 2 * k + 1];
    }
    g_as[idx] = s; g_ad[idx] = d;
}
__global__ void csr_count(const void* ei) {
    int idx = blockIdx.x * blockDim.x + threadIdx.x;
    if (idx >= T_ * E_) return;
    int t = idx / E_, e = idx - t * E_;
    int dst = (int)ld_idx(ei, (size_t)t * 2 * E_ + E_ + e);
    atomicAdd(&g_cnt[t * N_ + dst], 1);
}
__global__ void csr_scan() {
    int t = blockIdx.x, tid = threadIdx.x;
    __shared__ int sh[1024];
    int off = 0;
    for (int chunk = 0; chunk < N_; chunk += 1024) {
        int i = chunk + tid;
        int v = (i < N_) ? g_cnt[t * N_ + i] : 0;
        sh[tid] = v;
        __syncthreads();
        for (int d2 = 1; d2 < 1024; d2 <<= 1) {
            int x = 0;
            if (tid >= d2) x = sh[tid - d2];
            __syncthreads();
            sh[tid] += x;
            __syncthreads();
        }
        if (i < N_) g_rowptr[t * (N_ + 1) + i] = off + sh[tid] - v;
        int tot = sh[1023];
        __syncthreads();
        off += tot;
    }
    if (tid == 0) g_rowptr[t * (N_ + 1) + N_] = off;
}
__global__ void csr_scatter(const void* ei) {
    int idx = blockIdx.x * blockDim.x + threadIdx.x;
    if (idx >= T_ * E_) return;
    int t = idx / E_, e = idx - t * E_;
    int dst = (int)ld_idx(ei, (size_t)t * 2 * E_ + E_ + e);
    int pos = atomicAdd(&g_cursor[t * N_ + dst], 1);
    g_sorted[t * E_ + g_rowptr[t * (N_ + 1) + dst] + pos] = e;
}

template <int D, int DH>
__global__ void gat_gather(const void* ei, const float* __restrict__ ew,
                           const __half* __restrict__ hsrc, __half* __restrict__ oh) {
    int t = blockIdx.y, n = blockIdx.x, tid = threadIdx.x;
    int start = g_rowptr[t * (N_ + 1) + n];
    int end = g_rowptr[t * (N_ + 1) + n + 1];
    int head = tid / DH;
    __shared__ int s_src[64];
    __shared__ float s_ex[64][4];
    float4 ad4 = *(const float4*)&g_ad[(t * N_ + n) * 4];
    float acc = 0.f, den = 0.f;
    for (int base = start; base < end; base += 64) {
        int cnt = min(64, end - base);
        __syncthreads();
        for (int i = tid; i < cnt; i += D) {
            int eid = g_sorted[t * E_ + base + i];
            int src = (int)ld_idx(ei, (size_t)t * 2 * E_ + eid);
            s_src[i] = src;
            float4 s4 = *(const float4*)&g_as[(t * N_ + src) * 4];
            float wv = ew[(size_t)t * E_ + eid];
            float e0 = s4.x + ad4.x; e0 = e0 > 0.f ? e0 : 0.2f * e0;
            float e1 = s4.y + ad4.y; e1 = e1 > 0.f ? e1 : 0.2f * e1;
            float e2 = s4.z + ad4.z; e2 = e2 > 0.f ? e2 : 0.2f * e2;
            float e3 = s4.w + ad4.w; e3 = e3 > 0.f ? e3 : 0.2f * e3;
            s_ex[i][0] = __expf(e0) * wv;
            s_ex[i][1] = __expf(e1) * wv;
            s_ex[i][2] = __expf(e2) * wv;
            s_ex[i][3] = __expf(e3) * wv;
        }
        __syncthreads();
#pragma unroll 8
        for (int i = 0; i < cnt; i++) {
            float exv = s_ex[i][head];
            den += exv;
            acc += exv * __half2float(hsrc[((size_t)t * N_ + s_src[i]) * D + tid]);
        }
    }
    float v = acc / (den + 1e-16f);
    v = v > 0.f ? v : __expf(v) - 1.f;
    oh[((size_t)t * N_ + n) * 128 + tid] = __float2half(v);
}

// ===== meso (reads fp16 gather output directly) =====
#define MCHUNK 500
__global__ void meso_acc(const void* part, const float* __restrict__ Dw) {
    int t = blockIdx.y, c0 = blockIdx.x * MCHUNK, tid = threadIdx.x;
    __shared__ float sn[NCOM_ * 64];
    __shared__ float sd[NCOM_];
    __shared__ int sp[MCHUNK];
    __shared__ float sD[MCHUNK];
    for (int i = tid; i < NCOM_ * 64; i += blockDim.x) sn[i] = 0.f;
    for (int i = tid; i < NCOM_; i += blockDim.x) sd[i] = 0.f;
    int nmax = min(MCHUNK, N_ - c0);
    for (int i = tid; i < nmax; i += blockDim.x) {
        sp[i] = (int)ld_idx(part, (size_t)t * N_ + c0 + i);
        sD[i] = Dw[(size_t)t * N_ + c0 + i];
    }
    __syncthreads();
    for (int idx = tid; idx < nmax * 64; idx += blockDim.x) {
        int nl = idx >> 6, c = idx & 63;
        float g = __half2float(g_f[((size_t)t * N_ + c0 + nl) * 128 + c]);
        atomicAdd(&sn[sp[nl] * 64 + c], sD[nl] * g);
        if (c == 0) atomicAdd(&sd[sp[nl]], sD[nl]);
    }
    __syncthreads();
    for (int i = tid; i < NCOM_ * 64; i += blockDim.x)
        atomicAdd(&g_comnum[t * NCOM_ * 64 + i], sn[i]);
    for (int i = tid; i < NCOM_; i += blockDim.x)
        atomicAdd(&g_comden[t * NCOM_ + i], sd[i]);
}
__global__ void meso_scatter(const void* part, __half* __restrict__ oh) {
    int idx = blockIdx.x * blockDim.x + threadIdx.x;
    if (idx >= T_ * N_ * 64) return;
    int t = idx / (N_ * 64);
    int r = idx - t * N_ * 64;
    int n = r >> 6, c = r & 63;
    int p = (int)ld_idx(part, (size_t)t * N_ + n);
    float mean = g_comnum[(t * NCOM_ + p) * 64 + c] / (g_comden[t * NCOM_ + p] + 1e-16f);
    oh[((size_t)t * N_ + n) * 128 + 64 + c] = __float2half(mean);
}

// ===== decoder prep =====
__global__ void emb_tanh(const float* __restrict__ emb_b) {
    __shared__ float s[64];
    int tid = threadIdx.x;
    if (tid < 64) s[tid] = 0.f;
    __syncthreads();
    int idx = blockIdx.x * 256 + tid;
    if (idx < N_ * 64) {
        int n = idx >> 6, c = idx & 63;
        float v = tanhf(g_dec[n * 128 + c] + emb_b[c]);
        g_dec[n * 128 + c] = v;
        atomicAdd(&s[c], v * v);
    }
    __syncthreads();
    if (tid < 64) atomicAdd(&g_colsq[tid], s[tid]);
}
__global__ void build_P(const float* __restrict__ scal_b) {
    int n = blockIdx.x, c = threadIdx.x;
    float e = g_dec[n * 128 + c] * rsqrtf(g_colsq[c]);
    float s = sigf(g_dec[n * 128 + 64 + c] + scal_b[c]);
    float v = e * e;
#pragma unroll
    for (int o = 16; o; o >>= 1) v += __shfl_down_sync(0xffffffff, v, o);
    __shared__ float shm[2];
    if ((c & 31) == 0) shm[c >> 5] = v;
    __syncthreads();
    float sq = shm[0] + shm[1];
    size_t base = (size_t)n * 160;
    __half he = __float2half(1.41421356f * e);
    __half hs = __float2half(s);
    g_pa[base + c] = he;        g_pb[base + c] = he;
    g_pa[base + 80 + c] = hs;   g_pb[base + 80 + c] = hs;
    if (c < 16) {
        __half za = __float2half(0.f), zb = za;
        if (c == 0) { za = __float2half(sq);   zb = __float2half(-1.f); }
        if (c == 1) { za = __float2half(1.f);  zb = __float2half(-sq); }
        g_pa[base + 64 + c] = za;
        g_pb[base + 64 + c] = zb;
        g_pa[base + 144 + c] = __float2half(0.f);
        g_pb[base + 144 + c] = __float2half(0.f);
    }
}

// ===== host =====
extern "C" void kernel_launch(void* const* d_in, const int* in_sizes, int n_in,
                              void* d_out, int out_size) {
    const float* feat   = (const float*)d_in[0];
    const float* ew     = (const float*)d_in[1];
    const float* Dw     = (const float*)d_in[2];
    const float* W1     = (const float*)d_in[3];
    const float* a_s1   = (const float*)d_in[4];
    const float* a_d1   = (const float*)d_in[5];
    const float* W2     = (const float*)d_in[6];
    const float* a_s2   = (const float*)d_in[7];
    const float* a_d2   = (const float*)d_in[8];
    const float* Wx     = (const float*)d_in[9];
    const float* Wh     = (const float*)d_in[10];
    const float* b_lstm = (const float*)d_in[11];
    const float* embW   = (const float*)d_in[12];
    const float* embB   = (const float*)d_in[13];
    const float* scalW  = (const float*)d_in[14];
    const float* scalB  = (const float*)d_in[15];
    const void*  ei     = (const void*)d_in[16];
    const void*  part   = (const void*)d_in[17];
    float* out = (float*)d_out;

    cudaFuncSetAttribute(mma_gemm, cudaFuncAttributeMaxDynamicSharedMemorySize, MG_SMEM);
    cudaFuncSetAttribute(mma_gemm_128, cudaFuncAttributeMaxDynamicSharedMemorySize, MG2_SMEM);
    cudaFuncSetAttribute(mma_gemm_lstm, cudaFuncAttributeMaxDynamicSharedMemorySize, MG2_SMEM);
    cudaFuncSetAttribute(pairwise_mma, cudaFuncAttributeMaxDynamicSharedMemorySize, PW_SMEM);

    float *dec, *comnum, *comden, *colsq;
    int *cnt, *cursor;
    __half *h1h, *h2h, *f16, *hb0, *hb1, *wt, *Zx;
    cudaGetSymbolAddress((void**)&h1h, g_h1h);
    cudaGetSymbolAddress((void**)&h2h, g_h2h);
    cudaGetSymbolAddress((void**)&f16, g_f);
    cudaGetSymbolAddress((void**)&Zx, g_Zx);
    cudaGetSymbolAddress((void**)&dec, g_dec);
    cudaGetSymbolAddress((void**)&comnum, g_comnum);
    cudaGetSymbolAddress((void**)&comden, g_comden);
    cudaGetSymbolAddress((void**)&colsq, g_colsq);
    cudaGetSymbolAddress((void**)&cnt, g_cnt);
    cudaGetSymbolAddress((void**)&cursor, g_cursor);
    cudaGetSymbolAddress((void**)&hb0, g_hb0);
    cudaGetSymbolAddress((void**)&hb1, g_hb1);
    cudaGetSymbolAddress((void**)&wt, g_wt);
    __half* hbuf[2] = {hb0, hb1};

    const int MT = 79;
    const int TE = T_ * E_;
    const int TNH = T_ * N_ * H_;
    const int NS4 = T_ * N_ * 128 / 4;

    detect64_kernel<<<1, 1>>>((const int*)ei);

    // GAT layer 1 (Dn=128 -> 128x128 tile kernel)
    cvt16<<<(NS4 + 255) / 256, 256>>>((const float4*)feat, (__half2*)f16, NS4);
    wsplit16<<<(128 * 128 + 255) / 256, 256>>>(W1, wt, 128);
    mma_gemm_128<<<dim3(MT, 1, 8), 512, MG2_SMEM>>>(f16, wt, h1h, N_, 128,
                                                    (long long)N_ * 128, (long long)N_ * 128, 2);
    alpha_kernel<<<(TNH + 255) / 256, 256>>>(h1h, a_s1, a_d1, 32);

    fill_i<<<(T_ * N_ + 255) / 256, 256>>>(cnt, 0, T_ * N_);
    csr_count<<<(TE + 255) / 256, 256>>>(ei);
    csr_scan<<<T_, 1024>>>();
    fill_i<<<(T_ * N_ + 255) / 256, 256>>>(cursor, 0, T_ * N_);
    csr_scatter<<<(TE + 255) / 256, 256>>>(ei);

    gat_gather<128, 32><<<dim3(N_, T_), 128>>>(ei, ew, h1h, f16);

    // GAT layer 2 (Dn=64 -> 128x64 kernel)
    wsplit16<<<(64 * 128 + 255) / 256, 256>>>(W2, wt, 64);
    mma_gemm<<<dim3(MT, 1, 8), 256, MG_SMEM>>>(f16, wt, h2h, N_, 64,
                                               (long long)N_ * 128, (long long)N_ * 64, 2);
    alpha_kernel<<<(TNH + 255) / 256, 256>>>(h2h, a_s2, a_d2, 16);
    gat_gather<64, 16><<<dim3(N_, T_), 64>>>(ei, ew, h2h, f16);

    // meso
    fill_f<<<(T_ * NCOM_ * 64 + 255) / 256, 256>>>(comnum, 0.f, T_ * NCOM_ * 64);
    fill_f<<<(T_ * NCOM_ + 255) / 256, 256>>>(comden, 0.f, T_ * NCOM_);
    meso_acc<<<dim3((N_ + MCHUNK - 1) / MCHUNK, T_), 256>>>(part, Dw);
    meso_scatter<<<(T_ * N_ * 64 + 255) / 256, 256>>>(part, f16);

    // LSTM: Wx (permuted, fp16 Zx), then fused Wh+gates per step (128x128 tile)
    wsplit16_lstm<<<(512 * 128 + 255) / 256, 256>>>(Wx, wt);
    mma_gemm_128<<<dim3(MT, 4, 8), 512, MG2_SMEM>>>(f16, wt, Zx, N_, 512,
                                                    (long long)N_ * 128, (long long)N_ * 512, 2);
    wsplit16_lstm<<<(512 * 128 + 255) / 256, 256>>>(Wh, wt);
    lstm_pw0<<<(N_ * 128 + 255) / 256, 256>>>(b_lstm, hbuf[0]);
    for (int t = 1; t < T_; t++) {
        mma_gemm_lstm<<<dim3(MT, 4), 512, MG2_SMEM>>>(hbuf[(t - 1) & 1], wt,
                                                      Zx + (size_t)t * N_ * 512, b_lstm,
                                                      hbuf[t & 1]);
    }
    __half* hlast = hbuf[(T_ - 1) & 1];

    // decoder (Dn=128 -> 128x128 kernel)
    wsplit16<<<(64 * 128 + 255) / 256, 256>>>(embW, wt, 64);
    wsplit16<<<(64 * 128 + 255) / 256, 256>>>(scalW, wt + 64 * 128, 64);
    mma_gemm_128<<<dim3(MT, 1, 1), 512, MG2_SMEM>>>(hlast, wt, dec, N_, 128, 0, 0, 0);
    fill_f<<<1, 64>>>(colsq, 0.f, 64);
    emb_tanh<<<(N_ * 64 + 255) / 256, 256>>>(embB);
    build_P<<<N_, 64>>>(scalB);
    pairwise_mma<<<dim3(MT, MT), 512, PW_SMEM>>>(out);
}

// round 15
// speedup vs baseline: 4.8417x; 1.1584x over previous
#include <cuda_runtime.h>
#include <cuda_fp16.h>
#include <math.h>
#include <stdint.h>

#define T_ 8
#define N_ 10000
#define E_ 320000
#define H_ 4
#define NCOM_ 100

// ===== scratch =====
__device__ int   g_is64;
__device__ __align__(16) __half g_h1h[(size_t)T_ * N_ * 128];
__device__ __align__(16) __half g_h2h[(size_t)T_ * N_ * 64];
__device__ __align__(16) __half g_f[(size_t)T_ * N_ * 128];
__device__ __align__(16) float g_as[T_ * N_ * H_];
__device__ __align__(16) float g_ad[T_ * N_ * H_];
__device__ int   g_cnt[T_ * N_];
__device__ int   g_rowptr[T_ * (N_ + 1)];
__device__ int   g_cursor[T_ * N_];
__device__ int   g_sorted[T_ * E_];
__device__ float g_comnum[T_ * NCOM_ * 64];
__device__ float g_comden[T_ * NCOM_];
__device__ __align__(16) __half g_Zx[(size_t)T_ * N_ * 512];
__device__ __align__(16) float g_cbuf[N_ * 128];
__device__ __align__(16) float g_dec[N_ * 128];
__device__ float g_colsq[64];
__device__ __align__(16) __half g_hb0[N_ * 128];
__device__ __align__(16) __half g_hb1[N_ * 128];
__device__ __align__(16) __half g_pa[(size_t)N_ * 160];
__device__ __align__(16) __half g_pb[(size_t)N_ * 160];
__device__ __align__(16) __half g_wt[512 * 128];

// ===== helpers =====
__device__ __forceinline__ long long ld_idx(const void* p, size_t i) {
    if (g_is64) return ((const long long*)p)[i];
    return (long long)((const int*)p)[i];
}
__device__ __forceinline__ float sigf(float x) { return 1.f / (1.f + expf(-x)); }
__device__ __forceinline__ float sigf_fast(float x) {
    return __fdividef(1.f, 1.f + __expf(-x));
}
__device__ __forceinline__ float tanh_fast(float x) {
    float e = __expf(2.f * x);
    return 1.f - __fdividef(2.f, e + 1.f);
}
__device__ __forceinline__ float tanh_hw(float x) {
    float y;
    asm("tanh.approx.f32 %0, %1;" : "=f"(y) : "f"(x));
    return y;
}
__device__ __forceinline__ float one_p_tanh(float x) {
    float ax = fabsf(x);
    if (ax < 0.15f) {
        float x2 = x * x;
        return fmaf(x, fmaf(x2, -0.33333333f, 1.f), 1.f);
    }
    return 1.f + tanh_hw(x);
}
__device__ __forceinline__ void mma_f16(float* c, uint32_t a0, uint32_t a1, uint32_t a2,
                                        uint32_t a3, uint32_t b0, uint32_t b1) {
    asm volatile(
        "mma.sync.aligned.m16n8k16.row.col.f32.f16.f16.f32 "
        "{%0,%1,%2,%3}, {%4,%5,%6,%7}, {%8,%9}, {%0,%1,%2,%3};"
        : "+f"(c[0]), "+f"(c[1]), "+f"(c[2]), "+f"(c[3])
        : "r"(a0), "r"(a1), "r"(a2), "r"(a3), "r"(b0), "r"(b1));
}

__global__ void detect64_kernel(const int* ei32) {
    int ok = 1;
    for (int i = 1; i < 64; i += 2)
        if (ei32[i] != 0) ok = 0;
    g_is64 = ok;
}
__global__ void fill_f(float* p, float v, int n) {
    int i = blockIdx.x * blockDim.x + threadIdx.x;
    if (i < n) p[i] = v;
}
__global__ void fill_i(int* p, int v, int n) {
    int i = blockIdx.x * blockDim.x + threadIdx.x;
    if (i < n) p[i] = v;
}
__global__ void cvt16(const float4* __restrict__ x, __half2* __restrict__ y, int n4) {
    int i = blockIdx.x * blockDim.x + threadIdx.x;
    if (i >= n4) return;
    float4 v = x[i];
    y[2 * i]     = __floats2half2_rn(v.x, v.y);
    y[2 * i + 1] = __floats2half2_rn(v.z, v.w);
}
__global__ void wsplit16(const float* __restrict__ B, __half* __restrict__ bt, int Dn) {
    int idx = blockIdx.x * blockDim.x + threadIdx.x;
    if (idx >= Dn * 128) return;
    int n = idx >> 7, k = idx & 127;
    bt[idx] = __float2half(B[(size_t)k * Dn + n]);
}
// gate-interleaved permute for LSTM weights: p = (j/8)*32 + gate*8 + j%8
__global__ void wsplit16_lstm(const float* __restrict__ B, __half* __restrict__ bt) {
    int idx = blockIdx.x * blockDim.x + threadIdx.x;
    if (idx >= 512 * 128) return;
    int p = idx >> 7, k = idx & 127;
    int blk = p >> 5, r = p & 31, gate = r >> 3, jl = r & 7;
    int o = gate * 128 + blk * 8 + jl;
    bt[idx] = __float2half(B[(size_t)k * 512 + o]);
}

// ===== smem tile copy =====
template <int KU4, int SU4, int THREADS>
__device__ __forceinline__ void cp16(const uint4* __restrict__ G, char* sm, int off,
                                     int base, int Mlim, int tid, int rows) {
    int total = rows * KU4;
    for (int idx = tid; idx < total; idx += THREADS) {
        int row = idx / KU4, c = idx - row * KU4;
        uint4 v = make_uint4(0, 0, 0, 0);
        if (base + row < Mlim) v = G[(size_t)(base + row) * KU4 + c];
        ((uint4*)(sm + off))[row * SU4 + c] = v;
    }
}

// ===== fp16 MMA GEMM: CTA 128x64, 256 threads =====
#define SM_B 34816
#define MG_SMEM 52736

#define GEMM_MAINLOOP(ACC)                                                         \
    int ra0 = (wr * 32 + g) * 68;                                                  \
    int rb0 = ra0 + 8 * 68, ra1 = ra0 + 16 * 68, rb1 = ra0 + 24 * 68;              \
    _Pragma("unroll")                                                              \
    for (int kc = 0; kc < 8; kc++) {                                               \
        int ka = kc * 8 + tq;                                                      \
        uint32_t a00 = SA[ra0 + ka], a01 = SA[rb0 + ka];                           \
        uint32_t a02 = SA[ra0 + ka + 4], a03 = SA[rb0 + ka + 4];                   \
        uint32_t a10 = SA[ra1 + ka], a11 = SA[rb1 + ka];                           \
        uint32_t a12 = SA[ra1 + ka + 4], a13 = SA[rb1 + ka + 4];                   \
        _Pragma("unroll")                                                          \
        for (int nb = 0; nb < 4; nb++) {                                           \
            int nr = (wc * 32 + nb * 8 + g) * 68;                                  \
            uint32_t b0 = SB[nr + ka], b1 = SB[nr + ka + 4];                       \
            mma_f16(ACC[0][nb], a00, a01, a02, a03, b0, b1);                       \
            mma_f16(ACC[1][nb], a10, a11, a12, a13, b0, b1);                       \
        }                                                                          \
    }

// mode: 0 = store fp32, 2 = store fp16
__global__ __launch_bounds__(256, 3) void mma_gemm(
    const __half* __restrict__ A, const __half* __restrict__ B,
    void* __restrict__ Cv, int M, int Dn,
    long long sA, long long sC, int mode)
{
    extern __shared__ char sm[];
    int tid = threadIdx.x, w = tid >> 5, lane = tid & 31;
    int g = lane >> 2, tq = lane & 3;
    int wr = w >> 1, wc = w & 1;
    int m0 = blockIdx.x * 128, n0 = blockIdx.y * 64, t = blockIdx.z;
    A += (size_t)t * sA;

    cp16<16, 17, 256>((const uint4*)A, sm, 0, m0, M, tid, 128);
    cp16<16, 17, 256>((const uint4*)B, sm, SM_B, n0, Dn, tid, 64);
    __syncthreads();

    const uint32_t* SA = (const uint32_t*)sm;
    const uint32_t* SB = (const uint32_t*)(sm + SM_B);

    float acc[2][4][4];
#pragma unroll
    for (int rg = 0; rg < 2; rg++)
#pragma unroll
        for (int nb = 0; nb < 4; nb++)
#pragma unroll
            for (int q = 0; q < 4; q++) acc[rg][nb][q] = 0.f;

    GEMM_MAINLOOP(acc)

#pragma unroll
    for (int rg = 0; rg < 2; rg++) {
        int r0 = m0 + wr * 32 + rg * 16 + g, r1 = r0 + 8;
#pragma unroll
        for (int nb = 0; nb < 4; nb++) {
            int col = n0 + wc * 32 + nb * 8 + 2 * tq;
            if (mode == 2) {
                __half* Ch = (__half*)Cv + (size_t)t * sC;
                if (r0 < M)
                    *(__half2*)(Ch + (size_t)r0 * Dn + col) = __floats2half2_rn(acc[rg][nb][0], acc[rg][nb][1]);
                if (r1 < M)
                    *(__half2*)(Ch + (size_t)r1 * Dn + col) = __floats2half2_rn(acc[rg][nb][2], acc[rg][nb][3]);
            } else {
                float* C = (float*)Cv + (size_t)t * sC;
                if (r0 < M)
                    *(float2*)(C + (size_t)r0 * Dn + col) = make_float2(acc[rg][nb][0], acc[rg][nb][1]);
                if (r1 < M)
                    *(float2*)(C + (size_t)r1 * Dn + col) = make_float2(acc[rg][nb][2], acc[rg][nb][3]);
            }
        }
    }
}

// ===== fp16 MMA GEMM: CTA 128x128, 512 threads (Dn >= 128) =====
#define SM_B2 34816
#define MG2_SMEM 69632

__global__ __launch_bounds__(512, 2) void mma_gemm_128(
    const __half* __restrict__ A, const __half* __restrict__ B,
    void* __restrict__ Cv, int M, int Dn,
    long long sA, long long sC, int mode)
{
    extern __shared__ char sm[];
    int tid = threadIdx.x, w = tid >> 5, lane = tid & 31;
    int g = lane >> 2, tq = lane & 3;
    int wr = w >> 2, wc = w & 3;
    int m0 = blockIdx.x * 128, n0 = blockIdx.y * 128, t = blockIdx.z;
    A += (size_t)t * sA;

    cp16<16, 17, 512>((const uint4*)A, sm, 0, m0, M, tid, 128);
    cp16<16, 17, 512>((const uint4*)B, sm, SM_B2, n0, Dn, tid, 128);
    __syncthreads();

    const uint32_t* SA = (const uint32_t*)sm;
    const uint32_t* SB = (const uint32_t*)(sm + SM_B2);

    float acc[2][4][4];
#pragma unroll
    for (int rg = 0; rg < 2; rg++)
#pragma unroll
        for (int nb = 0; nb < 4; nb++)
#pragma unroll
            for (int q = 0; q < 4; q++) acc[rg][nb][q] = 0.f;

    GEMM_MAINLOOP(acc)

#pragma unroll
    for (int rg = 0; rg < 2; rg++) {
        int r0 = m0 + wr * 32 + rg * 16 + g, r1 = r0 + 8;
#pragma unroll
        for (int nb = 0; nb < 4; nb++) {
            int col = n0 + wc * 32 + nb * 8 + 2 * tq;
            if (mode == 2) {
                __half* Ch = (__half*)Cv + (size_t)t * sC;
                if (r0 < M)
                    *(__half2*)(Ch + (size_t)r0 * Dn + col) = __floats2half2_rn(acc[rg][nb][0], acc[rg][nb][1]);
                if (r1 < M)
                    *(__half2*)(Ch + (size_t)r1 * Dn + col) = __floats2half2_rn(acc[rg][nb][2], acc[rg][nb][3]);
            } else {
                float* C = (float*)Cv + (size_t)t * sC;
                if (r0 < M)
                    *(float2*)(C + (size_t)r0 * Dn + col) = make_float2(acc[rg][nb][0], acc[rg][nb][1]);
                if (r1 < M)
                    *(float2*)(C + (size_t)r1 * Dn + col) = make_float2(acc[rg][nb][2], acc[rg][nb][3]);
            }
        }
    }
}

// ===== fused LSTM GEMM (128x128 tile): z = Zx(fp16) + Wh*h (+b) =====
__global__ __launch_bounds__(512, 2) void mma_gemm_lstm(
    const __half* __restrict__ A, const __half* __restrict__ B,
    const __half* __restrict__ Zt, const float* __restrict__ bias,
    __half* __restrict__ hout)
{
    extern __shared__ char sm[];
    int tid = threadIdx.x, w = tid >> 5, lane = tid & 31;
    int g = lane >> 2, tq = lane & 3;
    int wr = w >> 2, wc = w & 3;
    int m0 = blockIdx.x * 128, n0 = blockIdx.y * 128;

    cp16<16, 17, 512>((const uint4*)A, sm, 0, m0, N_, tid, 128);
    cp16<16, 17, 512>((const uint4*)B, sm, SM_B2, n0, 512, tid, 128);
    __syncthreads();

    const uint32_t* SA = (const uint32_t*)sm;
    const uint32_t* SB = (const uint32_t*)(sm + SM_B2);

    float acc[2][4][4];
#pragma unroll
    for (int rg = 0; rg < 2; rg++)
#pragma unroll
        for (int nb = 0; nb < 4; nb++)
#pragma unroll
            for (int q = 0; q < 4; q++) acc[rg][nb][q] = 0.f;

    GEMM_MAINLOOP(acc)

    int pbase = n0 + wc * 32;
    int jb8 = (pbase >> 5) * 8;
    float bi[2], bf[2], bg[2], bo[2];
#pragma unroll
    for (int q01 = 0; q01 < 2; q01++) {
        int j = jb8 + 2 * tq + q01;
        bi[q01] = bias[j];
        bf[q01] = bias[128 + j];
        bg[q01] = bias[256 + j];
        bo[q01] = bias[384 + j];
    }
#pragma unroll
    for (int rg = 0; rg < 2; rg++) {
#pragma unroll
        for (int rr = 0; rr < 2; rr++) {
            int row = m0 + wr * 32 + rg * 16 + g + rr * 8;
            if (row >= N_) continue;
            int qoff = rr * 2;
            float hv[2], cv[2];
#pragma unroll
            for (int q01 = 0; q01 < 2; q01++) {
                int j = jb8 + 2 * tq + q01;
                const __half* zr = Zt + (size_t)row * 512 + pbase + 2 * tq + q01;
                float zi = acc[rg][0][qoff + q01] + __half2float(zr[0])  + bi[q01];
                float zf = acc[rg][1][qoff + q01] + __half2float(zr[8])  + bf[q01];
                float zg = acc[rg][2][qoff + q01] + __half2float(zr[16]) + bg[q01];
                float zo = acc[rg][3][qoff + q01] + __half2float(zr[24]) + bo[q01];
                float c = sigf_fast(zf) * g_cbuf[row * 128 + j] + sigf_fast(zi) * tanh_fast(zg);
                cv[q01] = c;
                hv[q01] = sigf_fast(zo) * tanh_fast(c);
            }
            int j0 = jb8 + 2 * tq;
            *(float2*)&g_cbuf[row * 128 + j0] = make_float2(cv[0], cv[1]);
            *(__half2*)&hout[row * 128 + j0] = __floats2half2_rn(hv[0], hv[1]);
        }
    }
}

// t=0 LSTM (c0 = 0)
__global__ void lstm_pw0(const float* __restrict__ b, __half* __restrict__ hout) {
    int idx = blockIdx.x * blockDim.x + threadIdx.x;
    if (idx >= N_ * 128) return;
    int n = idx >> 7, j = idx & 127;
    const __half* z = g_Zx + (size_t)n * 512 + (j >> 3) * 32 + (j & 7);
    float zi = __half2float(z[0]) + b[j];
    float zg = __half2float(z[16]) + b[256 + j];
    float zo = __half2float(z[24]) + b[384 + j];
    float c = sigf_fast(zi) * tanh_fast(zg);
    g_cbuf[idx] = c;
    hout[idx] = __float2half(sigf_fast(zo) * tanh_fast(c));
}

// ===== pairwise: CTA 128x128, 512 threads, K=160, streaming stores =====
#define PW_B 43008
#define PW_SMEM 86016

__global__ __launch_bounds__(512, 2) void pairwise_mma(float* __restrict__ out) {
    int bi = blockIdx.y, bj = blockIdx.x;
    if (bj < bi) return;
    int i0 = bi * 128, j0 = bj * 128;
    extern __shared__ char sm[];
    int tid = threadIdx.x, w = tid >> 5, lane = tid & 31;
    int g = lane >> 2, tq = lane & 3;
    int wr = w >> 2, wc = w & 3;

    cp16<20, 21, 512>((const uint4*)g_pa, sm, 0, i0, N_, tid, 128);
    cp16<20, 21, 512>((const uint4*)g_pb, sm, PW_B, j0, N_, tid, 128);
    __syncthreads();

    const uint32_t* SA = (const uint32_t*)sm;
    const uint32_t* SB = (const uint32_t*)(sm + PW_B);

    float accG[2][4][4], accS[2][4][4];
#pragma unroll
    for (int rg = 0; rg < 2; rg++)
#pragma unroll
        for (int nb = 0; nb < 4; nb++)
#pragma unroll
            for (int q = 0; q < 4; q++) { accG[rg][nb][q] = 0.f; accS[rg][nb][q] = 0.f; }

    int ra0 = (wr * 32 + g) * 84;
    int rb0 = ra0 + 8 * 84, ra1 = ra0 + 16 * 84, rb1 = ra0 + 24 * 84;
#pragma unroll
    for (int kc = 0; kc < 9; kc++) {
        int ka = kc * 8 + tq;
        uint32_t a00 = SA[ra0 + ka], a01 = SA[rb0 + ka];
        uint32_t a02 = SA[ra0 + ka + 4], a03 = SA[rb0 + ka + 4];
        uint32_t a10 = SA[ra1 + ka], a11 = SA[rb1 + ka];
        uint32_t a12 = SA[ra1 + ka + 4], a13 = SA[rb1 + ka + 4];
        float (*a0)[4] = (kc < 5) ? accG[0] : accS[0];
        float (*a1)[4] = (kc < 5) ? accG[1] : accS[1];
#pragma unroll
        for (int nb = 0; nb < 4; nb++) {
            int nr = (wc * 32 + nb * 8 + g) * 84;
            uint32_t b0 = SB[nr + ka], b1 = SB[nr + ka + 4];
            mma_f16(a0[nb], a00, a01, a02, a03, b0, b1);
            mma_f16(a1[nb], a10, a11, a12, a13, b0, b1);
        }
    }

    bool full = (i0 + 128 <= N_) && (j0 + 128 <= N_);
    float vv[2][4][4];
#pragma unroll
    for (int rg = 0; rg < 2; rg++) {
        int lr0 = wr * 32 + rg * 16 + g, lr1 = lr0 + 8;
        int ir0 = i0 + lr0, ir1 = i0 + lr1;
#pragma unroll
        for (int nb = 0; nb < 4; nb++) {
            int c0 = wc * 32 + nb * 8 + 2 * tq;
            vv[rg][nb][0] = one_p_tanh(accG[rg][nb][0] * accS[rg][nb][0]);
            vv[rg][nb][1] = one_p_tanh(accG[rg][nb][1] * accS[rg][nb][1]);
            vv[rg][nb][2] = one_p_tanh(accG[rg][nb][2] * accS[rg][nb][2]);
            vv[rg][nb][3] = one_p_tanh(accG[rg][nb][3] * accS[rg][nb][3]);
            if (full) {
                __stcs((float2*)(out + (size_t)ir0 * N_ + j0 + c0),
                       make_float2(vv[rg][nb][0], vv[rg][nb][1]));
                __stcs((float2*)(out + (size_t)ir1 * N_ + j0 + c0),
                       make_float2(vv[rg][nb][2], vv[rg][nb][3]));
            } else {
                if (ir0 < N_) {
                    if (j0 + c0 < N_)     __stcs(out + (size_t)ir0 * N_ + j0 + c0, vv[rg][nb][0]);
                    if (j0 + c0 + 1 < N_) __stcs(out + (size_t)ir0 * N_ + j0 + c0 + 1, vv[rg][nb][1]);
                }
                if (ir1 < N_) {
                    if (j0 + c0 < N_)     __stcs(out + (size_t)ir1 * N_ + j0 + c0, vv[rg][nb][2]);
                    if (j0 + c0 + 1 < N_) __stcs(out + (size_t)ir1 * N_ + j0 + c0 + 1, vv[rg][nb][3]);
                }
            }
        }
    }

    __syncthreads();
    float* vT = (float*)sm;  // [128][129]
#pragma unroll
    for (int rg = 0; rg < 2; rg++) {
        int lr0 = wr * 32 + rg * 16 + g, lr1 = lr0 + 8;
#pragma unroll
        for (int nb = 0; nb < 4; nb++) {
            int c0 = wc * 32 + nb * 8 + 2 * tq, c1 = c0 + 1;
            vT[c0 * 129 + lr0] = vv[rg][nb][0];
            vT[c1 * 129 + lr0] = vv[rg][nb][1];
            vT[c0 * 129 + lr1] = vv[rg][nb][2];
            vT[c1 * 129 + lr1] = vv[rg][nb][3];
        }
    }
    __syncthreads();
    for (int idx = tid; idx < 128 * 128; idx += 512) {
        int r2 = idx >> 7, c2 = idx & 127;
        int jj = j0 + r2, ii = i0 + c2;
        if (jj > ii && jj < N_ && ii < N_) __stcs(out + (size_t)jj * N_ + ii, vT[r2 * 129 + c2]);
    }
}

// ===== GAT kernels =====
__global__ void alpha_kernel(const __half* __restrict__ h, const float* __restrict__ a_s,
                             const float* __restrict__ a_d, int dh) {
    int idx = blockIdx.x * blockDim.x + threadIdx.x;
    if (idx >= T_ * N_ * H_) return;
    int hh = idx & 3, tn = idx >> 2;
    const __half2* hr = (const __half2*)(h + (size_t)tn * (H_ * dh) + hh * dh);
    float s = 0.f, d = 0.f;
    for (int k = 0; k < dh / 2; k++) {
        float2 v = __half22float2(hr[k]);
        s += v.x * a_s[hh * dh + 2 * k] + v.y * a_s[hh * dh + 2 * k + 1];
        d += v.x * a_d[hh * dh + 2 * k] + v.y * a_d[hh * dh + 2 * k + 1];
    }
    g_as[idx] = s; g_ad[idx] = d;
}
__global__ void csr_count(const void* ei) {
    int idx = blockIdx.x * blockDim.x + threadIdx.x;
    if (idx >= T_ * E_) return;
    int t = idx / E_, e = idx - t * E_;
    int dst = (int)ld_idx(ei, (size_t)t * 2 * E_ + E_ + e);
    atomicAdd(&g_cnt[t * N_ + dst], 1);
}
// warp-shuffle scan: 3 barriers per 1024-chunk
__global__ void csr_scan() {
    int t = blockIdx.x, tid = threadIdx.x;
    int lane = tid & 31, wid = tid >> 5;
    __shared__ int wsum[32];
    int off = 0;
    for (int chunk = 0; chunk < N_; chunk += 1024) {
        int i = chunk + tid;
        int v = (i < N_) ? g_cnt[t * N_ + i] : 0;
        int s = v;
#pragma unroll
        for (int o = 1; o < 32; o <<= 1) {
            int x = __shfl_up_sync(0xffffffffu, s, o);
            if (lane >= o) s += x;
        }
        if (lane == 31) wsum[wid] = s;
        __syncthreads();
        if (wid == 0) {
            int ws = wsum[lane];
#pragma unroll
            for (int o = 1; o < 32; o <<= 1) {
                int x = __shfl_up_sync(0xffffffffu, ws, o);
                if (lane >= o) ws += x;
            }
            wsum[lane] = ws;
        }
        __syncthreads();
        int base = off + (wid > 0 ? wsum[wid - 1] : 0);
        if (i < N_) g_rowptr[t * (N_ + 1) + i] = base + s - v;
        off += wsum[31];
        __syncthreads();
    }
    if (tid == 0) g_rowptr[t * (N_ + 1) + N_] = off;
}
__global__ void csr_scatter(const void* ei) {
    int idx = blockIdx.x * blockDim.x + threadIdx.x;
    if (idx >= T_ * E_) return;
    int t = idx / E_, e = idx - t * E_;
    int dst = (int)ld_idx(ei, (size_t)t * 2 * E_ + E_ + e);
    int pos = atomicAdd(&g_cursor[t * N_ + dst], 1);
    g_sorted[t * E_ + g_rowptr[t * (N_ + 1) + dst] + pos] = e;
}

// fused gather: THREADS threads, each owns 2 adjacent columns (half2).
// COLS = 2*THREADS source columns; head = col/DHEAD.
template <int THREADS, int COLS, int DHEAD>
__global__ void gat_gather(const void* ei, const float* __restrict__ ew,
                           const __half* __restrict__ hsrc, __half* __restrict__ oh) {
    int t = blockIdx.y, n = blockIdx.x, tid = threadIdx.x;
    int start = g_rowptr[t * (N_ + 1) + n];
    int end = g_rowptr[t * (N_ + 1) + n + 1];
    int head = (2 * tid) / DHEAD;
    __shared__ int s_src[64];
    __shared__ float s_ex[64][4];
    float4 ad4 = *(const float4*)&g_ad[(t * N_ + n) * 4];
    float accx = 0.f, accy = 0.f, den = 0.f;
    for (int base = start; base < end; base += 64) {
        int cnt = min(64, end - base);
        if (THREADS == 32) __syncwarp(); else __syncthreads();
        for (int i = tid; i < cnt; i += THREADS) {
            int eid = g_sorted[t * E_ + base + i];
            int src = (int)ld_idx(ei, (size_t)t * 2 * E_ + eid);
            s_src[i] = src;
            float4 s4 = *(const float4*)&g_as[(t * N_ + src) * 4];
            float wv = ew[(size_t)t * E_ + eid];
            float e0 = s4.x + ad4.x; e0 = e0 > 0.f ? e0 : 0.2f * e0;
            float e1 = s4.y + ad4.y; e1 = e1 > 0.f ? e1 : 0.2f * e1;
            float e2 = s4.z + ad4.z; e2 = e2 > 0.f ? e2 : 0.2f * e2;
            float e3 = s4.w + ad4.w; e3 = e3 > 0.f ? e3 : 0.2f * e3;
            s_ex[i][0] = __expf(e0) * wv;
            s_ex[i][1] = __expf(e1) * wv;
            s_ex[i][2] = __expf(e2) * wv;
            s_ex[i][3] = __expf(e3) * wv;
        }
        if (THREADS == 32) __syncwarp(); else __syncthreads();
#pragma unroll 8
        for (int i = 0; i < cnt; i++) {
            float exv = s_ex[i][head];
            den += exv;
            float2 hv = __half22float2(
                *(const __half2*)(hsrc + ((size_t)t * N_ + s_src[i]) * COLS + 2 * tid));
            accx = fmaf(exv, hv.x, accx);
            accy = fmaf(exv, hv.y, accy);
        }
    }
    float inv = __fdividef(1.f, den + 1e-16f);
    float vx = accx * inv, vy = accy * inv;
    vx = vx > 0.f ? vx : __expf(vx) - 1.f;
    vy = vy > 0.f ? vy : __expf(vy) - 1.f;
    *(__half2*)(oh + ((size_t)t * N_ + n) * 128 + 2 * tid) = __floats2half2_rn(vx, vy);
}

// ===== meso =====
#define MCHUNK 500
__global__ void meso_acc(const void* part, const float* __restrict__ Dw) {
    int t = blockIdx.y, c0 = blockIdx.x * MCHUNK, tid = threadIdx.x;
    __shared__ float sn[NCOM_ * 64];
    __shared__ float sd[NCOM_];
    __shared__ int sp[MCHUNK];
    __shared__ float sD[MCHUNK];
    for (int i = tid; i < NCOM_ * 64; i += blockDim.x) sn[i] = 0.f;
    for (int i = tid; i < NCOM_; i += blockDim.x) sd[i] = 0.f;
    int nmax = min(MCHUNK, N_ - c0);
    for (int i = tid; i < nmax; i += blockDim.x) {
        sp[i] = (int)ld_idx(part, (size_t)t * N_ + c0 + i);
        sD[i] = Dw[(size_t)t * N_ + c0 + i];
    }
    __syncthreads();
    for (int idx = tid; idx < nmax * 64; idx += blockDim.x) {
        int nl = idx >> 6, c = idx & 63;
        float g = __half2float(g_f[((size_t)t * N_ + c0 + nl) * 128 + c]);
        atomicAdd(&sn[sp[nl] * 64 + c], sD[nl] * g);
        if (c == 0) atomicAdd(&sd[sp[nl]], sD[nl]);
    }
    __syncthreads();
    for (int i = tid; i < NCOM_ * 64; i += blockDim.x)
        atomicAdd(&g_comnum[t * NCOM_ * 64 + i], sn[i]);
    for (int i = tid; i < NCOM_; i += blockDim.x)
        atomicAdd(&g_comden[t * NCOM_ + i], sd[i]);
}
__global__ void meso_scatter(const void* part, __half* __restrict__ oh) {
    int idx = blockIdx.x * blockDim.x + threadIdx.x;
    if (idx >= T_ * N_ * 64) return;
    int t = idx / (N_ * 64);
    int r = idx - t * N_ * 64;
    int n = r >> 6, c = r & 63;
    int p = (int)ld_idx(part, (size_t)t * N_ + n);
    float mean = g_comnum[(t * NCOM_ + p) * 64 + c] / (g_comden[t * NCOM_ + p] + 1e-16f);
    oh[((size_t)t * N_ + n) * 128 + 64 + c] = __float2half(mean);
}

// ===== decoder prep =====
__global__ void emb_tanh(const float* __restrict__ emb_b) {
    __shared__ float s[64];
    int tid = threadIdx.x;
    if (tid < 64) s[tid] = 0.f;
    __syncthreads();
    int idx = blockIdx.x * 256 + tid;
    if (idx < N_ * 64) {
        int n = idx >> 6, c = idx & 63;
        float v = tanhf(g_dec[n * 128 + c] + emb_b[c]);
        g_dec[n * 128 + c] = v;
        atomicAdd(&s[c], v * v);
    }
    __syncthreads();
    if (tid < 64) atomicAdd(&g_colsq[tid], s[tid]);
}
__global__ void build_P(const float* __restrict__ scal_b) {
    int n = blockIdx.x, c = threadIdx.x;
    float e = g_dec[n * 128 + c] * rsqrtf(g_colsq[c]);
    float s = sigf(g_dec[n * 128 + 64 + c] + scal_b[c]);
    float v = e * e;
#pragma unroll
    for (int o = 16; o; o >>= 1) v += __shfl_down_sync(0xffffffff, v, o);
    __shared__ float shm[2];
    if ((c & 31) == 0) shm[c >> 5] = v;
    __syncthreads();
    float sq = shm[0] + shm[1];
    size_t base = (size_t)n * 160;
    __half he = __float2half(1.41421356f * e);
    __half hs = __float2half(s);
    g_pa[base + c] = he;        g_pb[base + c] = he;
    g_pa[base + 80 + c] = hs;   g_pb[base + 80 + c] = hs;
    if (c < 16) {
        __half za = __float2half(0.f), zb = za;
        if (c == 0) { za = __float2half(sq);   zb = __float2half(-1.f); }
        if (c == 1) { za = __float2half(1.f);  zb = __float2half(-sq); }
        g_pa[base + 64 + c] = za;
        g_pb[base + 64 + c] = zb;
        g_pa[base + 144 + c] = __float2half(0.f);
        g_pb[base + 144 + c] = __float2half(0.f);
    }
}

// ===== host =====
extern "C" void kernel_launch(void* const* d_in, const int* in_sizes, int n_in,
                              void* d_out, int out_size) {
    const float* feat   = (const float*)d_in[0];
    const float* ew     = (const float*)d_in[1];
    const float* Dw     = (const float*)d_in[2];
    const float* W1     = (const float*)d_in[3];
    const float* a_s1   = (const float*)d_in[4];
    const float* a_d1   = (const float*)d_in[5];
    const float* W2     = (const float*)d_in[6];
    const float* a_s2   = (const float*)d_in[7];
    const float* a_d2   = (const float*)d_in[8];
    const float* Wx     = (const float*)d_in[9];
    const float* Wh     = (const float*)d_in[10];
    const float* b_lstm = (const float*)d_in[11];
    const float* embW   = (const float*)d_in[12];
    const float* embB   = (const float*)d_in[13];
    const float* scalW  = (const float*)d_in[14];
    const float* scalB  = (const float*)d_in[15];
    const void*  ei     = (const void*)d_in[16];
    const void*  part   = (const void*)d_in[17];
    float* out = (float*)d_out;

    cudaFuncSetAttribute(mma_gemm, cudaFuncAttributeMaxDynamicSharedMemorySize, MG_SMEM);
    cudaFuncSetAttribute(mma_gemm_128, cudaFuncAttributeMaxDynamicSharedMemorySize, MG2_SMEM);
    cudaFuncSetAttribute(mma_gemm_lstm, cudaFuncAttributeMaxDynamicSharedMemorySize, MG2_SMEM);
    cudaFuncSetAttribute(pairwise_mma, cudaFuncAttributeMaxDynamicSharedMemorySize, PW_SMEM);

    float *dec, *comnum, *comden, *colsq;
    int *cnt, *cursor;
    __half *h1h, *h2h, *f16, *hb0, *hb1, *wt, *Zx;
    cudaGetSymbolAddress((void**)&h1h, g_h1h);
    cudaGetSymbolAddress((void**)&h2h, g_h2h);
    cudaGetSymbolAddress((void**)&f16, g_f);
    cudaGetSymbolAddress((void**)&Zx, g_Zx);
    cudaGetSymbolAddress((void**)&dec, g_dec);
    cudaGetSymbolAddress((void**)&comnum, g_comnum);
    cudaGetSymbolAddress((void**)&comden, g_comden);
    cudaGetSymbolAddress((void**)&colsq, g_colsq);
    cudaGetSymbolAddress((void**)&cnt, g_cnt);
    cudaGetSymbolAddress((void**)&cursor, g_cursor);
    cudaGetSymbolAddress((void**)&hb0, g_hb0);
    cudaGetSymbolAddress((void**)&hb1, g_hb1);
    cudaGetSymbolAddress((void**)&wt, g_wt);
    __half* hbuf[2] = {hb0, hb1};

    const int MT = 79;
    const int TE = T_ * E_;
    const int TNH = T_ * N_ * H_;
    const int NS4 = T_ * N_ * 128 / 4;

    detect64_kernel<<<1, 1>>>((const int*)ei);

    // GAT layer 1
    cvt16<<<(NS4 + 255) / 256, 256>>>((const float4*)feat, (__half2*)f16, NS4);
    wsplit16<<<(128 * 128 + 255) / 256, 256>>>(W1, wt, 128);
    mma_gemm_128<<<dim3(MT, 1, 8), 512, MG2_SMEM>>>(f16, wt, h1h, N_, 128,
                                                    (long long)N_ * 128, (long long)N_ * 128, 2);
    alpha_kernel<<<(TNH + 255) / 256, 256>>>(h1h, a_s1, a_d1, 32);

    fill_i<<<(T_ * N_ + 255) / 256, 256>>>(cnt, 0, T_ * N_);
    csr_count<<<(TE + 255) / 256, 256>>>(ei);
    csr_scan<<<T_, 1024>>>();
    fill_i<<<(T_ * N_ + 255) / 256, 256>>>(cursor, 0, T_ * N_);
    csr_scatter<<<(TE + 255) / 256, 256>>>(ei);

    gat_gather<64, 128, 32><<<dim3(N_, T_), 64>>>(ei, ew, h1h, f16);

    // GAT layer 2
    wsplit16<<<(64 * 128 + 255) / 256, 256>>>(W2, wt, 64);
    mma_gemm<<<dim3(MT, 1, 8), 256, MG_SMEM>>>(f16, wt, h2h, N_, 64,
                                               (long long)N_ * 128, (long long)N_ * 64, 2);
    alpha_kernel<<<(TNH + 255) / 256, 256>>>(h2h, a_s2, a_d2, 16);
    gat_gather<32, 64, 16><<<dim3(N_, T_), 32>>>(ei, ew, h2h, f16);

    // meso
    fill_f<<<(T_ * NCOM_ * 64 + 255) / 256, 256>>>(comnum, 0.f, T_ * NCOM_ * 64);
    fill_f<<<(T_ * NCOM_ + 255) / 256, 256>>>(comden, 0.f, T_ * NCOM_);
    meso_acc<<<dim3((N_ + MCHUNK - 1) / MCHUNK, T_), 256>>>(part, Dw);
    meso_scatter<<<(T_ * N_ * 64 + 255) / 256, 256>>>(part, f16);

    // LSTM
    wsplit16_lstm<<<(512 * 128 + 255) / 256, 256>>>(Wx, wt);
    mma_gemm_128<<<dim3(MT, 4, 8), 512, MG2_SMEM>>>(f16, wt, Zx, N_, 512,
                                                    (long long)N_ * 128, (long long)N_ * 512, 2);
    wsplit16_lstm<<<(512 * 128 + 255) / 256, 256>>>(Wh, wt);
    lstm_pw0<<<(N_ * 128 + 255) / 256, 256>>>(b_lstm, hbuf[0]);
    for (int t = 1; t < T_; t++) {
        mma_gemm_lstm<<<dim3(MT, 4), 512, MG2_SMEM>>>(hbuf[(t - 1) & 1], wt,
                                                      Zx + (size_t)t * N_ * 512, b_lstm,
                                                      hbuf[t & 1]);
    }
    __half* hlast = hbuf[(T_ - 1) & 1];

    // decoder
    wsplit16<<<(64 * 128 + 255) / 256, 256>>>(embW, wt, 64);
    wsplit16<<<(64 * 128 + 255) / 256, 256>>>(scalW, wt + 64 * 128, 64);
    mma_gemm_128<<<dim3(MT, 1, 1), 512, MG2_SMEM>>>(hlast, wt, dec, N_, 128, 0, 0, 0);
    fill_f<<<1, 64>>>(colsq, 0.f, 64);
    emb_tanh<<<(N_ * 64 + 255) / 256, 256>>>(embB);
    build_P<<<N_, 64>>>(scalB);
    pairwise_mma<<<dim3(MT, MT), 512, PW_SMEM>>>(out);
}